// round 1
// baseline (speedup 1.0000x reference)
#include <cuda_runtime.h>
#include <math.h>

// Problem constants
#define SEQ   4096
#define EMBD  2048
#define NB    4
#define NHEAD 16
#define DHEAD 128
#define NSEG  8
#define SEGL  512
#define NBH   (NB * NHEAD)          // 64
#define MTOK  (NB * SEQ)            // 16384
#define TOTAL ((size_t)MTOK * EMBD) // 33554432

// -------- device scratch (allocation-free rule: static __device__ arrays) ----
__device__ float g_q[TOTAL];
__device__ float g_k[TOTAL];
__device__ float g_v[TOTAL];
__device__ float g_attn[TOTAL];
__device__ float g_scores[(size_t)NBH * SEGL * SEGL]; // 64*512*512
__device__ float g_mem[(size_t)NBH * DHEAD * DHEAD];  // 64*128*128
__device__ float g_Z[NBH * DHEAD];                    // 64*128

__device__ __forceinline__ float elu1(float x) {
    return (x > 0.f) ? (x + 1.f) : expf(x);
}

// ============================================================================
// K1: C[M,N] = A[M,K] @ B[K,N] + bias[N]   (128x128 tile, 8x8 per thread)
// ============================================================================
__global__ __launch_bounds__(256) void gemm_bias_k(
    const float* __restrict__ A, const float* __restrict__ B,
    const float* __restrict__ bias, float* __restrict__ C,
    int M, int N, int K)
{
    __shared__ float As[16][128];
    __shared__ float Bs[16][128];
    int tid = threadIdx.x;
    int tx = tid & 15, ty = tid >> 4;
    int bcol = blockIdx.x * 128;
    int brow = blockIdx.y * 128;
    float acc[8][8];
#pragma unroll
    for (int i = 0; i < 8; i++)
#pragma unroll
        for (int j = 0; j < 8; j++) acc[i][j] = 0.f;

    int ar = tid >> 2;   // 0..63
    int ac4 = tid & 3;   // 0..3
    int br = tid >> 5;   // 0..7
    int bc4 = tid & 31;  // 0..31

    for (int k0 = 0; k0 < K; k0 += 16) {
#pragma unroll
        for (int i = 0; i < 2; i++) {
            int r = ar + i * 64;
            float4 av = *(const float4*)&A[(size_t)(brow + r) * K + k0 + ac4 * 4];
            As[ac4 * 4 + 0][r] = av.x; As[ac4 * 4 + 1][r] = av.y;
            As[ac4 * 4 + 2][r] = av.z; As[ac4 * 4 + 3][r] = av.w;
        }
#pragma unroll
        for (int i = 0; i < 2; i++) {
            int r = br + i * 8;
            float4 bv = *(const float4*)&B[(size_t)(k0 + r) * N + bcol + bc4 * 4];
            *(float4*)&Bs[r][bc4 * 4] = bv;
        }
        __syncthreads();
#pragma unroll
        for (int kk = 0; kk < 16; kk++) {
            float ra[8], rb[8];
#pragma unroll
            for (int i = 0; i < 8; i++) ra[i] = As[kk][ty * 8 + i];
#pragma unroll
            for (int j = 0; j < 8; j++) rb[j] = Bs[kk][tx * 8 + j];
#pragma unroll
            for (int i = 0; i < 8; i++)
#pragma unroll
                for (int j = 0; j < 8; j++) acc[i][j] += ra[i] * rb[j];
        }
        __syncthreads();
    }
#pragma unroll
    for (int i = 0; i < 8; i++) {
        int row = brow + ty * 8 + i;
#pragma unroll
        for (int j = 0; j < 8; j += 4) {
            int col = bcol + tx * 8 + j;
            float4 o;
            o.x = acc[i][j + 0] + bias[col + 0];
            o.y = acc[i][j + 1] + bias[col + 1];
            o.z = acc[i][j + 2] + bias[col + 2];
            o.w = acc[i][j + 3] + bias[col + 3];
            *(float4*)&C[(size_t)row * N + col] = o;
        }
    }
}

// ============================================================================
// K2: RoPE over full EMB dim, applied to q and k in (B,T,C) layout
// ============================================================================
__global__ __launch_bounds__(256) void rope_k(float* __restrict__ q, float* __restrict__ k)
{
    size_t idx = (size_t)blockIdx.x * 256 + threadIdx.x; // over 16384*1024 pairs
    int rr = (int)(idx >> 10);      // global row 0..16383
    int i = (int)(idx & 1023);      // pair index 0..1023
    int t = rr & (SEQ - 1);         // position within sequence
    float inv = powf(10000.0f, -(float)(2 * i) * (1.0f / 2048.0f));
    float ang = (float)t * inv;
    float c = cosf(ang), s = sinf(ang);
    size_t base = (size_t)rr * EMBD + 2 * i;
    float a = q[base], b = q[base + 1];
    q[base] = a * c - b * s;
    q[base + 1] = a * s + b * c;
    a = k[base]; b = k[base + 1];
    k[base] = a * c - b * s;
    k[base + 1] = a * s + b * c;
}

// ============================================================================
// K3: scores[bh,l,m] = scale * q_seg[l,:] . k_seg[m,:]   (64x64 tile, 4x4/thr)
// ============================================================================
__global__ __launch_bounds__(256) void scores_k(
    const float* __restrict__ qb, const float* __restrict__ kb,
    float* __restrict__ S, int s)
{
    const float scale = 0.08838834764831845f; // 1/sqrt(128)
    int bh = blockIdx.z;
    int m0 = blockIdx.x * 64;
    int l0 = blockIdx.y * 64;
    size_t segbase = ((size_t)(bh * NSEG + s)) << 16;
    const float* qseg = qb + segbase;
    const float* kseg = kb + segbase;

    __shared__ float As[16][64];
    __shared__ float Bs[16][64];
    int tid = threadIdx.x;
    int tx = tid & 15, ty = tid >> 4;
    int r = tid >> 2, c4 = tid & 3;

    float acc[4][4];
#pragma unroll
    for (int i = 0; i < 4; i++)
#pragma unroll
        for (int j = 0; j < 4; j++) acc[i][j] = 0.f;

    for (int k0 = 0; k0 < DHEAD; k0 += 16) {
        float4 av = *(const float4*)&qseg[(size_t)(l0 + r) * DHEAD + k0 + c4 * 4];
        As[c4 * 4 + 0][r] = av.x; As[c4 * 4 + 1][r] = av.y;
        As[c4 * 4 + 2][r] = av.z; As[c4 * 4 + 3][r] = av.w;
        float4 bv = *(const float4*)&kseg[(size_t)(m0 + r) * DHEAD + k0 + c4 * 4];
        Bs[c4 * 4 + 0][r] = bv.x; Bs[c4 * 4 + 1][r] = bv.y;
        Bs[c4 * 4 + 2][r] = bv.z; Bs[c4 * 4 + 3][r] = bv.w;
        __syncthreads();
#pragma unroll
        for (int kk = 0; kk < 16; kk++) {
            float ra[4], rb[4];
#pragma unroll
            for (int i = 0; i < 4; i++) ra[i] = As[kk][ty * 4 + i];
#pragma unroll
            for (int j = 0; j < 4; j++) rb[j] = Bs[kk][tx * 4 + j];
#pragma unroll
            for (int i = 0; i < 4; i++)
#pragma unroll
                for (int j = 0; j < 4; j++) acc[i][j] += ra[i] * rb[j];
        }
        __syncthreads();
    }
    float* Sb = S + (size_t)bh * SEGL * SEGL;
#pragma unroll
    for (int i = 0; i < 4; i++)
#pragma unroll
        for (int j = 0; j < 4; j++)
            Sb[(size_t)(l0 + ty * 4 + i) * SEGL + m0 + tx * 4 + j] = acc[i][j] * scale;
}

// ============================================================================
// K4: row softmax in place on scores (one warp per row of 512)
// ============================================================================
__global__ __launch_bounds__(256) void softmax_k(float* __restrict__ S)
{
    int bh = blockIdx.y;
    int row = blockIdx.x * 8 + (threadIdx.x >> 5);
    int lane = threadIdx.x & 31;
    float* r = S + ((size_t)bh * SEGL + row) * SEGL;
    float vals[16];
    float mx = -1e30f;
#pragma unroll
    for (int i = 0; i < 16; i++) {
        vals[i] = r[lane + 32 * i];
        mx = fmaxf(mx, vals[i]);
    }
#pragma unroll
    for (int o = 16; o > 0; o >>= 1) mx = fmaxf(mx, __shfl_xor_sync(0xffffffffu, mx, o));
    float sum = 0.f;
#pragma unroll
    for (int i = 0; i < 16; i++) {
        vals[i] = expf(vals[i] - mx);
        sum += vals[i];
    }
#pragma unroll
    for (int o = 16; o > 0; o >>= 1) sum += __shfl_xor_sync(0xffffffffu, sum, o);
    float inv = 1.0f / sum;
#pragma unroll
    for (int i = 0; i < 16; i++) r[lane + 32 * i] = vals[i] * inv;
}

// ============================================================================
// K5: attn = g * (sq@mem)/(rowsum(sq)*Z + 1e-6) + (1-g) * P@v
//     block = (bh, 64-row l-tile), output 64x128, 4x8 per thread
// ============================================================================
__global__ __launch_bounds__(256) void attn_combine_k(
    const float* __restrict__ qb, const float* __restrict__ vb,
    const float* __restrict__ P, const float* __restrict__ mem,
    const float* __restrict__ Z, const float* __restrict__ beta,
    float* __restrict__ attnb, int s)
{
    int bh = blockIdx.y;
    int l0 = blockIdx.x * 64;
    size_t segbase = ((size_t)(bh * NSEG + s)) << 16;
    const float* qseg = qb + segbase;
    const float* vseg = vb + segbase;
    const float* Pseg = P + (size_t)bh * SEGL * SEGL;
    const float* memb = mem + (size_t)bh * DHEAD * DHEAD;
    const float* Zb = Z + bh * DHEAD;
    float g = 1.0f / (1.0f + expf(-beta[0]));

    __shared__ float As[16][64];
    __shared__ float Bs[16][128];
    __shared__ float rowsum[64];
    __shared__ float Zs[128];

    int tid = threadIdx.x;
    int tx = tid & 15, ty = tid >> 4;

    // rowsum of sq over d (4 threads per row, 32 elems each)
    {
        int r = tid >> 2, qd = (tid & 3) * 32;
        float sm = 0.f;
#pragma unroll 8
        for (int d = 0; d < 32; d++)
            sm += elu1(qseg[(size_t)(l0 + r) * DHEAD + qd + d]);
        sm += __shfl_xor_sync(0xffffffffu, sm, 1);
        sm += __shfl_xor_sync(0xffffffffu, sm, 2);
        if ((tid & 3) == 0) rowsum[r] = sm;
    }
    if (tid < 128) Zs[tid] = Zb[tid];

    int ar = tid >> 2, ac4 = tid & 3;
    int br = tid >> 5, bc4 = tid & 31;

    // GEMM1: sq @ mem  (K = 128)
    float acc[4][8];
#pragma unroll
    for (int i = 0; i < 4; i++)
#pragma unroll
        for (int j = 0; j < 8; j++) acc[i][j] = 0.f;

    for (int k0 = 0; k0 < DHEAD; k0 += 16) {
        float4 av = *(const float4*)&qseg[(size_t)(l0 + ar) * DHEAD + k0 + ac4 * 4];
        As[ac4 * 4 + 0][ar] = elu1(av.x); As[ac4 * 4 + 1][ar] = elu1(av.y);
        As[ac4 * 4 + 2][ar] = elu1(av.z); As[ac4 * 4 + 3][ar] = elu1(av.w);
#pragma unroll
        for (int i = 0; i < 2; i++) {
            float4 bv = *(const float4*)&memb[(size_t)(k0 + br + i * 8) * DHEAD + bc4 * 4];
            *(float4*)&Bs[br + i * 8][bc4 * 4] = bv;
        }
        __syncthreads();
#pragma unroll
        for (int kk = 0; kk < 16; kk++) {
            float ra[4], rb[8];
#pragma unroll
            for (int i = 0; i < 4; i++) ra[i] = As[kk][ty * 4 + i];
#pragma unroll
            for (int j = 0; j < 8; j++) rb[j] = Bs[kk][tx * 8 + j];
#pragma unroll
            for (int i = 0; i < 4; i++)
#pragma unroll
                for (int j = 0; j < 8; j++) acc[i][j] += ra[i] * rb[j];
        }
        __syncthreads();
    }

    float outv[4][8];
#pragma unroll
    for (int i = 0; i < 4; i++)
#pragma unroll
        for (int j = 0; j < 8; j++)
            outv[i][j] = g * acc[i][j] / (rowsum[ty * 4 + i] * Zs[tx * 8 + j] + 1e-6f);

    // GEMM2: P @ v  (K = 512)
#pragma unroll
    for (int i = 0; i < 4; i++)
#pragma unroll
        for (int j = 0; j < 8; j++) acc[i][j] = 0.f;

    for (int m0 = 0; m0 < SEGL; m0 += 16) {
        float4 pv = *(const float4*)&Pseg[(size_t)(l0 + ar) * SEGL + m0 + ac4 * 4];
        As[ac4 * 4 + 0][ar] = pv.x; As[ac4 * 4 + 1][ar] = pv.y;
        As[ac4 * 4 + 2][ar] = pv.z; As[ac4 * 4 + 3][ar] = pv.w;
#pragma unroll
        for (int i = 0; i < 2; i++) {
            float4 vv = *(const float4*)&vseg[(size_t)(m0 + br + i * 8) * DHEAD + bc4 * 4];
            *(float4*)&Bs[br + i * 8][bc4 * 4] = vv;
        }
        __syncthreads();
#pragma unroll
        for (int kk = 0; kk < 16; kk++) {
            float ra[4], rb[8];
#pragma unroll
            for (int i = 0; i < 4; i++) ra[i] = As[kk][ty * 4 + i];
#pragma unroll
            for (int j = 0; j < 8; j++) rb[j] = Bs[kk][tx * 8 + j];
#pragma unroll
            for (int i = 0; i < 4; i++)
#pragma unroll
                for (int j = 0; j < 8; j++) acc[i][j] += ra[i] * rb[j];
        }
        __syncthreads();
    }

    float gm1 = 1.0f - g;
#pragma unroll
    for (int i = 0; i < 4; i++)
#pragma unroll
        for (int j = 0; j < 8; j++)
            attnb[segbase + (size_t)(l0 + ty * 4 + i) * DHEAD + tx * 8 + j] =
                outv[i][j] + gm1 * acc[i][j];
}

// ============================================================================
// K6: mem[d,e] += sum_l sk[l,d]*v[l,e];  Z[d] += sum_l sk[l,d]
//     one block per bh, output 128x128, 8x8 per thread
// ============================================================================
__global__ __launch_bounds__(256) void mem_update_k(
    const float* __restrict__ kb, const float* __restrict__ vb,
    float* __restrict__ mem, float* __restrict__ Z, int s)
{
    int bh = blockIdx.x;
    size_t segbase = ((size_t)(bh * NSEG + s)) << 16;
    const float* kseg = kb + segbase;
    const float* vseg = vb + segbase;

    __shared__ float As[16][128]; // sk[l', d]
    __shared__ float Bs[16][128]; // v[l', e]
    int tid = threadIdx.x;
    int tx = tid & 15, ty = tid >> 4;
    int br = tid >> 5, bc4 = tid & 31;

    float acc[8][8];
    float zacc[8];
#pragma unroll
    for (int i = 0; i < 8; i++) {
        zacc[i] = 0.f;
#pragma unroll
        for (int j = 0; j < 8; j++) acc[i][j] = 0.f;
    }

    for (int l0 = 0; l0 < SEGL; l0 += 16) {
#pragma unroll
        for (int i = 0; i < 2; i++) {
            int r = br + i * 8;
            float4 kv = *(const float4*)&kseg[(size_t)(l0 + r) * DHEAD + bc4 * 4];
            As[r][bc4 * 4 + 0] = elu1(kv.x); As[r][bc4 * 4 + 1] = elu1(kv.y);
            As[r][bc4 * 4 + 2] = elu1(kv.z); As[r][bc4 * 4 + 3] = elu1(kv.w);
            float4 vv = *(const float4*)&vseg[(size_t)(l0 + r) * DHEAD + bc4 * 4];
            *(float4*)&Bs[r][bc4 * 4] = vv;
        }
        __syncthreads();
#pragma unroll
        for (int kk = 0; kk < 16; kk++) {
            float ra[8], rb[8];
#pragma unroll
            for (int i = 0; i < 8; i++) ra[i] = As[kk][ty * 8 + i];
#pragma unroll
            for (int j = 0; j < 8; j++) rb[j] = Bs[kk][tx * 8 + j];
#pragma unroll
            for (int i = 0; i < 8; i++)
#pragma unroll
                for (int j = 0; j < 8; j++) acc[i][j] += ra[i] * rb[j];
            if (tx == 0) {
#pragma unroll
                for (int i = 0; i < 8; i++) zacc[i] += ra[i];
            }
        }
        __syncthreads();
    }
    float* memb = mem + (size_t)bh * DHEAD * DHEAD;
#pragma unroll
    for (int i = 0; i < 8; i++)
#pragma unroll
        for (int j = 0; j < 8; j++)
            memb[(size_t)(ty * 8 + i) * DHEAD + tx * 8 + j] += acc[i][j];
    if (tx == 0) {
#pragma unroll
        for (int i = 0; i < 8; i++) Z[bh * DHEAD + ty * 8 + i] += zacc[i];
    }
}

// ============================================================================
// Host launch
// ============================================================================
extern "C" void kernel_launch(void* const* d_in, const int* in_sizes, int n_in,
                              void* d_out, int out_size)
{
    (void)in_sizes; (void)n_in; (void)out_size;
    const float* x    = (const float*)d_in[0];
    const float* Wq   = (const float*)d_in[1];
    const float* bq   = (const float*)d_in[2];
    const float* Wk   = (const float*)d_in[3];
    const float* bk   = (const float*)d_in[4];
    const float* Wv   = (const float*)d_in[5];
    const float* bv   = (const float*)d_in[6];
    const float* Wo   = (const float*)d_in[7];
    const float* bo   = (const float*)d_in[8];
    const float* beta = (const float*)d_in[9];
    float* out = (float*)d_out;

    static float *pq = nullptr, *pk = nullptr, *pv = nullptr, *pattn = nullptr,
                 *pscores = nullptr, *pmem = nullptr, *pZ = nullptr;
    if (!pq) {
        cudaGetSymbolAddress((void**)&pq, g_q);
        cudaGetSymbolAddress((void**)&pk, g_k);
        cudaGetSymbolAddress((void**)&pv, g_v);
        cudaGetSymbolAddress((void**)&pattn, g_attn);
        cudaGetSymbolAddress((void**)&pscores, g_scores);
        cudaGetSymbolAddress((void**)&pmem, g_mem);
        cudaGetSymbolAddress((void**)&pZ, g_Z);
    }

    // carry state must be zero at the start of every call (graph replays!)
    cudaMemsetAsync(pmem, 0, (size_t)NBH * DHEAD * DHEAD * sizeof(float), 0);
    cudaMemsetAsync(pZ, 0, (size_t)NBH * DHEAD * sizeof(float), 0);

    dim3 ggrid(EMBD / 128, MTOK / 128);
    gemm_bias_k<<<ggrid, 256>>>(x, Wq, bq, pq, MTOK, EMBD, EMBD);
    gemm_bias_k<<<ggrid, 256>>>(x, Wk, bk, pk, MTOK, EMBD, EMBD);
    gemm_bias_k<<<ggrid, 256>>>(x, Wv, bv, pv, MTOK, EMBD, EMBD);

    rope_k<<<(MTOK * (EMBD / 2)) / 256, 256>>>(pq, pk);

    for (int s = 0; s < NSEG; s++) {
        scores_k<<<dim3(SEGL / 64, SEGL / 64, NBH), 256>>>(pq, pk, pscores, s);
        softmax_k<<<dim3(SEGL / 8, NBH), 256>>>(pscores);
        attn_combine_k<<<dim3(SEGL / 64, NBH), 256>>>(pq, pv, pscores, pmem, pZ,
                                                      beta, pattn, s);
        mem_update_k<<<NBH, 256>>>(pk, pv, pmem, pZ, s);
    }

    gemm_bias_k<<<ggrid, 256>>>(pattn, Wo, bo, out, MTOK, EMBD, EMBD);
}

// round 3
// speedup vs baseline: 2.1031x; 2.1031x over previous
#include <cuda_runtime.h>
#include <math.h>
#include <stdint.h>

// Problem constants
#define SEQ   4096
#define EMBD  2048
#define NB    4
#define NHEAD 16
#define DHEAD 128
#define NSEG  8
#define SEGL  512
#define NBH   (NB * NHEAD)          // 64
#define MTOK  (NB * SEQ)            // 16384
#define TOTAL ((size_t)MTOK * EMBD) // 33554432

// -------- device scratch (allocation-free rule: static __device__ arrays) ----
__device__ float g_q[TOTAL];
__device__ float g_k[TOTAL];
__device__ float g_v[TOTAL];
__device__ float g_attn[TOTAL];
__device__ float g_scores[(size_t)NBH * SEGL * SEGL]; // 64*512*512
__device__ float g_mem[(size_t)NBH * DHEAD * DHEAD];  // 64*128*128
__device__ float g_Z[NBH * DHEAD];                    // 64*128
__device__ float g_Wt[(size_t)4 * EMBD * EMBD];       // transposed weights

__device__ __forceinline__ float elu1(float x) {
    return (x > 0.f) ? (x + 1.f) : expf(x);
}

__device__ __forceinline__ uint32_t smem_u32(const void* p) {
    uint32_t a;
    asm("{ .reg .u64 t; cvta.to.shared.u64 t, %1; cvt.u32.u64 %0, t; }"
        : "=r"(a) : "l"(p));
    return a;
}

__device__ __forceinline__ void cp16(uint32_t saddr, const void* g) {
    asm volatile("cp.async.cg.shared.global [%0], [%1], 16;" :: "r"(saddr), "l"(g));
}

__device__ __forceinline__ uint32_t f2tf32(float x) {
    uint32_t u;
    asm("cvt.rna.tf32.f32 %0, %1;" : "=r"(u) : "f"(x));
    return u;
}

__device__ __forceinline__ void mma_tf32(float* d, const uint32_t* a, const uint32_t* b) {
    asm volatile(
        "mma.sync.aligned.m16n8k8.row.col.f32.tf32.tf32.f32 "
        "{%0,%1,%2,%3}, {%4,%5,%6,%7}, {%8,%9}, {%0,%1,%2,%3};"
        : "+f"(d[0]), "+f"(d[1]), "+f"(d[2]), "+f"(d[3])
        : "r"(a[0]), "r"(a[1]), "r"(a[2]), "r"(a[3]), "r"(b[0]), "r"(b[1]));
}

// ============================================================================
// K0: 32x32 tiled transpose Wt[n,k] = W[k,n]
// ============================================================================
__global__ __launch_bounds__(256) void transpose_k(const float* __restrict__ W,
                                                   float* __restrict__ Wt)
{
    __shared__ float t[32][33];
    int bx = blockIdx.x * 32, by = blockIdx.y * 32;
    int txx = threadIdx.x;
    for (int i = threadIdx.y; i < 32; i += 8)
        t[i][txx] = W[(size_t)(by + i) * EMBD + bx + txx];
    __syncthreads();
    for (int i = threadIdx.y; i < 32; i += 8)
        Wt[(size_t)(bx + i) * EMBD + by + txx] = t[txx][i];
}

// ============================================================================
// K1: tf32 mma.sync GEMM  C[M,N] = A[M,K] @ Bt[N,K]^T + bias
//     CTA 128x128x32, 8 warps (2x4), warp tile 64x32, 2-stage cp.async
// ============================================================================
#define BM 128
#define BN 128
#define BK 32
#define BKP 36
#define GEMM_SMEM_FLOATS (2 * BM * BKP + 2 * BN * BKP)  // 18432 floats
#define GEMM_SMEM_BYTES (GEMM_SMEM_FLOATS * 4)          // 73728 bytes

__device__ __forceinline__ void load_stage(const float* __restrict__ A,
                                           const float* __restrict__ Bt,
                                           int brow, int bcol, int k0,
                                           uint32_t sA, uint32_t sB, int tid)
{
#pragma unroll
    for (int it = 0; it < 4; it++) {
        int idx = tid + it * 256;
        int row = idx >> 3, c4 = idx & 7;
        cp16(sA + (row * BKP + c4 * 4) * 4,
             A + (size_t)(brow + row) * EMBD + k0 + c4 * 4);
    }
#pragma unroll
    for (int it = 0; it < 4; it++) {
        int idx = tid + it * 256;
        int row = idx >> 3, c4 = idx & 7;
        cp16(sB + (row * BKP + c4 * 4) * 4,
             Bt + (size_t)(bcol + row) * EMBD + k0 + c4 * 4);
    }
    asm volatile("cp.async.commit_group;" ::: "memory");
}

__global__ __launch_bounds__(256) void gemm_mma_k(
    const float* __restrict__ A, const float* __restrict__ Bt,
    const float* __restrict__ bias, float* __restrict__ C)
{
    extern __shared__ float dsm[];
    float* Ash = dsm;                       // [2][BM][BKP]
    float* Bsh = dsm + 2 * BM * BKP;        // [2][BN][BKP]
    uint32_t sAu = smem_u32(Ash);
    uint32_t sBu = smem_u32(Bsh);

    const int tid = threadIdx.x;
    const int wid = tid >> 5;
    const int lane = tid & 31;
    const int lr = lane >> 2;       // 0..7
    const int lc = lane & 3;        // 0..3
    const int wm = (wid >> 2) * 64; // 0 or 64
    const int wn = (wid & 3) * 32;  // 0..96

    int brow = blockIdx.y * BM;
    int bcol = blockIdx.x * BN;

    float acc[4][4][4];
#pragma unroll
    for (int mt = 0; mt < 4; mt++)
#pragma unroll
        for (int nt = 0; nt < 4; nt++)
#pragma unroll
            for (int r = 0; r < 4; r++) acc[mt][nt][r] = 0.f;

    // prologue
    load_stage(A, Bt, brow, bcol, 0, sAu, sBu, tid);
    load_stage(A, Bt, brow, bcol, BK, sAu + BM * BKP * 4, sBu + BN * BKP * 4, tid);

    const int NIT = EMBD / BK; // 64
    for (int it = 0; it < NIT; it++) {
        int s = it & 1;
        if (it == NIT - 1) asm volatile("cp.async.wait_group 0;" ::: "memory");
        else               asm volatile("cp.async.wait_group 1;" ::: "memory");
        __syncthreads();

        const float* As = Ash + s * BM * BKP;
        const float* Bs = Bsh + s * BN * BKP;

#pragma unroll
        for (int kb = 0; kb < BK; kb += 8) {
            uint32_t af[4][4], bf[4][2];
#pragma unroll
            for (int mt = 0; mt < 4; mt++) {
                int r = wm + mt * 16 + lr;
                af[mt][0] = f2tf32(As[r * BKP + kb + lc]);
                af[mt][1] = f2tf32(As[(r + 8) * BKP + kb + lc]);
                af[mt][2] = f2tf32(As[r * BKP + kb + lc + 4]);
                af[mt][3] = f2tf32(As[(r + 8) * BKP + kb + lc + 4]);
            }
#pragma unroll
            for (int nt = 0; nt < 4; nt++) {
                int cN = wn + nt * 8 + lr;
                bf[nt][0] = f2tf32(Bs[cN * BKP + kb + lc]);
                bf[nt][1] = f2tf32(Bs[cN * BKP + kb + lc + 4]);
            }
#pragma unroll
            for (int mt = 0; mt < 4; mt++)
#pragma unroll
                for (int nt = 0; nt < 4; nt++)
                    mma_tf32(acc[mt][nt], af[mt], bf[nt]);
        }
        __syncthreads();

        if (it + 2 < NIT) {
            load_stage(A, Bt, brow, bcol, (it + 2) * BK,
                       sAu + s * BM * BKP * 4, sBu + s * BN * BKP * 4, tid);
        }
    }

    // epilogue: direct STG.64 with bias
#pragma unroll
    for (int nt = 0; nt < 4; nt++) {
        int col = bcol + wn + nt * 8 + 2 * lc;
        float b0 = bias[col], b1 = bias[col + 1];
#pragma unroll
        for (int mt = 0; mt < 4; mt++) {
            int row = brow + wm + mt * 16 + lr;
            float2 v0 = make_float2(acc[mt][nt][0] + b0, acc[mt][nt][1] + b1);
            float2 v1 = make_float2(acc[mt][nt][2] + b0, acc[mt][nt][3] + b1);
            *(float2*)&C[(size_t)row * EMBD + col] = v0;
            *(float2*)&C[(size_t)(row + 8) * EMBD + col] = v1;
        }
    }
}

// ============================================================================
// K2: RoPE over full EMB dim, applied to q and k in (B,T,C) layout
// ============================================================================
__global__ __launch_bounds__(256) void rope_k(float* __restrict__ q, float* __restrict__ k)
{
    size_t idx = (size_t)blockIdx.x * 256 + threadIdx.x;
    int rr = (int)(idx >> 10);
    int i = (int)(idx & 1023);
    int t = rr & (SEQ - 1);
    float inv = powf(10000.0f, -(float)(2 * i) * (1.0f / 2048.0f));
    float ang = (float)t * inv;
    float c = cosf(ang), s = sinf(ang);
    size_t base = (size_t)rr * EMBD + 2 * i;
    float a = q[base], b = q[base + 1];
    q[base] = a * c - b * s;
    q[base + 1] = a * s + b * c;
    a = k[base]; b = k[base + 1];
    k[base] = a * c - b * s;
    k[base + 1] = a * s + b * c;
}

// ============================================================================
// K3: scores[bh,l,m] = scale * q_seg[l,:] . k_seg[m,:]
// ============================================================================
__global__ __launch_bounds__(256) void scores_k(
    const float* __restrict__ qb, const float* __restrict__ kb,
    float* __restrict__ S, int s)
{
    const float scale = 0.08838834764831845f;
    int bh = blockIdx.z;
    int m0 = blockIdx.x * 64;
    int l0 = blockIdx.y * 64;
    size_t segbase = ((size_t)(bh * NSEG + s)) << 16;
    const float* qseg = qb + segbase;
    const float* kseg = kb + segbase;

    __shared__ float As[16][64];
    __shared__ float Bs[16][64];
    int tid = threadIdx.x;
    int tx = tid & 15, ty = tid >> 4;
    int r = tid >> 2, c4 = tid & 3;

    float acc[4][4];
#pragma unroll
    for (int i = 0; i < 4; i++)
#pragma unroll
        for (int j = 0; j < 4; j++) acc[i][j] = 0.f;

    for (int k0 = 0; k0 < DHEAD; k0 += 16) {
        float4 av = *(const float4*)&qseg[(size_t)(l0 + r) * DHEAD + k0 + c4 * 4];
        As[c4 * 4 + 0][r] = av.x; As[c4 * 4 + 1][r] = av.y;
        As[c4 * 4 + 2][r] = av.z; As[c4 * 4 + 3][r] = av.w;
        float4 bv = *(const float4*)&kseg[(size_t)(m0 + r) * DHEAD + k0 + c4 * 4];
        Bs[c4 * 4 + 0][r] = bv.x; Bs[c4 * 4 + 1][r] = bv.y;
        Bs[c4 * 4 + 2][r] = bv.z; Bs[c4 * 4 + 3][r] = bv.w;
        __syncthreads();
#pragma unroll
        for (int kk = 0; kk < 16; kk++) {
            float ra[4], rb[4];
#pragma unroll
            for (int i = 0; i < 4; i++) ra[i] = As[kk][ty * 4 + i];
#pragma unroll
            for (int j = 0; j < 4; j++) rb[j] = Bs[kk][tx * 4 + j];
#pragma unroll
            for (int i = 0; i < 4; i++)
#pragma unroll
                for (int j = 0; j < 4; j++) acc[i][j] += ra[i] * rb[j];
        }
        __syncthreads();
    }
    float* Sb = S + (size_t)bh * SEGL * SEGL;
#pragma unroll
    for (int i = 0; i < 4; i++)
#pragma unroll
        for (int j = 0; j < 4; j++)
            Sb[(size_t)(l0 + ty * 4 + i) * SEGL + m0 + tx * 4 + j] = acc[i][j] * scale;
}

// ============================================================================
// K4: row softmax in place on scores
// ============================================================================
__global__ __launch_bounds__(256) void softmax_k(float* __restrict__ S)
{
    int bh = blockIdx.y;
    int row = blockIdx.x * 8 + (threadIdx.x >> 5);
    int lane = threadIdx.x & 31;
    float* r = S + ((size_t)bh * SEGL + row) * SEGL;
    float vals[16];
    float mx = -1e30f;
#pragma unroll
    for (int i = 0; i < 16; i++) {
        vals[i] = r[lane + 32 * i];
        mx = fmaxf(mx, vals[i]);
    }
#pragma unroll
    for (int o = 16; o > 0; o >>= 1) mx = fmaxf(mx, __shfl_xor_sync(0xffffffffu, mx, o));
    float sum = 0.f;
#pragma unroll
    for (int i = 0; i < 16; i++) {
        vals[i] = expf(vals[i] - mx);
        sum += vals[i];
    }
#pragma unroll
    for (int o = 16; o > 0; o >>= 1) sum += __shfl_xor_sync(0xffffffffu, sum, o);
    float inv = 1.0f / sum;
#pragma unroll
    for (int i = 0; i < 16; i++) r[lane + 32 * i] = vals[i] * inv;
}

// ============================================================================
// K5: attn = g * (sq@mem)/(rowsum(sq)*Z + 1e-6) + (1-g) * P@v
// ============================================================================
__global__ __launch_bounds__(256) void attn_combine_k(
    const float* __restrict__ qb, const float* __restrict__ vb,
    const float* __restrict__ P, const float* __restrict__ mem,
    const float* __restrict__ Z, const float* __restrict__ beta,
    float* __restrict__ attnb, int s)
{
    int bh = blockIdx.y;
    int l0 = blockIdx.x * 64;
    size_t segbase = ((size_t)(bh * NSEG + s)) << 16;
    const float* qseg = qb + segbase;
    const float* vseg = vb + segbase;
    const float* Pseg = P + (size_t)bh * SEGL * SEGL;
    const float* memb = mem + (size_t)bh * DHEAD * DHEAD;
    const float* Zb = Z + bh * DHEAD;
    float g = 1.0f / (1.0f + expf(-beta[0]));

    __shared__ float As[16][64];
    __shared__ float Bs[16][128];
    __shared__ float rowsum[64];
    __shared__ float Zs[128];

    int tid = threadIdx.x;
    int tx = tid & 15, ty = tid >> 4;

    {
        int r = tid >> 2, qd = (tid & 3) * 32;
        float sm = 0.f;
#pragma unroll 8
        for (int d = 0; d < 32; d++)
            sm += elu1(qseg[(size_t)(l0 + r) * DHEAD + qd + d]);
        sm += __shfl_xor_sync(0xffffffffu, sm, 1);
        sm += __shfl_xor_sync(0xffffffffu, sm, 2);
        if ((tid & 3) == 0) rowsum[r] = sm;
    }
    if (tid < 128) Zs[tid] = Zb[tid];

    int ar = tid >> 2, ac4 = tid & 3;
    int br = tid >> 5, bc4 = tid & 31;

    float acc[4][8];
#pragma unroll
    for (int i = 0; i < 4; i++)
#pragma unroll
        for (int j = 0; j < 8; j++) acc[i][j] = 0.f;

    for (int k0 = 0; k0 < DHEAD; k0 += 16) {
        float4 av = *(const float4*)&qseg[(size_t)(l0 + ar) * DHEAD + k0 + ac4 * 4];
        As[ac4 * 4 + 0][ar] = elu1(av.x); As[ac4 * 4 + 1][ar] = elu1(av.y);
        As[ac4 * 4 + 2][ar] = elu1(av.z); As[ac4 * 4 + 3][ar] = elu1(av.w);
#pragma unroll
        for (int i = 0; i < 2; i++) {
            float4 bv = *(const float4*)&memb[(size_t)(k0 + br + i * 8) * DHEAD + bc4 * 4];
            *(float4*)&Bs[br + i * 8][bc4 * 4] = bv;
        }
        __syncthreads();
#pragma unroll
        for (int kk = 0; kk < 16; kk++) {
            float ra[4], rb[8];
#pragma unroll
            for (int i = 0; i < 4; i++) ra[i] = As[kk][ty * 4 + i];
#pragma unroll
            for (int j = 0; j < 8; j++) rb[j] = Bs[kk][tx * 8 + j];
#pragma unroll
            for (int i = 0; i < 4; i++)
#pragma unroll
                for (int j = 0; j < 8; j++) acc[i][j] += ra[i] * rb[j];
        }
        __syncthreads();
    }

    float outv[4][8];
#pragma unroll
    for (int i = 0; i < 4; i++)
#pragma unroll
        for (int j = 0; j < 8; j++)
            outv[i][j] = g * acc[i][j] / (rowsum[ty * 4 + i] * Zs[tx * 8 + j] + 1e-6f);

#pragma unroll
    for (int i = 0; i < 4; i++)
#pragma unroll
        for (int j = 0; j < 8; j++) acc[i][j] = 0.f;

    for (int m0 = 0; m0 < SEGL; m0 += 16) {
        float4 pv = *(const float4*)&Pseg[(size_t)(l0 + ar) * SEGL + m0 + ac4 * 4];
        As[ac4 * 4 + 0][ar] = pv.x; As[ac4 * 4 + 1][ar] = pv.y;
        As[ac4 * 4 + 2][ar] = pv.z; As[ac4 * 4 + 3][ar] = pv.w;
#pragma unroll
        for (int i = 0; i < 2; i++) {
            float4 vv = *(const float4*)&vseg[(size_t)(m0 + br + i * 8) * DHEAD + bc4 * 4];
            *(float4*)&Bs[br + i * 8][bc4 * 4] = vv;
        }
        __syncthreads();
#pragma unroll
        for (int kk = 0; kk < 16; kk++) {
            float ra[4], rb[8];
#pragma unroll
            for (int i = 0; i < 4; i++) ra[i] = As[kk][ty * 4 + i];
#pragma unroll
            for (int j = 0; j < 8; j++) rb[j] = Bs[kk][tx * 8 + j];
#pragma unroll
            for (int i = 0; i < 4; i++)
#pragma unroll
                for (int j = 0; j < 8; j++) acc[i][j] += ra[i] * rb[j];
        }
        __syncthreads();
    }

    float gm1 = 1.0f - g;
#pragma unroll
    for (int i = 0; i < 4; i++)
#pragma unroll
        for (int j = 0; j < 8; j++)
            attnb[segbase + (size_t)(l0 + ty * 4 + i) * DHEAD + tx * 8 + j] =
                outv[i][j] + gm1 * acc[i][j];
}

// ============================================================================
// K6: mem[d,e] += sum_l sk[l,d]*v[l,e];  Z[d] += sum_l sk[l,d]
// ============================================================================
__global__ __launch_bounds__(256) void mem_update_k(
    const float* __restrict__ kb, const float* __restrict__ vb,
    float* __restrict__ mem, float* __restrict__ Z, int s)
{
    int bh = blockIdx.x;
    size_t segbase = ((size_t)(bh * NSEG + s)) << 16;
    const float* kseg = kb + segbase;
    const float* vseg = vb + segbase;

    __shared__ float As[16][128];
    __shared__ float Bs[16][128];
    int tid = threadIdx.x;
    int tx = tid & 15, ty = tid >> 4;
    int br = tid >> 5, bc4 = tid & 31;

    float acc[8][8];
    float zacc[8];
#pragma unroll
    for (int i = 0; i < 8; i++) {
        zacc[i] = 0.f;
#pragma unroll
        for (int j = 0; j < 8; j++) acc[i][j] = 0.f;
    }

    for (int l0 = 0; l0 < SEGL; l0 += 16) {
#pragma unroll
        for (int i = 0; i < 2; i++) {
            int r = br + i * 8;
            float4 kv = *(const float4*)&kseg[(size_t)(l0 + r) * DHEAD + bc4 * 4];
            As[r][bc4 * 4 + 0] = elu1(kv.x); As[r][bc4 * 4 + 1] = elu1(kv.y);
            As[r][bc4 * 4 + 2] = elu1(kv.z); As[r][bc4 * 4 + 3] = elu1(kv.w);
            float4 vv = *(const float4*)&vseg[(size_t)(l0 + r) * DHEAD + bc4 * 4];
            *(float4*)&Bs[r][bc4 * 4] = vv;
        }
        __syncthreads();
#pragma unroll
        for (int kk = 0; kk < 16; kk++) {
            float ra[8], rb[8];
#pragma unroll
            for (int i = 0; i < 8; i++) ra[i] = As[kk][ty * 8 + i];
#pragma unroll
            for (int j = 0; j < 8; j++) rb[j] = Bs[kk][tx * 8 + j];
#pragma unroll
            for (int i = 0; i < 8; i++)
#pragma unroll
                for (int j = 0; j < 8; j++) acc[i][j] += ra[i] * rb[j];
            if (tx == 0) {
#pragma unroll
                for (int i = 0; i < 8; i++) zacc[i] += ra[i];
            }
        }
        __syncthreads();
    }
    float* memb = mem + (size_t)bh * DHEAD * DHEAD;
#pragma unroll
    for (int i = 0; i < 8; i++)
#pragma unroll
        for (int j = 0; j < 8; j++)
            memb[(size_t)(ty * 8 + i) * DHEAD + tx * 8 + j] += acc[i][j];
    if (tx == 0) {
#pragma unroll
        for (int i = 0; i < 8; i++) Z[bh * DHEAD + ty * 8 + i] += zacc[i];
    }
}

// ============================================================================
// Host launch
// ============================================================================
extern "C" void kernel_launch(void* const* d_in, const int* in_sizes, int n_in,
                              void* d_out, int out_size)
{
    (void)in_sizes; (void)n_in; (void)out_size;
    const float* x    = (const float*)d_in[0];
    const float* Wq   = (const float*)d_in[1];
    const float* bq   = (const float*)d_in[2];
    const float* Wk   = (const float*)d_in[3];
    const float* bk   = (const float*)d_in[4];
    const float* Wv   = (const float*)d_in[5];
    const float* bv   = (const float*)d_in[6];
    const float* Wo   = (const float*)d_in[7];
    const float* bo   = (const float*)d_in[8];
    const float* beta = (const float*)d_in[9];
    float* out = (float*)d_out;

    static float *pq = nullptr, *pk = nullptr, *pv = nullptr, *pattn = nullptr,
                 *pscores = nullptr, *pmem = nullptr, *pZ = nullptr, *pWt = nullptr;
    if (!pq) {
        cudaGetSymbolAddress((void**)&pq, g_q);
        cudaGetSymbolAddress((void**)&pk, g_k);
        cudaGetSymbolAddress((void**)&pv, g_v);
        cudaGetSymbolAddress((void**)&pattn, g_attn);
        cudaGetSymbolAddress((void**)&pscores, g_scores);
        cudaGetSymbolAddress((void**)&pmem, g_mem);
        cudaGetSymbolAddress((void**)&pZ, g_Z);
        cudaGetSymbolAddress((void**)&pWt, g_Wt);
        cudaFuncSetAttribute(gemm_mma_k, cudaFuncAttributeMaxDynamicSharedMemorySize,
                             GEMM_SMEM_BYTES);
    }

    // carry state must be zero at the start of every call (graph replays!)
    cudaMemsetAsync(pmem, 0, (size_t)NBH * DHEAD * DHEAD * sizeof(float), 0);
    cudaMemsetAsync(pZ, 0, (size_t)NBH * DHEAD * sizeof(float), 0);

    const size_t WSZ = (size_t)EMBD * EMBD;
    dim3 tgrid(EMBD / 32, EMBD / 32);
    dim3 tblk(32, 8);
    transpose_k<<<tgrid, tblk>>>(Wq, pWt + 0 * WSZ);
    transpose_k<<<tgrid, tblk>>>(Wk, pWt + 1 * WSZ);
    transpose_k<<<tgrid, tblk>>>(Wv, pWt + 2 * WSZ);
    transpose_k<<<tgrid, tblk>>>(Wo, pWt + 3 * WSZ);

    dim3 ggrid(EMBD / BN, MTOK / BM); // (16, 128)
    gemm_mma_k<<<ggrid, 256, GEMM_SMEM_BYTES>>>(x, pWt + 0 * WSZ, bq, pq);
    gemm_mma_k<<<ggrid, 256, GEMM_SMEM_BYTES>>>(x, pWt + 1 * WSZ, bk, pk);
    gemm_mma_k<<<ggrid, 256, GEMM_SMEM_BYTES>>>(x, pWt + 2 * WSZ, bv, pv);

    rope_k<<<(MTOK * (EMBD / 2)) / 256, 256>>>(pq, pk);

    for (int s = 0; s < NSEG; s++) {
        scores_k<<<dim3(SEGL / 64, SEGL / 64, NBH), 256>>>(pq, pk, pscores, s);
        softmax_k<<<dim3(SEGL / 8, NBH), 256>>>(pscores);
        attn_combine_k<<<dim3(SEGL / 64, NBH), 256>>>(pq, pv, pscores, pmem, pZ,
                                                      beta, pattn, s);
        mem_update_k<<<NBH, 256>>>(pk, pv, pmem, pZ, s);
    }

    gemm_mma_k<<<ggrid, 256, GEMM_SMEM_BYTES>>>(pattn, pWt + 3 * WSZ, bo, out);
}

// round 4
// speedup vs baseline: 2.8675x; 1.3634x over previous
#include <cuda_runtime.h>
#include <math.h>
#include <stdint.h>

// Problem constants
#define SEQ   4096
#define EMBD  2048
#define NB    4
#define NHEAD 16
#define DHEAD 128
#define NSEG  8
#define SEGL  512
#define NBH   (NB * NHEAD)          // 64
#define MTOK  (NB * SEQ)            // 16384
#define TOTAL ((size_t)MTOK * EMBD) // 33554432

// -------- device scratch ----------------------------------------------------
__device__ float g_q[TOTAL];
__device__ float g_k[TOTAL];
__device__ float g_v[TOTAL];
__device__ float g_attn[TOTAL];
__device__ float g_scores[(size_t)NBH * NSEG * SEGL * SEGL]; // 512MB
__device__ float g_mem[(size_t)NBH * DHEAD * DHEAD];
__device__ float g_Z[NBH * DHEAD];
__device__ float g_Wt[(size_t)4 * EMBD * EMBD];

__device__ __forceinline__ float elu1(float x) {
    return (x > 0.f) ? (x + 1.f) : expf(x);
}

__device__ __forceinline__ uint32_t smem_u32(const void* p) {
    uint32_t a;
    asm("{ .reg .u64 t; cvta.to.shared.u64 t, %1; cvt.u32.u64 %0, t; }"
        : "=r"(a) : "l"(p));
    return a;
}

__device__ __forceinline__ void cp16(uint32_t saddr, const void* g) {
    asm volatile("cp.async.cg.shared.global [%0], [%1], 16;" :: "r"(saddr), "l"(g));
}

__device__ __forceinline__ uint32_t f2tf32(float x) {
    uint32_t u;
    asm("cvt.rna.tf32.f32 %0, %1;" : "=r"(u) : "f"(x));
    return u;
}

__device__ __forceinline__ void mma_tf32(float* d, const uint32_t* a, const uint32_t* b) {
    asm volatile(
        "mma.sync.aligned.m16n8k8.row.col.f32.tf32.tf32.f32 "
        "{%0,%1,%2,%3}, {%4,%5,%6,%7}, {%8,%9}, {%0,%1,%2,%3};"
        : "+f"(d[0]), "+f"(d[1]), "+f"(d[2]), "+f"(d[3])
        : "r"(a[0]), "r"(a[1]), "r"(a[2]), "r"(a[3]), "r"(b[0]), "r"(b[1]));
}

// ============================================================================
// K0: 32x32 tiled transpose Wt[n,k] = W[k,n]
// ============================================================================
__global__ __launch_bounds__(256) void transpose_k(const float* __restrict__ W,
                                                   float* __restrict__ Wt)
{
    __shared__ float t[32][33];
    int bx = blockIdx.x * 32, by = blockIdx.y * 32;
    int txx = threadIdx.x;
    for (int i = threadIdx.y; i < 32; i += 8)
        t[i][txx] = W[(size_t)(by + i) * EMBD + bx + txx];
    __syncthreads();
    for (int i = threadIdx.y; i < 32; i += 8)
        Wt[(size_t)(bx + i) * EMBD + by + txx] = t[txx][i];
}

// ============================================================================
// K1: tf32 mma.sync GEMM  C[M,N] = A[M,K] @ Bt[N,K]^T + bias
// ============================================================================
#define BM 128
#define BN 128
#define BK 32
#define BKP 36
#define GEMM_SMEM_BYTES (2 * (BM + BN) * BKP * 4)  // 73728 bytes

__device__ __forceinline__ void load_stage(const float* __restrict__ A,
                                           const float* __restrict__ Bt,
                                           int brow, int bcol, int k0,
                                           uint32_t sA, uint32_t sB, int tid)
{
#pragma unroll
    for (int it = 0; it < 4; it++) {
        int idx = tid + it * 256;
        int row = idx >> 3, c4 = idx & 7;
        cp16(sA + (row * BKP + c4 * 4) * 4,
             A + (size_t)(brow + row) * EMBD + k0 + c4 * 4);
    }
#pragma unroll
    for (int it = 0; it < 4; it++) {
        int idx = tid + it * 256;
        int row = idx >> 3, c4 = idx & 7;
        cp16(sB + (row * BKP + c4 * 4) * 4,
             Bt + (size_t)(bcol + row) * EMBD + k0 + c4 * 4);
    }
    asm volatile("cp.async.commit_group;" ::: "memory");
}

__global__ __launch_bounds__(256) void gemm_mma_k(
    const float* __restrict__ A, const float* __restrict__ Bt,
    const float* __restrict__ bias, float* __restrict__ C)
{
    extern __shared__ float dsm[];
    float* Ash = dsm;
    float* Bsh = dsm + 2 * BM * BKP;
    uint32_t sAu = smem_u32(Ash);
    uint32_t sBu = smem_u32(Bsh);

    const int tid = threadIdx.x;
    const int wid = tid >> 5;
    const int lane = tid & 31;
    const int lr = lane >> 2;
    const int lc = lane & 3;
    const int wm = (wid >> 2) * 64;
    const int wn = (wid & 3) * 32;

    int brow = blockIdx.y * BM;
    int bcol = blockIdx.x * BN;

    float acc[4][4][4];
#pragma unroll
    for (int mt = 0; mt < 4; mt++)
#pragma unroll
        for (int nt = 0; nt < 4; nt++)
#pragma unroll
            for (int r = 0; r < 4; r++) acc[mt][nt][r] = 0.f;

    load_stage(A, Bt, brow, bcol, 0, sAu, sBu, tid);
    load_stage(A, Bt, brow, bcol, BK, sAu + BM * BKP * 4, sBu + BN * BKP * 4, tid);

    const int NIT = EMBD / BK;
    for (int it = 0; it < NIT; it++) {
        int s = it & 1;
        if (it == NIT - 1) asm volatile("cp.async.wait_group 0;" ::: "memory");
        else               asm volatile("cp.async.wait_group 1;" ::: "memory");
        __syncthreads();

        const float* As = Ash + s * BM * BKP;
        const float* Bs = Bsh + s * BN * BKP;

#pragma unroll
        for (int kb = 0; kb < BK; kb += 8) {
            uint32_t af[4][4], bf[4][2];
#pragma unroll
            for (int mt = 0; mt < 4; mt++) {
                int r = wm + mt * 16 + lr;
                af[mt][0] = f2tf32(As[r * BKP + kb + lc]);
                af[mt][1] = f2tf32(As[(r + 8) * BKP + kb + lc]);
                af[mt][2] = f2tf32(As[r * BKP + kb + lc + 4]);
                af[mt][3] = f2tf32(As[(r + 8) * BKP + kb + lc + 4]);
            }
#pragma unroll
            for (int nt = 0; nt < 4; nt++) {
                int cN = wn + nt * 8 + lr;
                bf[nt][0] = f2tf32(Bs[cN * BKP + kb + lc]);
                bf[nt][1] = f2tf32(Bs[cN * BKP + kb + lc + 4]);
            }
#pragma unroll
            for (int mt = 0; mt < 4; mt++)
#pragma unroll
                for (int nt = 0; nt < 4; nt++)
                    mma_tf32(acc[mt][nt], af[mt], bf[nt]);
        }
        __syncthreads();

        if (it + 2 < NIT) {
            load_stage(A, Bt, brow, bcol, (it + 2) * BK,
                       sAu + s * BM * BKP * 4, sBu + s * BN * BKP * 4, tid);
        }
    }

#pragma unroll
    for (int nt = 0; nt < 4; nt++) {
        int col = bcol + wn + nt * 8 + 2 * lc;
        float b0 = bias[col], b1 = bias[col + 1];
#pragma unroll
        for (int mt = 0; mt < 4; mt++) {
            int row = brow + wm + mt * 16 + lr;
            float2 v0 = make_float2(acc[mt][nt][0] + b0, acc[mt][nt][1] + b1);
            float2 v1 = make_float2(acc[mt][nt][2] + b0, acc[mt][nt][3] + b1);
            *(float2*)&C[(size_t)row * EMBD + col] = v0;
            *(float2*)&C[(size_t)(row + 8) * EMBD + col] = v1;
        }
    }
}

// ============================================================================
// K2: RoPE
// ============================================================================
__global__ __launch_bounds__(256) void rope_k(float* __restrict__ q, float* __restrict__ k)
{
    size_t idx = (size_t)blockIdx.x * 256 + threadIdx.x;
    int rr = (int)(idx >> 10);
    int i = (int)(idx & 1023);
    int t = rr & (SEQ - 1);
    float inv = powf(10000.0f, -(float)(2 * i) * (1.0f / 2048.0f));
    float ang = (float)t * inv;
    float c = cosf(ang), s = sinf(ang);
    size_t base = (size_t)rr * EMBD + 2 * i;
    float a = q[base], b = q[base + 1];
    q[base] = a * c - b * s;
    q[base + 1] = a * s + b * c;
    a = k[base]; b = k[base + 1];
    k[base] = a * c - b * s;
    k[base + 1] = a * s + b * c;
}

// ============================================================================
// K3: batched scores (ALL segments):  S = scale * q_seg @ k_seg^T  (tf32 mma)
//     grid (m-tile 4, l-tile 4, bhs 512), CTA 128x128, K=128
// ============================================================================
__global__ __launch_bounds__(256) void scores_mma_k(
    const float* __restrict__ qb, const float* __restrict__ kb,
    float* __restrict__ S)
{
    extern __shared__ float dsm[];
    float* Ash = dsm;
    float* Bsh = dsm + 2 * BM * BKP;
    uint32_t sAu = smem_u32(Ash);
    uint32_t sBu = smem_u32(Bsh);

    const float scale = 0.08838834764831845f;
    const int tid = threadIdx.x;
    const int wid = tid >> 5;
    const int lane = tid & 31;
    const int lr = lane >> 2;
    const int lc = lane & 3;
    const int wm = (wid >> 2) * 64;
    const int wn = (wid & 3) * 32;

    int bhs = blockIdx.z;                    // bh*NSEG + s
    size_t segbase = ((size_t)bhs) << 16;
    const float* A = qb + segbase;           // [512][128]
    const float* B = kb + segbase;
    int brow = blockIdx.y * BM;
    int bcol = blockIdx.x * BN;

    float acc[4][4][4];
#pragma unroll
    for (int mt = 0; mt < 4; mt++)
#pragma unroll
        for (int nt = 0; nt < 4; nt++)
#pragma unroll
            for (int r = 0; r < 4; r++) acc[mt][nt][r] = 0.f;

    // loaders (stride = DHEAD)
    auto load_st = [&](int k0, uint32_t sA, uint32_t sB) {
#pragma unroll
        for (int it = 0; it < 4; it++) {
            int idx = tid + it * 256;
            int row = idx >> 3, c4 = idx & 7;
            cp16(sA + (row * BKP + c4 * 4) * 4,
                 A + (size_t)(brow + row) * DHEAD + k0 + c4 * 4);
        }
#pragma unroll
        for (int it = 0; it < 4; it++) {
            int idx = tid + it * 256;
            int row = idx >> 3, c4 = idx & 7;
            cp16(sB + (row * BKP + c4 * 4) * 4,
                 B + (size_t)(bcol + row) * DHEAD + k0 + c4 * 4);
        }
        asm volatile("cp.async.commit_group;" ::: "memory");
    };

    load_st(0, sAu, sBu);
    load_st(BK, sAu + BM * BKP * 4, sBu + BN * BKP * 4);

    const int NIT = DHEAD / BK;   // 4
    for (int it = 0; it < NIT; it++) {
        int s = it & 1;
        if (it == NIT - 1) asm volatile("cp.async.wait_group 0;" ::: "memory");
        else               asm volatile("cp.async.wait_group 1;" ::: "memory");
        __syncthreads();

        const float* As = Ash + s * BM * BKP;
        const float* Bs = Bsh + s * BN * BKP;
#pragma unroll
        for (int kb = 0; kb < BK; kb += 8) {
            uint32_t af[4][4], bf[4][2];
#pragma unroll
            for (int mt = 0; mt < 4; mt++) {
                int r = wm + mt * 16 + lr;
                af[mt][0] = f2tf32(As[r * BKP + kb + lc]);
                af[mt][1] = f2tf32(As[(r + 8) * BKP + kb + lc]);
                af[mt][2] = f2tf32(As[r * BKP + kb + lc + 4]);
                af[mt][3] = f2tf32(As[(r + 8) * BKP + kb + lc + 4]);
            }
#pragma unroll
            for (int nt = 0; nt < 4; nt++) {
                int cN = wn + nt * 8 + lr;
                bf[nt][0] = f2tf32(Bs[cN * BKP + kb + lc]);
                bf[nt][1] = f2tf32(Bs[cN * BKP + kb + lc + 4]);
            }
#pragma unroll
            for (int mt = 0; mt < 4; mt++)
#pragma unroll
                for (int nt = 0; nt < 4; nt++)
                    mma_tf32(acc[mt][nt], af[mt], bf[nt]);
        }
        __syncthreads();
        if (it + 2 < NIT)
            load_st((it + 2) * BK, sAu + s * BM * BKP * 4, sBu + s * BN * BKP * 4);
    }

    float* Sb = S + (size_t)bhs * SEGL * SEGL;
#pragma unroll
    for (int nt = 0; nt < 4; nt++) {
        int col = bcol + wn + nt * 8 + 2 * lc;
#pragma unroll
        for (int mt = 0; mt < 4; mt++) {
            int row = brow + wm + mt * 16 + lr;
            float2 v0 = make_float2(acc[mt][nt][0] * scale, acc[mt][nt][1] * scale);
            float2 v1 = make_float2(acc[mt][nt][2] * scale, acc[mt][nt][3] * scale);
            *(float2*)&Sb[(size_t)row * SEGL + col] = v0;
            *(float2*)&Sb[(size_t)(row + 8) * SEGL + col] = v1;
        }
    }
}

// ============================================================================
// K4: batched row softmax, grid (64, 512)
// ============================================================================
__global__ __launch_bounds__(256) void softmax_k(float* __restrict__ S)
{
    int bhs = blockIdx.y;
    int row = blockIdx.x * 8 + (threadIdx.x >> 5);
    int lane = threadIdx.x & 31;
    float* r = S + ((size_t)bhs * SEGL + row) * SEGL;
    float vals[16];
    float mx = -1e30f;
#pragma unroll
    for (int i = 0; i < 16; i++) {
        vals[i] = r[lane + 32 * i];
        mx = fmaxf(mx, vals[i]);
    }
#pragma unroll
    for (int o = 16; o > 0; o >>= 1) mx = fmaxf(mx, __shfl_xor_sync(0xffffffffu, mx, o));
    float sum = 0.f;
#pragma unroll
    for (int i = 0; i < 16; i++) {
        vals[i] = expf(vals[i] - mx);
        sum += vals[i];
    }
#pragma unroll
    for (int o = 16; o > 0; o >>= 1) sum += __shfl_xor_sync(0xffffffffu, sum, o);
    float inv = 1.0f / sum;
#pragma unroll
    for (int i = 0; i < 16; i++) r[lane + 32 * i] = vals[i] * inv;
}

// ============================================================================
// K5: batched PV: attn = (1-g) * P @ v   (tf32 mma, V read transposed)
//     grid (l-tile 4, bhs 512), CTA 128x128, K=512
// ============================================================================
#define VEP 136
#define PV_SMEM_BYTES ((2 * BM * BKP + 2 * BK * VEP) * 4)  // 36864+34816

__global__ __launch_bounds__(256) void pv_mma_k(
    const float* __restrict__ P, const float* __restrict__ vb,
    const float* __restrict__ beta, float* __restrict__ attnb)
{
    extern __shared__ float dsm[];
    float* Ash = dsm;                      // [2][128][36]
    float* Vsh = dsm + 2 * BM * BKP;       // [2][32][136]
    uint32_t sAu = smem_u32(Ash);
    uint32_t sVu = smem_u32(Vsh);

    const int tid = threadIdx.x;
    const int wid = tid >> 5;
    const int lane = tid & 31;
    const int lr = lane >> 2;
    const int lc = lane & 3;
    const int wm = (wid >> 2) * 64;
    const int wn = (wid & 3) * 32;

    int bhs = blockIdx.y;
    size_t segbase = ((size_t)bhs) << 16;
    const float* Pseg = P + (size_t)bhs * SEGL * SEGL;
    const float* vseg = vb + segbase;
    int brow = blockIdx.x * BM;
    float gm1 = 1.0f - 1.0f / (1.0f + expf(-beta[0]));

    float acc[4][4][4];
#pragma unroll
    for (int mt = 0; mt < 4; mt++)
#pragma unroll
        for (int nt = 0; nt < 4; nt++)
#pragma unroll
            for (int r = 0; r < 4; r++) acc[mt][nt][r] = 0.f;

    auto load_st = [&](int k0, uint32_t sA, uint32_t sV) {
#pragma unroll
        for (int it = 0; it < 4; it++) {              // P: 128 rows x 8 chunks
            int idx = tid + it * 256;
            int row = idx >> 3, c4 = idx & 7;
            cp16(sA + (row * BKP + c4 * 4) * 4,
                 Pseg + (size_t)(brow + row) * SEGL + k0 + c4 * 4);
        }
#pragma unroll
        for (int it = 0; it < 4; it++) {              // V: 32 rows x 32 chunks
            int idx = tid + it * 256;
            int row = idx >> 5, c4 = idx & 31;
            cp16(sV + (row * VEP + c4 * 4) * 4,
                 vseg + (size_t)(k0 + row) * DHEAD + c4 * 4);
        }
        asm volatile("cp.async.commit_group;" ::: "memory");
    };

    load_st(0, sAu, sVu);
    load_st(BK, sAu + BM * BKP * 4, sVu + BK * VEP * 4);

    const int NIT = SEGL / BK; // 16
    for (int it = 0; it < NIT; it++) {
        int s = it & 1;
        if (it == NIT - 1) asm volatile("cp.async.wait_group 0;" ::: "memory");
        else               asm volatile("cp.async.wait_group 1;" ::: "memory");
        __syncthreads();

        const float* As = Ash + s * BM * BKP;
        const float* Vs = Vsh + s * BK * VEP;
#pragma unroll
        for (int kb = 0; kb < BK; kb += 8) {
            uint32_t af[4][4], bf[4][2];
#pragma unroll
            for (int mt = 0; mt < 4; mt++) {
                int r = wm + mt * 16 + lr;
                af[mt][0] = f2tf32(As[r * BKP + kb + lc]);
                af[mt][1] = f2tf32(As[(r + 8) * BKP + kb + lc]);
                af[mt][2] = f2tf32(As[r * BKP + kb + lc + 4]);
                af[mt][3] = f2tf32(As[(r + 8) * BKP + kb + lc + 4]);
            }
#pragma unroll
            for (int nt = 0; nt < 4; nt++) {
                int cN = wn + nt * 8 + lr;             // output col (head dim e)
                bf[nt][0] = f2tf32(Vs[(kb + lc) * VEP + cN]);
                bf[nt][1] = f2tf32(Vs[(kb + lc + 4) * VEP + cN]);
            }
#pragma unroll
            for (int mt = 0; mt < 4; mt++)
#pragma unroll
                for (int nt = 0; nt < 4; nt++)
                    mma_tf32(acc[mt][nt], af[mt], bf[nt]);
        }
        __syncthreads();
        if (it + 2 < NIT)
            load_st((it + 2) * BK, sAu + s * BM * BKP * 4, sVu + s * BK * VEP * 4);
    }

#pragma unroll
    for (int nt = 0; nt < 4; nt++) {
        int col = wn + nt * 8 + 2 * lc;
#pragma unroll
        for (int mt = 0; mt < 4; mt++) {
            int row = brow + wm + mt * 16 + lr;
            float2 v0 = make_float2(acc[mt][nt][0] * gm1, acc[mt][nt][1] * gm1);
            float2 v1 = make_float2(acc[mt][nt][2] * gm1, acc[mt][nt][3] * gm1);
            *(float2*)&attnb[segbase + (size_t)row * DHEAD + col] = v0;
            *(float2*)&attnb[segbase + (size_t)(row + 8) * DHEAD + col] = v1;
        }
    }
}

// ============================================================================
// K6: A_mem accumulate: attn += g * (sq@mem)/(rowsum(sq)*Z + 1e-6)
//     grid (8 l-tiles of 64, 64 bh)  -- fp32 SIMT (recurrent path)
// ============================================================================
__global__ __launch_bounds__(256) void amem_k(
    const float* __restrict__ qb, const float* __restrict__ mem,
    const float* __restrict__ Z, const float* __restrict__ beta,
    float* __restrict__ attnb, int s)
{
    int bh = blockIdx.y;
    int l0 = blockIdx.x * 64;
    size_t segbase = ((size_t)(bh * NSEG + s)) << 16;
    const float* qseg = qb + segbase;
    const float* memb = mem + (size_t)bh * DHEAD * DHEAD;
    const float* Zb = Z + bh * DHEAD;
    float g = 1.0f / (1.0f + expf(-beta[0]));

    __shared__ float As[16][64];
    __shared__ float Bs[16][128];
    __shared__ float rowsum[64];
    __shared__ float Zs[128];

    int tid = threadIdx.x;
    int tx = tid & 15, ty = tid >> 4;

    {
        int r = tid >> 2, qd = (tid & 3) * 32;
        float sm = 0.f;
#pragma unroll 8
        for (int d = 0; d < 32; d++)
            sm += elu1(qseg[(size_t)(l0 + r) * DHEAD + qd + d]);
        sm += __shfl_xor_sync(0xffffffffu, sm, 1);
        sm += __shfl_xor_sync(0xffffffffu, sm, 2);
        if ((tid & 3) == 0) rowsum[r] = sm;
    }
    if (tid < 128) Zs[tid] = Zb[tid];

    int ar = tid >> 2, ac4 = tid & 3;
    int br = tid >> 5, bc4 = tid & 31;

    float acc[4][8];
#pragma unroll
    for (int i = 0; i < 4; i++)
#pragma unroll
        for (int j = 0; j < 8; j++) acc[i][j] = 0.f;

    for (int k0 = 0; k0 < DHEAD; k0 += 16) {
        float4 av = *(const float4*)&qseg[(size_t)(l0 + ar) * DHEAD + k0 + ac4 * 4];
        As[ac4 * 4 + 0][ar] = elu1(av.x); As[ac4 * 4 + 1][ar] = elu1(av.y);
        As[ac4 * 4 + 2][ar] = elu1(av.z); As[ac4 * 4 + 3][ar] = elu1(av.w);
#pragma unroll
        for (int i = 0; i < 2; i++) {
            float4 bv = *(const float4*)&memb[(size_t)(k0 + br + i * 8) * DHEAD + bc4 * 4];
            *(float4*)&Bs[br + i * 8][bc4 * 4] = bv;
        }
        __syncthreads();
#pragma unroll
        for (int kk = 0; kk < 16; kk++) {
            float ra[4], rb[8];
#pragma unroll
            for (int i = 0; i < 4; i++) ra[i] = As[kk][ty * 4 + i];
#pragma unroll
            for (int j = 0; j < 8; j++) rb[j] = Bs[kk][tx * 8 + j];
#pragma unroll
            for (int i = 0; i < 4; i++)
#pragma unroll
                for (int j = 0; j < 8; j++) acc[i][j] += ra[i] * rb[j];
        }
        __syncthreads();
    }

#pragma unroll
    for (int i = 0; i < 4; i++) {
        float rs = rowsum[ty * 4 + i];
        size_t rbase = segbase + (size_t)(l0 + ty * 4 + i) * DHEAD;
#pragma unroll
        for (int j = 0; j < 8; j++) {
            float* dst = &attnb[rbase + tx * 8 + j];
            *dst += g * acc[i][j] / (rs * Zs[tx * 8 + j] + 1e-6f);
        }
    }
}

// ============================================================================
// K7: mem[d,e] += sum_l sk[l,d]*v[l,e];  Z[d] += sum_l sk[l,d]
// ============================================================================
__global__ __launch_bounds__(256) void mem_update_k(
    const float* __restrict__ kb, const float* __restrict__ vb,
    float* __restrict__ mem, float* __restrict__ Z, int s)
{
    int bh = blockIdx.x;
    size_t segbase = ((size_t)(bh * NSEG + s)) << 16;
    const float* kseg = kb + segbase;
    const float* vseg = vb + segbase;

    __shared__ float As[16][128];
    __shared__ float Bs[16][128];
    int tid = threadIdx.x;
    int tx = tid & 15, ty = tid >> 4;
    int br = tid >> 5, bc4 = tid & 31;

    float acc[8][8];
    float zacc[8];
#pragma unroll
    for (int i = 0; i < 8; i++) {
        zacc[i] = 0.f;
#pragma unroll
        for (int j = 0; j < 8; j++) acc[i][j] = 0.f;
    }

    for (int l0 = 0; l0 < SEGL; l0 += 16) {
#pragma unroll
        for (int i = 0; i < 2; i++) {
            int r = br + i * 8;
            float4 kv = *(const float4*)&kseg[(size_t)(l0 + r) * DHEAD + bc4 * 4];
            As[r][bc4 * 4 + 0] = elu1(kv.x); As[r][bc4 * 4 + 1] = elu1(kv.y);
            As[r][bc4 * 4 + 2] = elu1(kv.z); As[r][bc4 * 4 + 3] = elu1(kv.w);
            float4 vv = *(const float4*)&vseg[(size_t)(l0 + r) * DHEAD + bc4 * 4];
            *(float4*)&Bs[r][bc4 * 4] = vv;
        }
        __syncthreads();
#pragma unroll
        for (int kk = 0; kk < 16; kk++) {
            float ra[8], rb[8];
#pragma unroll
            for (int i = 0; i < 8; i++) ra[i] = As[kk][ty * 8 + i];
#pragma unroll
            for (int j = 0; j < 8; j++) rb[j] = Bs[kk][tx * 8 + j];
#pragma unroll
            for (int i = 0; i < 8; i++)
#pragma unroll
                for (int j = 0; j < 8; j++) acc[i][j] += ra[i] * rb[j];
            if (tx == 0) {
#pragma unroll
                for (int i = 0; i < 8; i++) zacc[i] += ra[i];
            }
        }
        __syncthreads();
    }
    float* memb = mem + (size_t)bh * DHEAD * DHEAD;
#pragma unroll
    for (int i = 0; i < 8; i++)
#pragma unroll
        for (int j = 0; j < 8; j++)
            memb[(size_t)(ty * 8 + i) * DHEAD + tx * 8 + j] += acc[i][j];
    if (tx == 0) {
#pragma unroll
        for (int i = 0; i < 8; i++) Z[bh * DHEAD + ty * 8 + i] += zacc[i];
    }
}

// ============================================================================
// Host launch
// ============================================================================
extern "C" void kernel_launch(void* const* d_in, const int* in_sizes, int n_in,
                              void* d_out, int out_size)
{
    (void)in_sizes; (void)n_in; (void)out_size;
    const float* x    = (const float*)d_in[0];
    const float* Wq   = (const float*)d_in[1];
    const float* bq   = (const float*)d_in[2];
    const float* Wk   = (const float*)d_in[3];
    const float* bk   = (const float*)d_in[4];
    const float* Wv   = (const float*)d_in[5];
    const float* bv   = (const float*)d_in[6];
    const float* Wo   = (const float*)d_in[7];
    const float* bo   = (const float*)d_in[8];
    const float* beta = (const float*)d_in[9];
    float* out = (float*)d_out;

    static float *pq = nullptr, *pk = nullptr, *pv = nullptr, *pattn = nullptr,
                 *pscores = nullptr, *pmem = nullptr, *pZ = nullptr, *pWt = nullptr;
    if (!pq) {
        cudaGetSymbolAddress((void**)&pq, g_q);
        cudaGetSymbolAddress((void**)&pk, g_k);
        cudaGetSymbolAddress((void**)&pv, g_v);
        cudaGetSymbolAddress((void**)&pattn, g_attn);
        cudaGetSymbolAddress((void**)&pscores, g_scores);
        cudaGetSymbolAddress((void**)&pmem, g_mem);
        cudaGetSymbolAddress((void**)&pZ, g_Z);
        cudaGetSymbolAddress((void**)&pWt, g_Wt);
        cudaFuncSetAttribute(gemm_mma_k, cudaFuncAttributeMaxDynamicSharedMemorySize,
                             GEMM_SMEM_BYTES);
        cudaFuncSetAttribute(scores_mma_k, cudaFuncAttributeMaxDynamicSharedMemorySize,
                             GEMM_SMEM_BYTES);
        cudaFuncSetAttribute(pv_mma_k, cudaFuncAttributeMaxDynamicSharedMemorySize,
                             PV_SMEM_BYTES);
    }

    cudaMemsetAsync(pmem, 0, (size_t)NBH * DHEAD * DHEAD * sizeof(float), 0);
    cudaMemsetAsync(pZ, 0, (size_t)NBH * DHEAD * sizeof(float), 0);

    const size_t WSZ = (size_t)EMBD * EMBD;
    dim3 tgrid(EMBD / 32, EMBD / 32);
    dim3 tblk(32, 8);
    transpose_k<<<tgrid, tblk>>>(Wq, pWt + 0 * WSZ);
    transpose_k<<<tgrid, tblk>>>(Wk, pWt + 1 * WSZ);
    transpose_k<<<tgrid, tblk>>>(Wv, pWt + 2 * WSZ);
    transpose_k<<<tgrid, tblk>>>(Wo, pWt + 3 * WSZ);

    dim3 ggrid(EMBD / BN, MTOK / BM);
    gemm_mma_k<<<ggrid, 256, GEMM_SMEM_BYTES>>>(x, pWt + 0 * WSZ, bq, pq);
    gemm_mma_k<<<ggrid, 256, GEMM_SMEM_BYTES>>>(x, pWt + 1 * WSZ, bk, pk);
    gemm_mma_k<<<ggrid, 256, GEMM_SMEM_BYTES>>>(x, pWt + 2 * WSZ, bv, pv);

    rope_k<<<(MTOK * (EMBD / 2)) / 256, 256>>>(pq, pk);

    // batched (no mem dependence): scores -> softmax -> (1-g)*PV
    scores_mma_k<<<dim3(SEGL / BN, SEGL / BM, NBH * NSEG), 256, GEMM_SMEM_BYTES>>>(
        pq, pk, pscores);
    softmax_k<<<dim3(SEGL / 8, NBH * NSEG), 256>>>(pscores);
    pv_mma_k<<<dim3(SEGL / BM, NBH * NSEG), 256, PV_SMEM_BYTES>>>(
        pscores, pv, beta, pattn);

    // sequential recurrent chain
    for (int s = 0; s < NSEG; s++) {
        amem_k<<<dim3(SEGL / 64, NBH), 256>>>(pq, pmem, pZ, beta, pattn, s);
        mem_update_k<<<NBH, 256>>>(pk, pv, pmem, pZ, s);
    }

    gemm_mma_k<<<ggrid, 256, GEMM_SMEM_BYTES>>>(pattn, pWt + 3 * WSZ, bo, out);
}

// round 5
// speedup vs baseline: 3.0480x; 1.0630x over previous
#include <cuda_runtime.h>
#include <math.h>
#include <stdint.h>

// Problem constants
#define SEQ   4096
#define EMBD  2048
#define NB    4
#define NHEAD 16
#define DHEAD 128
#define NSEG  8
#define SEGL  512
#define NBH   (NB * NHEAD)          // 64
#define MTOK  (NB * SEQ)            // 16384
#define TOTAL ((size_t)MTOK * EMBD) // 33554432

// -------- device scratch ----------------------------------------------------
__device__ float g_q[TOTAL];
__device__ float g_k[TOTAL];
__device__ float g_v[TOTAL];
__device__ float g_attn[TOTAL];
__device__ float g_scores[(size_t)NBH * NSEG * SEGL * SEGL]; // 512MB
__device__ float g_mem[(size_t)NBH * DHEAD * DHEAD];
__device__ float g_Z[NBH * DHEAD];
__device__ uint32_t g_Wt[(size_t)4 * EMBD * EMBD];   // transposed+permuted tf32
__device__ uint32_t g_xp[TOTAL];                     // permuted tf32 x
__device__ uint32_t g_attnp[TOTAL];                  // permuted tf32 attn

__device__ __forceinline__ float elu1(float x) {
    return (x > 0.f) ? (x + 1.f) : expf(x);
}

__device__ __forceinline__ uint32_t smem_u32(const void* p) {
    uint32_t a;
    asm("{ .reg .u64 t; cvta.to.shared.u64 t, %1; cvt.u32.u64 %0, t; }"
        : "=r"(a) : "l"(p));
    return a;
}

__device__ __forceinline__ void cp16(uint32_t saddr, const void* g) {
    asm volatile("cp.async.cg.shared.global [%0], [%1], 16;" :: "r"(saddr), "l"(g));
}

__device__ __forceinline__ uint32_t f2tf32(float x) {
    uint32_t u;
    asm("cvt.rna.tf32.f32 %0, %1;" : "=r"(u) : "f"(x));
    return u;
}

__device__ __forceinline__ void mma_tf32(float* d, const uint32_t* a, const uint32_t* b) {
    asm volatile(
        "mma.sync.aligned.m16n8k8.row.col.f32.tf32.tf32.f32 "
        "{%0,%1,%2,%3}, {%4,%5,%6,%7}, {%8,%9}, {%0,%1,%2,%3};"
        : "+f"(d[0]), "+f"(d[1]), "+f"(d[2]), "+f"(d[3])
        : "r"(a[0]), "r"(a[1]), "r"(a[2]), "r"(a[3]), "r"(b[0]), "r"(b[1]));
}

// ============================================================================
// K0a: transpose + k-permute + tf32 convert:  Wt[n, perm(k)] = tf32(W[k, n])
//      perm within each 8-group: p -> 2*(p%4) + p/4
// ============================================================================
__global__ __launch_bounds__(256) void transpose_tf32_k(const float* __restrict__ W,
                                                        uint32_t* __restrict__ Wt)
{
    __shared__ float t[32][33];
    int bx = blockIdx.x * 32, by = blockIdx.y * 32;
    int txx = threadIdx.x;
    for (int i = threadIdx.y; i < 32; i += 8)
        t[i][txx] = W[(size_t)(by + i) * EMBD + bx + txx];
    __syncthreads();
    int p = txx & 7;
    int kcol = by + (txx & ~7) + 2 * (p & 3) + (p >> 2);
    for (int i = threadIdx.y; i < 32; i += 8)
        Wt[(size_t)(bx + i) * EMBD + kcol] = f2tf32(t[txx][i]);
}

// ============================================================================
// K0b: k-permute + tf32 convert of an activation matrix (row-major [*, EMBD])
//      each thread handles one 8-float group
// ============================================================================
__global__ __launch_bounds__(256) void perm_cvt_k(const float* __restrict__ src,
                                                  uint32_t* __restrict__ dst)
{
    size_t g8 = (size_t)blockIdx.x * 256 + threadIdx.x; // group index
    size_t base = g8 * 8;
    float4 in0 = *(const float4*)&src[base];
    float4 in1 = *(const float4*)&src[base + 4];
    uint4 o0, o1;
    o0.x = f2tf32(in0.x); o0.y = f2tf32(in1.x);
    o0.z = f2tf32(in0.y); o0.w = f2tf32(in1.y);
    o1.x = f2tf32(in0.z); o1.y = f2tf32(in1.z);
    o1.z = f2tf32(in0.w); o1.w = f2tf32(in1.w);
    *(uint4*)&dst[base] = o0;
    *(uint4*)&dst[base + 4] = o1;
}

// ============================================================================
// K1: tf32 mma.sync GEMM on pre-converted, k-permuted operands
//     C[M,N] = A[M,K] @ Bt[N,K]^T + bias.  CTA 128x128x32, 8 warps.
// ============================================================================
#define BM 128
#define BN 128
#define BK 32
#define BKP 40
#define GEMM_SMEM_BYTES (2 * (BM + BN) * BKP * 4)  // 81920 bytes

__device__ __forceinline__ void load_stage_u(const uint32_t* __restrict__ A,
                                             const uint32_t* __restrict__ Bt,
                                             int brow, int bcol, int k0,
                                             uint32_t sA, uint32_t sB, int tid)
{
#pragma unroll
    for (int it = 0; it < 4; it++) {
        int idx = tid + it * 256;
        int row = idx >> 3, c4 = idx & 7;
        cp16(sA + (row * BKP + c4 * 4) * 4,
             A + (size_t)(brow + row) * EMBD + k0 + c4 * 4);
    }
#pragma unroll
    for (int it = 0; it < 4; it++) {
        int idx = tid + it * 256;
        int row = idx >> 3, c4 = idx & 7;
        cp16(sB + (row * BKP + c4 * 4) * 4,
             Bt + (size_t)(bcol + row) * EMBD + k0 + c4 * 4);
    }
    asm volatile("cp.async.commit_group;" ::: "memory");
}

__global__ __launch_bounds__(256) void gemm_mma_k(
    const uint32_t* __restrict__ A, const uint32_t* __restrict__ Bt,
    const float* __restrict__ bias, float* __restrict__ C)
{
    extern __shared__ uint32_t dsm_u[];
    uint32_t* Ash = dsm_u;
    uint32_t* Bsh = dsm_u + 2 * BM * BKP;
    uint32_t sAu = smem_u32(Ash);
    uint32_t sBu = smem_u32(Bsh);

    const int tid = threadIdx.x;
    const int wid = tid >> 5;
    const int lane = tid & 31;
    const int lr = lane >> 2;
    const int lc = lane & 3;
    const int wm = (wid >> 2) * 64;
    const int wn = (wid & 3) * 32;

    int brow = blockIdx.y * BM;
    int bcol = blockIdx.x * BN;

    float acc[4][4][4];
#pragma unroll
    for (int mt = 0; mt < 4; mt++)
#pragma unroll
        for (int nt = 0; nt < 4; nt++)
#pragma unroll
            for (int r = 0; r < 4; r++) acc[mt][nt][r] = 0.f;

    load_stage_u(A, Bt, brow, bcol, 0, sAu, sBu, tid);
    load_stage_u(A, Bt, brow, bcol, BK, sAu + BM * BKP * 4, sBu + BN * BKP * 4, tid);

    const int NIT = EMBD / BK;
    for (int it = 0; it < NIT; it++) {
        int s = it & 1;
        if (it == NIT - 1) asm volatile("cp.async.wait_group 0;" ::: "memory");
        else               asm volatile("cp.async.wait_group 1;" ::: "memory");
        __syncthreads();

        const uint32_t* As = Ash + s * BM * BKP;
        const uint32_t* Bs = Bsh + s * BN * BKP;

#pragma unroll
        for (int kb = 0; kb < BK; kb += 8) {
            uint32_t af[4][4], bf[4][2];
#pragma unroll
            for (int mt = 0; mt < 4; mt++) {
                int r = wm + mt * 16 + lr;
                uint2 a0 = *(const uint2*)&As[r * BKP + kb + 2 * lc];
                uint2 a1 = *(const uint2*)&As[(r + 8) * BKP + kb + 2 * lc];
                af[mt][0] = a0.x; af[mt][2] = a0.y;
                af[mt][1] = a1.x; af[mt][3] = a1.y;
            }
#pragma unroll
            for (int nt = 0; nt < 4; nt++) {
                int cN = wn + nt * 8 + lr;
                uint2 b = *(const uint2*)&Bs[cN * BKP + kb + 2 * lc];
                bf[nt][0] = b.x; bf[nt][1] = b.y;
            }
#pragma unroll
            for (int mt = 0; mt < 4; mt++)
#pragma unroll
                for (int nt = 0; nt < 4; nt++)
                    mma_tf32(acc[mt][nt], af[mt], bf[nt]);
        }
        __syncthreads();

        if (it + 2 < NIT) {
            load_stage_u(A, Bt, brow, bcol, (it + 2) * BK,
                         sAu + s * BM * BKP * 4, sBu + s * BN * BKP * 4, tid);
        }
    }

#pragma unroll
    for (int nt = 0; nt < 4; nt++) {
        int col = bcol + wn + nt * 8 + 2 * lc;
        float b0 = bias[col], b1 = bias[col + 1];
#pragma unroll
        for (int mt = 0; mt < 4; mt++) {
            int row = brow + wm + mt * 16 + lr;
            float2 v0 = make_float2(acc[mt][nt][0] + b0, acc[mt][nt][1] + b1);
            float2 v1 = make_float2(acc[mt][nt][2] + b0, acc[mt][nt][3] + b1);
            *(float2*)&C[(size_t)row * EMBD + col] = v0;
            *(float2*)&C[(size_t)(row + 8) * EMBD + col] = v1;
        }
    }
}

// ============================================================================
// K2: RoPE
// ============================================================================
__global__ __launch_bounds__(256) void rope_k(float* __restrict__ q, float* __restrict__ k)
{
    size_t idx = (size_t)blockIdx.x * 256 + threadIdx.x;
    int rr = (int)(idx >> 10);
    int i = (int)(idx & 1023);
    int t = rr & (SEQ - 1);
    float inv = powf(10000.0f, -(float)(2 * i) * (1.0f / 2048.0f));
    float ang = (float)t * inv;
    float c = cosf(ang), s = sinf(ang);
    size_t base = (size_t)rr * EMBD + 2 * i;
    float a = q[base], b = q[base + 1];
    q[base] = a * c - b * s;
    q[base + 1] = a * s + b * c;
    a = k[base]; b = k[base + 1];
    k[base] = a * c - b * s;
    k[base + 1] = a * s + b * c;
}

// ============================================================================
// K3: batched scores:  S = scale * q_seg @ k_seg^T  (tf32 mma, cvt in-loop)
// ============================================================================
#define SBKP 36
__global__ __launch_bounds__(256) void scores_mma_k(
    const float* __restrict__ qb, const float* __restrict__ kb,
    float* __restrict__ S)
{
    extern __shared__ float dsm[];
    float* Ash = dsm;
    float* Bsh = dsm + 2 * BM * SBKP;
    uint32_t sAu = smem_u32(Ash);
    uint32_t sBu = smem_u32(Bsh);

    const float scale = 0.08838834764831845f;
    const int tid = threadIdx.x;
    const int wid = tid >> 5;
    const int lane = tid & 31;
    const int lr = lane >> 2;
    const int lc = lane & 3;
    const int wm = (wid >> 2) * 64;
    const int wn = (wid & 3) * 32;

    int bhs = blockIdx.z;
    size_t segbase = ((size_t)bhs) << 16;
    const float* A = qb + segbase;
    const float* B = kb + segbase;
    int brow = blockIdx.y * BM;
    int bcol = blockIdx.x * BN;

    float acc[4][4][4];
#pragma unroll
    for (int mt = 0; mt < 4; mt++)
#pragma unroll
        for (int nt = 0; nt < 4; nt++)
#pragma unroll
            for (int r = 0; r < 4; r++) acc[mt][nt][r] = 0.f;

    auto load_st = [&](int k0, uint32_t sA, uint32_t sB) {
#pragma unroll
        for (int it = 0; it < 4; it++) {
            int idx = tid + it * 256;
            int row = idx >> 3, c4 = idx & 7;
            cp16(sA + (row * SBKP + c4 * 4) * 4,
                 A + (size_t)(brow + row) * DHEAD + k0 + c4 * 4);
        }
#pragma unroll
        for (int it = 0; it < 4; it++) {
            int idx = tid + it * 256;
            int row = idx >> 3, c4 = idx & 7;
            cp16(sB + (row * SBKP + c4 * 4) * 4,
                 B + (size_t)(bcol + row) * DHEAD + k0 + c4 * 4);
        }
        asm volatile("cp.async.commit_group;" ::: "memory");
    };

    load_st(0, sAu, sBu);
    load_st(BK, sAu + BM * SBKP * 4, sBu + BN * SBKP * 4);

    const int NIT = DHEAD / BK;
    for (int it = 0; it < NIT; it++) {
        int s = it & 1;
        if (it == NIT - 1) asm volatile("cp.async.wait_group 0;" ::: "memory");
        else               asm volatile("cp.async.wait_group 1;" ::: "memory");
        __syncthreads();

        const float* As = Ash + s * BM * SBKP;
        const float* Bs = Bsh + s * BN * SBKP;
#pragma unroll
        for (int kb = 0; kb < BK; kb += 8) {
            uint32_t af[4][4], bf[4][2];
#pragma unroll
            for (int mt = 0; mt < 4; mt++) {
                int r = wm + mt * 16 + lr;
                af[mt][0] = f2tf32(As[r * SBKP + kb + lc]);
                af[mt][1] = f2tf32(As[(r + 8) * SBKP + kb + lc]);
                af[mt][2] = f2tf32(As[r * SBKP + kb + lc + 4]);
                af[mt][3] = f2tf32(As[(r + 8) * SBKP + kb + lc + 4]);
            }
#pragma unroll
            for (int nt = 0; nt < 4; nt++) {
                int cN = wn + nt * 8 + lr;
                bf[nt][0] = f2tf32(Bs[cN * SBKP + kb + lc]);
                bf[nt][1] = f2tf32(Bs[cN * SBKP + kb + lc + 4]);
            }
#pragma unroll
            for (int mt = 0; mt < 4; mt++)
#pragma unroll
                for (int nt = 0; nt < 4; nt++)
                    mma_tf32(acc[mt][nt], af[mt], bf[nt]);
        }
        __syncthreads();
        if (it + 2 < NIT)
            load_st((it + 2) * BK, sAu + s * BM * SBKP * 4, sBu + s * BN * SBKP * 4);
    }

    float* Sb = S + (size_t)bhs * SEGL * SEGL;
#pragma unroll
    for (int nt = 0; nt < 4; nt++) {
        int col = bcol + wn + nt * 8 + 2 * lc;
#pragma unroll
        for (int mt = 0; mt < 4; mt++) {
            int row = brow + wm + mt * 16 + lr;
            float2 v0 = make_float2(acc[mt][nt][0] * scale, acc[mt][nt][1] * scale);
            float2 v1 = make_float2(acc[mt][nt][2] * scale, acc[mt][nt][3] * scale);
            *(float2*)&Sb[(size_t)row * SEGL + col] = v0;
            *(float2*)&Sb[(size_t)(row + 8) * SEGL + col] = v1;
        }
    }
}
#define SCORES_SMEM_BYTES (2 * (BM + BN) * SBKP * 4)

// ============================================================================
// K4: batched row softmax
// ============================================================================
__global__ __launch_bounds__(256) void softmax_k(float* __restrict__ S)
{
    int bhs = blockIdx.y;
    int row = blockIdx.x * 8 + (threadIdx.x >> 5);
    int lane = threadIdx.x & 31;
    float* r = S + ((size_t)bhs * SEGL + row) * SEGL;
    float vals[16];
    float mx = -1e30f;
#pragma unroll
    for (int i = 0; i < 16; i++) {
        vals[i] = r[lane + 32 * i];
        mx = fmaxf(mx, vals[i]);
    }
#pragma unroll
    for (int o = 16; o > 0; o >>= 1) mx = fmaxf(mx, __shfl_xor_sync(0xffffffffu, mx, o));
    float sum = 0.f;
#pragma unroll
    for (int i = 0; i < 16; i++) {
        vals[i] = expf(vals[i] - mx);
        sum += vals[i];
    }
#pragma unroll
    for (int o = 16; o > 0; o >>= 1) sum += __shfl_xor_sync(0xffffffffu, sum, o);
    float inv = 1.0f / sum;
#pragma unroll
    for (int i = 0; i < 16; i++) r[lane + 32 * i] = vals[i] * inv;
}

// ============================================================================
// K5: batched PV: attn = (1-g) * P @ v
// ============================================================================
#define VEP 136
#define PV_SMEM_BYTES ((2 * BM * SBKP + 2 * BK * VEP) * 4)

__global__ __launch_bounds__(256) void pv_mma_k(
    const float* __restrict__ P, const float* __restrict__ vb,
    const float* __restrict__ beta, float* __restrict__ attnb)
{
    extern __shared__ float dsm[];
    float* Ash = dsm;
    float* Vsh = dsm + 2 * BM * SBKP;
    uint32_t sAu = smem_u32(Ash);
    uint32_t sVu = smem_u32(Vsh);

    const int tid = threadIdx.x;
    const int wid = tid >> 5;
    const int lane = tid & 31;
    const int lr = lane >> 2;
    const int lc = lane & 3;
    const int wm = (wid >> 2) * 64;
    const int wn = (wid & 3) * 32;

    int bhs = blockIdx.y;
    size_t segbase = ((size_t)bhs) << 16;
    const float* Pseg = P + (size_t)bhs * SEGL * SEGL;
    const float* vseg = vb + segbase;
    int brow = blockIdx.x * BM;
    float gm1 = 1.0f - 1.0f / (1.0f + expf(-beta[0]));

    float acc[4][4][4];
#pragma unroll
    for (int mt = 0; mt < 4; mt++)
#pragma unroll
        for (int nt = 0; nt < 4; nt++)
#pragma unroll
            for (int r = 0; r < 4; r++) acc[mt][nt][r] = 0.f;

    auto load_st = [&](int k0, uint32_t sA, uint32_t sV) {
#pragma unroll
        for (int it = 0; it < 4; it++) {
            int idx = tid + it * 256;
            int row = idx >> 3, c4 = idx & 7;
            cp16(sA + (row * SBKP + c4 * 4) * 4,
                 Pseg + (size_t)(brow + row) * SEGL + k0 + c4 * 4);
        }
#pragma unroll
        for (int it = 0; it < 4; it++) {
            int idx = tid + it * 256;
            int row = idx >> 5, c4 = idx & 31;
            cp16(sV + (row * VEP + c4 * 4) * 4,
                 vseg + (size_t)(k0 + row) * DHEAD + c4 * 4);
        }
        asm volatile("cp.async.commit_group;" ::: "memory");
    };

    load_st(0, sAu, sVu);
    load_st(BK, sAu + BM * SBKP * 4, sVu + BK * VEP * 4);

    const int NIT = SEGL / BK;
    for (int it = 0; it < NIT; it++) {
        int s = it & 1;
        if (it == NIT - 1) asm volatile("cp.async.wait_group 0;" ::: "memory");
        else               asm volatile("cp.async.wait_group 1;" ::: "memory");
        __syncthreads();

        const float* As = Ash + s * BM * SBKP;
        const float* Vs = Vsh + s * BK * VEP;
#pragma unroll
        for (int kb = 0; kb < BK; kb += 8) {
            uint32_t af[4][4], bf[4][2];
#pragma unroll
            for (int mt = 0; mt < 4; mt++) {
                int r = wm + mt * 16 + lr;
                af[mt][0] = f2tf32(As[r * SBKP + kb + lc]);
                af[mt][1] = f2tf32(As[(r + 8) * SBKP + kb + lc]);
                af[mt][2] = f2tf32(As[r * SBKP + kb + lc + 4]);
                af[mt][3] = f2tf32(As[(r + 8) * SBKP + kb + lc + 4]);
            }
#pragma unroll
            for (int nt = 0; nt < 4; nt++) {
                int cN = wn + nt * 8 + lr;
                bf[nt][0] = f2tf32(Vs[(kb + lc) * VEP + cN]);
                bf[nt][1] = f2tf32(Vs[(kb + lc + 4) * VEP + cN]);
            }
#pragma unroll
            for (int mt = 0; mt < 4; mt++)
#pragma unroll
                for (int nt = 0; nt < 4; nt++)
                    mma_tf32(acc[mt][nt], af[mt], bf[nt]);
        }
        __syncthreads();
        if (it + 2 < NIT)
            load_st((it + 2) * BK, sAu + s * BM * SBKP * 4, sVu + s * BK * VEP * 4);
    }

#pragma unroll
    for (int nt = 0; nt < 4; nt++) {
        int col = wn + nt * 8 + 2 * lc;
#pragma unroll
        for (int mt = 0; mt < 4; mt++) {
            int row = brow + wm + mt * 16 + lr;
            float2 v0 = make_float2(acc[mt][nt][0] * gm1, acc[mt][nt][1] * gm1);
            float2 v1 = make_float2(acc[mt][nt][2] * gm1, acc[mt][nt][3] * gm1);
            *(float2*)&attnb[segbase + (size_t)row * DHEAD + col] = v0;
            *(float2*)&attnb[segbase + (size_t)(row + 8) * DHEAD + col] = v1;
        }
    }
}

// ============================================================================
// K6: A_mem accumulate: attn += g * (sq@mem)/(rowsum(sq)*Z + 1e-6)
// ============================================================================
__global__ __launch_bounds__(256) void amem_k(
    const float* __restrict__ qb, const float* __restrict__ mem,
    const float* __restrict__ Z, const float* __restrict__ beta,
    float* __restrict__ attnb, int s)
{
    int bh = blockIdx.y;
    int l0 = blockIdx.x * 64;
    size_t segbase = ((size_t)(bh * NSEG + s)) << 16;
    const float* qseg = qb + segbase;
    const float* memb = mem + (size_t)bh * DHEAD * DHEAD;
    const float* Zb = Z + bh * DHEAD;
    float g = 1.0f / (1.0f + expf(-beta[0]));

    __shared__ float As[16][64];
    __shared__ float Bs[16][128];
    __shared__ float rowsum[64];
    __shared__ float Zs[128];

    int tid = threadIdx.x;
    int tx = tid & 15, ty = tid >> 4;

    {
        int r = tid >> 2, qd = (tid & 3) * 32;
        float sm = 0.f;
#pragma unroll 8
        for (int d = 0; d < 32; d++)
            sm += elu1(qseg[(size_t)(l0 + r) * DHEAD + qd + d]);
        sm += __shfl_xor_sync(0xffffffffu, sm, 1);
        sm += __shfl_xor_sync(0xffffffffu, sm, 2);
        if ((tid & 3) == 0) rowsum[r] = sm;
    }
    if (tid < 128) Zs[tid] = Zb[tid];

    int ar = tid >> 2, ac4 = tid & 3;
    int br = tid >> 5, bc4 = tid & 31;

    float acc[4][8];
#pragma unroll
    for (int i = 0; i < 4; i++)
#pragma unroll
        for (int j = 0; j < 8; j++) acc[i][j] = 0.f;

    for (int k0 = 0; k0 < DHEAD; k0 += 16) {
        float4 av = *(const float4*)&qseg[(size_t)(l0 + ar) * DHEAD + k0 + ac4 * 4];
        As[ac4 * 4 + 0][ar] = elu1(av.x); As[ac4 * 4 + 1][ar] = elu1(av.y);
        As[ac4 * 4 + 2][ar] = elu1(av.z); As[ac4 * 4 + 3][ar] = elu1(av.w);
#pragma unroll
        for (int i = 0; i < 2; i++) {
            float4 bv = *(const float4*)&memb[(size_t)(k0 + br + i * 8) * DHEAD + bc4 * 4];
            *(float4*)&Bs[br + i * 8][bc4 * 4] = bv;
        }
        __syncthreads();
#pragma unroll
        for (int kk = 0; kk < 16; kk++) {
            float ra[4], rb[8];
#pragma unroll
            for (int i = 0; i < 4; i++) ra[i] = As[kk][ty * 4 + i];
#pragma unroll
            for (int j = 0; j < 8; j++) rb[j] = Bs[kk][tx * 8 + j];
#pragma unroll
            for (int i = 0; i < 4; i++)
#pragma unroll
                for (int j = 0; j < 8; j++) acc[i][j] += ra[i] * rb[j];
        }
        __syncthreads();
    }

#pragma unroll
    for (int i = 0; i < 4; i++) {
        float rs = rowsum[ty * 4 + i];
        size_t rbase = segbase + (size_t)(l0 + ty * 4 + i) * DHEAD;
#pragma unroll
        for (int j = 0; j < 8; j++) {
            float* dst = &attnb[rbase + tx * 8 + j];
            *dst += g * acc[i][j] / (rs * Zs[tx * 8 + j] + 1e-6f);
        }
    }
}

// ============================================================================
// K7: mem[d,e] += sum_l sk[l,d]*v[l,e];  Z[d] += sum_l sk[l,d]
// ============================================================================
__global__ __launch_bounds__(256) void mem_update_k(
    const float* __restrict__ kb, const float* __restrict__ vb,
    float* __restrict__ mem, float* __restrict__ Z, int s)
{
    int bh = blockIdx.x;
    size_t segbase = ((size_t)(bh * NSEG + s)) << 16;
    const float* kseg = kb + segbase;
    const float* vseg = vb + segbase;

    __shared__ float As[16][128];
    __shared__ float Bs[16][128];
    int tid = threadIdx.x;
    int tx = tid & 15, ty = tid >> 4;
    int br = tid >> 5, bc4 = tid & 31;

    float acc[8][8];
    float zacc[8];
#pragma unroll
    for (int i = 0; i < 8; i++) {
        zacc[i] = 0.f;
#pragma unroll
        for (int j = 0; j < 8; j++) acc[i][j] = 0.f;
    }

    for (int l0 = 0; l0 < SEGL; l0 += 16) {
#pragma unroll
        for (int i = 0; i < 2; i++) {
            int r = br + i * 8;
            float4 kv = *(const float4*)&kseg[(size_t)(l0 + r) * DHEAD + bc4 * 4];
            As[r][bc4 * 4 + 0] = elu1(kv.x); As[r][bc4 * 4 + 1] = elu1(kv.y);
            As[r][bc4 * 4 + 2] = elu1(kv.z); As[r][bc4 * 4 + 3] = elu1(kv.w);
            float4 vv = *(const float4*)&vseg[(size_t)(l0 + r) * DHEAD + bc4 * 4];
            *(float4*)&Bs[r][bc4 * 4] = vv;
        }
        __syncthreads();
#pragma unroll
        for (int kk = 0; kk < 16; kk++) {
            float ra[8], rb[8];
#pragma unroll
            for (int i = 0; i < 8; i++) ra[i] = As[kk][ty * 8 + i];
#pragma unroll
            for (int j = 0; j < 8; j++) rb[j] = Bs[kk][tx * 8 + j];
#pragma unroll
            for (int i = 0; i < 8; i++)
#pragma unroll
                for (int j = 0; j < 8; j++) acc[i][j] += ra[i] * rb[j];
            if (tx == 0) {
#pragma unroll
                for (int i = 0; i < 8; i++) zacc[i] += ra[i];
            }
        }
        __syncthreads();
    }
    float* memb = mem + (size_t)bh * DHEAD * DHEAD;
#pragma unroll
    for (int i = 0; i < 8; i++)
#pragma unroll
        for (int j = 0; j < 8; j++)
            memb[(size_t)(ty * 8 + i) * DHEAD + tx * 8 + j] += acc[i][j];
    if (tx == 0) {
#pragma unroll
        for (int i = 0; i < 8; i++) Z[bh * DHEAD + ty * 8 + i] += zacc[i];
    }
}

// ============================================================================
// Host launch
// ============================================================================
extern "C" void kernel_launch(void* const* d_in, const int* in_sizes, int n_in,
                              void* d_out, int out_size)
{
    (void)in_sizes; (void)n_in; (void)out_size;
    const float* x    = (const float*)d_in[0];
    const float* Wq   = (const float*)d_in[1];
    const float* bq   = (const float*)d_in[2];
    const float* Wk   = (const float*)d_in[3];
    const float* bk   = (const float*)d_in[4];
    const float* Wv   = (const float*)d_in[5];
    const float* bv   = (const float*)d_in[6];
    const float* Wo   = (const float*)d_in[7];
    const float* bo   = (const float*)d_in[8];
    const float* beta = (const float*)d_in[9];
    float* out = (float*)d_out;

    static float *pq = nullptr, *pk = nullptr, *pv = nullptr, *pattn = nullptr,
                 *pscores = nullptr, *pmem = nullptr, *pZ = nullptr;
    static uint32_t *pWt = nullptr, *pxp = nullptr, *pattnp = nullptr;
    if (!pq) {
        cudaGetSymbolAddress((void**)&pq, g_q);
        cudaGetSymbolAddress((void**)&pk, g_k);
        cudaGetSymbolAddress((void**)&pv, g_v);
        cudaGetSymbolAddress((void**)&pattn, g_attn);
        cudaGetSymbolAddress((void**)&pscores, g_scores);
        cudaGetSymbolAddress((void**)&pmem, g_mem);
        cudaGetSymbolAddress((void**)&pZ, g_Z);
        cudaGetSymbolAddress((void**)&pWt, g_Wt);
        cudaGetSymbolAddress((void**)&pxp, g_xp);
        cudaGetSymbolAddress((void**)&pattnp, g_attnp);
        cudaFuncSetAttribute(gemm_mma_k, cudaFuncAttributeMaxDynamicSharedMemorySize,
                             GEMM_SMEM_BYTES);
        cudaFuncSetAttribute(scores_mma_k, cudaFuncAttributeMaxDynamicSharedMemorySize,
                             SCORES_SMEM_BYTES);
        cudaFuncSetAttribute(pv_mma_k, cudaFuncAttributeMaxDynamicSharedMemorySize,
                             PV_SMEM_BYTES);
    }

    cudaMemsetAsync(pmem, 0, (size_t)NBH * DHEAD * DHEAD * sizeof(float), 0);
    cudaMemsetAsync(pZ, 0, (size_t)NBH * DHEAD * sizeof(float), 0);

    const size_t WSZ = (size_t)EMBD * EMBD;
    dim3 tgrid(EMBD / 32, EMBD / 32);
    dim3 tblk(32, 8);
    transpose_tf32_k<<<tgrid, tblk>>>(Wq, pWt + 0 * WSZ);
    transpose_tf32_k<<<tgrid, tblk>>>(Wk, pWt + 1 * WSZ);
    transpose_tf32_k<<<tgrid, tblk>>>(Wv, pWt + 2 * WSZ);
    transpose_tf32_k<<<tgrid, tblk>>>(Wo, pWt + 3 * WSZ);

    perm_cvt_k<<<(int)(TOTAL / 8 / 256), 256>>>(x, pxp);

    dim3 ggrid(EMBD / BN, MTOK / BM);
    gemm_mma_k<<<ggrid, 256, GEMM_SMEM_BYTES>>>(pxp, pWt + 0 * WSZ, bq, pq);
    gemm_mma_k<<<ggrid, 256, GEMM_SMEM_BYTES>>>(pxp, pWt + 1 * WSZ, bk, pk);
    gemm_mma_k<<<ggrid, 256, GEMM_SMEM_BYTES>>>(pxp, pWt + 2 * WSZ, bv, pv);

    rope_k<<<(MTOK * (EMBD / 2)) / 256, 256>>>(pq, pk);

    // batched (no mem dependence): scores -> softmax -> (1-g)*PV
    scores_mma_k<<<dim3(SEGL / BN, SEGL / BM, NBH * NSEG), 256, SCORES_SMEM_BYTES>>>(
        pq, pk, pscores);
    softmax_k<<<dim3(SEGL / 8, NBH * NSEG), 256>>>(pscores);
    pv_mma_k<<<dim3(SEGL / BM, NBH * NSEG), 256, PV_SMEM_BYTES>>>(
        pscores, pv, beta, pattn);

    // sequential recurrent chain
    for (int s = 0; s < NSEG; s++) {
        amem_k<<<dim3(SEGL / 64, NBH), 256>>>(pq, pmem, pZ, beta, pattn, s);
        mem_update_k<<<NBH, 256>>>(pk, pv, pmem, pZ, s);
    }

    perm_cvt_k<<<(int)(TOTAL / 8 / 256), 256>>>(pattn, pattnp);
    gemm_mma_k<<<ggrid, 256, GEMM_SMEM_BYTES>>>(pattnp, pWt + 3 * WSZ, bo, out);
}

// round 6
// speedup vs baseline: 3.3430x; 1.0968x over previous
#include <cuda_runtime.h>
#include <math.h>
#include <stdint.h>

// Problem constants
#define SEQ   4096
#define EMBD  2048
#define NB    4
#define NHEAD 16
#define DHEAD 128
#define NSEG  8
#define SEGL  512
#define NBH   (NB * NHEAD)          // 64
#define MTOK  (NB * SEQ)            // 16384
#define TOTAL ((size_t)MTOK * EMBD) // 33554432

// -------- device scratch ----------------------------------------------------
__device__ float g_q[TOTAL];
__device__ float g_k[TOTAL];
__device__ float g_v[TOTAL];
__device__ float g_attn[TOTAL];
__device__ float g_scores[(size_t)NBH * NSEG * SEGL * SEGL]; // 512MB
__device__ float g_memseg[(size_t)NBH * NSEG * DHEAD * DHEAD]; // 33.5MB
__device__ float g_Zseg[NBH * NSEG * DHEAD];
__device__ uint32_t g_Wt[(size_t)4 * EMBD * EMBD];   // transposed+permuted tf32
__device__ uint32_t g_xp[TOTAL];                     // permuted tf32 x
__device__ uint32_t g_attnp[TOTAL];                  // permuted tf32 attn

__device__ __forceinline__ float elu1(float x) {
    return (x > 0.f) ? (x + 1.f) : expf(x);
}

__device__ __forceinline__ uint32_t smem_u32(const void* p) {
    uint32_t a;
    asm("{ .reg .u64 t; cvta.to.shared.u64 t, %1; cvt.u32.u64 %0, t; }"
        : "=r"(a) : "l"(p));
    return a;
}

__device__ __forceinline__ void cp16(uint32_t saddr, const void* g) {
    asm volatile("cp.async.cg.shared.global [%0], [%1], 16;" :: "r"(saddr), "l"(g));
}

__device__ __forceinline__ uint32_t f2tf32(float x) {
    uint32_t u;
    asm("cvt.rna.tf32.f32 %0, %1;" : "=r"(u) : "f"(x));
    return u;
}

__device__ __forceinline__ void mma_tf32(float* d, const uint32_t* a, const uint32_t* b) {
    asm volatile(
        "mma.sync.aligned.m16n8k8.row.col.f32.tf32.tf32.f32 "
        "{%0,%1,%2,%3}, {%4,%5,%6,%7}, {%8,%9}, {%0,%1,%2,%3};"
        : "+f"(d[0]), "+f"(d[1]), "+f"(d[2]), "+f"(d[3])
        : "r"(a[0]), "r"(a[1]), "r"(a[2]), "r"(a[3]), "r"(b[0]), "r"(b[1]));
}

// ============================================================================
// K0a: transpose + k-permute + tf32 convert:  Wt[n, perm(k)] = tf32(W[k, n])
// ============================================================================
__global__ __launch_bounds__(256) void transpose_tf32_k(const float* __restrict__ W,
                                                        uint32_t* __restrict__ Wt)
{
    __shared__ float t[32][33];
    int bx = blockIdx.x * 32, by = blockIdx.y * 32;
    int txx = threadIdx.x;
    for (int i = threadIdx.y; i < 32; i += 8)
        t[i][txx] = W[(size_t)(by + i) * EMBD + bx + txx];
    __syncthreads();
    int p = txx & 7;
    int kcol = by + (txx & ~7) + 2 * (p & 3) + (p >> 2);
    for (int i = threadIdx.y; i < 32; i += 8)
        Wt[(size_t)(bx + i) * EMBD + kcol] = f2tf32(t[txx][i]);
}

// ============================================================================
// K0b: k-permute + tf32 convert of an activation matrix
// ============================================================================
__global__ __launch_bounds__(256) void perm_cvt_k(const float* __restrict__ src,
                                                  uint32_t* __restrict__ dst)
{
    size_t g8 = (size_t)blockIdx.x * 256 + threadIdx.x;
    size_t base = g8 * 8;
    float4 in0 = *(const float4*)&src[base];
    float4 in1 = *(const float4*)&src[base + 4];
    uint4 o0, o1;
    o0.x = f2tf32(in0.x); o0.y = f2tf32(in1.x);
    o0.z = f2tf32(in0.y); o0.w = f2tf32(in1.y);
    o1.x = f2tf32(in0.z); o1.y = f2tf32(in1.z);
    o1.z = f2tf32(in0.w); o1.w = f2tf32(in1.w);
    *(uint4*)&dst[base] = o0;
    *(uint4*)&dst[base + 4] = o1;
}

// ============================================================================
// K1: tf32 mma.sync GEMM, CTA 128x256x32, 3-stage pipeline, warp tile 64x64
// ============================================================================
#define BM 128
#define BN 256
#define BK 32
#define BKP 40
#define NSTG 3
#define STG_U ((BM + BN) * BKP)                 // uint32 per stage = 15360
#define GEMM_SMEM_BYTES (NSTG * STG_U * 4)      // 184320

__device__ __forceinline__ void load_stage_u(const uint32_t* __restrict__ A,
                                             const uint32_t* __restrict__ Bt,
                                             int brow, int bcol, int k0,
                                             uint32_t sA, uint32_t sB, int tid)
{
#pragma unroll
    for (int it = 0; it < 4; it++) {        // A: 128 x 32
        int idx = tid + it * 256;
        int row = idx >> 3, c4 = idx & 7;
        cp16(sA + (row * BKP + c4 * 4) * 4,
             A + (size_t)(brow + row) * EMBD + k0 + c4 * 4);
    }
#pragma unroll
    for (int it = 0; it < 8; it++) {        // B: 256 x 32
        int idx = tid + it * 256;
        int row = idx >> 3, c4 = idx & 7;
        cp16(sB + (row * BKP + c4 * 4) * 4,
             Bt + (size_t)(bcol + row) * EMBD + k0 + c4 * 4);
    }
    asm volatile("cp.async.commit_group;" ::: "memory");
}

__global__ __launch_bounds__(256) void gemm_mma_k(
    const uint32_t* __restrict__ A, const uint32_t* __restrict__ Bt,
    const float* __restrict__ bias, float* __restrict__ C)
{
    extern __shared__ uint32_t dsm_u[];
    uint32_t sbase = smem_u32(dsm_u);

    const int tid = threadIdx.x;
    const int wid = tid >> 5;
    const int lane = tid & 31;
    const int lr = lane >> 2;
    const int lc = lane & 3;
    const int wm = (wid >> 2) * 64;   // 0 / 64
    const int wn = (wid & 3) * 64;    // 0..192

    int brow = blockIdx.y * BM;
    int bcol = blockIdx.x * BN;

    float acc[4][8][4];
#pragma unroll
    for (int mt = 0; mt < 4; mt++)
#pragma unroll
        for (int nt = 0; nt < 8; nt++)
#pragma unroll
            for (int r = 0; r < 4; r++) acc[mt][nt][r] = 0.f;

    uint32_t sA[NSTG], sB[NSTG];
#pragma unroll
    for (int s = 0; s < NSTG; s++) {
        sA[s] = sbase + s * STG_U * 4;
        sB[s] = sA[s] + BM * BKP * 4;
    }

    load_stage_u(A, Bt, brow, bcol, 0 * BK, sA[0], sB[0], tid);
    load_stage_u(A, Bt, brow, bcol, 1 * BK, sA[1], sB[1], tid);
    load_stage_u(A, Bt, brow, bcol, 2 * BK, sA[2], sB[2], tid);

    const int NIT = EMBD / BK; // 64
    for (int it = 0; it < NIT; it++) {
        if (it < NIT - 2)       asm volatile("cp.async.wait_group 2;" ::: "memory");
        else if (it == NIT - 2) asm volatile("cp.async.wait_group 1;" ::: "memory");
        else                    asm volatile("cp.async.wait_group 0;" ::: "memory");
        __syncthreads();

        int s = it % NSTG;
        const uint32_t* As = (const uint32_t*)(dsm_u + (size_t)s * STG_U);
        const uint32_t* Bs = As + BM * BKP;

#pragma unroll
        for (int kb = 0; kb < BK; kb += 8) {
            uint32_t af[4][4], bf[8][2];
#pragma unroll
            for (int mt = 0; mt < 4; mt++) {
                int r = wm + mt * 16 + lr;
                uint2 a0 = *(const uint2*)&As[r * BKP + kb + 2 * lc];
                uint2 a1 = *(const uint2*)&As[(r + 8) * BKP + kb + 2 * lc];
                af[mt][0] = a0.x; af[mt][2] = a0.y;
                af[mt][1] = a1.x; af[mt][3] = a1.y;
            }
#pragma unroll
            for (int nt = 0; nt < 8; nt++) {
                int cN = wn + nt * 8 + lr;
                uint2 b = *(const uint2*)&Bs[cN * BKP + kb + 2 * lc];
                bf[nt][0] = b.x; bf[nt][1] = b.y;
            }
#pragma unroll
            for (int mt = 0; mt < 4; mt++)
#pragma unroll
                for (int nt = 0; nt < 8; nt++)
                    mma_tf32(acc[mt][nt], af[mt], bf[nt]);
        }
        __syncthreads();

        if (it + NSTG < NIT)
            load_stage_u(A, Bt, brow, bcol, (it + NSTG) * BK, sA[s], sB[s], tid);
    }

#pragma unroll
    for (int nt = 0; nt < 8; nt++) {
        int col = bcol + wn + nt * 8 + 2 * lc;
        float b0 = bias[col], b1 = bias[col + 1];
#pragma unroll
        for (int mt = 0; mt < 4; mt++) {
            int row = brow + wm + mt * 16 + lr;
            float2 v0 = make_float2(acc[mt][nt][0] + b0, acc[mt][nt][1] + b1);
            float2 v1 = make_float2(acc[mt][nt][2] + b0, acc[mt][nt][3] + b1);
            *(float2*)&C[(size_t)row * EMBD + col] = v0;
            *(float2*)&C[(size_t)(row + 8) * EMBD + col] = v1;
        }
    }
}

// ============================================================================
// K2: RoPE
// ============================================================================
__global__ __launch_bounds__(256) void rope_k(float* __restrict__ q, float* __restrict__ k)
{
    size_t idx = (size_t)blockIdx.x * 256 + threadIdx.x;
    int rr = (int)(idx >> 10);
    int i = (int)(idx & 1023);
    int t = rr & (SEQ - 1);
    float inv = powf(10000.0f, -(float)(2 * i) * (1.0f / 2048.0f));
    float ang = (float)t * inv;
    float c = cosf(ang), s = sinf(ang);
    size_t base = (size_t)rr * EMBD + 2 * i;
    float a = q[base], b = q[base + 1];
    q[base] = a * c - b * s;
    q[base + 1] = a * s + b * c;
    a = k[base]; b = k[base + 1];
    k[base] = a * c - b * s;
    k[base + 1] = a * s + b * c;
}

// ============================================================================
// K3: batched scores:  S = scale * q_seg @ k_seg^T  (tf32 mma)
// ============================================================================
#define SBM 128
#define SBN 128
#define SBKP 36
__global__ __launch_bounds__(256) void scores_mma_k(
    const float* __restrict__ qb, const float* __restrict__ kb,
    float* __restrict__ S)
{
    extern __shared__ float dsm[];
    float* Ash = dsm;
    float* Bsh = dsm + 2 * SBM * SBKP;
    uint32_t sAu = smem_u32(Ash);
    uint32_t sBu = smem_u32(Bsh);

    const float scale = 0.08838834764831845f;
    const int tid = threadIdx.x;
    const int wid = tid >> 5;
    const int lane = tid & 31;
    const int lr = lane >> 2;
    const int lc = lane & 3;
    const int wm = (wid >> 2) * 64;
    const int wn = (wid & 3) * 32;

    int bhs = blockIdx.z;
    size_t segbase = ((size_t)bhs) << 16;
    const float* A = qb + segbase;
    const float* B = kb + segbase;
    int brow = blockIdx.y * SBM;
    int bcol = blockIdx.x * SBN;

    float acc[4][4][4];
#pragma unroll
    for (int mt = 0; mt < 4; mt++)
#pragma unroll
        for (int nt = 0; nt < 4; nt++)
#pragma unroll
            for (int r = 0; r < 4; r++) acc[mt][nt][r] = 0.f;

    auto load_st = [&](int k0, uint32_t sA, uint32_t sB) {
#pragma unroll
        for (int it = 0; it < 4; it++) {
            int idx = tid + it * 256;
            int row = idx >> 3, c4 = idx & 7;
            cp16(sA + (row * SBKP + c4 * 4) * 4,
                 A + (size_t)(brow + row) * DHEAD + k0 + c4 * 4);
        }
#pragma unroll
        for (int it = 0; it < 4; it++) {
            int idx = tid + it * 256;
            int row = idx >> 3, c4 = idx & 7;
            cp16(sB + (row * SBKP + c4 * 4) * 4,
                 B + (size_t)(bcol + row) * DHEAD + k0 + c4 * 4);
        }
        asm volatile("cp.async.commit_group;" ::: "memory");
    };

    load_st(0, sAu, sBu);
    load_st(BK, sAu + SBM * SBKP * 4, sBu + SBN * SBKP * 4);

    const int NIT = DHEAD / BK;
    for (int it = 0; it < NIT; it++) {
        int s = it & 1;
        if (it == NIT - 1) asm volatile("cp.async.wait_group 0;" ::: "memory");
        else               asm volatile("cp.async.wait_group 1;" ::: "memory");
        __syncthreads();

        const float* As = Ash + s * SBM * SBKP;
        const float* Bs = Bsh + s * SBN * SBKP;
#pragma unroll
        for (int kb = 0; kb < BK; kb += 8) {
            uint32_t af[4][4], bf[4][2];
#pragma unroll
            for (int mt = 0; mt < 4; mt++) {
                int r = wm + mt * 16 + lr;
                af[mt][0] = f2tf32(As[r * SBKP + kb + lc]);
                af[mt][1] = f2tf32(As[(r + 8) * SBKP + kb + lc]);
                af[mt][2] = f2tf32(As[r * SBKP + kb + lc + 4]);
                af[mt][3] = f2tf32(As[(r + 8) * SBKP + kb + lc + 4]);
            }
#pragma unroll
            for (int nt = 0; nt < 4; nt++) {
                int cN = wn + nt * 8 + lr;
                bf[nt][0] = f2tf32(Bs[cN * SBKP + kb + lc]);
                bf[nt][1] = f2tf32(Bs[cN * SBKP + kb + lc + 4]);
            }
#pragma unroll
            for (int mt = 0; mt < 4; mt++)
#pragma unroll
                for (int nt = 0; nt < 4; nt++)
                    mma_tf32(acc[mt][nt], af[mt], bf[nt]);
        }
        __syncthreads();
        if (it + 2 < NIT)
            load_st((it + 2) * BK, sAu + s * SBM * SBKP * 4, sBu + s * SBN * SBKP * 4);
    }

    float* Sb = S + (size_t)bhs * SEGL * SEGL;
#pragma unroll
    for (int nt = 0; nt < 4; nt++) {
        int col = bcol + wn + nt * 8 + 2 * lc;
#pragma unroll
        for (int mt = 0; mt < 4; mt++) {
            int row = brow + wm + mt * 16 + lr;
            float2 v0 = make_float2(acc[mt][nt][0] * scale, acc[mt][nt][1] * scale);
            float2 v1 = make_float2(acc[mt][nt][2] * scale, acc[mt][nt][3] * scale);
            *(float2*)&Sb[(size_t)row * SEGL + col] = v0;
            *(float2*)&Sb[(size_t)(row + 8) * SEGL + col] = v1;
        }
    }
}
#define SCORES_SMEM_BYTES (2 * (SBM + SBN) * SBKP * 4)

// ============================================================================
// K4: batched row softmax
// ============================================================================
__global__ __launch_bounds__(256) void softmax_k(float* __restrict__ S)
{
    int bhs = blockIdx.y;
    int row = blockIdx.x * 8 + (threadIdx.x >> 5);
    int lane = threadIdx.x & 31;
    float* r = S + ((size_t)bhs * SEGL + row) * SEGL;
    float vals[16];
    float mx = -1e30f;
#pragma unroll
    for (int i = 0; i < 16; i++) {
        vals[i] = r[lane + 32 * i];
        mx = fmaxf(mx, vals[i]);
    }
#pragma unroll
    for (int o = 16; o > 0; o >>= 1) mx = fmaxf(mx, __shfl_xor_sync(0xffffffffu, mx, o));
    float sum = 0.f;
#pragma unroll
    for (int i = 0; i < 16; i++) {
        vals[i] = expf(vals[i] - mx);
        sum += vals[i];
    }
#pragma unroll
    for (int o = 16; o > 0; o >>= 1) sum += __shfl_xor_sync(0xffffffffu, sum, o);
    float inv = 1.0f / sum;
#pragma unroll
    for (int i = 0; i < 16; i++) r[lane + 32 * i] = vals[i] * inv;
}

// ============================================================================
// K5: batched PV: attn = (1-g) * P @ v
// ============================================================================
#define VEP 136
#define PV_SMEM_BYTES ((2 * SBM * SBKP + 2 * BK * VEP) * 4)

__global__ __launch_bounds__(256) void pv_mma_k(
    const float* __restrict__ P, const float* __restrict__ vb,
    const float* __restrict__ beta, float* __restrict__ attnb)
{
    extern __shared__ float dsm[];
    float* Ash = dsm;
    float* Vsh = dsm + 2 * SBM * SBKP;
    uint32_t sAu = smem_u32(Ash);
    uint32_t sVu = smem_u32(Vsh);

    const int tid = threadIdx.x;
    const int wid = tid >> 5;
    const int lane = tid & 31;
    const int lr = lane >> 2;
    const int lc = lane & 3;
    const int wm = (wid >> 2) * 64;
    const int wn = (wid & 3) * 32;

    int bhs = blockIdx.y;
    size_t segbase = ((size_t)bhs) << 16;
    const float* Pseg = P + (size_t)bhs * SEGL * SEGL;
    const float* vseg = vb + segbase;
    int brow = blockIdx.x * SBM;
    float gm1 = 1.0f - 1.0f / (1.0f + expf(-beta[0]));

    float acc[4][4][4];
#pragma unroll
    for (int mt = 0; mt < 4; mt++)
#pragma unroll
        for (int nt = 0; nt < 4; nt++)
#pragma unroll
            for (int r = 0; r < 4; r++) acc[mt][nt][r] = 0.f;

    auto load_st = [&](int k0, uint32_t sA, uint32_t sV) {
#pragma unroll
        for (int it = 0; it < 4; it++) {
            int idx = tid + it * 256;
            int row = idx >> 3, c4 = idx & 7;
            cp16(sA + (row * SBKP + c4 * 4) * 4,
                 Pseg + (size_t)(brow + row) * SEGL + k0 + c4 * 4);
        }
#pragma unroll
        for (int it = 0; it < 4; it++) {
            int idx = tid + it * 256;
            int row = idx >> 5, c4 = idx & 31;
            cp16(sV + (row * VEP + c4 * 4) * 4,
                 vseg + (size_t)(k0 + row) * DHEAD + c4 * 4);
        }
        asm volatile("cp.async.commit_group;" ::: "memory");
    };

    load_st(0, sAu, sVu);
    load_st(BK, sAu + SBM * SBKP * 4, sVu + BK * VEP * 4);

    const int NIT = SEGL / BK;
    for (int it = 0; it < NIT; it++) {
        int s = it & 1;
        if (it == NIT - 1) asm volatile("cp.async.wait_group 0;" ::: "memory");
        else               asm volatile("cp.async.wait_group 1;" ::: "memory");
        __syncthreads();

        const float* As = Ash + s * SBM * SBKP;
        const float* Vs = Vsh + s * BK * VEP;
#pragma unroll
        for (int kb = 0; kb < BK; kb += 8) {
            uint32_t af[4][4], bf[4][2];
#pragma unroll
            for (int mt = 0; mt < 4; mt++) {
                int r = wm + mt * 16 + lr;
                af[mt][0] = f2tf32(As[r * SBKP + kb + lc]);
                af[mt][1] = f2tf32(As[(r + 8) * SBKP + kb + lc]);
                af[mt][2] = f2tf32(As[r * SBKP + kb + lc + 4]);
                af[mt][3] = f2tf32(As[(r + 8) * SBKP + kb + lc + 4]);
            }
#pragma unroll
            for (int nt = 0; nt < 4; nt++) {
                int cN = wn + nt * 8 + lr;
                bf[nt][0] = f2tf32(Vs[(kb + lc) * VEP + cN]);
                bf[nt][1] = f2tf32(Vs[(kb + lc + 4) * VEP + cN]);
            }
#pragma unroll
            for (int mt = 0; mt < 4; mt++)
#pragma unroll
                for (int nt = 0; nt < 4; nt++)
                    mma_tf32(acc[mt][nt], af[mt], bf[nt]);
        }
        __syncthreads();
        if (it + 2 < NIT)
            load_st((it + 2) * BK, sAu + s * SBM * SBKP * 4, sVu + s * BK * VEP * 4);
    }

#pragma unroll
    for (int nt = 0; nt < 4; nt++) {
        int col = wn + nt * 8 + 2 * lc;
#pragma unroll
        for (int mt = 0; mt < 4; mt++) {
            int row = brow + wm + mt * 16 + lr;
            float2 v0 = make_float2(acc[mt][nt][0] * gm1, acc[mt][nt][1] * gm1);
            float2 v1 = make_float2(acc[mt][nt][2] * gm1, acc[mt][nt][3] * gm1);
            *(float2*)&attnb[segbase + (size_t)row * DHEAD + col] = v0;
            *(float2*)&attnb[segbase + (size_t)(row + 8) * DHEAD + col] = v1;
        }
    }
}

// ============================================================================
// K6: per-segment outer products (parallel over all bh,s):
//     memseg[bhs][d][e] = sum_l sk[l,d]*v[l,e];  Zseg[bhs][d] = sum_l sk[l,d]
// ============================================================================
__global__ __launch_bounds__(256) void outer_k(
    const float* __restrict__ kb, const float* __restrict__ vb,
    float* __restrict__ memseg, float* __restrict__ Zseg)
{
    int bhs = blockIdx.x;
    size_t segbase = ((size_t)bhs) << 16;
    const float* kseg = kb + segbase;
    const float* vseg = vb + segbase;

    __shared__ float As[16][128];
    __shared__ float Bs[16][128];
    int tid = threadIdx.x;
    int tx = tid & 15, ty = tid >> 4;
    int br = tid >> 5, bc4 = tid & 31;

    float acc[8][8];
    float zacc[8];
#pragma unroll
    for (int i = 0; i < 8; i++) {
        zacc[i] = 0.f;
#pragma unroll
        for (int j = 0; j < 8; j++) acc[i][j] = 0.f;
    }

    for (int l0 = 0; l0 < SEGL; l0 += 16) {
#pragma unroll
        for (int i = 0; i < 2; i++) {
            int r = br + i * 8;
            float4 kv = *(const float4*)&kseg[(size_t)(l0 + r) * DHEAD + bc4 * 4];
            As[r][bc4 * 4 + 0] = elu1(kv.x); As[r][bc4 * 4 + 1] = elu1(kv.y);
            As[r][bc4 * 4 + 2] = elu1(kv.z); As[r][bc4 * 4 + 3] = elu1(kv.w);
            float4 vv = *(const float4*)&vseg[(size_t)(l0 + r) * DHEAD + bc4 * 4];
            *(float4*)&Bs[r][bc4 * 4] = vv;
        }
        __syncthreads();
#pragma unroll
        for (int kk = 0; kk < 16; kk++) {
            float ra[8], rb[8];
#pragma unroll
            for (int i = 0; i < 8; i++) ra[i] = As[kk][ty * 8 + i];
#pragma unroll
            for (int j = 0; j < 8; j++) rb[j] = Bs[kk][tx * 8 + j];
#pragma unroll
            for (int i = 0; i < 8; i++)
#pragma unroll
                for (int j = 0; j < 8; j++) acc[i][j] += ra[i] * rb[j];
            if (tx == 0) {
#pragma unroll
                for (int i = 0; i < 8; i++) zacc[i] += ra[i];
            }
        }
        __syncthreads();
    }
    float* memb = memseg + (size_t)bhs * DHEAD * DHEAD;
#pragma unroll
    for (int i = 0; i < 8; i++)
#pragma unroll
        for (int j = 0; j < 8; j++)
            memb[(size_t)(ty * 8 + i) * DHEAD + tx * 8 + j] = acc[i][j];
    if (tx == 0) {
#pragma unroll
        for (int i = 0; i < 8; i++) Zseg[bhs * DHEAD + ty * 8 + i] = zacc[i];
    }
}

// ============================================================================
// K7: in-place exclusive prefix over the 8 segments (mem and Z)
// ============================================================================
__global__ __launch_bounds__(256) void prefix_mem_k(float* __restrict__ memseg)
{
    size_t idx = (size_t)blockIdx.x * 256 + threadIdx.x; // over NBH*16384
    int bh = (int)(idx >> 14);
    int off = (int)(idx & 16383);
    size_t base = ((size_t)bh * NSEG) * 16384 + off;
    float run = 0.f;
#pragma unroll
    for (int s = 0; s < NSEG; s++) {
        float t = memseg[base + (size_t)s * 16384];
        memseg[base + (size_t)s * 16384] = run;
        run += t;
    }
}

__global__ __launch_bounds__(256) void prefix_Z_k(float* __restrict__ Zseg)
{
    int idx = blockIdx.x * 256 + threadIdx.x; // over NBH*128
    int bh = idx >> 7;
    int d = idx & 127;
    int base = bh * NSEG * DHEAD + d;
    float run = 0.f;
#pragma unroll
    for (int s = 0; s < NSEG; s++) {
        float t = Zseg[base + s * DHEAD];
        Zseg[base + s * DHEAD] = run;
        run += t;
    }
}

// ============================================================================
// K8: A_mem accumulate for ALL segments in parallel:
//     attn[bhs] += g * (sq@memseg[bhs])/(rowsum(sq)*Zseg[bhs] + 1e-6)
// ============================================================================
__global__ __launch_bounds__(256) void amem_all_k(
    const float* __restrict__ qb, const float* __restrict__ memseg,
    const float* __restrict__ Zseg, const float* __restrict__ beta,
    float* __restrict__ attnb)
{
    int bhs = blockIdx.y;
    int l0 = blockIdx.x * 64;
    size_t segbase = ((size_t)bhs) << 16;
    const float* qseg = qb + segbase;
    const float* memb = memseg + (size_t)bhs * DHEAD * DHEAD;
    const float* Zb = Zseg + bhs * DHEAD;
    float g = 1.0f / (1.0f + expf(-beta[0]));

    __shared__ float As[16][64];
    __shared__ float Bs[16][128];
    __shared__ float rowsum[64];
    __shared__ float Zs[128];

    int tid = threadIdx.x;
    int tx = tid & 15, ty = tid >> 4;

    {
        int r = tid >> 2, qd = (tid & 3) * 32;
        float sm = 0.f;
#pragma unroll 8
        for (int d = 0; d < 32; d++)
            sm += elu1(qseg[(size_t)(l0 + r) * DHEAD + qd + d]);
        sm += __shfl_xor_sync(0xffffffffu, sm, 1);
        sm += __shfl_xor_sync(0xffffffffu, sm, 2);
        if ((tid & 3) == 0) rowsum[r] = sm;
    }
    if (tid < 128) Zs[tid] = Zb[tid];

    int ar = tid >> 2, ac4 = tid & 3;
    int br = tid >> 5, bc4 = tid & 31;

    float acc[4][8];
#pragma unroll
    for (int i = 0; i < 4; i++)
#pragma unroll
        for (int j = 0; j < 8; j++) acc[i][j] = 0.f;

    for (int k0 = 0; k0 < DHEAD; k0 += 16) {
        float4 av = *(const float4*)&qseg[(size_t)(l0 + ar) * DHEAD + k0 + ac4 * 4];
        As[ac4 * 4 + 0][ar] = elu1(av.x); As[ac4 * 4 + 1][ar] = elu1(av.y);
        As[ac4 * 4 + 2][ar] = elu1(av.z); As[ac4 * 4 + 3][ar] = elu1(av.w);
#pragma unroll
        for (int i = 0; i < 2; i++) {
            float4 bv = *(const float4*)&memb[(size_t)(k0 + br + i * 8) * DHEAD + bc4 * 4];
            *(float4*)&Bs[br + i * 8][bc4 * 4] = bv;
        }
        __syncthreads();
#pragma unroll
        for (int kk = 0; kk < 16; kk++) {
            float ra[4], rb[8];
#pragma unroll
            for (int i = 0; i < 4; i++) ra[i] = As[kk][ty * 4 + i];
#pragma unroll
            for (int j = 0; j < 8; j++) rb[j] = Bs[kk][tx * 8 + j];
#pragma unroll
            for (int i = 0; i < 4; i++)
#pragma unroll
                for (int j = 0; j < 8; j++) acc[i][j] += ra[i] * rb[j];
        }
        __syncthreads();
    }

#pragma unroll
    for (int i = 0; i < 4; i++) {
        float rs = rowsum[ty * 4 + i];
        size_t rbase = segbase + (size_t)(l0 + ty * 4 + i) * DHEAD;
#pragma unroll
        for (int j = 0; j < 8; j++) {
            float* dst = &attnb[rbase + tx * 8 + j];
            *dst += g * acc[i][j] / (rs * Zs[tx * 8 + j] + 1e-6f);
        }
    }
}

// ============================================================================
// Host launch
// ============================================================================
extern "C" void kernel_launch(void* const* d_in, const int* in_sizes, int n_in,
                              void* d_out, int out_size)
{
    (void)in_sizes; (void)n_in; (void)out_size;
    const float* x    = (const float*)d_in[0];
    const float* Wq   = (const float*)d_in[1];
    const float* bq   = (const float*)d_in[2];
    const float* Wk   = (const float*)d_in[3];
    const float* bk   = (const float*)d_in[4];
    const float* Wv   = (const float*)d_in[5];
    const float* bv   = (const float*)d_in[6];
    const float* Wo   = (const float*)d_in[7];
    const float* bo   = (const float*)d_in[8];
    const float* beta = (const float*)d_in[9];
    float* out = (float*)d_out;

    static float *pq = nullptr, *pk = nullptr, *pv = nullptr, *pattn = nullptr,
                 *pscores = nullptr, *pmemseg = nullptr, *pZseg = nullptr;
    static uint32_t *pWt = nullptr, *pxp = nullptr, *pattnp = nullptr;
    if (!pq) {
        cudaGetSymbolAddress((void**)&pq, g_q);
        cudaGetSymbolAddress((void**)&pk, g_k);
        cudaGetSymbolAddress((void**)&pv, g_v);
        cudaGetSymbolAddress((void**)&pattn, g_attn);
        cudaGetSymbolAddress((void**)&pscores, g_scores);
        cudaGetSymbolAddress((void**)&pmemseg, g_memseg);
        cudaGetSymbolAddress((void**)&pZseg, g_Zseg);
        cudaGetSymbolAddress((void**)&pWt, g_Wt);
        cudaGetSymbolAddress((void**)&pxp, g_xp);
        cudaGetSymbolAddress((void**)&pattnp, g_attnp);
        cudaFuncSetAttribute(gemm_mma_k, cudaFuncAttributeMaxDynamicSharedMemorySize,
                             GEMM_SMEM_BYTES);
        cudaFuncSetAttribute(scores_mma_k, cudaFuncAttributeMaxDynamicSharedMemorySize,
                             SCORES_SMEM_BYTES);
        cudaFuncSetAttribute(pv_mma_k, cudaFuncAttributeMaxDynamicSharedMemorySize,
                             PV_SMEM_BYTES);
    }

    const size_t WSZ = (size_t)EMBD * EMBD;
    dim3 tgrid(EMBD / 32, EMBD / 32);
    dim3 tblk(32, 8);
    transpose_tf32_k<<<tgrid, tblk>>>(Wq, pWt + 0 * WSZ);
    transpose_tf32_k<<<tgrid, tblk>>>(Wk, pWt + 1 * WSZ);
    transpose_tf32_k<<<tgrid, tblk>>>(Wv, pWt + 2 * WSZ);
    transpose_tf32_k<<<tgrid, tblk>>>(Wo, pWt + 3 * WSZ);

    perm_cvt_k<<<(int)(TOTAL / 8 / 256), 256>>>(x, pxp);

    dim3 ggrid(EMBD / BN, MTOK / BM); // (8, 128)
    gemm_mma_k<<<ggrid, 256, GEMM_SMEM_BYTES>>>(pxp, pWt + 0 * WSZ, bq, pq);
    gemm_mma_k<<<ggrid, 256, GEMM_SMEM_BYTES>>>(pxp, pWt + 1 * WSZ, bk, pk);
    gemm_mma_k<<<ggrid, 256, GEMM_SMEM_BYTES>>>(pxp, pWt + 2 * WSZ, bv, pv);

    rope_k<<<(MTOK * (EMBD / 2)) / 256, 256>>>(pq, pk);

    // parallel linear-memory path: outer products -> exclusive prefix
    outer_k<<<NBH * NSEG, 256>>>(pk, pv, pmemseg, pZseg);
    prefix_mem_k<<<(NBH * 16384) / 256, 256>>>(pmemseg);
    prefix_Z_k<<<(NBH * DHEAD) / 256, 256>>>(pZseg);

    // batched attention: scores -> softmax -> (1-g)*PV
    scores_mma_k<<<dim3(SEGL / SBN, SEGL / SBM, NBH * NSEG), 256, SCORES_SMEM_BYTES>>>(
        pq, pk, pscores);
    softmax_k<<<dim3(SEGL / 8, NBH * NSEG), 256>>>(pscores);
    pv_mma_k<<<dim3(SEGL / SBM, NBH * NSEG), 256, PV_SMEM_BYTES>>>(
        pscores, pv, beta, pattn);

    // A_mem for all segments at once (uses exclusive-prefix mem/Z)
    amem_all_k<<<dim3(SEGL / 64, NBH * NSEG), 256>>>(pq, pmemseg, pZseg, beta, pattn);

    perm_cvt_k<<<(int)(TOTAL / 8 / 256), 256>>>(pattn, pattnp);
    gemm_mma_k<<<ggrid, 256, GEMM_SMEM_BYTES>>>(pattnp, pWt + 3 * WSZ, bo, out);
}

// round 7
// speedup vs baseline: 3.4251x; 1.0246x over previous
#include <cuda_runtime.h>
#include <math.h>
#include <stdint.h>

// Problem constants
#define SEQ   4096
#define EMBD  2048
#define NB    4
#define NHEAD 16
#define DHEAD 128
#define NSEG  8
#define SEGL  512
#define NBH   (NB * NHEAD)          // 64
#define MTOK  (NB * SEQ)            // 16384
#define TOTAL ((size_t)MTOK * EMBD) // 33554432

// -------- device scratch ----------------------------------------------------
__device__ float g_q[TOTAL];
__device__ float g_k[TOTAL];
__device__ float g_v[TOTAL];
__device__ float g_attn[TOTAL];
__device__ float g_scores[(size_t)NBH * NSEG * SEGL * SEGL]; // 512MB
__device__ float g_memseg[(size_t)NBH * NSEG * DHEAD * DHEAD];
__device__ float g_Zseg[NBH * NSEG * DHEAD];
__device__ uint32_t g_Wt[(size_t)4 * EMBD * EMBD];   // transposed+permuted tf32
__device__ uint32_t g_xp[TOTAL];                     // permuted tf32 x
__device__ uint32_t g_attnp[TOTAL];                  // permuted tf32 attn

__device__ __forceinline__ float elu1(float x) {
    return (x > 0.f) ? (x + 1.f) : expf(x);
}

__device__ __forceinline__ uint32_t smem_u32(const void* p) {
    uint32_t a;
    asm("{ .reg .u64 t; cvta.to.shared.u64 t, %1; cvt.u32.u64 %0, t; }"
        : "=r"(a) : "l"(p));
    return a;
}

__device__ __forceinline__ void cp16(uint32_t saddr, const void* g) {
    asm volatile("cp.async.cg.shared.global [%0], [%1], 16;" :: "r"(saddr), "l"(g));
}

__device__ __forceinline__ uint32_t f2tf32(float x) {
    uint32_t u;
    asm("cvt.rna.tf32.f32 %0, %1;" : "=r"(u) : "f"(x));
    return u;
}

__device__ __forceinline__ void mma_tf32(float* d, const uint32_t* a, const uint32_t* b) {
    asm volatile(
        "mma.sync.aligned.m16n8k8.row.col.f32.tf32.tf32.f32 "
        "{%0,%1,%2,%3}, {%4,%5,%6,%7}, {%8,%9}, {%0,%1,%2,%3};"
        : "+f"(d[0]), "+f"(d[1]), "+f"(d[2]), "+f"(d[3])
        : "r"(a[0]), "r"(a[1]), "r"(a[2]), "r"(a[3]), "r"(b[0]), "r"(b[1]));
}

// permuted storage index of col j within an 8-group (matches perm_cvt_k)
__device__ __forceinline__ int pidx(int j) { return (j < 4) ? 2 * j : 2 * (j - 4) + 1; }

// ============================================================================
// K0a: transpose + k-permute + tf32 convert:  Wt[n, perm(k)] = tf32(W[k, n])
// ============================================================================
__global__ __launch_bounds__(256) void transpose_tf32_k(const float* __restrict__ W,
                                                        uint32_t* __restrict__ Wt)
{
    __shared__ float t[32][33];
    int bx = blockIdx.x * 32, by = blockIdx.y * 32;
    int txx = threadIdx.x;
    for (int i = threadIdx.y; i < 32; i += 8)
        t[i][txx] = W[(size_t)(by + i) * EMBD + bx + txx];
    __syncthreads();
    int p = txx & 7;
    int kcol = by + (txx & ~7) + 2 * (p & 3) + (p >> 2);
    for (int i = threadIdx.y; i < 32; i += 8)
        Wt[(size_t)(bx + i) * EMBD + kcol] = f2tf32(t[txx][i]);
}

// ============================================================================
// K0b: k-permute + tf32 convert of an activation matrix
// ============================================================================
__global__ __launch_bounds__(256) void perm_cvt_k(const float* __restrict__ src,
                                                  uint32_t* __restrict__ dst)
{
    size_t g8 = (size_t)blockIdx.x * 256 + threadIdx.x;
    size_t base = g8 * 8;
    float4 in0 = *(const float4*)&src[base];
    float4 in1 = *(const float4*)&src[base + 4];
    uint4 o0, o1;
    o0.x = f2tf32(in0.x); o0.y = f2tf32(in1.x);
    o0.z = f2tf32(in0.y); o0.w = f2tf32(in1.y);
    o1.x = f2tf32(in0.z); o1.y = f2tf32(in1.z);
    o1.z = f2tf32(in0.w); o1.w = f2tf32(in1.w);
    *(uint4*)&dst[base] = o0;
    *(uint4*)&dst[base + 4] = o1;
}

// ============================================================================
// K1: tf32 mma.sync GEMM, CTA 128x256x32, 3-stage pipeline, warp tile 64x64
// ============================================================================
#define BM 128
#define BN 256
#define BK 32
#define BKP 40
#define NSTG 3
#define STG_U ((BM + BN) * BKP)
#define GEMM_SMEM_BYTES (NSTG * STG_U * 4)

__device__ __forceinline__ void load_stage_u(const uint32_t* __restrict__ A,
                                             const uint32_t* __restrict__ Bt,
                                             int brow, int bcol, int k0,
                                             uint32_t sA, uint32_t sB, int tid)
{
#pragma unroll
    for (int it = 0; it < 4; it++) {
        int idx = tid + it * 256;
        int row = idx >> 3, c4 = idx & 7;
        cp16(sA + (row * BKP + c4 * 4) * 4,
             A + (size_t)(brow + row) * EMBD + k0 + c4 * 4);
    }
#pragma unroll
    for (int it = 0; it < 8; it++) {
        int idx = tid + it * 256;
        int row = idx >> 3, c4 = idx & 7;
        cp16(sB + (row * BKP + c4 * 4) * 4,
             Bt + (size_t)(bcol + row) * EMBD + k0 + c4 * 4);
    }
    asm volatile("cp.async.commit_group;" ::: "memory");
}

__device__ __forceinline__ void gemm_body(
    const uint32_t* __restrict__ A, const uint32_t* __restrict__ Bt,
    const float* __restrict__ bias, float* __restrict__ C,
    uint32_t* dsm_u)
{
    uint32_t sbase = smem_u32(dsm_u);
    const int tid = threadIdx.x;
    const int wid = tid >> 5;
    const int lane = tid & 31;
    const int lr = lane >> 2;
    const int lc = lane & 3;
    const int wm = (wid >> 2) * 64;
    const int wn = (wid & 3) * 64;

    int brow = blockIdx.y * BM;
    int bcol = blockIdx.x * BN;

    float acc[4][8][4];
#pragma unroll
    for (int mt = 0; mt < 4; mt++)
#pragma unroll
        for (int nt = 0; nt < 8; nt++)
#pragma unroll
            for (int r = 0; r < 4; r++) acc[mt][nt][r] = 0.f;

    uint32_t sA[NSTG], sB[NSTG];
#pragma unroll
    for (int s = 0; s < NSTG; s++) {
        sA[s] = sbase + s * STG_U * 4;
        sB[s] = sA[s] + BM * BKP * 4;
    }

    load_stage_u(A, Bt, brow, bcol, 0 * BK, sA[0], sB[0], tid);
    load_stage_u(A, Bt, brow, bcol, 1 * BK, sA[1], sB[1], tid);
    load_stage_u(A, Bt, brow, bcol, 2 * BK, sA[2], sB[2], tid);

    const int NIT = EMBD / BK;
    for (int it = 0; it < NIT; it++) {
        if (it < NIT - 2)       asm volatile("cp.async.wait_group 2;" ::: "memory");
        else if (it == NIT - 2) asm volatile("cp.async.wait_group 1;" ::: "memory");
        else                    asm volatile("cp.async.wait_group 0;" ::: "memory");
        __syncthreads();

        int s = it % NSTG;
        const uint32_t* As = dsm_u + (size_t)s * STG_U;
        const uint32_t* Bs = As + BM * BKP;

#pragma unroll
        for (int kb = 0; kb < BK; kb += 8) {
            uint32_t af[4][4], bf[8][2];
#pragma unroll
            for (int mt = 0; mt < 4; mt++) {
                int r = wm + mt * 16 + lr;
                uint2 a0 = *(const uint2*)&As[r * BKP + kb + 2 * lc];
                uint2 a1 = *(const uint2*)&As[(r + 8) * BKP + kb + 2 * lc];
                af[mt][0] = a0.x; af[mt][2] = a0.y;
                af[mt][1] = a1.x; af[mt][3] = a1.y;
            }
#pragma unroll
            for (int nt = 0; nt < 8; nt++) {
                int cN = wn + nt * 8 + lr;
                uint2 b = *(const uint2*)&Bs[cN * BKP + kb + 2 * lc];
                bf[nt][0] = b.x; bf[nt][1] = b.y;
            }
#pragma unroll
            for (int mt = 0; mt < 4; mt++)
#pragma unroll
                for (int nt = 0; nt < 8; nt++)
                    mma_tf32(acc[mt][nt], af[mt], bf[nt]);
        }
        __syncthreads();

        if (it + NSTG < NIT)
            load_stage_u(A, Bt, brow, bcol, (it + NSTG) * BK, sA[s], sB[s], tid);
    }

#pragma unroll
    for (int nt = 0; nt < 8; nt++) {
        int col = bcol + wn + nt * 8 + 2 * lc;
        float b0 = bias[col], b1 = bias[col + 1];
#pragma unroll
        for (int mt = 0; mt < 4; mt++) {
            int row = brow + wm + mt * 16 + lr;
            float2 v0 = make_float2(acc[mt][nt][0] + b0, acc[mt][nt][1] + b1);
            float2 v1 = make_float2(acc[mt][nt][2] + b0, acc[mt][nt][3] + b1);
            *(float2*)&C[(size_t)row * EMBD + col] = v0;
            *(float2*)&C[(size_t)(row + 8) * EMBD + col] = v1;
        }
    }
}

__global__ __launch_bounds__(256) void gemm_mma_k(
    const uint32_t* __restrict__ A, const uint32_t* __restrict__ Bt,
    const float* __restrict__ bias, float* __restrict__ C)
{
    extern __shared__ uint32_t dsm_u[];
    gemm_body(A, Bt, bias, C, dsm_u);
}

// merged QKV: blockIdx.z selects weight/bias/output
__global__ __launch_bounds__(256) void gemm_qkv_k(
    const uint32_t* __restrict__ A, const uint32_t* __restrict__ WtBase,
    const float* __restrict__ bq, const float* __restrict__ bk,
    const float* __restrict__ bv,
    float* __restrict__ q, float* __restrict__ k, float* __restrict__ v)
{
    extern __shared__ uint32_t dsm_u[];
    int z = blockIdx.z;
    const uint32_t* Bt = WtBase + (size_t)z * EMBD * EMBD;
    const float* bias = (z == 0) ? bq : (z == 1) ? bk : bv;
    float* C = (z == 0) ? q : (z == 1) ? k : v;
    gemm_body(A, Bt, bias, C, dsm_u);
}

// ============================================================================
// K2: RoPE
// ============================================================================
__global__ __launch_bounds__(256) void rope_k(float* __restrict__ q, float* __restrict__ k)
{
    size_t idx = (size_t)blockIdx.x * 256 + threadIdx.x;
    int rr = (int)(idx >> 10);
    int i = (int)(idx & 1023);
    int t = rr & (SEQ - 1);
    float inv = powf(10000.0f, -(float)(2 * i) * (1.0f / 2048.0f));
    float ang = (float)t * inv;
    float c = cosf(ang), s = sinf(ang);
    size_t base = (size_t)rr * EMBD + 2 * i;
    float a = q[base], b = q[base + 1];
    q[base] = a * c - b * s;
    q[base + 1] = a * s + b * c;
    a = k[base]; b = k[base + 1];
    k[base] = a * c - b * s;
    k[base + 1] = a * s + b * c;
}

// ============================================================================
// K3: batched scores:  S = scale * q_seg @ k_seg^T  (tf32 mma)
// ============================================================================
#define SBM 128
#define SBN 128
#define SBKP 36
__global__ __launch_bounds__(256) void scores_mma_k(
    const float* __restrict__ qb, const float* __restrict__ kb,
    float* __restrict__ S)
{
    extern __shared__ float dsm[];
    float* Ash = dsm;
    float* Bsh = dsm + 2 * SBM * SBKP;
    uint32_t sAu = smem_u32(Ash);
    uint32_t sBu = smem_u32(Bsh);

    const float scale = 0.08838834764831845f;
    const int tid = threadIdx.x;
    const int wid = tid >> 5;
    const int lane = tid & 31;
    const int lr = lane >> 2;
    const int lc = lane & 3;
    const int wm = (wid >> 2) * 64;
    const int wn = (wid & 3) * 32;

    int bhs = blockIdx.z;
    size_t segbase = ((size_t)bhs) << 16;
    const float* A = qb + segbase;
    const float* B = kb + segbase;
    int brow = blockIdx.y * SBM;
    int bcol = blockIdx.x * SBN;

    float acc[4][4][4];
#pragma unroll
    for (int mt = 0; mt < 4; mt++)
#pragma unroll
        for (int nt = 0; nt < 4; nt++)
#pragma unroll
            for (int r = 0; r < 4; r++) acc[mt][nt][r] = 0.f;

    auto load_st = [&](int k0, uint32_t sA, uint32_t sB) {
#pragma unroll
        for (int it = 0; it < 4; it++) {
            int idx = tid + it * 256;
            int row = idx >> 3, c4 = idx & 7;
            cp16(sA + (row * SBKP + c4 * 4) * 4,
                 A + (size_t)(brow + row) * DHEAD + k0 + c4 * 4);
        }
#pragma unroll
        for (int it = 0; it < 4; it++) {
            int idx = tid + it * 256;
            int row = idx >> 3, c4 = idx & 7;
            cp16(sB + (row * SBKP + c4 * 4) * 4,
                 B + (size_t)(bcol + row) * DHEAD + k0 + c4 * 4);
        }
        asm volatile("cp.async.commit_group;" ::: "memory");
    };

    load_st(0, sAu, sBu);
    load_st(BK, sAu + SBM * SBKP * 4, sBu + SBN * SBKP * 4);

    const int NIT = DHEAD / BK;
    for (int it = 0; it < NIT; it++) {
        int s = it & 1;
        if (it == NIT - 1) asm volatile("cp.async.wait_group 0;" ::: "memory");
        else               asm volatile("cp.async.wait_group 1;" ::: "memory");
        __syncthreads();

        const float* As = Ash + s * SBM * SBKP;
        const float* Bs = Bsh + s * SBN * SBKP;
#pragma unroll
        for (int kb = 0; kb < BK; kb += 8) {
            uint32_t af[4][4], bf[4][2];
#pragma unroll
            for (int mt = 0; mt < 4; mt++) {
                int r = wm + mt * 16 + lr;
                af[mt][0] = f2tf32(As[r * SBKP + kb + lc]);
                af[mt][1] = f2tf32(As[(r + 8) * SBKP + kb + lc]);
                af[mt][2] = f2tf32(As[r * SBKP + kb + lc + 4]);
                af[mt][3] = f2tf32(As[(r + 8) * SBKP + kb + lc + 4]);
            }
#pragma unroll
            for (int nt = 0; nt < 4; nt++) {
                int cN = wn + nt * 8 + lr;
                bf[nt][0] = f2tf32(Bs[cN * SBKP + kb + lc]);
                bf[nt][1] = f2tf32(Bs[cN * SBKP + kb + lc + 4]);
            }
#pragma unroll
            for (int mt = 0; mt < 4; mt++)
#pragma unroll
                for (int nt = 0; nt < 4; nt++)
                    mma_tf32(acc[mt][nt], af[mt], bf[nt]);
        }
        __syncthreads();
        if (it + 2 < NIT)
            load_st((it + 2) * BK, sAu + s * SBM * SBKP * 4, sBu + s * SBN * SBKP * 4);
    }

    float* Sb = S + (size_t)bhs * SEGL * SEGL;
#pragma unroll
    for (int nt = 0; nt < 4; nt++) {
        int col = bcol + wn + nt * 8 + 2 * lc;
#pragma unroll
        for (int mt = 0; mt < 4; mt++) {
            int row = brow + wm + mt * 16 + lr;
            float2 v0 = make_float2(acc[mt][nt][0] * scale, acc[mt][nt][1] * scale);
            float2 v1 = make_float2(acc[mt][nt][2] * scale, acc[mt][nt][3] * scale);
            *(float2*)&Sb[(size_t)row * SEGL + col] = v0;
            *(float2*)&Sb[(size_t)(row + 8) * SEGL + col] = v1;
        }
    }
}
#define SCORES_SMEM_BYTES (2 * (SBM + SBN) * SBKP * 4)

// ============================================================================
// K4: batched row softmax
// ============================================================================
__global__ __launch_bounds__(256) void softmax_k(float* __restrict__ S)
{
    int bhs = blockIdx.y;
    int row = blockIdx.x * 8 + (threadIdx.x >> 5);
    int lane = threadIdx.x & 31;
    float* r = S + ((size_t)bhs * SEGL + row) * SEGL;
    float vals[16];
    float mx = -1e30f;
#pragma unroll
    for (int i = 0; i < 16; i++) {
        vals[i] = r[lane + 32 * i];
        mx = fmaxf(mx, vals[i]);
    }
#pragma unroll
    for (int o = 16; o > 0; o >>= 1) mx = fmaxf(mx, __shfl_xor_sync(0xffffffffu, mx, o));
    float sum = 0.f;
#pragma unroll
    for (int i = 0; i < 16; i++) {
        vals[i] = expf(vals[i] - mx);
        sum += vals[i];
    }
#pragma unroll
    for (int o = 16; o > 0; o >>= 1) sum += __shfl_xor_sync(0xffffffffu, sum, o);
    float inv = 1.0f / sum;
#pragma unroll
    for (int i = 0; i < 16; i++) r[lane + 32 * i] = vals[i] * inv;
}

// ============================================================================
// K5: batched PV: attn = (1-g) * P @ v
// ============================================================================
#define VEP 136
#define PV_SMEM_BYTES ((2 * SBM * SBKP + 2 * BK * VEP) * 4)

__global__ __launch_bounds__(256) void pv_mma_k(
    const float* __restrict__ P, const float* __restrict__ vb,
    const float* __restrict__ beta, float* __restrict__ attnb)
{
    extern __shared__ float dsm[];
    float* Ash = dsm;
    float* Vsh = dsm + 2 * SBM * SBKP;
    uint32_t sAu = smem_u32(Ash);
    uint32_t sVu = smem_u32(Vsh);

    const int tid = threadIdx.x;
    const int wid = tid >> 5;
    const int lane = tid & 31;
    const int lr = lane >> 2;
    const int lc = lane & 3;
    const int wm = (wid >> 2) * 64;
    const int wn = (wid & 3) * 32;

    int bhs = blockIdx.y;
    size_t segbase = ((size_t)bhs) << 16;
    const float* Pseg = P + (size_t)bhs * SEGL * SEGL;
    const float* vseg = vb + segbase;
    int brow = blockIdx.x * SBM;
    float gm1 = 1.0f - 1.0f / (1.0f + expf(-beta[0]));

    float acc[4][4][4];
#pragma unroll
    for (int mt = 0; mt < 4; mt++)
#pragma unroll
        for (int nt = 0; nt < 4; nt++)
#pragma unroll
            for (int r = 0; r < 4; r++) acc[mt][nt][r] = 0.f;

    auto load_st = [&](int k0, uint32_t sA, uint32_t sV) {
#pragma unroll
        for (int it = 0; it < 4; it++) {
            int idx = tid + it * 256;
            int row = idx >> 3, c4 = idx & 7;
            cp16(sA + (row * SBKP + c4 * 4) * 4,
                 Pseg + (size_t)(brow + row) * SEGL + k0 + c4 * 4);
        }
#pragma unroll
        for (int it = 0; it < 4; it++) {
            int idx = tid + it * 256;
            int row = idx >> 5, c4 = idx & 31;
            cp16(sV + (row * VEP + c4 * 4) * 4,
                 vseg + (size_t)(k0 + row) * DHEAD + c4 * 4);
        }
        asm volatile("cp.async.commit_group;" ::: "memory");
    };

    load_st(0, sAu, sVu);
    load_st(BK, sAu + SBM * SBKP * 4, sVu + BK * VEP * 4);

    const int NIT = SEGL / BK;
    for (int it = 0; it < NIT; it++) {
        int s = it & 1;
        if (it == NIT - 1) asm volatile("cp.async.wait_group 0;" ::: "memory");
        else               asm volatile("cp.async.wait_group 1;" ::: "memory");
        __syncthreads();

        const float* As = Ash + s * SBM * SBKP;
        const float* Vs = Vsh + s * BK * VEP;
#pragma unroll
        for (int kb = 0; kb < BK; kb += 8) {
            uint32_t af[4][4], bf[4][2];
#pragma unroll
            for (int mt = 0; mt < 4; mt++) {
                int r = wm + mt * 16 + lr;
                af[mt][0] = f2tf32(As[r * SBKP + kb + lc]);
                af[mt][1] = f2tf32(As[(r + 8) * SBKP + kb + lc]);
                af[mt][2] = f2tf32(As[r * SBKP + kb + lc + 4]);
                af[mt][3] = f2tf32(As[(r + 8) * SBKP + kb + lc + 4]);
            }
#pragma unroll
            for (int nt = 0; nt < 4; nt++) {
                int cN = wn + nt * 8 + lr;
                bf[nt][0] = f2tf32(Vs[(kb + lc) * VEP + cN]);
                bf[nt][1] = f2tf32(Vs[(kb + lc + 4) * VEP + cN]);
            }
#pragma unroll
            for (int mt = 0; mt < 4; mt++)
#pragma unroll
                for (int nt = 0; nt < 4; nt++)
                    mma_tf32(acc[mt][nt], af[mt], bf[nt]);
        }
        __syncthreads();
        if (it + 2 < NIT)
            load_st((it + 2) * BK, sAu + s * SBM * SBKP * 4, sVu + s * BK * VEP * 4);
    }

#pragma unroll
    for (int nt = 0; nt < 4; nt++) {
        int col = wn + nt * 8 + 2 * lc;
#pragma unroll
        for (int mt = 0; mt < 4; mt++) {
            int row = brow + wm + mt * 16 + lr;
            float2 v0 = make_float2(acc[mt][nt][0] * gm1, acc[mt][nt][1] * gm1);
            float2 v1 = make_float2(acc[mt][nt][2] * gm1, acc[mt][nt][3] * gm1);
            *(float2*)&attnb[segbase + (size_t)row * DHEAD + col] = v0;
            *(float2*)&attnb[segbase + (size_t)(row + 8) * DHEAD + col] = v1;
        }
    }
}

// ============================================================================
// K6: per-segment outer products
// ============================================================================
__global__ __launch_bounds__(256) void outer_k(
    const float* __restrict__ kb, const float* __restrict__ vb,
    float* __restrict__ memseg, float* __restrict__ Zseg)
{
    int bhs = blockIdx.x;
    size_t segbase = ((size_t)bhs) << 16;
    const float* kseg = kb + segbase;
    const float* vseg = vb + segbase;

    __shared__ float As[16][128];
    __shared__ float Bs[16][128];
    int tid = threadIdx.x;
    int tx = tid & 15, ty = tid >> 4;
    int br = tid >> 5, bc4 = tid & 31;

    float acc[8][8];
    float zacc[8];
#pragma unroll
    for (int i = 0; i < 8; i++) {
        zacc[i] = 0.f;
#pragma unroll
        for (int j = 0; j < 8; j++) acc[i][j] = 0.f;
    }

    for (int l0 = 0; l0 < SEGL; l0 += 16) {
#pragma unroll
        for (int i = 0; i < 2; i++) {
            int r = br + i * 8;
            float4 kv = *(const float4*)&kseg[(size_t)(l0 + r) * DHEAD + bc4 * 4];
            As[r][bc4 * 4 + 0] = elu1(kv.x); As[r][bc4 * 4 + 1] = elu1(kv.y);
            As[r][bc4 * 4 + 2] = elu1(kv.z); As[r][bc4 * 4 + 3] = elu1(kv.w);
            float4 vv = *(const float4*)&vseg[(size_t)(l0 + r) * DHEAD + bc4 * 4];
            *(float4*)&Bs[r][bc4 * 4] = vv;
        }
        __syncthreads();
#pragma unroll
        for (int kk = 0; kk < 16; kk++) {
            float ra[8], rb[8];
#pragma unroll
            for (int i = 0; i < 8; i++) ra[i] = As[kk][ty * 8 + i];
#pragma unroll
            for (int j = 0; j < 8; j++) rb[j] = Bs[kk][tx * 8 + j];
#pragma unroll
            for (int i = 0; i < 8; i++)
#pragma unroll
                for (int j = 0; j < 8; j++) acc[i][j] += ra[i] * rb[j];
            if (tx == 0) {
#pragma unroll
                for (int i = 0; i < 8; i++) zacc[i] += ra[i];
            }
        }
        __syncthreads();
    }
    float* memb = memseg + (size_t)bhs * DHEAD * DHEAD;
#pragma unroll
    for (int i = 0; i < 8; i++)
#pragma unroll
        for (int j = 0; j < 8; j++)
            memb[(size_t)(ty * 8 + i) * DHEAD + tx * 8 + j] = acc[i][j];
    if (tx == 0) {
#pragma unroll
        for (int i = 0; i < 8; i++) Zseg[bhs * DHEAD + ty * 8 + i] = zacc[i];
    }
}

// ============================================================================
// K7: in-place exclusive prefix over the 8 segments
// ============================================================================
__global__ __launch_bounds__(256) void prefix_mem_k(float* __restrict__ memseg)
{
    size_t idx = (size_t)blockIdx.x * 256 + threadIdx.x;
    int bh = (int)(idx >> 14);
    int off = (int)(idx & 16383);
    size_t base = ((size_t)bh * NSEG) * 16384 + off;
    float run = 0.f;
#pragma unroll
    for (int s = 0; s < NSEG; s++) {
        float t = memseg[base + (size_t)s * 16384];
        memseg[base + (size_t)s * 16384] = run;
        run += t;
    }
}

__global__ __launch_bounds__(256) void prefix_Z_k(float* __restrict__ Zseg)
{
    int idx = blockIdx.x * 256 + threadIdx.x;
    int bh = idx >> 7;
    int d = idx & 127;
    int base = bh * NSEG * DHEAD + d;
    float run = 0.f;
#pragma unroll
    for (int s = 0; s < NSEG; s++) {
        float t = Zseg[base + s * DHEAD];
        Zseg[base + s * DHEAD] = run;
        run += t;
    }
}

// ============================================================================
// K8: tensorized A_mem for ALL segments, fused final-combine + perm-cvt:
//     attnp = permcvt( g*(sq@mem)/(rowsum(sq)*Z+1e-6) + attn )
//     CTA = (128 l-rows x 128 e-cols), K=128, single smem-resident stage
// ============================================================================
#define AMP 136
#define AMEM_SMEM_BYTES ((2 * 128 * AMP + 256) * 4)

__global__ __launch_bounds__(256) void amem_mma_k(
    const float* __restrict__ qb, const float* __restrict__ memseg,
    const float* __restrict__ Zseg, const float* __restrict__ beta,
    const float* __restrict__ attnb, uint32_t* __restrict__ attnp)
{
    extern __shared__ uint32_t smu[];
    uint32_t* qs = smu;                  // [128][AMP] tf32(elu1(q))
    uint32_t* ms = smu + 128 * AMP;      // [128][AMP] tf32(mem)
    float* rowsumS = (float*)(smu + 2 * 128 * AMP); // [128]
    float* Zs = rowsumS + 128;                      // [128]
    uint32_t sqb = smem_u32(qs);
    uint32_t smb = smem_u32(ms);

    const int tid = threadIdx.x;
    const int wid = tid >> 5;
    const int lane = tid & 31;
    const int lr = lane >> 2;
    const int lc = lane & 3;
    const int wm = (wid >> 2) * 64;
    const int wn = (wid & 3) * 32;

    int bhs = blockIdx.y;
    int l0 = blockIdx.x * 128;
    size_t segbase = ((size_t)bhs) << 16;
    const float* qseg = qb + segbase;
    const float* memb = memseg + (size_t)bhs * DHEAD * DHEAD;
    float g = 1.0f / (1.0f + expf(-beta[0]));

    // stage q tile and mem tile (each 128x128 fp32)
#pragma unroll
    for (int it = 0; it < 16; it++) {
        int idx = tid + it * 256;
        int row = idx >> 5, c4 = idx & 31;
        cp16(sqb + (row * AMP + c4 * 4) * 4,
             qseg + (size_t)(l0 + row) * DHEAD + c4 * 4);
    }
#pragma unroll
    for (int it = 0; it < 16; it++) {
        int idx = tid + it * 256;
        int row = idx >> 5, c4 = idx & 31;
        cp16(smb + (row * AMP + c4 * 4) * 4,
             memb + (size_t)row * DHEAD + c4 * 4);
    }
    asm volatile("cp.async.commit_group;" ::: "memory");
    asm volatile("cp.async.wait_group 0;" ::: "memory");
    __syncthreads();

    // in-place convert: q -> tf32(elu1(q)) with rowsum; mem -> tf32(mem)
    {
        int r = tid >> 1;
        int half = (tid & 1) * 64;
        float partial = 0.f;
#pragma unroll 16
        for (int j = 0; j < 64; j++) {
            uint32_t* p = &qs[r * AMP + half + j];
            float e = elu1(__uint_as_float(*p));
            partial += e;
            *p = f2tf32(e);
        }
        partial += __shfl_xor_sync(0xffffffffu, partial, 1);
        if ((tid & 1) == 0) rowsumS[r] = partial;
#pragma unroll 16
        for (int j = 0; j < 64; j++) {
            uint32_t* p = &ms[r * AMP + half + j];
            *p = f2tf32(__uint_as_float(*p));
        }
    }
    if (tid < 128) Zs[tid] = Zseg[bhs * DHEAD + tid];
    __syncthreads();

    float acc[4][4][4];
#pragma unroll
    for (int mt = 0; mt < 4; mt++)
#pragma unroll
        for (int nt = 0; nt < 4; nt++)
#pragma unroll
            for (int r = 0; r < 4; r++) acc[mt][nt][r] = 0.f;

#pragma unroll
    for (int kb = 0; kb < 128; kb += 8) {
        uint32_t af[4][4], bf[4][2];
#pragma unroll
        for (int mt = 0; mt < 4; mt++) {
            int r = wm + mt * 16 + lr;
            af[mt][0] = qs[r * AMP + kb + lc];
            af[mt][1] = qs[(r + 8) * AMP + kb + lc];
            af[mt][2] = qs[r * AMP + kb + lc + 4];
            af[mt][3] = qs[(r + 8) * AMP + kb + lc + 4];
        }
#pragma unroll
        for (int nt = 0; nt < 4; nt++) {
            int cN = wn + nt * 8 + lr;
            bf[nt][0] = ms[(kb + lc) * AMP + cN];
            bf[nt][1] = ms[(kb + lc + 4) * AMP + cN];
        }
#pragma unroll
        for (int mt = 0; mt < 4; mt++)
#pragma unroll
            for (int nt = 0; nt < 4; nt++)
                mma_tf32(acc[mt][nt], af[mt], bf[nt]);
    }

    // epilogue: combine + permuted tf32 store
#pragma unroll
    for (int nt = 0; nt < 4; nt++) {
        int col = wn + nt * 8 + 2 * lc;           // even
        int gb = col & ~7;
        int st0 = gb + pidx(col & 7);
        int st1 = gb + pidx((col & 7) + 1);
        float Z0 = Zs[col], Z1 = Zs[col + 1];
#pragma unroll
        for (int mt = 0; mt < 4; mt++) {
#pragma unroll
            for (int h = 0; h < 2; h++) {
                int rloc = wm + mt * 16 + lr + h * 8;
                int row = l0 + rloc;
                float rs = rowsumS[rloc];
                float2 at = *(const float2*)&attnb[segbase + (size_t)row * DHEAD + col];
                float a0 = g * acc[mt][nt][2 * h + 0] / (rs * Z0 + 1e-6f) + at.x;
                float a1 = g * acc[mt][nt][2 * h + 1] / (rs * Z1 + 1e-6f) + at.y;
                attnp[segbase + (size_t)row * DHEAD + st0] = f2tf32(a0);
                attnp[segbase + (size_t)row * DHEAD + st1] = f2tf32(a1);
            }
        }
    }
}

// ============================================================================
// Host launch
// ============================================================================
extern "C" void kernel_launch(void* const* d_in, const int* in_sizes, int n_in,
                              void* d_out, int out_size)
{
    (void)in_sizes; (void)n_in; (void)out_size;
    const float* x    = (const float*)d_in[0];
    const float* Wq   = (const float*)d_in[1];
    const float* bq   = (const float*)d_in[2];
    const float* Wk   = (const float*)d_in[3];
    const float* bk   = (const float*)d_in[4];
    const float* Wv   = (const float*)d_in[5];
    const float* bv   = (const float*)d_in[6];
    const float* Wo   = (const float*)d_in[7];
    const float* bo   = (const float*)d_in[8];
    const float* beta = (const float*)d_in[9];
    float* out = (float*)d_out;

    static float *pq = nullptr, *pk = nullptr, *pv = nullptr, *pattn = nullptr,
                 *pscores = nullptr, *pmemseg = nullptr, *pZseg = nullptr;
    static uint32_t *pWt = nullptr, *pxp = nullptr, *pattnp = nullptr;
    if (!pq) {
        cudaGetSymbolAddress((void**)&pq, g_q);
        cudaGetSymbolAddress((void**)&pk, g_k);
        cudaGetSymbolAddress((void**)&pv, g_v);
        cudaGetSymbolAddress((void**)&pattn, g_attn);
        cudaGetSymbolAddress((void**)&pscores, g_scores);
        cudaGetSymbolAddress((void**)&pmemseg, g_memseg);
        cudaGetSymbolAddress((void**)&pZseg, g_Zseg);
        cudaGetSymbolAddress((void**)&pWt, g_Wt);
        cudaGetSymbolAddress((void**)&pxp, g_xp);
        cudaGetSymbolAddress((void**)&pattnp, g_attnp);
        cudaFuncSetAttribute(gemm_mma_k, cudaFuncAttributeMaxDynamicSharedMemorySize,
                             GEMM_SMEM_BYTES);
        cudaFuncSetAttribute(gemm_qkv_k, cudaFuncAttributeMaxDynamicSharedMemorySize,
                             GEMM_SMEM_BYTES);
        cudaFuncSetAttribute(scores_mma_k, cudaFuncAttributeMaxDynamicSharedMemorySize,
                             SCORES_SMEM_BYTES);
        cudaFuncSetAttribute(pv_mma_k, cudaFuncAttributeMaxDynamicSharedMemorySize,
                             PV_SMEM_BYTES);
        cudaFuncSetAttribute(amem_mma_k, cudaFuncAttributeMaxDynamicSharedMemorySize,
                             AMEM_SMEM_BYTES);
    }

    const size_t WSZ = (size_t)EMBD * EMBD;
    dim3 tgrid(EMBD / 32, EMBD / 32);
    dim3 tblk(32, 8);
    transpose_tf32_k<<<tgrid, tblk>>>(Wq, pWt + 0 * WSZ);
    transpose_tf32_k<<<tgrid, tblk>>>(Wk, pWt + 1 * WSZ);
    transpose_tf32_k<<<tgrid, tblk>>>(Wv, pWt + 2 * WSZ);
    transpose_tf32_k<<<tgrid, tblk>>>(Wo, pWt + 3 * WSZ);

    perm_cvt_k<<<(int)(TOTAL / 8 / 256), 256>>>(x, pxp);

    dim3 qkvgrid(EMBD / BN, MTOK / BM, 3); // (8, 128, 3)
    gemm_qkv_k<<<qkvgrid, 256, GEMM_SMEM_BYTES>>>(pxp, pWt, bq, bk, bv, pq, pk, pv);

    rope_k<<<(MTOK * (EMBD / 2)) / 256, 256>>>(pq, pk);

    // parallel linear-memory path
    outer_k<<<NBH * NSEG, 256>>>(pk, pv, pmemseg, pZseg);
    prefix_mem_k<<<(NBH * 16384) / 256, 256>>>(pmemseg);
    prefix_Z_k<<<(NBH * DHEAD) / 256, 256>>>(pZseg);

    // batched attention: scores -> softmax -> (1-g)*PV
    scores_mma_k<<<dim3(SEGL / SBN, SEGL / SBM, NBH * NSEG), 256, SCORES_SMEM_BYTES>>>(
        pq, pk, pscores);
    softmax_k<<<dim3(SEGL / 8, NBH * NSEG), 256>>>(pscores);
    pv_mma_k<<<dim3(SEGL / SBM, NBH * NSEG), 256, PV_SMEM_BYTES>>>(
        pscores, pv, beta, pattn);

    // tensorized A_mem + combine + perm-cvt fused
    amem_mma_k<<<dim3(SEGL / 128, NBH * NSEG), 256, AMEM_SMEM_BYTES>>>(
        pq, pmemseg, pZseg, beta, pattn, pattnp);

    gemm_mma_k<<<dim3(EMBD / BN, MTOK / BM), 256, GEMM_SMEM_BYTES>>>(
        pattnp, pWt + 3 * WSZ, bo, out);
}

// round 8
// speedup vs baseline: 3.4293x; 1.0012x over previous
#include <cuda_runtime.h>
#include <math.h>
#include <stdint.h>

// Problem constants
#define SEQ   4096
#define EMBD  2048
#define NB    4
#define NHEAD 16
#define DHEAD 128
#define NSEG  8
#define SEGL  512
#define NBH   (NB * NHEAD)          // 64
#define MTOK  (NB * SEQ)            // 16384
#define TOTAL ((size_t)MTOK * EMBD) // 33554432

// -------- device scratch ----------------------------------------------------
__device__ float g_q[TOTAL];
__device__ float g_k[TOTAL];
__device__ float g_v[TOTAL];
__device__ float g_attn[TOTAL];
__device__ float g_scores[(size_t)NBH * NSEG * SEGL * SEGL]; // 512MB
__device__ float g_memseg[(size_t)NBH * NSEG * DHEAD * DHEAD];
__device__ float g_Zseg[NBH * NSEG * DHEAD];
__device__ uint32_t g_Wt[(size_t)4 * EMBD * EMBD];   // transposed+permuted tf32
__device__ uint32_t g_xp[TOTAL];                     // permuted tf32 x
__device__ uint32_t g_attnp[TOTAL];                  // permuted tf32 attn

__device__ __forceinline__ float elu1(float x) {
    return (x > 0.f) ? (x + 1.f) : expf(x);
}

__device__ __forceinline__ uint32_t smem_u32(const void* p) {
    uint32_t a;
    asm("{ .reg .u64 t; cvta.to.shared.u64 t, %1; cvt.u32.u64 %0, t; }"
        : "=r"(a) : "l"(p));
    return a;
}

__device__ __forceinline__ void cp16(uint32_t saddr, const void* g) {
    asm volatile("cp.async.cg.shared.global [%0], [%1], 16;" :: "r"(saddr), "l"(g));
}

__device__ __forceinline__ uint32_t f2tf32(float x) {
    uint32_t u;
    asm("cvt.rna.tf32.f32 %0, %1;" : "=r"(u) : "f"(x));
    return u;
}

__device__ __forceinline__ void mma_tf32(float* d, const uint32_t* a, const uint32_t* b) {
    asm volatile(
        "mma.sync.aligned.m16n8k8.row.col.f32.tf32.tf32.f32 "
        "{%0,%1,%2,%3}, {%4,%5,%6,%7}, {%8,%9}, {%0,%1,%2,%3};"
        : "+f"(d[0]), "+f"(d[1]), "+f"(d[2]), "+f"(d[3])
        : "r"(a[0]), "r"(a[1]), "r"(a[2]), "r"(a[3]), "r"(b[0]), "r"(b[1]));
}

// permuted storage index of col j within an 8-group (matches perm_cvt_k)
__device__ __forceinline__ int pidx(int j) { return (j < 4) ? 2 * j : 2 * (j - 4) + 1; }

// ============================================================================
// K0a: transpose + k-permute + tf32 convert:  Wt[n, perm(k)] = tf32(W[k, n])
// ============================================================================
__global__ __launch_bounds__(256) void transpose_tf32_k(const float* __restrict__ W,
                                                        uint32_t* __restrict__ Wt)
{
    __shared__ float t[32][33];
    int bx = blockIdx.x * 32, by = blockIdx.y * 32;
    int txx = threadIdx.x;
    for (int i = threadIdx.y; i < 32; i += 8)
        t[i][txx] = W[(size_t)(by + i) * EMBD + bx + txx];
    __syncthreads();
    int p = txx & 7;
    int kcol = by + (txx & ~7) + 2 * (p & 3) + (p >> 2);
    for (int i = threadIdx.y; i < 32; i += 8)
        Wt[(size_t)(bx + i) * EMBD + kcol] = f2tf32(t[txx][i]);
}

// ============================================================================
// K0b: k-permute + tf32 convert of an activation matrix
// ============================================================================
__global__ __launch_bounds__(256) void perm_cvt_k(const float* __restrict__ src,
                                                  uint32_t* __restrict__ dst)
{
    size_t g8 = (size_t)blockIdx.x * 256 + threadIdx.x;
    size_t base = g8 * 8;
    float4 in0 = *(const float4*)&src[base];
    float4 in1 = *(const float4*)&src[base + 4];
    uint4 o0, o1;
    o0.x = f2tf32(in0.x); o0.y = f2tf32(in1.x);
    o0.z = f2tf32(in0.y); o0.w = f2tf32(in1.y);
    o1.x = f2tf32(in0.z); o1.y = f2tf32(in1.z);
    o1.z = f2tf32(in0.w); o1.w = f2tf32(in1.w);
    *(uint4*)&dst[base] = o0;
    *(uint4*)&dst[base + 4] = o1;
}

// ============================================================================
// K1: tf32 mma.sync GEMM, CTA 128x256x32, 3-stage pipeline, warp tile 64x64
// ============================================================================
#define BM 128
#define BN 256
#define BK 32
#define BKP 40
#define NSTG 3
#define STG_U ((BM + BN) * BKP)
#define GEMM_SMEM_BYTES (NSTG * STG_U * 4)

__device__ __forceinline__ void load_stage_u(const uint32_t* __restrict__ A,
                                             const uint32_t* __restrict__ Bt,
                                             int brow, int bcol, int k0,
                                             uint32_t sA, uint32_t sB, int tid)
{
#pragma unroll
    for (int it = 0; it < 4; it++) {
        int idx = tid + it * 256;
        int row = idx >> 3, c4 = idx & 7;
        cp16(sA + (row * BKP + c4 * 4) * 4,
             A + (size_t)(brow + row) * EMBD + k0 + c4 * 4);
    }
#pragma unroll
    for (int it = 0; it < 8; it++) {
        int idx = tid + it * 256;
        int row = idx >> 3, c4 = idx & 7;
        cp16(sB + (row * BKP + c4 * 4) * 4,
             Bt + (size_t)(bcol + row) * EMBD + k0 + c4 * 4);
    }
    asm volatile("cp.async.commit_group;" ::: "memory");
}

__device__ __forceinline__ void gemm_body(
    const uint32_t* __restrict__ A, const uint32_t* __restrict__ Bt,
    const float* __restrict__ bias, float* __restrict__ C,
    uint32_t* dsm_u)
{
    uint32_t sbase = smem_u32(dsm_u);
    const int tid = threadIdx.x;
    const int wid = tid >> 5;
    const int lane = tid & 31;
    const int lr = lane >> 2;
    const int lc = lane & 3;
    const int wm = (wid >> 2) * 64;
    const int wn = (wid & 3) * 64;

    int brow = blockIdx.y * BM;
    int bcol = blockIdx.x * BN;

    float acc[4][8][4];
#pragma unroll
    for (int mt = 0; mt < 4; mt++)
#pragma unroll
        for (int nt = 0; nt < 8; nt++)
#pragma unroll
            for (int r = 0; r < 4; r++) acc[mt][nt][r] = 0.f;

    uint32_t sA[NSTG], sB[NSTG];
#pragma unroll
    for (int s = 0; s < NSTG; s++) {
        sA[s] = sbase + s * STG_U * 4;
        sB[s] = sA[s] + BM * BKP * 4;
    }

    load_stage_u(A, Bt, brow, bcol, 0 * BK, sA[0], sB[0], tid);
    load_stage_u(A, Bt, brow, bcol, 1 * BK, sA[1], sB[1], tid);
    load_stage_u(A, Bt, brow, bcol, 2 * BK, sA[2], sB[2], tid);

    const int NIT = EMBD / BK;
    for (int it = 0; it < NIT; it++) {
        if (it < NIT - 2)       asm volatile("cp.async.wait_group 2;" ::: "memory");
        else if (it == NIT - 2) asm volatile("cp.async.wait_group 1;" ::: "memory");
        else                    asm volatile("cp.async.wait_group 0;" ::: "memory");
        __syncthreads();

        int s = it % NSTG;
        const uint32_t* As = dsm_u + (size_t)s * STG_U;
        const uint32_t* Bs = As + BM * BKP;

#pragma unroll
        for (int kb = 0; kb < BK; kb += 8) {
            uint32_t af[4][4], bf[8][2];
#pragma unroll
            for (int mt = 0; mt < 4; mt++) {
                int r = wm + mt * 16 + lr;
                uint2 a0 = *(const uint2*)&As[r * BKP + kb + 2 * lc];
                uint2 a1 = *(const uint2*)&As[(r + 8) * BKP + kb + 2 * lc];
                af[mt][0] = a0.x; af[mt][2] = a0.y;
                af[mt][1] = a1.x; af[mt][3] = a1.y;
            }
#pragma unroll
            for (int nt = 0; nt < 8; nt++) {
                int cN = wn + nt * 8 + lr;
                uint2 b = *(const uint2*)&Bs[cN * BKP + kb + 2 * lc];
                bf[nt][0] = b.x; bf[nt][1] = b.y;
            }
#pragma unroll
            for (int mt = 0; mt < 4; mt++)
#pragma unroll
                for (int nt = 0; nt < 8; nt++)
                    mma_tf32(acc[mt][nt], af[mt], bf[nt]);
        }
        __syncthreads();

        if (it + NSTG < NIT)
            load_stage_u(A, Bt, brow, bcol, (it + NSTG) * BK, sA[s], sB[s], tid);
    }

#pragma unroll
    for (int nt = 0; nt < 8; nt++) {
        int col = bcol + wn + nt * 8 + 2 * lc;
        float b0 = bias[col], b1 = bias[col + 1];
#pragma unroll
        for (int mt = 0; mt < 4; mt++) {
            int row = brow + wm + mt * 16 + lr;
            float2 v0 = make_float2(acc[mt][nt][0] + b0, acc[mt][nt][1] + b1);
            float2 v1 = make_float2(acc[mt][nt][2] + b0, acc[mt][nt][3] + b1);
            *(float2*)&C[(size_t)row * EMBD + col] = v0;
            *(float2*)&C[(size_t)(row + 8) * EMBD + col] = v1;
        }
    }
}

__global__ __launch_bounds__(256) void gemm_mma_k(
    const uint32_t* __restrict__ A, const uint32_t* __restrict__ Bt,
    const float* __restrict__ bias, float* __restrict__ C)
{
    extern __shared__ uint32_t dsm_u[];
    gemm_body(A, Bt, bias, C, dsm_u);
}

// merged QKV: blockIdx.z selects weight/bias/output
__global__ __launch_bounds__(256) void gemm_qkv_k(
    const uint32_t* __restrict__ A, const uint32_t* __restrict__ WtBase,
    const float* __restrict__ bq, const float* __restrict__ bk,
    const float* __restrict__ bv,
    float* __restrict__ q, float* __restrict__ k, float* __restrict__ v)
{
    extern __shared__ uint32_t dsm_u[];
    int z = blockIdx.z;
    const uint32_t* Bt = WtBase + (size_t)z * EMBD * EMBD;
    const float* bias = (z == 0) ? bq : (z == 1) ? bk : bv;
    float* C = (z == 0) ? q : (z == 1) ? k : v;
    gemm_body(A, Bt, bias, C, dsm_u);
}

// ============================================================================
// K2: RoPE
// ============================================================================
__global__ __launch_bounds__(256) void rope_k(float* __restrict__ q, float* __restrict__ k)
{
    size_t idx = (size_t)blockIdx.x * 256 + threadIdx.x;
    int rr = (int)(idx >> 10);
    int i = (int)(idx & 1023);
    int t = rr & (SEQ - 1);
    float inv = powf(10000.0f, -(float)(2 * i) * (1.0f / 2048.0f));
    float ang = (float)t * inv;
    float c = cosf(ang), s = sinf(ang);
    size_t base = (size_t)rr * EMBD + 2 * i;
    float a = q[base], b = q[base + 1];
    q[base] = a * c - b * s;
    q[base + 1] = a * s + b * c;
    a = k[base]; b = k[base + 1];
    k[base] = a * c - b * s;
    k[base + 1] = a * s + b * c;
}

// ============================================================================
// K3: batched scores:  S = scale * q_seg @ k_seg^T  (tf32 mma)
// ============================================================================
#define SBM 128
#define SBN 128
#define SBKP 36
__global__ __launch_bounds__(256) void scores_mma_k(
    const float* __restrict__ qb, const float* __restrict__ kb,
    float* __restrict__ S)
{
    extern __shared__ float dsm[];
    float* Ash = dsm;
    float* Bsh = dsm + 2 * SBM * SBKP;
    uint32_t sAu = smem_u32(Ash);
    uint32_t sBu = smem_u32(Bsh);

    const float scale = 0.08838834764831845f;
    const int tid = threadIdx.x;
    const int wid = tid >> 5;
    const int lane = tid & 31;
    const int lr = lane >> 2;
    const int lc = lane & 3;
    const int wm = (wid >> 2) * 64;
    const int wn = (wid & 3) * 32;

    int bhs = blockIdx.z;
    size_t segbase = ((size_t)bhs) << 16;
    const float* A = qb + segbase;
    const float* B = kb + segbase;
    int brow = blockIdx.y * SBM;
    int bcol = blockIdx.x * SBN;

    float acc[4][4][4];
#pragma unroll
    for (int mt = 0; mt < 4; mt++)
#pragma unroll
        for (int nt = 0; nt < 4; nt++)
#pragma unroll
            for (int r = 0; r < 4; r++) acc[mt][nt][r] = 0.f;

    auto load_st = [&](int k0, uint32_t sA, uint32_t sB) {
#pragma unroll
        for (int it = 0; it < 4; it++) {
            int idx = tid + it * 256;
            int row = idx >> 3, c4 = idx & 7;
            cp16(sA + (row * SBKP + c4 * 4) * 4,
                 A + (size_t)(brow + row) * DHEAD + k0 + c4 * 4);
        }
#pragma unroll
        for (int it = 0; it < 4; it++) {
            int idx = tid + it * 256;
            int row = idx >> 3, c4 = idx & 7;
            cp16(sB + (row * SBKP + c4 * 4) * 4,
                 B + (size_t)(bcol + row) * DHEAD + k0 + c4 * 4);
        }
        asm volatile("cp.async.commit_group;" ::: "memory");
    };

    load_st(0, sAu, sBu);
    load_st(BK, sAu + SBM * SBKP * 4, sBu + SBN * SBKP * 4);

    const int NIT = DHEAD / BK;
    for (int it = 0; it < NIT; it++) {
        int s = it & 1;
        if (it == NIT - 1) asm volatile("cp.async.wait_group 0;" ::: "memory");
        else               asm volatile("cp.async.wait_group 1;" ::: "memory");
        __syncthreads();

        const float* As = Ash + s * SBM * SBKP;
        const float* Bs = Bsh + s * SBN * SBKP;
#pragma unroll
        for (int kb = 0; kb < BK; kb += 8) {
            uint32_t af[4][4], bf[4][2];
#pragma unroll
            for (int mt = 0; mt < 4; mt++) {
                int r = wm + mt * 16 + lr;
                af[mt][0] = f2tf32(As[r * SBKP + kb + lc]);
                af[mt][1] = f2tf32(As[(r + 8) * SBKP + kb + lc]);
                af[mt][2] = f2tf32(As[r * SBKP + kb + lc + 4]);
                af[mt][3] = f2tf32(As[(r + 8) * SBKP + kb + lc + 4]);
            }
#pragma unroll
            for (int nt = 0; nt < 4; nt++) {
                int cN = wn + nt * 8 + lr;
                bf[nt][0] = f2tf32(Bs[cN * SBKP + kb + lc]);
                bf[nt][1] = f2tf32(Bs[cN * SBKP + kb + lc + 4]);
            }
#pragma unroll
            for (int mt = 0; mt < 4; mt++)
#pragma unroll
                for (int nt = 0; nt < 4; nt++)
                    mma_tf32(acc[mt][nt], af[mt], bf[nt]);
        }
        __syncthreads();
        if (it + 2 < NIT)
            load_st((it + 2) * BK, sAu + s * SBM * SBKP * 4, sBu + s * SBN * SBKP * 4);
    }

    float* Sb = S + (size_t)bhs * SEGL * SEGL;
#pragma unroll
    for (int nt = 0; nt < 4; nt++) {
        int col = bcol + wn + nt * 8 + 2 * lc;
#pragma unroll
        for (int mt = 0; mt < 4; mt++) {
            int row = brow + wm + mt * 16 + lr;
            float2 v0 = make_float2(acc[mt][nt][0] * scale, acc[mt][nt][1] * scale);
            float2 v1 = make_float2(acc[mt][nt][2] * scale, acc[mt][nt][3] * scale);
            *(float2*)&Sb[(size_t)row * SEGL + col] = v0;
            *(float2*)&Sb[(size_t)(row + 8) * SEGL + col] = v1;
        }
    }
}
#define SCORES_SMEM_BYTES (2 * (SBM + SBN) * SBKP * 4)

// ============================================================================
// K4: batched row softmax
// ============================================================================
__global__ __launch_bounds__(256) void softmax_k(float* __restrict__ S)
{
    int bhs = blockIdx.y;
    int row = blockIdx.x * 8 + (threadIdx.x >> 5);
    int lane = threadIdx.x & 31;
    float* r = S + ((size_t)bhs * SEGL + row) * SEGL;
    float vals[16];
    float mx = -1e30f;
#pragma unroll
    for (int i = 0; i < 16; i++) {
        vals[i] = r[lane + 32 * i];
        mx = fmaxf(mx, vals[i]);
    }
#pragma unroll
    for (int o = 16; o > 0; o >>= 1) mx = fmaxf(mx, __shfl_xor_sync(0xffffffffu, mx, o));
    float sum = 0.f;
#pragma unroll
    for (int i = 0; i < 16; i++) {
        vals[i] = expf(vals[i] - mx);
        sum += vals[i];
    }
#pragma unroll
    for (int o = 16; o > 0; o >>= 1) sum += __shfl_xor_sync(0xffffffffu, sum, o);
    float inv = 1.0f / sum;
#pragma unroll
    for (int i = 0; i < 16; i++) r[lane + 32 * i] = vals[i] * inv;
}

// ============================================================================
// K5: batched PV: attn = (1-g) * P @ v
// ============================================================================
#define VEP 136
#define PV_SMEM_BYTES ((2 * SBM * SBKP + 2 * BK * VEP) * 4)

__global__ __launch_bounds__(256) void pv_mma_k(
    const float* __restrict__ P, const float* __restrict__ vb,
    const float* __restrict__ beta, float* __restrict__ attnb)
{
    extern __shared__ float dsm[];
    float* Ash = dsm;
    float* Vsh = dsm + 2 * SBM * SBKP;
    uint32_t sAu = smem_u32(Ash);
    uint32_t sVu = smem_u32(Vsh);

    const int tid = threadIdx.x;
    const int wid = tid >> 5;
    const int lane = tid & 31;
    const int lr = lane >> 2;
    const int lc = lane & 3;
    const int wm = (wid >> 2) * 64;
    const int wn = (wid & 3) * 32;

    int bhs = blockIdx.y;
    size_t segbase = ((size_t)bhs) << 16;
    const float* Pseg = P + (size_t)bhs * SEGL * SEGL;
    const float* vseg = vb + segbase;
    int brow = blockIdx.x * SBM;
    float gm1 = 1.0f - 1.0f / (1.0f + expf(-beta[0]));

    float acc[4][4][4];
#pragma unroll
    for (int mt = 0; mt < 4; mt++)
#pragma unroll
        for (int nt = 0; nt < 4; nt++)
#pragma unroll
            for (int r = 0; r < 4; r++) acc[mt][nt][r] = 0.f;

    auto load_st = [&](int k0, uint32_t sA, uint32_t sV) {
#pragma unroll
        for (int it = 0; it < 4; it++) {
            int idx = tid + it * 256;
            int row = idx >> 3, c4 = idx & 7;
            cp16(sA + (row * SBKP + c4 * 4) * 4,
                 Pseg + (size_t)(brow + row) * SEGL + k0 + c4 * 4);
        }
#pragma unroll
        for (int it = 0; it < 4; it++) {
            int idx = tid + it * 256;
            int row = idx >> 5, c4 = idx & 31;
            cp16(sV + (row * VEP + c4 * 4) * 4,
                 vseg + (size_t)(k0 + row) * DHEAD + c4 * 4);
        }
        asm volatile("cp.async.commit_group;" ::: "memory");
    };

    load_st(0, sAu, sVu);
    load_st(BK, sAu + SBM * SBKP * 4, sVu + BK * VEP * 4);

    const int NIT = SEGL / BK;
    for (int it = 0; it < NIT; it++) {
        int s = it & 1;
        if (it == NIT - 1) asm volatile("cp.async.wait_group 0;" ::: "memory");
        else               asm volatile("cp.async.wait_group 1;" ::: "memory");
        __syncthreads();

        const float* As = Ash + s * SBM * SBKP;
        const float* Vs = Vsh + s * BK * VEP;
#pragma unroll
        for (int kb = 0; kb < BK; kb += 8) {
            uint32_t af[4][4], bf[4][2];
#pragma unroll
            for (int mt = 0; mt < 4; mt++) {
                int r = wm + mt * 16 + lr;
                af[mt][0] = f2tf32(As[r * SBKP + kb + lc]);
                af[mt][1] = f2tf32(As[(r + 8) * SBKP + kb + lc]);
                af[mt][2] = f2tf32(As[r * SBKP + kb + lc + 4]);
                af[mt][3] = f2tf32(As[(r + 8) * SBKP + kb + lc + 4]);
            }
#pragma unroll
            for (int nt = 0; nt < 4; nt++) {
                int cN = wn + nt * 8 + lr;
                bf[nt][0] = f2tf32(Vs[(kb + lc) * VEP + cN]);
                bf[nt][1] = f2tf32(Vs[(kb + lc + 4) * VEP + cN]);
            }
#pragma unroll
            for (int mt = 0; mt < 4; mt++)
#pragma unroll
                for (int nt = 0; nt < 4; nt++)
                    mma_tf32(acc[mt][nt], af[mt], bf[nt]);
        }
        __syncthreads();
        if (it + 2 < NIT)
            load_st((it + 2) * BK, sAu + s * SBM * SBKP * 4, sVu + s * BK * VEP * 4);
    }

#pragma unroll
    for (int nt = 0; nt < 4; nt++) {
        int col = wn + nt * 8 + 2 * lc;
#pragma unroll
        for (int mt = 0; mt < 4; mt++) {
            int row = brow + wm + mt * 16 + lr;
            float2 v0 = make_float2(acc[mt][nt][0] * gm1, acc[mt][nt][1] * gm1);
            float2 v1 = make_float2(acc[mt][nt][2] * gm1, acc[mt][nt][3] * gm1);
            *(float2*)&attnb[segbase + (size_t)row * DHEAD + col] = v0;
            *(float2*)&attnb[segbase + (size_t)(row + 8) * DHEAD + col] = v1;
        }
    }
}

// ============================================================================
// K6: per-segment outer products
// ============================================================================
__global__ __launch_bounds__(256) void outer_k(
    const float* __restrict__ kb, const float* __restrict__ vb,
    float* __restrict__ memseg, float* __restrict__ Zseg)
{
    int bhs = blockIdx.x;
    size_t segbase = ((size_t)bhs) << 16;
    const float* kseg = kb + segbase;
    const float* vseg = vb + segbase;

    __shared__ float As[16][128];
    __shared__ float Bs[16][128];
    int tid = threadIdx.x;
    int tx = tid & 15, ty = tid >> 4;
    int br = tid >> 5, bc4 = tid & 31;

    float acc[8][8];
    float zacc[8];
#pragma unroll
    for (int i = 0; i < 8; i++) {
        zacc[i] = 0.f;
#pragma unroll
        for (int j = 0; j < 8; j++) acc[i][j] = 0.f;
    }

    for (int l0 = 0; l0 < SEGL; l0 += 16) {
#pragma unroll
        for (int i = 0; i < 2; i++) {
            int r = br + i * 8;
            float4 kv = *(const float4*)&kseg[(size_t)(l0 + r) * DHEAD + bc4 * 4];
            As[r][bc4 * 4 + 0] = elu1(kv.x); As[r][bc4 * 4 + 1] = elu1(kv.y);
            As[r][bc4 * 4 + 2] = elu1(kv.z); As[r][bc4 * 4 + 3] = elu1(kv.w);
            float4 vv = *(const float4*)&vseg[(size_t)(l0 + r) * DHEAD + bc4 * 4];
            *(float4*)&Bs[r][bc4 * 4] = vv;
        }
        __syncthreads();
#pragma unroll
        for (int kk = 0; kk < 16; kk++) {
            float ra[8], rb[8];
#pragma unroll
            for (int i = 0; i < 8; i++) ra[i] = As[kk][ty * 8 + i];
#pragma unroll
            for (int j = 0; j < 8; j++) rb[j] = Bs[kk][tx * 8 + j];
#pragma unroll
            for (int i = 0; i < 8; i++)
#pragma unroll
                for (int j = 0; j < 8; j++) acc[i][j] += ra[i] * rb[j];
            if (tx == 0) {
#pragma unroll
                for (int i = 0; i < 8; i++) zacc[i] += ra[i];
            }
        }
        __syncthreads();
    }
    float* memb = memseg + (size_t)bhs * DHEAD * DHEAD;
#pragma unroll
    for (int i = 0; i < 8; i++)
#pragma unroll
        for (int j = 0; j < 8; j++)
            memb[(size_t)(ty * 8 + i) * DHEAD + tx * 8 + j] = acc[i][j];
    if (tx == 0) {
#pragma unroll
        for (int i = 0; i < 8; i++) Zseg[bhs * DHEAD + ty * 8 + i] = zacc[i];
    }
}

// ============================================================================
// K7: in-place exclusive prefix over the 8 segments
// ============================================================================
__global__ __launch_bounds__(256) void prefix_mem_k(float* __restrict__ memseg)
{
    size_t idx = (size_t)blockIdx.x * 256 + threadIdx.x;
    int bh = (int)(idx >> 14);
    int off = (int)(idx & 16383);
    size_t base = ((size_t)bh * NSEG) * 16384 + off;
    float run = 0.f;
#pragma unroll
    for (int s = 0; s < NSEG; s++) {
        float t = memseg[base + (size_t)s * 16384];
        memseg[base + (size_t)s * 16384] = run;
        run += t;
    }
}

__global__ __launch_bounds__(256) void prefix_Z_k(float* __restrict__ Zseg)
{
    int idx = blockIdx.x * 256 + threadIdx.x;
    int bh = idx >> 7;
    int d = idx & 127;
    int base = bh * NSEG * DHEAD + d;
    float run = 0.f;
#pragma unroll
    for (int s = 0; s < NSEG; s++) {
        float t = Zseg[base + s * DHEAD];
        Zseg[base + s * DHEAD] = run;
        run += t;
    }
}

// ============================================================================
// K8: tensorized A_mem for ALL segments, fused final-combine + perm-cvt:
//     attnp = permcvt( g*(sq@mem)/(rowsum(sq)*Z+1e-6) + attn )
//     CTA = (128 l-rows x 128 e-cols), K=128, single smem-resident stage
// ============================================================================
#define AMP 136
#define AMEM_SMEM_BYTES ((2 * 128 * AMP + 256) * 4)

__global__ __launch_bounds__(256) void amem_mma_k(
    const float* __restrict__ qb, const float* __restrict__ memseg,
    const float* __restrict__ Zseg, const float* __restrict__ beta,
    const float* __restrict__ attnb, uint32_t* __restrict__ attnp)
{
    extern __shared__ uint32_t smu[];
    uint32_t* qs = smu;                  // [128][AMP] tf32(elu1(q))
    uint32_t* ms = smu + 128 * AMP;      // [128][AMP] tf32(mem)
    float* rowsumS = (float*)(smu + 2 * 128 * AMP); // [128]
    float* Zs = rowsumS + 128;                      // [128]
    uint32_t sqb = smem_u32(qs);
    uint32_t smb = smem_u32(ms);

    const int tid = threadIdx.x;
    const int wid = tid >> 5;
    const int lane = tid & 31;
    const int lr = lane >> 2;
    const int lc = lane & 3;
    const int wm = (wid >> 2) * 64;
    const int wn = (wid & 3) * 32;

    int bhs = blockIdx.y;
    int l0 = blockIdx.x * 128;
    size_t segbase = ((size_t)bhs) << 16;
    const float* qseg = qb + segbase;
    const float* memb = memseg + (size_t)bhs * DHEAD * DHEAD;
    float g = 1.0f / (1.0f + expf(-beta[0]));

    // stage q tile and mem tile (each 128x128 fp32)
#pragma unroll
    for (int it = 0; it < 16; it++) {
        int idx = tid + it * 256;
        int row = idx >> 5, c4 = idx & 31;
        cp16(sqb + (row * AMP + c4 * 4) * 4,
             qseg + (size_t)(l0 + row) * DHEAD + c4 * 4);
    }
#pragma unroll
    for (int it = 0; it < 16; it++) {
        int idx = tid + it * 256;
        int row = idx >> 5, c4 = idx & 31;
        cp16(smb + (row * AMP + c4 * 4) * 4,
             memb + (size_t)row * DHEAD + c4 * 4);
    }
    asm volatile("cp.async.commit_group;" ::: "memory");
    asm volatile("cp.async.wait_group 0;" ::: "memory");
    __syncthreads();

    // in-place convert: q -> tf32(elu1(q)) with rowsum; mem -> tf32(mem)
    {
        int r = tid >> 1;
        int half = (tid & 1) * 64;
        float partial = 0.f;
#pragma unroll 16
        for (int j = 0; j < 64; j++) {
            uint32_t* p = &qs[r * AMP + half + j];
            float e = elu1(__uint_as_float(*p));
            partial += e;
            *p = f2tf32(e);
        }
        partial += __shfl_xor_sync(0xffffffffu, partial, 1);
        if ((tid & 1) == 0) rowsumS[r] = partial;
#pragma unroll 16
        for (int j = 0; j < 64; j++) {
            uint32_t* p = &ms[r * AMP + half + j];
            *p = f2tf32(__uint_as_float(*p));
        }
    }
    if (tid < 128) Zs[tid] = Zseg[bhs * DHEAD + tid];
    __syncthreads();

    float acc[4][4][4];
#pragma unroll
    for (int mt = 0; mt < 4; mt++)
#pragma unroll
        for (int nt = 0; nt < 4; nt++)
#pragma unroll
            for (int r = 0; r < 4; r++) acc[mt][nt][r] = 0.f;

#pragma unroll
    for (int kb = 0; kb < 128; kb += 8) {
        uint32_t af[4][4], bf[4][2];
#pragma unroll
        for (int mt = 0; mt < 4; mt++) {
            int r = wm + mt * 16 + lr;
            af[mt][0] = qs[r * AMP + kb + lc];
            af[mt][1] = qs[(r + 8) * AMP + kb + lc];
            af[mt][2] = qs[r * AMP + kb + lc + 4];
            af[mt][3] = qs[(r + 8) * AMP + kb + lc + 4];
        }
#pragma unroll
        for (int nt = 0; nt < 4; nt++) {
            int cN = wn + nt * 8 + lr;
            bf[nt][0] = ms[(kb + lc) * AMP + cN];
            bf[nt][1] = ms[(kb + lc + 4) * AMP + cN];
        }
#pragma unroll
        for (int mt = 0; mt < 4; mt++)
#pragma unroll
            for (int nt = 0; nt < 4; nt++)
                mma_tf32(acc[mt][nt], af[mt], bf[nt]);
    }

    // epilogue: combine + permuted tf32 store
#pragma unroll
    for (int nt = 0; nt < 4; nt++) {
        int col = wn + nt * 8 + 2 * lc;           // even
        int gb = col & ~7;
        int st0 = gb + pidx(col & 7);
        int st1 = gb + pidx((col & 7) + 1);
        float Z0 = Zs[col], Z1 = Zs[col + 1];
#pragma unroll
        for (int mt = 0; mt < 4; mt++) {
#pragma unroll
            for (int h = 0; h < 2; h++) {
                int rloc = wm + mt * 16 + lr + h * 8;
                int row = l0 + rloc;
                float rs = rowsumS[rloc];
                float2 at = *(const float2*)&attnb[segbase + (size_t)row * DHEAD + col];
                float a0 = g * acc[mt][nt][2 * h + 0] / (rs * Z0 + 1e-6f) + at.x;
                float a1 = g * acc[mt][nt][2 * h + 1] / (rs * Z1 + 1e-6f) + at.y;
                attnp[segbase + (size_t)row * DHEAD + st0] = f2tf32(a0);
                attnp[segbase + (size_t)row * DHEAD + st1] = f2tf32(a1);
            }
        }
    }
}

// ============================================================================
// Host launch
// ============================================================================
extern "C" void kernel_launch(void* const* d_in, const int* in_sizes, int n_in,
                              void* d_out, int out_size)
{
    (void)in_sizes; (void)n_in; (void)out_size;
    const float* x    = (const float*)d_in[0];
    const float* Wq   = (const float*)d_in[1];
    const float* bq   = (const float*)d_in[2];
    const float* Wk   = (const float*)d_in[3];
    const float* bk   = (const float*)d_in[4];
    const float* Wv   = (const float*)d_in[5];
    const float* bv   = (const float*)d_in[6];
    const float* Wo   = (const float*)d_in[7];
    const float* bo   = (const float*)d_in[8];
    const float* beta = (const float*)d_in[9];
    float* out = (float*)d_out;

    static float *pq = nullptr, *pk = nullptr, *pv = nullptr, *pattn = nullptr,
                 *pscores = nullptr, *pmemseg = nullptr, *pZseg = nullptr;
    static uint32_t *pWt = nullptr, *pxp = nullptr, *pattnp = nullptr;
    if (!pq) {
        cudaGetSymbolAddress((void**)&pq, g_q);
        cudaGetSymbolAddress((void**)&pk, g_k);
        cudaGetSymbolAddress((void**)&pv, g_v);
        cudaGetSymbolAddress((void**)&pattn, g_attn);
        cudaGetSymbolAddress((void**)&pscores, g_scores);
        cudaGetSymbolAddress((void**)&pmemseg, g_memseg);
        cudaGetSymbolAddress((void**)&pZseg, g_Zseg);
        cudaGetSymbolAddress((void**)&pWt, g_Wt);
        cudaGetSymbolAddress((void**)&pxp, g_xp);
        cudaGetSymbolAddress((void**)&pattnp, g_attnp);
        cudaFuncSetAttribute(gemm_mma_k, cudaFuncAttributeMaxDynamicSharedMemorySize,
                             GEMM_SMEM_BYTES);
        cudaFuncSetAttribute(gemm_qkv_k, cudaFuncAttributeMaxDynamicSharedMemorySize,
                             GEMM_SMEM_BYTES);
        cudaFuncSetAttribute(scores_mma_k, cudaFuncAttributeMaxDynamicSharedMemorySize,
                             SCORES_SMEM_BYTES);
        cudaFuncSetAttribute(pv_mma_k, cudaFuncAttributeMaxDynamicSharedMemorySize,
                             PV_SMEM_BYTES);
        cudaFuncSetAttribute(amem_mma_k, cudaFuncAttributeMaxDynamicSharedMemorySize,
                             AMEM_SMEM_BYTES);
    }

    const size_t WSZ = (size_t)EMBD * EMBD;
    dim3 tgrid(EMBD / 32, EMBD / 32);
    dim3 tblk(32, 8);
    transpose_tf32_k<<<tgrid, tblk>>>(Wq, pWt + 0 * WSZ);
    transpose_tf32_k<<<tgrid, tblk>>>(Wk, pWt + 1 * WSZ);
    transpose_tf32_k<<<tgrid, tblk>>>(Wv, pWt + 2 * WSZ);
    transpose_tf32_k<<<tgrid, tblk>>>(Wo, pWt + 3 * WSZ);

    perm_cvt_k<<<(int)(TOTAL / 8 / 256), 256>>>(x, pxp);

    dim3 qkvgrid(EMBD / BN, MTOK / BM, 3); // (8, 128, 3)
    gemm_qkv_k<<<qkvgrid, 256, GEMM_SMEM_BYTES>>>(pxp, pWt, bq, bk, bv, pq, pk, pv);

    rope_k<<<(MTOK * (EMBD / 2)) / 256, 256>>>(pq, pk);

    // parallel linear-memory path
    outer_k<<<NBH * NSEG, 256>>>(pk, pv, pmemseg, pZseg);
    prefix_mem_k<<<(NBH * 16384) / 256, 256>>>(pmemseg);
    prefix_Z_k<<<(NBH * DHEAD) / 256, 256>>>(pZseg);

    // batched attention: scores -> softmax -> (1-g)*PV
    scores_mma_k<<<dim3(SEGL / SBN, SEGL / SBM, NBH * NSEG), 256, SCORES_SMEM_BYTES>>>(
        pq, pk, pscores);
    softmax_k<<<dim3(SEGL / 8, NBH * NSEG), 256>>>(pscores);
    pv_mma_k<<<dim3(SEGL / SBM, NBH * NSEG), 256, PV_SMEM_BYTES>>>(
        pscores, pv, beta, pattn);

    // tensorized A_mem + combine + perm-cvt fused
    amem_mma_k<<<dim3(SEGL / 128, NBH * NSEG), 256, AMEM_SMEM_BYTES>>>(
        pq, pmemseg, pZseg, beta, pattn, pattnp);

    gemm_mma_k<<<dim3(EMBD / BN, MTOK / BM), 256, GEMM_SMEM_BYTES>>>(
        pattnp, pWt + 3 * WSZ, bo, out);
}

// round 9
// speedup vs baseline: 4.8124x; 1.4033x over previous
#include <cuda_runtime.h>
#include <cuda_fp16.h>
#include <math.h>
#include <stdint.h>

// Problem constants
#define SEQ   4096
#define EMBD  2048
#define NB    4
#define NHEAD 16
#define DHEAD 128
#define NSEG  8
#define SEGL  512
#define NBH   (NB * NHEAD)          // 64
#define MTOK  (NB * SEQ)            // 16384
#define TOTAL ((size_t)MTOK * EMBD) // 33554432
#define EMBD_U (EMBD / 2)           // 1024 u32 (fp16 pairs) per row

// -------- device scratch ----------------------------------------------------
__device__ float g_q[TOTAL];
__device__ float g_k[TOTAL];
__device__ float g_v[TOTAL];
__device__ float g_attn[TOTAL];
__device__ float g_scores[(size_t)NBH * NSEG * SEGL * SEGL]; // 512MB
__device__ float g_memseg[(size_t)NBH * NSEG * DHEAD * DHEAD];
__device__ float g_Zseg[NBH * NSEG * DHEAD];
__device__ uint32_t g_Wth[(size_t)4 * EMBD * EMBD_U]; // transposed+permuted fp16
__device__ uint32_t g_xh[TOTAL / 2];                  // permuted fp16 x
__device__ uint32_t g_attnh[TOTAL / 2];               // permuted fp16 attn

__device__ __forceinline__ float elu1(float x) {
    return (x > 0.f) ? (x + 1.f) : expf(x);
}

__device__ __forceinline__ uint32_t smem_u32(const void* p) {
    uint32_t a;
    asm("{ .reg .u64 t; cvta.to.shared.u64 t, %1; cvt.u32.u64 %0, t; }"
        : "=r"(a) : "l"(p));
    return a;
}

__device__ __forceinline__ void cp16(uint32_t saddr, const void* g) {
    asm volatile("cp.async.cg.shared.global [%0], [%1], 16;" :: "r"(saddr), "l"(g));
}

__device__ __forceinline__ uint32_t f2tf32(float x) {
    uint32_t u;
    asm("cvt.rna.tf32.f32 %0, %1;" : "=r"(u) : "f"(x));
    return u;
}

__device__ __forceinline__ uint32_t packh2(float lo, float hi) {
    __half2 h = __floats2half2_rn(lo, hi);
    return *(uint32_t*)&h;
}

__device__ __forceinline__ void mma_tf32(float* d, const uint32_t* a, const uint32_t* b) {
    asm volatile(
        "mma.sync.aligned.m16n8k8.row.col.f32.tf32.tf32.f32 "
        "{%0,%1,%2,%3}, {%4,%5,%6,%7}, {%8,%9}, {%0,%1,%2,%3};"
        : "+f"(d[0]), "+f"(d[1]), "+f"(d[2]), "+f"(d[3])
        : "r"(a[0]), "r"(a[1]), "r"(a[2]), "r"(a[3]), "r"(b[0]), "r"(b[1]));
}

__device__ __forceinline__ void mma_f16(float* d, const uint32_t* a, const uint32_t* b) {
    asm volatile(
        "mma.sync.aligned.m16n8k16.row.col.f32.f16.f16.f32 "
        "{%0,%1,%2,%3}, {%4,%5,%6,%7}, {%8,%9}, {%0,%1,%2,%3};"
        : "+f"(d[0]), "+f"(d[1]), "+f"(d[2]), "+f"(d[3])
        : "r"(a[0]), "r"(a[1]), "r"(a[2]), "r"(a[3]), "r"(b[0]), "r"(b[1]));
}

// permuted u32 position within an 8-u32 (16 fp16) group
__device__ __forceinline__ int pposu(int j) { return (j < 4) ? 2 * j : 2 * (j - 4) + 1; }

// ============================================================================
// K0a: transpose + u32-permute + fp16 convert:  Wth[n][perm(k/2)] = h2(W[k,n],W[k+1,n])
// ============================================================================
__global__ __launch_bounds__(256) void transpose_fp16_k(const float* __restrict__ W,
                                                        uint32_t* __restrict__ Wth)
{
    __shared__ float t[32][33];
    int bx = blockIdx.x * 32, by = blockIdx.y * 32;
    int txx = threadIdx.x;
    for (int i = threadIdx.y; i < 32; i += 8)
        t[i][txx] = W[(size_t)(by + i) * EMBD + bx + txx];
    __syncthreads();
    if (txx < 16) {
        int j = txx & 7;
        int pos = (by >> 1) + (txx >> 3) * 8 + pposu(j);
        for (int i = threadIdx.y; i < 32; i += 8) {
            uint32_t u = packh2(t[2 * txx][i], t[2 * txx + 1][i]);
            Wth[(size_t)(bx + i) * EMBD_U + pos] = u;
        }
    }
}

// ============================================================================
// K0b: u32-permute + fp16 convert of an activation matrix (one 16-group / thread)
// ============================================================================
__global__ __launch_bounds__(256) void perm_cvt_fp16_k(const float* __restrict__ src,
                                                       uint32_t* __restrict__ dst)
{
    size_t g16 = (size_t)blockIdx.x * 256 + threadIdx.x;
    size_t base = g16 * 16;
    float4 f0 = *(const float4*)&src[base];
    float4 f1 = *(const float4*)&src[base + 4];
    float4 f2 = *(const float4*)&src[base + 8];
    float4 f3 = *(const float4*)&src[base + 12];
    // orig u32 j holds (2j, 2j+1); permuted order [0,4,1,5,2,6,3,7]
    uint4 o0, o1;
    o0.x = packh2(f0.x, f0.y);   // orig 0
    o0.y = packh2(f2.x, f2.y);   // orig 4
    o0.z = packh2(f0.z, f0.w);   // orig 1
    o0.w = packh2(f2.z, f2.w);   // orig 5
    o1.x = packh2(f1.x, f1.y);   // orig 2
    o1.y = packh2(f3.x, f3.y);   // orig 6
    o1.z = packh2(f1.z, f1.w);   // orig 3
    o1.w = packh2(f3.z, f3.w);   // orig 7
    *(uint4*)&dst[g16 * 8] = o0;
    *(uint4*)&dst[g16 * 8 + 4] = o1;
}

// ============================================================================
// K1: fp16 mma.sync GEMM, CTA 128x256x32, 3-stage pipeline, warp tile 64x64
// ============================================================================
#define BM 128
#define BN 256
#define BK 32                       // elements; 16 u32 per row per stage
#define BKU 16
#define BKP_U 24
#define NSTG 3
#define STG_U ((BM + BN) * BKP_U)   // 9216 u32 per stage
#define GEMM_SMEM_BYTES (NSTG * STG_U * 4)  // 110592

__device__ __forceinline__ void load_stage_h(const uint32_t* __restrict__ A,
                                             const uint32_t* __restrict__ Bt,
                                             int brow, int bcol, int k0u,
                                             uint32_t sA, uint32_t sB, int tid)
{
#pragma unroll
    for (int it = 0; it < 2; it++) {        // A: 128 rows x 4 cp16
        int idx = tid + it * 256;
        int row = idx >> 2, c4 = idx & 3;
        cp16(sA + (row * BKP_U + c4 * 4) * 4,
             A + (size_t)(brow + row) * EMBD_U + k0u + c4 * 4);
    }
#pragma unroll
    for (int it = 0; it < 4; it++) {        // B: 256 rows x 4 cp16
        int idx = tid + it * 256;
        int row = idx >> 2, c4 = idx & 3;
        cp16(sB + (row * BKP_U + c4 * 4) * 4,
             Bt + (size_t)(bcol + row) * EMBD_U + k0u + c4 * 4);
    }
    asm volatile("cp.async.commit_group;" ::: "memory");
}

__device__ __forceinline__ void gemm_body(
    const uint32_t* __restrict__ A, const uint32_t* __restrict__ Bt,
    const float* __restrict__ bias, float* __restrict__ C,
    uint32_t* dsm_u)
{
    uint32_t sbase = smem_u32(dsm_u);
    const int tid = threadIdx.x;
    const int wid = tid >> 5;
    const int lane = tid & 31;
    const int lr = lane >> 2;
    const int lc = lane & 3;
    const int wm = (wid >> 2) * 64;
    const int wn = (wid & 3) * 64;

    int brow = blockIdx.y * BM;
    int bcol = blockIdx.x * BN;

    float acc[4][8][4];
#pragma unroll
    for (int mt = 0; mt < 4; mt++)
#pragma unroll
        for (int nt = 0; nt < 8; nt++)
#pragma unroll
            for (int r = 0; r < 4; r++) acc[mt][nt][r] = 0.f;

    uint32_t sA[NSTG], sB[NSTG];
#pragma unroll
    for (int s = 0; s < NSTG; s++) {
        sA[s] = sbase + s * STG_U * 4;
        sB[s] = sA[s] + BM * BKP_U * 4;
    }

    load_stage_h(A, Bt, brow, bcol, 0 * BKU, sA[0], sB[0], tid);
    load_stage_h(A, Bt, brow, bcol, 1 * BKU, sA[1], sB[1], tid);
    load_stage_h(A, Bt, brow, bcol, 2 * BKU, sA[2], sB[2], tid);

    const int NIT = EMBD / BK; // 64
    for (int it = 0; it < NIT; it++) {
        if (it < NIT - 2)       asm volatile("cp.async.wait_group 2;" ::: "memory");
        else if (it == NIT - 2) asm volatile("cp.async.wait_group 1;" ::: "memory");
        else                    asm volatile("cp.async.wait_group 0;" ::: "memory");
        __syncthreads();

        int s = it % NSTG;
        const uint32_t* As = dsm_u + (size_t)s * STG_U;
        const uint32_t* Bs = As + BM * BKP_U;

#pragma unroll
        for (int kc = 0; kc < 2; kc++) {     // two k16 chunks per BK=32
            int off = kc * 8 + 2 * lc;
            uint32_t af[4][4], bf[8][2];
#pragma unroll
            for (int mt = 0; mt < 4; mt++) {
                int r = wm + mt * 16 + lr;
                uint2 a0 = *(const uint2*)&As[r * BKP_U + off];
                uint2 a1 = *(const uint2*)&As[(r + 8) * BKP_U + off];
                af[mt][0] = a0.x; af[mt][2] = a0.y;   // (lc) , (lc+4)
                af[mt][1] = a1.x; af[mt][3] = a1.y;
            }
#pragma unroll
            for (int nt = 0; nt < 8; nt++) {
                int cN = wn + nt * 8 + lr;
                uint2 b = *(const uint2*)&Bs[cN * BKP_U + off];
                bf[nt][0] = b.x; bf[nt][1] = b.y;
            }
#pragma unroll
            for (int mt = 0; mt < 4; mt++)
#pragma unroll
                for (int nt = 0; nt < 8; nt++)
                    mma_f16(acc[mt][nt], af[mt], bf[nt]);
        }
        __syncthreads();

        if (it + NSTG < NIT)
            load_stage_h(A, Bt, brow, bcol, (it + NSTG) * BKU, sA[s], sB[s], tid);
    }

#pragma unroll
    for (int nt = 0; nt < 8; nt++) {
        int col = bcol + wn + nt * 8 + 2 * lc;
        float b0 = bias[col], b1 = bias[col + 1];
#pragma unroll
        for (int mt = 0; mt < 4; mt++) {
            int row = brow + wm + mt * 16 + lr;
            float2 v0 = make_float2(acc[mt][nt][0] + b0, acc[mt][nt][1] + b1);
            float2 v1 = make_float2(acc[mt][nt][2] + b0, acc[mt][nt][3] + b1);
            *(float2*)&C[(size_t)row * EMBD + col] = v0;
            *(float2*)&C[(size_t)(row + 8) * EMBD + col] = v1;
        }
    }
}

__global__ __launch_bounds__(256) void gemm_mma_k(
    const uint32_t* __restrict__ A, const uint32_t* __restrict__ Bt,
    const float* __restrict__ bias, float* __restrict__ C)
{
    extern __shared__ uint32_t dsm_u[];
    gemm_body(A, Bt, bias, C, dsm_u);
}

__global__ __launch_bounds__(256) void gemm_qkv_k(
    const uint32_t* __restrict__ A, const uint32_t* __restrict__ WtBase,
    const float* __restrict__ bq, const float* __restrict__ bk,
    const float* __restrict__ bv,
    float* __restrict__ q, float* __restrict__ k, float* __restrict__ v)
{
    extern __shared__ uint32_t dsm_u[];
    int z = blockIdx.z;
    const uint32_t* Bt = WtBase + (size_t)z * EMBD * EMBD_U;
    const float* bias = (z == 0) ? bq : (z == 1) ? bk : bv;
    float* C = (z == 0) ? q : (z == 1) ? k : v;
    gemm_body(A, Bt, bias, C, dsm_u);
}

// ============================================================================
// K2: RoPE
// ============================================================================
__global__ __launch_bounds__(256) void rope_k(float* __restrict__ q, float* __restrict__ k)
{
    size_t idx = (size_t)blockIdx.x * 256 + threadIdx.x;
    int rr = (int)(idx >> 10);
    int i = (int)(idx & 1023);
    int t = rr & (SEQ - 1);
    float inv = powf(10000.0f, -(float)(2 * i) * (1.0f / 2048.0f));
    float ang = (float)t * inv;
    float c = cosf(ang), s = sinf(ang);
    size_t base = (size_t)rr * EMBD + 2 * i;
    float a = q[base], b = q[base + 1];
    q[base] = a * c - b * s;
    q[base + 1] = a * s + b * c;
    a = k[base]; b = k[base + 1];
    k[base] = a * c - b * s;
    k[base + 1] = a * s + b * c;
}

// ============================================================================
// K3: batched scores (tf32 mma, unchanged)
// ============================================================================
#define SBM 128
#define SBN 128
#define SBK 32
#define SBKP 36
__global__ __launch_bounds__(256) void scores_mma_k(
    const float* __restrict__ qb, const float* __restrict__ kb,
    float* __restrict__ S)
{
    extern __shared__ float dsm[];
    float* Ash = dsm;
    float* Bsh = dsm + 2 * SBM * SBKP;
    uint32_t sAu = smem_u32(Ash);
    uint32_t sBu = smem_u32(Bsh);

    const float scale = 0.08838834764831845f;
    const int tid = threadIdx.x;
    const int wid = tid >> 5;
    const int lane = tid & 31;
    const int lr = lane >> 2;
    const int lc = lane & 3;
    const int wm = (wid >> 2) * 64;
    const int wn = (wid & 3) * 32;

    int bhs = blockIdx.z;
    size_t segbase = ((size_t)bhs) << 16;
    const float* A = qb + segbase;
    const float* B = kb + segbase;
    int brow = blockIdx.y * SBM;
    int bcol = blockIdx.x * SBN;

    float acc[4][4][4];
#pragma unroll
    for (int mt = 0; mt < 4; mt++)
#pragma unroll
        for (int nt = 0; nt < 4; nt++)
#pragma unroll
            for (int r = 0; r < 4; r++) acc[mt][nt][r] = 0.f;

    auto load_st = [&](int k0, uint32_t sA, uint32_t sB) {
#pragma unroll
        for (int it = 0; it < 4; it++) {
            int idx = tid + it * 256;
            int row = idx >> 3, c4 = idx & 7;
            cp16(sA + (row * SBKP + c4 * 4) * 4,
                 A + (size_t)(brow + row) * DHEAD + k0 + c4 * 4);
        }
#pragma unroll
        for (int it = 0; it < 4; it++) {
            int idx = tid + it * 256;
            int row = idx >> 3, c4 = idx & 7;
            cp16(sB + (row * SBKP + c4 * 4) * 4,
                 B + (size_t)(bcol + row) * DHEAD + k0 + c4 * 4);
        }
        asm volatile("cp.async.commit_group;" ::: "memory");
    };

    load_st(0, sAu, sBu);
    load_st(SBK, sAu + SBM * SBKP * 4, sBu + SBN * SBKP * 4);

    const int NIT = DHEAD / SBK;
    for (int it = 0; it < NIT; it++) {
        int s = it & 1;
        if (it == NIT - 1) asm volatile("cp.async.wait_group 0;" ::: "memory");
        else               asm volatile("cp.async.wait_group 1;" ::: "memory");
        __syncthreads();

        const float* As = Ash + s * SBM * SBKP;
        const float* Bs = Bsh + s * SBN * SBKP;
#pragma unroll
        for (int kb = 0; kb < SBK; kb += 8) {
            uint32_t af[4][4], bf[4][2];
#pragma unroll
            for (int mt = 0; mt < 4; mt++) {
                int r = wm + mt * 16 + lr;
                af[mt][0] = f2tf32(As[r * SBKP + kb + lc]);
                af[mt][1] = f2tf32(As[(r + 8) * SBKP + kb + lc]);
                af[mt][2] = f2tf32(As[r * SBKP + kb + lc + 4]);
                af[mt][3] = f2tf32(As[(r + 8) * SBKP + kb + lc + 4]);
            }
#pragma unroll
            for (int nt = 0; nt < 4; nt++) {
                int cN = wn + nt * 8 + lr;
                bf[nt][0] = f2tf32(Bs[cN * SBKP + kb + lc]);
                bf[nt][1] = f2tf32(Bs[cN * SBKP + kb + lc + 4]);
            }
#pragma unroll
            for (int mt = 0; mt < 4; mt++)
#pragma unroll
                for (int nt = 0; nt < 4; nt++)
                    mma_tf32(acc[mt][nt], af[mt], bf[nt]);
        }
        __syncthreads();
        if (it + 2 < NIT)
            load_st((it + 2) * SBK, sAu + s * SBM * SBKP * 4, sBu + s * SBN * SBKP * 4);
    }

    float* Sb = S + (size_t)bhs * SEGL * SEGL;
#pragma unroll
    for (int nt = 0; nt < 4; nt++) {
        int col = bcol + wn + nt * 8 + 2 * lc;
#pragma unroll
        for (int mt = 0; mt < 4; mt++) {
            int row = brow + wm + mt * 16 + lr;
            float2 v0 = make_float2(acc[mt][nt][0] * scale, acc[mt][nt][1] * scale);
            float2 v1 = make_float2(acc[mt][nt][2] * scale, acc[mt][nt][3] * scale);
            *(float2*)&Sb[(size_t)row * SEGL + col] = v0;
            *(float2*)&Sb[(size_t)(row + 8) * SEGL + col] = v1;
        }
    }
}
#define SCORES_SMEM_BYTES (2 * (SBM + SBN) * SBKP * 4)

// ============================================================================
// K4: batched row softmax
// ============================================================================
__global__ __launch_bounds__(256) void softmax_k(float* __restrict__ S)
{
    int bhs = blockIdx.y;
    int row = blockIdx.x * 8 + (threadIdx.x >> 5);
    int lane = threadIdx.x & 31;
    float* r = S + ((size_t)bhs * SEGL + row) * SEGL;
    float vals[16];
    float mx = -1e30f;
#pragma unroll
    for (int i = 0; i < 16; i++) {
        vals[i] = r[lane + 32 * i];
        mx = fmaxf(mx, vals[i]);
    }
#pragma unroll
    for (int o = 16; o > 0; o >>= 1) mx = fmaxf(mx, __shfl_xor_sync(0xffffffffu, mx, o));
    float sum = 0.f;
#pragma unroll
    for (int i = 0; i < 16; i++) {
        vals[i] = expf(vals[i] - mx);
        sum += vals[i];
    }
#pragma unroll
    for (int o = 16; o > 0; o >>= 1) sum += __shfl_xor_sync(0xffffffffu, sum, o);
    float inv = 1.0f / sum;
#pragma unroll
    for (int i = 0; i < 16; i++) r[lane + 32 * i] = vals[i] * inv;
}

// ============================================================================
// K5: batched PV (tf32 mma, unchanged)
// ============================================================================
#define VEP 136
#define PV_SMEM_BYTES ((2 * SBM * SBKP + 2 * SBK * VEP) * 4)

__global__ __launch_bounds__(256) void pv_mma_k(
    const float* __restrict__ P, const float* __restrict__ vb,
    const float* __restrict__ beta, float* __restrict__ attnb)
{
    extern __shared__ float dsm[];
    float* Ash = dsm;
    float* Vsh = dsm + 2 * SBM * SBKP;
    uint32_t sAu = smem_u32(Ash);
    uint32_t sVu = smem_u32(Vsh);

    const int tid = threadIdx.x;
    const int wid = tid >> 5;
    const int lane = tid & 31;
    const int lr = lane >> 2;
    const int lc = lane & 3;
    const int wm = (wid >> 2) * 64;
    const int wn = (wid & 3) * 32;

    int bhs = blockIdx.y;
    size_t segbase = ((size_t)bhs) << 16;
    const float* Pseg = P + (size_t)bhs * SEGL * SEGL;
    const float* vseg = vb + segbase;
    int brow = blockIdx.x * SBM;
    float gm1 = 1.0f - 1.0f / (1.0f + expf(-beta[0]));

    float acc[4][4][4];
#pragma unroll
    for (int mt = 0; mt < 4; mt++)
#pragma unroll
        for (int nt = 0; nt < 4; nt++)
#pragma unroll
            for (int r = 0; r < 4; r++) acc[mt][nt][r] = 0.f;

    auto load_st = [&](int k0, uint32_t sA, uint32_t sV) {
#pragma unroll
        for (int it = 0; it < 4; it++) {
            int idx = tid + it * 256;
            int row = idx >> 3, c4 = idx & 7;
            cp16(sA + (row * SBKP + c4 * 4) * 4,
                 Pseg + (size_t)(brow + row) * SEGL + k0 + c4 * 4);
        }
#pragma unroll
        for (int it = 0; it < 4; it++) {
            int idx = tid + it * 256;
            int row = idx >> 5, c4 = idx & 31;
            cp16(sV + (row * VEP + c4 * 4) * 4,
                 vseg + (size_t)(k0 + row) * DHEAD + c4 * 4);
        }
        asm volatile("cp.async.commit_group;" ::: "memory");
    };

    load_st(0, sAu, sVu);
    load_st(SBK, sAu + SBM * SBKP * 4, sVu + SBK * VEP * 4);

    const int NIT = SEGL / SBK;
    for (int it = 0; it < NIT; it++) {
        int s = it & 1;
        if (it == NIT - 1) asm volatile("cp.async.wait_group 0;" ::: "memory");
        else               asm volatile("cp.async.wait_group 1;" ::: "memory");
        __syncthreads();

        const float* As = Ash + s * SBM * SBKP;
        const float* Vs = Vsh + s * SBK * VEP;
#pragma unroll
        for (int kb = 0; kb < SBK; kb += 8) {
            uint32_t af[4][4], bf[4][2];
#pragma unroll
            for (int mt = 0; mt < 4; mt++) {
                int r = wm + mt * 16 + lr;
                af[mt][0] = f2tf32(As[r * SBKP + kb + lc]);
                af[mt][1] = f2tf32(As[(r + 8) * SBKP + kb + lc]);
                af[mt][2] = f2tf32(As[r * SBKP + kb + lc + 4]);
                af[mt][3] = f2tf32(As[(r + 8) * SBKP + kb + lc + 4]);
            }
#pragma unroll
            for (int nt = 0; nt < 4; nt++) {
                int cN = wn + nt * 8 + lr;
                bf[nt][0] = f2tf32(Vs[(kb + lc) * VEP + cN]);
                bf[nt][1] = f2tf32(Vs[(kb + lc + 4) * VEP + cN]);
            }
#pragma unroll
            for (int mt = 0; mt < 4; mt++)
#pragma unroll
                for (int nt = 0; nt < 4; nt++)
                    mma_tf32(acc[mt][nt], af[mt], bf[nt]);
        }
        __syncthreads();
        if (it + 2 < NIT)
            load_st((it + 2) * SBK, sAu + s * SBM * SBKP * 4, sVu + s * SBK * VEP * 4);
    }

#pragma unroll
    for (int nt = 0; nt < 4; nt++) {
        int col = wn + nt * 8 + 2 * lc;
#pragma unroll
        for (int mt = 0; mt < 4; mt++) {
            int row = brow + wm + mt * 16 + lr;
            float2 v0 = make_float2(acc[mt][nt][0] * gm1, acc[mt][nt][1] * gm1);
            float2 v1 = make_float2(acc[mt][nt][2] * gm1, acc[mt][nt][3] * gm1);
            *(float2*)&attnb[segbase + (size_t)row * DHEAD + col] = v0;
            *(float2*)&attnb[segbase + (size_t)(row + 8) * DHEAD + col] = v1;
        }
    }
}

// ============================================================================
// K6: per-segment outer products
// ============================================================================
__global__ __launch_bounds__(256) void outer_k(
    const float* __restrict__ kb, const float* __restrict__ vb,
    float* __restrict__ memseg, float* __restrict__ Zseg)
{
    int bhs = blockIdx.x;
    size_t segbase = ((size_t)bhs) << 16;
    const float* kseg = kb + segbase;
    const float* vseg = vb + segbase;

    __shared__ float As[16][128];
    __shared__ float Bs[16][128];
    int tid = threadIdx.x;
    int tx = tid & 15, ty = tid >> 4;
    int br = tid >> 5, bc4 = tid & 31;

    float acc[8][8];
    float zacc[8];
#pragma unroll
    for (int i = 0; i < 8; i++) {
        zacc[i] = 0.f;
#pragma unroll
        for (int j = 0; j < 8; j++) acc[i][j] = 0.f;
    }

    for (int l0 = 0; l0 < SEGL; l0 += 16) {
#pragma unroll
        for (int i = 0; i < 2; i++) {
            int r = br + i * 8;
            float4 kv = *(const float4*)&kseg[(size_t)(l0 + r) * DHEAD + bc4 * 4];
            As[r][bc4 * 4 + 0] = elu1(kv.x); As[r][bc4 * 4 + 1] = elu1(kv.y);
            As[r][bc4 * 4 + 2] = elu1(kv.z); As[r][bc4 * 4 + 3] = elu1(kv.w);
            float4 vv = *(const float4*)&vseg[(size_t)(l0 + r) * DHEAD + bc4 * 4];
            *(float4*)&Bs[r][bc4 * 4] = vv;
        }
        __syncthreads();
#pragma unroll
        for (int kk = 0; kk < 16; kk++) {
            float ra[8], rb[8];
#pragma unroll
            for (int i = 0; i < 8; i++) ra[i] = As[kk][ty * 8 + i];
#pragma unroll
            for (int j = 0; j < 8; j++) rb[j] = Bs[kk][tx * 8 + j];
#pragma unroll
            for (int i = 0; i < 8; i++)
#pragma unroll
                for (int j = 0; j < 8; j++) acc[i][j] += ra[i] * rb[j];
            if (tx == 0) {
#pragma unroll
                for (int i = 0; i < 8; i++) zacc[i] += ra[i];
            }
        }
        __syncthreads();
    }
    float* memb = memseg + (size_t)bhs * DHEAD * DHEAD;
#pragma unroll
    for (int i = 0; i < 8; i++)
#pragma unroll
        for (int j = 0; j < 8; j++)
            memb[(size_t)(ty * 8 + i) * DHEAD + tx * 8 + j] = acc[i][j];
    if (tx == 0) {
#pragma unroll
        for (int i = 0; i < 8; i++) Zseg[bhs * DHEAD + ty * 8 + i] = zacc[i];
    }
}

// ============================================================================
// K7: in-place exclusive prefix over the 8 segments
// ============================================================================
__global__ __launch_bounds__(256) void prefix_mem_k(float* __restrict__ memseg)
{
    size_t idx = (size_t)blockIdx.x * 256 + threadIdx.x;
    int bh = (int)(idx >> 14);
    int off = (int)(idx & 16383);
    size_t base = ((size_t)bh * NSEG) * 16384 + off;
    float run = 0.f;
#pragma unroll
    for (int s = 0; s < NSEG; s++) {
        float t = memseg[base + (size_t)s * 16384];
        memseg[base + (size_t)s * 16384] = run;
        run += t;
    }
}

__global__ __launch_bounds__(256) void prefix_Z_k(float* __restrict__ Zseg)
{
    int idx = blockIdx.x * 256 + threadIdx.x;
    int bh = idx >> 7;
    int d = idx & 127;
    int base = bh * NSEG * DHEAD + d;
    float run = 0.f;
#pragma unroll
    for (int s = 0; s < NSEG; s++) {
        float t = Zseg[base + s * DHEAD];
        Zseg[base + s * DHEAD] = run;
        run += t;
    }
}

// ============================================================================
// K8: tensorized A_mem + fused combine + fp16-permuted output
// ============================================================================
#define AMP 136
#define AMEM_SMEM_BYTES ((2 * 128 * AMP + 256) * 4)

__global__ __launch_bounds__(256) void amem_mma_k(
    const float* __restrict__ qb, const float* __restrict__ memseg,
    const float* __restrict__ Zseg, const float* __restrict__ beta,
    const float* __restrict__ attnb, uint32_t* __restrict__ attnh)
{
    extern __shared__ uint32_t smu[];
    uint32_t* qs = smu;                  // [128][AMP] tf32(elu1(q))
    uint32_t* ms = smu + 128 * AMP;      // [128][AMP] tf32(mem)
    float* rowsumS = (float*)(smu + 2 * 128 * AMP);
    float* Zs = rowsumS + 128;
    uint32_t sqb = smem_u32(qs);
    uint32_t smb = smem_u32(ms);

    const int tid = threadIdx.x;
    const int wid = tid >> 5;
    const int lane = tid & 31;
    const int lr = lane >> 2;
    const int lc = lane & 3;
    const int wm = (wid >> 2) * 64;
    const int wn = (wid & 3) * 32;

    int bhs = blockIdx.y;
    int l0 = blockIdx.x * 128;
    size_t segbase = ((size_t)bhs) << 16;
    size_t segbase_u = ((size_t)bhs) << 15;
    const float* qseg = qb + segbase;
    const float* memb = memseg + (size_t)bhs * DHEAD * DHEAD;
    float g = 1.0f / (1.0f + expf(-beta[0]));

#pragma unroll
    for (int it = 0; it < 16; it++) {
        int idx = tid + it * 256;
        int row = idx >> 5, c4 = idx & 31;
        cp16(sqb + (row * AMP + c4 * 4) * 4,
             qseg + (size_t)(l0 + row) * DHEAD + c4 * 4);
    }
#pragma unroll
    for (int it = 0; it < 16; it++) {
        int idx = tid + it * 256;
        int row = idx >> 5, c4 = idx & 31;
        cp16(smb + (row * AMP + c4 * 4) * 4,
             memb + (size_t)row * DHEAD + c4 * 4);
    }
    asm volatile("cp.async.commit_group;" ::: "memory");
    asm volatile("cp.async.wait_group 0;" ::: "memory");
    __syncthreads();

    {
        int r = tid >> 1;
        int half = (tid & 1) * 64;
        float partial = 0.f;
#pragma unroll 16
        for (int j = 0; j < 64; j++) {
            uint32_t* p = &qs[r * AMP + half + j];
            float e = elu1(__uint_as_float(*p));
            partial += e;
            *p = f2tf32(e);
        }
        partial += __shfl_xor_sync(0xffffffffu, partial, 1);
        if ((tid & 1) == 0) rowsumS[r] = partial;
#pragma unroll 16
        for (int j = 0; j < 64; j++) {
            uint32_t* p = &ms[r * AMP + half + j];
            *p = f2tf32(__uint_as_float(*p));
        }
    }
    if (tid < 128) Zs[tid] = Zseg[bhs * DHEAD + tid];
    __syncthreads();

    float acc[4][4][4];
#pragma unroll
    for (int mt = 0; mt < 4; mt++)
#pragma unroll
        for (int nt = 0; nt < 4; nt++)
#pragma unroll
            for (int r = 0; r < 4; r++) acc[mt][nt][r] = 0.f;

#pragma unroll
    for (int kb = 0; kb < 128; kb += 8) {
        uint32_t af[4][4], bf[4][2];
#pragma unroll
        for (int mt = 0; mt < 4; mt++) {
            int r = wm + mt * 16 + lr;
            af[mt][0] = qs[r * AMP + kb + lc];
            af[mt][1] = qs[(r + 8) * AMP + kb + lc];
            af[mt][2] = qs[r * AMP + kb + lc + 4];
            af[mt][3] = qs[(r + 8) * AMP + kb + lc + 4];
        }
#pragma unroll
        for (int nt = 0; nt < 4; nt++) {
            int cN = wn + nt * 8 + lr;
            bf[nt][0] = ms[(kb + lc) * AMP + cN];
            bf[nt][1] = ms[(kb + lc + 4) * AMP + cN];
        }
#pragma unroll
        for (int mt = 0; mt < 4; mt++)
#pragma unroll
            for (int nt = 0; nt < 4; nt++)
                mma_tf32(acc[mt][nt], af[mt], bf[nt]);
    }

    // epilogue: combine + fp16 pack into permuted layout
#pragma unroll
    for (int nt = 0; nt < 4; nt++) {
        int col = wn + nt * 8 + 2 * lc;               // even
        int j = (col & 15) >> 1;                       // orig u32 within 16-group
        int pos = (col >> 4) * 8 + pposu(j);           // permuted u32 within row (d/16 groups)
        float Z0 = Zs[col], Z1 = Zs[col + 1];
#pragma unroll
        for (int mt = 0; mt < 4; mt++) {
#pragma unroll
            for (int h = 0; h < 2; h++) {
                int rloc = wm + mt * 16 + lr + h * 8;
                int row = l0 + rloc;
                float rs = rowsumS[rloc];
                float2 at = *(const float2*)&attnb[segbase + (size_t)row * DHEAD + col];
                float a0 = g * acc[mt][nt][2 * h + 0] / (rs * Z0 + 1e-6f) + at.x;
                float a1 = g * acc[mt][nt][2 * h + 1] / (rs * Z1 + 1e-6f) + at.y;
                attnh[segbase_u + (size_t)row * (DHEAD / 2) + pos] = packh2(a0, a1);
            }
        }
    }
}

// ============================================================================
// Host launch
// ============================================================================
extern "C" void kernel_launch(void* const* d_in, const int* in_sizes, int n_in,
                              void* d_out, int out_size)
{
    (void)in_sizes; (void)n_in; (void)out_size;
    const float* x    = (const float*)d_in[0];
    const float* Wq   = (const float*)d_in[1];
    const float* bq   = (const float*)d_in[2];
    const float* Wk   = (const float*)d_in[3];
    const float* bk   = (const float*)d_in[4];
    const float* Wv   = (const float*)d_in[5];
    const float* bv   = (const float*)d_in[6];
    const float* Wo   = (const float*)d_in[7];
    const float* bo   = (const float*)d_in[8];
    const float* beta = (const float*)d_in[9];
    float* out = (float*)d_out;

    static float *pq = nullptr, *pk = nullptr, *pv = nullptr, *pattn = nullptr,
                 *pscores = nullptr, *pmemseg = nullptr, *pZseg = nullptr;
    static uint32_t *pWth = nullptr, *pxh = nullptr, *pattnh = nullptr;
    if (!pq) {
        cudaGetSymbolAddress((void**)&pq, g_q);
        cudaGetSymbolAddress((void**)&pk, g_k);
        cudaGetSymbolAddress((void**)&pv, g_v);
        cudaGetSymbolAddress((void**)&pattn, g_attn);
        cudaGetSymbolAddress((void**)&pscores, g_scores);
        cudaGetSymbolAddress((void**)&pmemseg, g_memseg);
        cudaGetSymbolAddress((void**)&pZseg, g_Zseg);
        cudaGetSymbolAddress((void**)&pWth, g_Wth);
        cudaGetSymbolAddress((void**)&pxh, g_xh);
        cudaGetSymbolAddress((void**)&pattnh, g_attnh);
        cudaFuncSetAttribute(gemm_mma_k, cudaFuncAttributeMaxDynamicSharedMemorySize,
                             GEMM_SMEM_BYTES);
        cudaFuncSetAttribute(gemm_qkv_k, cudaFuncAttributeMaxDynamicSharedMemorySize,
                             GEMM_SMEM_BYTES);
        cudaFuncSetAttribute(scores_mma_k, cudaFuncAttributeMaxDynamicSharedMemorySize,
                             SCORES_SMEM_BYTES);
        cudaFuncSetAttribute(pv_mma_k, cudaFuncAttributeMaxDynamicSharedMemorySize,
                             PV_SMEM_BYTES);
        cudaFuncSetAttribute(amem_mma_k, cudaFuncAttributeMaxDynamicSharedMemorySize,
                             AMEM_SMEM_BYTES);
    }

    const size_t WSZ_U = (size_t)EMBD * EMBD_U;
    dim3 tgrid(EMBD / 32, EMBD / 32);
    dim3 tblk(32, 8);
    transpose_fp16_k<<<tgrid, tblk>>>(Wq, pWth + 0 * WSZ_U);
    transpose_fp16_k<<<tgrid, tblk>>>(Wk, pWth + 1 * WSZ_U);
    transpose_fp16_k<<<tgrid, tblk>>>(Wv, pWth + 2 * WSZ_U);
    transpose_fp16_k<<<tgrid, tblk>>>(Wo, pWth + 3 * WSZ_U);

    perm_cvt_fp16_k<<<(int)(TOTAL / 16 / 256), 256>>>(x, pxh);

    dim3 qkvgrid(EMBD / BN, MTOK / BM, 3); // (8, 128, 3)
    gemm_qkv_k<<<qkvgrid, 256, GEMM_SMEM_BYTES>>>(pxh, pWth, bq, bk, bv, pq, pk, pv);

    rope_k<<<(MTOK * (EMBD / 2)) / 256, 256>>>(pq, pk);

    // parallel linear-memory path
    outer_k<<<NBH * NSEG, 256>>>(pk, pv, pmemseg, pZseg);
    prefix_mem_k<<<(NBH * 16384) / 256, 256>>>(pmemseg);
    prefix_Z_k<<<(NBH * DHEAD) / 256, 256>>>(pZseg);

    // batched attention: scores -> softmax -> (1-g)*PV
    scores_mma_k<<<dim3(SEGL / SBN, SEGL / SBM, NBH * NSEG), 256, SCORES_SMEM_BYTES>>>(
        pq, pk, pscores);
    softmax_k<<<dim3(SEGL / 8, NBH * NSEG), 256>>>(pscores);
    pv_mma_k<<<dim3(SEGL / SBM, NBH * NSEG), 256, PV_SMEM_BYTES>>>(
        pscores, pv, beta, pattn);

    // tensorized A_mem + combine + fp16 perm-cvt fused
    amem_mma_k<<<dim3(SEGL / 128, NBH * NSEG), 256, AMEM_SMEM_BYTES>>>(
        pq, pmemseg, pZseg, beta, pattn, pattnh);

    gemm_mma_k<<<dim3(EMBD / BN, MTOK / BM), 256, GEMM_SMEM_BYTES>>>(
        pattnh, pWth + 3 * WSZ_U, bo, out);
}

// round 10
// speedup vs baseline: 4.9907x; 1.0371x over previous
#include <cuda_runtime.h>
#include <cuda_fp16.h>
#include <math.h>
#include <stdint.h>

// Problem constants
#define SEQ   4096
#define EMBD  2048
#define NB    4
#define NHEAD 16
#define DHEAD 128
#define NSEG  8
#define SEGL  512
#define NBH   (NB * NHEAD)          // 64
#define MTOK  (NB * SEQ)            // 16384
#define TOTAL ((size_t)MTOK * EMBD) // 33554432
#define EMBD_U (EMBD / 2)           // 1024 u32 per row
#define SEGL_U (SEGL / 2)           // 256

// -------- device scratch ----------------------------------------------------
__device__ float g_q[TOTAL];
__device__ float g_k[TOTAL];
__device__ float g_v[TOTAL];
__device__ float g_attn[TOTAL];
__device__ float g_scores[(size_t)NBH * NSEG * SEGL * SEGL]; // fp32 512MB
__device__ uint32_t g_Ph[(size_t)NBH * NSEG * SEGL * SEGL_U]; // fp16 P 256MB
__device__ float g_memseg[(size_t)NBH * NSEG * DHEAD * DHEAD];
__device__ float g_Zseg[NBH * NSEG * DHEAD];
__device__ uint32_t g_Wth[(size_t)4 * EMBD * EMBD_U]; // transposed+permuted fp16
__device__ uint32_t g_xh[TOTAL / 2];                  // permuted fp16 x
__device__ uint32_t g_attnh[TOTAL / 2];               // permuted fp16 attn
__device__ uint32_t g_qh[TOTAL / 2];                  // fp16 q (pairs along d)
__device__ uint32_t g_kh[TOTAL / 2];                  // fp16 k (pairs along d)
__device__ uint32_t g_vth[(size_t)NBH * NSEG * DHEAD * SEGL_U]; // fp16 v^T (pairs along l)

__device__ __forceinline__ float elu1(float x) {
    return (x > 0.f) ? (x + 1.f) : expf(x);
}

__device__ __forceinline__ uint32_t smem_u32(const void* p) {
    uint32_t a;
    asm("{ .reg .u64 t; cvta.to.shared.u64 t, %1; cvt.u32.u64 %0, t; }"
        : "=r"(a) : "l"(p));
    return a;
}

__device__ __forceinline__ void cp16(uint32_t saddr, const void* g) {
    asm volatile("cp.async.cg.shared.global [%0], [%1], 16;" :: "r"(saddr), "l"(g));
}

__device__ __forceinline__ uint32_t f2tf32(float x) {
    uint32_t u;
    asm("cvt.rna.tf32.f32 %0, %1;" : "=r"(u) : "f"(x));
    return u;
}

__device__ __forceinline__ uint32_t packh2(float lo, float hi) {
    __half2 h = __floats2half2_rn(lo, hi);
    return *(uint32_t*)&h;
}

__device__ __forceinline__ void mma_tf32(float* d, const uint32_t* a, const uint32_t* b) {
    asm volatile(
        "mma.sync.aligned.m16n8k8.row.col.f32.tf32.tf32.f32 "
        "{%0,%1,%2,%3}, {%4,%5,%6,%7}, {%8,%9}, {%0,%1,%2,%3};"
        : "+f"(d[0]), "+f"(d[1]), "+f"(d[2]), "+f"(d[3])
        : "r"(a[0]), "r"(a[1]), "r"(a[2]), "r"(a[3]), "r"(b[0]), "r"(b[1]));
}

__device__ __forceinline__ void mma_f16(float* d, const uint32_t* a, const uint32_t* b) {
    asm volatile(
        "mma.sync.aligned.m16n8k16.row.col.f32.f16.f16.f32 "
        "{%0,%1,%2,%3}, {%4,%5,%6,%7}, {%8,%9}, {%0,%1,%2,%3};"
        : "+f"(d[0]), "+f"(d[1]), "+f"(d[2]), "+f"(d[3])
        : "r"(a[0]), "r"(a[1]), "r"(a[2]), "r"(a[3]), "r"(b[0]), "r"(b[1]));
}

__device__ __forceinline__ int pposu(int j) { return (j < 4) ? 2 * j : 2 * (j - 4) + 1; }

// ============================================================================
// K0a: transpose + u32-permute + fp16 convert of weights
// ============================================================================
__global__ __launch_bounds__(256) void transpose_fp16_k(const float* __restrict__ W,
                                                        uint32_t* __restrict__ Wth)
{
    __shared__ float t[32][33];
    int bx = blockIdx.x * 32, by = blockIdx.y * 32;
    int txx = threadIdx.x;
    for (int i = threadIdx.y; i < 32; i += 8)
        t[i][txx] = W[(size_t)(by + i) * EMBD + bx + txx];
    __syncthreads();
    if (txx < 16) {
        int j = txx & 7;
        int pos = (by >> 1) + (txx >> 3) * 8 + pposu(j);
        for (int i = threadIdx.y; i < 32; i += 8) {
            uint32_t u = packh2(t[2 * txx][i], t[2 * txx + 1][i]);
            Wth[(size_t)(bx + i) * EMBD_U + pos] = u;
        }
    }
}

// ============================================================================
// K0b: u32-permute + fp16 convert of x
// ============================================================================
__global__ __launch_bounds__(256) void perm_cvt_fp16_k(const float* __restrict__ src,
                                                       uint32_t* __restrict__ dst)
{
    size_t g16 = (size_t)blockIdx.x * 256 + threadIdx.x;
    size_t base = g16 * 16;
    float4 f0 = *(const float4*)&src[base];
    float4 f1 = *(const float4*)&src[base + 4];
    float4 f2 = *(const float4*)&src[base + 8];
    float4 f3 = *(const float4*)&src[base + 12];
    uint4 o0, o1;
    o0.x = packh2(f0.x, f0.y);
    o0.y = packh2(f2.x, f2.y);
    o0.z = packh2(f0.z, f0.w);
    o0.w = packh2(f2.z, f2.w);
    o1.x = packh2(f1.x, f1.y);
    o1.y = packh2(f3.x, f3.y);
    o1.z = packh2(f1.z, f1.w);
    o1.w = packh2(f3.z, f3.w);
    *(uint4*)&dst[g16 * 8] = o0;
    *(uint4*)&dst[g16 * 8 + 4] = o1;
}

// ============================================================================
// K1: fp16 mma.sync GEMM, CTA 128x256x32, 3-stage pipeline, warp tile 64x64
// ============================================================================
#define BM 128
#define BN 256
#define BK 32
#define BKU 16
#define BKP_U 24
#define NSTG 3
#define STG_U ((BM + BN) * BKP_U)
#define GEMM_SMEM_BYTES (NSTG * STG_U * 4)

__device__ __forceinline__ void load_stage_h(const uint32_t* __restrict__ A,
                                             const uint32_t* __restrict__ Bt,
                                             int brow, int bcol, int k0u,
                                             uint32_t sA, uint32_t sB, int tid)
{
#pragma unroll
    for (int it = 0; it < 2; it++) {
        int idx = tid + it * 256;
        int row = idx >> 2, c4 = idx & 3;
        cp16(sA + (row * BKP_U + c4 * 4) * 4,
             A + (size_t)(brow + row) * EMBD_U + k0u + c4 * 4);
    }
#pragma unroll
    for (int it = 0; it < 4; it++) {
        int idx = tid + it * 256;
        int row = idx >> 2, c4 = idx & 3;
        cp16(sB + (row * BKP_U + c4 * 4) * 4,
             Bt + (size_t)(bcol + row) * EMBD_U + k0u + c4 * 4);
    }
    asm volatile("cp.async.commit_group;" ::: "memory");
}

__device__ __forceinline__ void gemm_body(
    const uint32_t* __restrict__ A, const uint32_t* __restrict__ Bt,
    const float* __restrict__ bias, float* __restrict__ C,
    uint32_t* dsm_u)
{
    uint32_t sbase = smem_u32(dsm_u);
    const int tid = threadIdx.x;
    const int wid = tid >> 5;
    const int lane = tid & 31;
    const int lr = lane >> 2;
    const int lc = lane & 3;
    const int wm = (wid >> 2) * 64;
    const int wn = (wid & 3) * 64;

    int brow = blockIdx.y * BM;
    int bcol = blockIdx.x * BN;

    float acc[4][8][4];
#pragma unroll
    for (int mt = 0; mt < 4; mt++)
#pragma unroll
        for (int nt = 0; nt < 8; nt++)
#pragma unroll
            for (int r = 0; r < 4; r++) acc[mt][nt][r] = 0.f;

    uint32_t sA[NSTG], sB[NSTG];
#pragma unroll
    for (int s = 0; s < NSTG; s++) {
        sA[s] = sbase + s * STG_U * 4;
        sB[s] = sA[s] + BM * BKP_U * 4;
    }

    load_stage_h(A, Bt, brow, bcol, 0 * BKU, sA[0], sB[0], tid);
    load_stage_h(A, Bt, brow, bcol, 1 * BKU, sA[1], sB[1], tid);
    load_stage_h(A, Bt, brow, bcol, 2 * BKU, sA[2], sB[2], tid);

    const int NIT = EMBD / BK;
    for (int it = 0; it < NIT; it++) {
        if (it < NIT - 2)       asm volatile("cp.async.wait_group 2;" ::: "memory");
        else if (it == NIT - 2) asm volatile("cp.async.wait_group 1;" ::: "memory");
        else                    asm volatile("cp.async.wait_group 0;" ::: "memory");
        __syncthreads();

        int s = it % NSTG;
        const uint32_t* As = dsm_u + (size_t)s * STG_U;
        const uint32_t* Bs = As + BM * BKP_U;

#pragma unroll
        for (int kc = 0; kc < 2; kc++) {
            int off = kc * 8 + 2 * lc;
            uint32_t af[4][4], bf[8][2];
#pragma unroll
            for (int mt = 0; mt < 4; mt++) {
                int r = wm + mt * 16 + lr;
                uint2 a0 = *(const uint2*)&As[r * BKP_U + off];
                uint2 a1 = *(const uint2*)&As[(r + 8) * BKP_U + off];
                af[mt][0] = a0.x; af[mt][2] = a0.y;
                af[mt][1] = a1.x; af[mt][3] = a1.y;
            }
#pragma unroll
            for (int nt = 0; nt < 8; nt++) {
                int cN = wn + nt * 8 + lr;
                uint2 b = *(const uint2*)&Bs[cN * BKP_U + off];
                bf[nt][0] = b.x; bf[nt][1] = b.y;
            }
#pragma unroll
            for (int mt = 0; mt < 4; mt++)
#pragma unroll
                for (int nt = 0; nt < 8; nt++)
                    mma_f16(acc[mt][nt], af[mt], bf[nt]);
        }
        __syncthreads();

        if (it + NSTG < NIT)
            load_stage_h(A, Bt, brow, bcol, (it + NSTG) * BKU, sA[s], sB[s], tid);
    }

#pragma unroll
    for (int nt = 0; nt < 8; nt++) {
        int col = bcol + wn + nt * 8 + 2 * lc;
        float b0 = bias[col], b1 = bias[col + 1];
#pragma unroll
        for (int mt = 0; mt < 4; mt++) {
            int row = brow + wm + mt * 16 + lr;
            float2 v0 = make_float2(acc[mt][nt][0] + b0, acc[mt][nt][1] + b1);
            float2 v1 = make_float2(acc[mt][nt][2] + b0, acc[mt][nt][3] + b1);
            *(float2*)&C[(size_t)row * EMBD + col] = v0;
            *(float2*)&C[(size_t)(row + 8) * EMBD + col] = v1;
        }
    }
}

__global__ __launch_bounds__(256) void gemm_mma_k(
    const uint32_t* __restrict__ A, const uint32_t* __restrict__ Bt,
    const float* __restrict__ bias, float* __restrict__ C)
{
    extern __shared__ uint32_t dsm_u[];
    gemm_body(A, Bt, bias, C, dsm_u);
}

__global__ __launch_bounds__(256) void gemm_qkv_k(
    const uint32_t* __restrict__ A, const uint32_t* __restrict__ WtBase,
    const float* __restrict__ bq, const float* __restrict__ bk,
    const float* __restrict__ bv,
    float* __restrict__ q, float* __restrict__ k, float* __restrict__ v)
{
    extern __shared__ uint32_t dsm_u[];
    int z = blockIdx.z;
    const uint32_t* Bt = WtBase + (size_t)z * EMBD * EMBD_U;
    const float* bias = (z == 0) ? bq : (z == 1) ? bk : bv;
    float* C = (z == 0) ? q : (z == 1) ? k : v;
    gemm_body(A, Bt, bias, C, dsm_u);
}

// ============================================================================
// K2: RoPE (fp32 in place) + fp16 packed copies of q,k
// ============================================================================
__global__ __launch_bounds__(256) void rope_k(float* __restrict__ q, float* __restrict__ k,
                                              uint32_t* __restrict__ qh,
                                              uint32_t* __restrict__ kh)
{
    size_t idx = (size_t)blockIdx.x * 256 + threadIdx.x;
    int rr = (int)(idx >> 10);
    int i = (int)(idx & 1023);
    int t = rr & (SEQ - 1);
    float inv = powf(10000.0f, -(float)(2 * i) * (1.0f / 2048.0f));
    float ang = (float)t * inv;
    float c = cosf(ang), s = sinf(ang);
    size_t base = (size_t)rr * EMBD + 2 * i;
    size_t ubase = (size_t)rr * EMBD_U + i;
    float a = q[base], b = q[base + 1];
    float qa = a * c - b * s, qb = a * s + b * c;
    q[base] = qa; q[base + 1] = qb;
    qh[ubase] = packh2(qa, qb);
    a = k[base]; b = k[base + 1];
    float ka = a * c - b * s, kb = a * s + b * c;
    k[base] = ka; k[base + 1] = kb;
    kh[ubase] = packh2(ka, kb);
}

// ============================================================================
// K2b: v -> fp16 transposed per segment: vt[d][lp] = h2(v[2lp][d], v[2lp+1][d])
// ============================================================================
__global__ __launch_bounds__(256) void vt_k(const float* __restrict__ vb,
                                            uint32_t* __restrict__ vth)
{
    __shared__ float t[32][33];
    int bhs = blockIdx.z;
    int d0 = blockIdx.x * 32;
    int l0 = blockIdx.y * 32;
    size_t segbase = ((size_t)bhs) << 16;
    const float* vseg = vb + segbase;
    uint32_t* vtseg = vth + (size_t)bhs * DHEAD * SEGL_U;
    int txx = threadIdx.x;
    for (int i = threadIdx.y; i < 32; i += 8)
        t[i][txx] = vseg[(size_t)(l0 + i) * DHEAD + d0 + txx];
    __syncthreads();
    int c = txx & 15, rh = txx >> 4;
    for (int i = threadIdx.y; i < 16; i += 8) {
        int r = 2 * i + rh;
        vtseg[(size_t)(d0 + r) * SEGL_U + (l0 >> 1) + c] =
            packh2(t[2 * c][r], t[2 * c + 1][r]);
    }
}

// ============================================================================
// K3: batched scores, fp16 mma:  S = scale * q_seg @ k_seg^T
//     CTA 128x128, K=128 (64 u32), single-stage smem
// ============================================================================
#define SCP 68
#define SCORES_SMEM_BYTES (2 * 128 * SCP * 4)  // 69632

__global__ __launch_bounds__(256) void scores_h_k(
    const uint32_t* __restrict__ qh, const uint32_t* __restrict__ kh,
    float* __restrict__ S)
{
    extern __shared__ uint32_t smu[];
    uint32_t* As = smu;                 // [128][SCP]
    uint32_t* Bs = smu + 128 * SCP;     // [128][SCP]
    uint32_t sAu = smem_u32(As);
    uint32_t sBu = smem_u32(Bs);

    const float scale = 0.08838834764831845f;
    const int tid = threadIdx.x;
    const int wid = tid >> 5;
    const int lane = tid & 31;
    const int lr = lane >> 2;
    const int lc = lane & 3;
    const int wm = (wid >> 2) * 64;
    const int wn = (wid & 3) * 32;

    int bhs = blockIdx.z;
    size_t segbase_u = ((size_t)bhs) << 15;  // *SEGL*DHEAD_U = 512*64
    const uint32_t* A = qh + segbase_u;
    const uint32_t* B = kh + segbase_u;
    int brow = blockIdx.y * 128;
    int bcol = blockIdx.x * 128;

    // load full tiles: 128 rows x 64 u32 each
#pragma unroll
    for (int it = 0; it < 8; it++) {
        int idx = tid + it * 256;
        int row = idx >> 4, c4 = idx & 15;
        cp16(sAu + (row * SCP + c4 * 4) * 4,
             A + (size_t)(brow + row) * 64 + c4 * 4);
    }
#pragma unroll
    for (int it = 0; it < 8; it++) {
        int idx = tid + it * 256;
        int row = idx >> 4, c4 = idx & 15;
        cp16(sBu + (row * SCP + c4 * 4) * 4,
             B + (size_t)(bcol + row) * 64 + c4 * 4);
    }
    asm volatile("cp.async.commit_group;" ::: "memory");
    asm volatile("cp.async.wait_group 0;" ::: "memory");
    __syncthreads();

    float acc[4][4][4];
#pragma unroll
    for (int mt = 0; mt < 4; mt++)
#pragma unroll
        for (int nt = 0; nt < 4; nt++)
#pragma unroll
            for (int r = 0; r < 4; r++) acc[mt][nt][r] = 0.f;

#pragma unroll
    for (int kb = 0; kb < 64; kb += 8) {
        uint32_t af[4][4], bf[4][2];
#pragma unroll
        for (int mt = 0; mt < 4; mt++) {
            int r = wm + mt * 16 + lr;
            af[mt][0] = As[r * SCP + kb + lc];
            af[mt][1] = As[(r + 8) * SCP + kb + lc];
            af[mt][2] = As[r * SCP + kb + lc + 4];
            af[mt][3] = As[(r + 8) * SCP + kb + lc + 4];
        }
#pragma unroll
        for (int nt = 0; nt < 4; nt++) {
            int cN = wn + nt * 8 + lr;
            bf[nt][0] = Bs[cN * SCP + kb + lc];
            bf[nt][1] = Bs[cN * SCP + kb + lc + 4];
        }
#pragma unroll
        for (int mt = 0; mt < 4; mt++)
#pragma unroll
            for (int nt = 0; nt < 4; nt++)
                mma_f16(acc[mt][nt], af[mt], bf[nt]);
    }

    float* Sb = S + (size_t)bhs * SEGL * SEGL;
#pragma unroll
    for (int nt = 0; nt < 4; nt++) {
        int col = bcol + wn + nt * 8 + 2 * lc;
#pragma unroll
        for (int mt = 0; mt < 4; mt++) {
            int row = brow + wm + mt * 16 + lr;
            float2 v0 = make_float2(acc[mt][nt][0] * scale, acc[mt][nt][1] * scale);
            float2 v1 = make_float2(acc[mt][nt][2] * scale, acc[mt][nt][3] * scale);
            *(float2*)&Sb[(size_t)row * SEGL + col] = v0;
            *(float2*)&Sb[(size_t)(row + 8) * SEGL + col] = v1;
        }
    }
}

// ============================================================================
// K4: batched row softmax; reads fp32 scores, writes packed fp16 P
// ============================================================================
__global__ __launch_bounds__(256) void softmax_h_k(const float* __restrict__ S,
                                                   uint32_t* __restrict__ Ph)
{
    int bhs = blockIdx.y;
    int row = blockIdx.x * 8 + (threadIdx.x >> 5);
    int lane = threadIdx.x & 31;
    const float* r = S + ((size_t)bhs * SEGL + row) * SEGL;
    float vals[16];
#pragma unroll
    for (int j = 0; j < 4; j++) {
        float4 f = *(const float4*)&r[lane * 16 + j * 4];
        vals[j * 4 + 0] = f.x; vals[j * 4 + 1] = f.y;
        vals[j * 4 + 2] = f.z; vals[j * 4 + 3] = f.w;
    }
    float mx = -1e30f;
#pragma unroll
    for (int i = 0; i < 16; i++) mx = fmaxf(mx, vals[i]);
#pragma unroll
    for (int o = 16; o > 0; o >>= 1) mx = fmaxf(mx, __shfl_xor_sync(0xffffffffu, mx, o));
    float sum = 0.f;
#pragma unroll
    for (int i = 0; i < 16; i++) {
        vals[i] = expf(vals[i] - mx);
        sum += vals[i];
    }
#pragma unroll
    for (int o = 16; o > 0; o >>= 1) sum += __shfl_xor_sync(0xffffffffu, sum, o);
    float invs = 1.0f / sum;
    uint32_t* pr = Ph + ((size_t)bhs * SEGL + row) * SEGL_U + lane * 8;
    uint4 o0, o1;
    o0.x = packh2(vals[0] * invs, vals[1] * invs);
    o0.y = packh2(vals[2] * invs, vals[3] * invs);
    o0.z = packh2(vals[4] * invs, vals[5] * invs);
    o0.w = packh2(vals[6] * invs, vals[7] * invs);
    o1.x = packh2(vals[8] * invs, vals[9] * invs);
    o1.y = packh2(vals[10] * invs, vals[11] * invs);
    o1.z = packh2(vals[12] * invs, vals[13] * invs);
    o1.w = packh2(vals[14] * invs, vals[15] * invs);
    *(uint4*)pr = o0;
    *(uint4*)(pr + 4) = o1;
}

// ============================================================================
// K5: batched PV, fp16 mma: attn = (1-g) * P @ v  (P fp16, v^T fp16)
//     CTA 128(l) x 128(d), K=512 (chunks of 64 elems = 32 u32, 2-stage)
// ============================================================================
#define PVP 36
#define PV_SMEM_BYTES (2 * 2 * 128 * PVP * 4)  // 73728

__global__ __launch_bounds__(256) void pv_h_k(
    const uint32_t* __restrict__ Ph, const uint32_t* __restrict__ vth,
    const float* __restrict__ beta, float* __restrict__ attnb)
{
    extern __shared__ uint32_t smu[];
    uint32_t* Ash = smu;                    // [2][128][PVP]
    uint32_t* Bsh = smu + 2 * 128 * PVP;    // [2][128][PVP]
    uint32_t sAu = smem_u32(Ash);
    uint32_t sBu = smem_u32(Bsh);

    const int tid = threadIdx.x;
    const int wid = tid >> 5;
    const int lane = tid & 31;
    const int lr = lane >> 2;
    const int lc = lane & 3;
    const int wm = (wid >> 2) * 64;
    const int wn = (wid & 3) * 32;

    int bhs = blockIdx.y;
    size_t segbase = ((size_t)bhs) << 16;
    const uint32_t* Pseg = Ph + (size_t)bhs * SEGL * SEGL_U;
    const uint32_t* vtseg = vth + (size_t)bhs * DHEAD * SEGL_U;
    int brow = blockIdx.x * 128;
    float gm1 = 1.0f - 1.0f / (1.0f + expf(-beta[0]));

    float acc[4][4][4];
#pragma unroll
    for (int mt = 0; mt < 4; mt++)
#pragma unroll
        for (int nt = 0; nt < 4; nt++)
#pragma unroll
            for (int r = 0; r < 4; r++) acc[mt][nt][r] = 0.f;

    auto load_st = [&](int k0u, uint32_t sA, uint32_t sB) {
#pragma unroll
        for (int it = 0; it < 4; it++) {       // P: 128 rows x 8 cp16 (32 u32)
            int idx = tid + it * 256;
            int row = idx >> 3, c4 = idx & 7;
            cp16(sA + (row * PVP + c4 * 4) * 4,
                 Pseg + (size_t)(brow + row) * SEGL_U + k0u + c4 * 4);
        }
#pragma unroll
        for (int it = 0; it < 4; it++) {       // vt: 128 rows x 8 cp16
            int idx = tid + it * 256;
            int row = idx >> 3, c4 = idx & 7;
            cp16(sB + (row * PVP + c4 * 4) * 4,
                 vtseg + (size_t)row * SEGL_U + k0u + c4 * 4);
        }
        asm volatile("cp.async.commit_group;" ::: "memory");
    };

    load_st(0, sAu, sBu);
    load_st(32, sAu + 128 * PVP * 4, sBu + 128 * PVP * 4);

    const int NIT = SEGL_U / 32; // 8 chunks of 32 u32 (64 elems)
    for (int it = 0; it < NIT; it++) {
        int s = it & 1;
        if (it == NIT - 1) asm volatile("cp.async.wait_group 0;" ::: "memory");
        else               asm volatile("cp.async.wait_group 1;" ::: "memory");
        __syncthreads();

        const uint32_t* As = Ash + s * 128 * PVP;
        const uint32_t* Bs = Bsh + s * 128 * PVP;
#pragma unroll
        for (int kb = 0; kb < 32; kb += 8) {
            uint32_t af[4][4], bf[4][2];
#pragma unroll
            for (int mt = 0; mt < 4; mt++) {
                int r = wm + mt * 16 + lr;
                af[mt][0] = As[r * PVP + kb + lc];
                af[mt][1] = As[(r + 8) * PVP + kb + lc];
                af[mt][2] = As[r * PVP + kb + lc + 4];
                af[mt][3] = As[(r + 8) * PVP + kb + lc + 4];
            }
#pragma unroll
            for (int nt = 0; nt < 4; nt++) {
                int cN = wn + nt * 8 + lr;
                bf[nt][0] = Bs[cN * PVP + kb + lc];
                bf[nt][1] = Bs[cN * PVP + kb + lc + 4];
            }
#pragma unroll
            for (int mt = 0; mt < 4; mt++)
#pragma unroll
                for (int nt = 0; nt < 4; nt++)
                    mma_f16(acc[mt][nt], af[mt], bf[nt]);
        }
        __syncthreads();
        if (it + 2 < NIT)
            load_st((it + 2) * 32, sAu + s * 128 * PVP * 4, sBu + s * 128 * PVP * 4);
    }

#pragma unroll
    for (int nt = 0; nt < 4; nt++) {
        int col = wn + nt * 8 + 2 * lc;
#pragma unroll
        for (int mt = 0; mt < 4; mt++) {
            int row = brow + wm + mt * 16 + lr;
            float2 v0 = make_float2(acc[mt][nt][0] * gm1, acc[mt][nt][1] * gm1);
            float2 v1 = make_float2(acc[mt][nt][2] * gm1, acc[mt][nt][3] * gm1);
            *(float2*)&attnb[segbase + (size_t)row * DHEAD + col] = v0;
            *(float2*)&attnb[segbase + (size_t)(row + 8) * DHEAD + col] = v1;
        }
    }
}

// ============================================================================
// K6: per-segment outer products (fp32 SIMT)
// ============================================================================
__global__ __launch_bounds__(256) void outer_k(
    const float* __restrict__ kb, const float* __restrict__ vb,
    float* __restrict__ memseg, float* __restrict__ Zseg)
{
    int bhs = blockIdx.x;
    size_t segbase = ((size_t)bhs) << 16;
    const float* kseg = kb + segbase;
    const float* vseg = vb + segbase;

    __shared__ float As[16][128];
    __shared__ float Bs[16][128];
    int tid = threadIdx.x;
    int tx = tid & 15, ty = tid >> 4;
    int br = tid >> 5, bc4 = tid & 31;

    float acc[8][8];
    float zacc[8];
#pragma unroll
    for (int i = 0; i < 8; i++) {
        zacc[i] = 0.f;
#pragma unroll
        for (int j = 0; j < 8; j++) acc[i][j] = 0.f;
    }

    for (int l0 = 0; l0 < SEGL; l0 += 16) {
#pragma unroll
        for (int i = 0; i < 2; i++) {
            int r = br + i * 8;
            float4 kv = *(const float4*)&kseg[(size_t)(l0 + r) * DHEAD + bc4 * 4];
            As[r][bc4 * 4 + 0] = elu1(kv.x); As[r][bc4 * 4 + 1] = elu1(kv.y);
            As[r][bc4 * 4 + 2] = elu1(kv.z); As[r][bc4 * 4 + 3] = elu1(kv.w);
            float4 vv = *(const float4*)&vseg[(size_t)(l0 + r) * DHEAD + bc4 * 4];
            *(float4*)&Bs[r][bc4 * 4] = vv;
        }
        __syncthreads();
#pragma unroll
        for (int kk = 0; kk < 16; kk++) {
            float ra[8], rb[8];
#pragma unroll
            for (int i = 0; i < 8; i++) ra[i] = As[kk][ty * 8 + i];
#pragma unroll
            for (int j = 0; j < 8; j++) rb[j] = Bs[kk][tx * 8 + j];
#pragma unroll
            for (int i = 0; i < 8; i++)
#pragma unroll
                for (int j = 0; j < 8; j++) acc[i][j] += ra[i] * rb[j];
            if (tx == 0) {
#pragma unroll
                for (int i = 0; i < 8; i++) zacc[i] += ra[i];
            }
        }
        __syncthreads();
    }
    float* memb = memseg + (size_t)bhs * DHEAD * DHEAD;
#pragma unroll
    for (int i = 0; i < 8; i++)
#pragma unroll
        for (int j = 0; j < 8; j++)
            memb[(size_t)(ty * 8 + i) * DHEAD + tx * 8 + j] = acc[i][j];
    if (tx == 0) {
#pragma unroll
        for (int i = 0; i < 8; i++) Zseg[bhs * DHEAD + ty * 8 + i] = zacc[i];
    }
}

// ============================================================================
// K7: in-place exclusive prefix over the 8 segments
// ============================================================================
__global__ __launch_bounds__(256) void prefix_mem_k(float* __restrict__ memseg)
{
    size_t idx = (size_t)blockIdx.x * 256 + threadIdx.x;
    int bh = (int)(idx >> 14);
    int off = (int)(idx & 16383);
    size_t base = ((size_t)bh * NSEG) * 16384 + off;
    float run = 0.f;
#pragma unroll
    for (int s = 0; s < NSEG; s++) {
        float t = memseg[base + (size_t)s * 16384];
        memseg[base + (size_t)s * 16384] = run;
        run += t;
    }
}

__global__ __launch_bounds__(256) void prefix_Z_k(float* __restrict__ Zseg)
{
    int idx = blockIdx.x * 256 + threadIdx.x;
    int bh = idx >> 7;
    int d = idx & 127;
    int base = bh * NSEG * DHEAD + d;
    float run = 0.f;
#pragma unroll
    for (int s = 0; s < NSEG; s++) {
        float t = Zseg[base + s * DHEAD];
        Zseg[base + s * DHEAD] = run;
        run += t;
    }
}

// ============================================================================
// K8: tensorized A_mem (tf32) + fused combine + fp16-permuted output
// ============================================================================
#define AMP 136
#define AMEM_SMEM_BYTES ((2 * 128 * AMP + 256) * 4)

__global__ __launch_bounds__(256) void amem_mma_k(
    const float* __restrict__ qb, const float* __restrict__ memseg,
    const float* __restrict__ Zseg, const float* __restrict__ beta,
    const float* __restrict__ attnb, uint32_t* __restrict__ attnh)
{
    extern __shared__ uint32_t smu[];
    uint32_t* qs = smu;
    uint32_t* ms = smu + 128 * AMP;
    float* rowsumS = (float*)(smu + 2 * 128 * AMP);
    float* Zs = rowsumS + 128;
    uint32_t sqb = smem_u32(qs);
    uint32_t smb = smem_u32(ms);

    const int tid = threadIdx.x;
    const int wid = tid >> 5;
    const int lane = tid & 31;
    const int lr = lane >> 2;
    const int lc = lane & 3;
    const int wm = (wid >> 2) * 64;
    const int wn = (wid & 3) * 32;

    int bhs = blockIdx.y;
    int l0 = blockIdx.x * 128;
    size_t segbase = ((size_t)bhs) << 16;
    size_t segbase_u = ((size_t)bhs) << 15;
    const float* qseg = qb + segbase;
    const float* memb = memseg + (size_t)bhs * DHEAD * DHEAD;
    float g = 1.0f / (1.0f + expf(-beta[0]));

#pragma unroll
    for (int it = 0; it < 16; it++) {
        int idx = tid + it * 256;
        int row = idx >> 5, c4 = idx & 31;
        cp16(sqb + (row * AMP + c4 * 4) * 4,
             qseg + (size_t)(l0 + row) * DHEAD + c4 * 4);
    }
#pragma unroll
    for (int it = 0; it < 16; it++) {
        int idx = tid + it * 256;
        int row = idx >> 5, c4 = idx & 31;
        cp16(smb + (row * AMP + c4 * 4) * 4,
             memb + (size_t)row * DHEAD + c4 * 4);
    }
    asm volatile("cp.async.commit_group;" ::: "memory");
    asm volatile("cp.async.wait_group 0;" ::: "memory");
    __syncthreads();

    {
        int r = tid >> 1;
        int half = (tid & 1) * 64;
        float partial = 0.f;
#pragma unroll 16
        for (int j = 0; j < 64; j++) {
            uint32_t* p = &qs[r * AMP + half + j];
            float e = elu1(__uint_as_float(*p));
            partial += e;
            *p = f2tf32(e);
        }
        partial += __shfl_xor_sync(0xffffffffu, partial, 1);
        if ((tid & 1) == 0) rowsumS[r] = partial;
#pragma unroll 16
        for (int j = 0; j < 64; j++) {
            uint32_t* p = &ms[r * AMP + half + j];
            *p = f2tf32(__uint_as_float(*p));
        }
    }
    if (tid < 128) Zs[tid] = Zseg[bhs * DHEAD + tid];
    __syncthreads();

    float acc[4][4][4];
#pragma unroll
    for (int mt = 0; mt < 4; mt++)
#pragma unroll
        for (int nt = 0; nt < 4; nt++)
#pragma unroll
            for (int r = 0; r < 4; r++) acc[mt][nt][r] = 0.f;

#pragma unroll
    for (int kb = 0; kb < 128; kb += 8) {
        uint32_t af[4][4], bf[4][2];
#pragma unroll
        for (int mt = 0; mt < 4; mt++) {
            int r = wm + mt * 16 + lr;
            af[mt][0] = qs[r * AMP + kb + lc];
            af[mt][1] = qs[(r + 8) * AMP + kb + lc];
            af[mt][2] = qs[r * AMP + kb + lc + 4];
            af[mt][3] = qs[(r + 8) * AMP + kb + lc + 4];
        }
#pragma unroll
        for (int nt = 0; nt < 4; nt++) {
            int cN = wn + nt * 8 + lr;
            bf[nt][0] = ms[(kb + lc) * AMP + cN];
            bf[nt][1] = ms[(kb + lc + 4) * AMP + cN];
        }
#pragma unroll
        for (int mt = 0; mt < 4; mt++)
#pragma unroll
            for (int nt = 0; nt < 4; nt++)
                mma_tf32(acc[mt][nt], af[mt], bf[nt]);
    }

#pragma unroll
    for (int nt = 0; nt < 4; nt++) {
        int col = wn + nt * 8 + 2 * lc;
        int j = (col & 15) >> 1;
        int pos = (col >> 4) * 8 + pposu(j);
        float Z0 = Zs[col], Z1 = Zs[col + 1];
#pragma unroll
        for (int mt = 0; mt < 4; mt++) {
#pragma unroll
            for (int h = 0; h < 2; h++) {
                int rloc = wm + mt * 16 + lr + h * 8;
                int row = l0 + rloc;
                float rs = rowsumS[rloc];
                float2 at = *(const float2*)&attnb[segbase + (size_t)row * DHEAD + col];
                float a0 = g * acc[mt][nt][2 * h + 0] / (rs * Z0 + 1e-6f) + at.x;
                float a1 = g * acc[mt][nt][2 * h + 1] / (rs * Z1 + 1e-6f) + at.y;
                attnh[segbase_u + (size_t)row * (DHEAD / 2) + pos] = packh2(a0, a1);
            }
        }
    }
}

// ============================================================================
// Host launch
// ============================================================================
extern "C" void kernel_launch(void* const* d_in, const int* in_sizes, int n_in,
                              void* d_out, int out_size)
{
    (void)in_sizes; (void)n_in; (void)out_size;
    const float* x    = (const float*)d_in[0];
    const float* Wq   = (const float*)d_in[1];
    const float* bq   = (const float*)d_in[2];
    const float* Wk   = (const float*)d_in[3];
    const float* bk   = (const float*)d_in[4];
    const float* Wv   = (const float*)d_in[5];
    const float* bv   = (const float*)d_in[6];
    const float* Wo   = (const float*)d_in[7];
    const float* bo   = (const float*)d_in[8];
    const float* beta = (const float*)d_in[9];
    float* out = (float*)d_out;

    static float *pq = nullptr, *pk = nullptr, *pv = nullptr, *pattn = nullptr,
                 *pscores = nullptr, *pmemseg = nullptr, *pZseg = nullptr;
    static uint32_t *pWth = nullptr, *pxh = nullptr, *pattnh = nullptr,
                    *pqh = nullptr, *pkh = nullptr, *pvth = nullptr, *pPh = nullptr;
    if (!pq) {
        cudaGetSymbolAddress((void**)&pq, g_q);
        cudaGetSymbolAddress((void**)&pk, g_k);
        cudaGetSymbolAddress((void**)&pv, g_v);
        cudaGetSymbolAddress((void**)&pattn, g_attn);
        cudaGetSymbolAddress((void**)&pscores, g_scores);
        cudaGetSymbolAddress((void**)&pmemseg, g_memseg);
        cudaGetSymbolAddress((void**)&pZseg, g_Zseg);
        cudaGetSymbolAddress((void**)&pWth, g_Wth);
        cudaGetSymbolAddress((void**)&pxh, g_xh);
        cudaGetSymbolAddress((void**)&pattnh, g_attnh);
        cudaGetSymbolAddress((void**)&pqh, g_qh);
        cudaGetSymbolAddress((void**)&pkh, g_kh);
        cudaGetSymbolAddress((void**)&pvth, g_vth);
        cudaGetSymbolAddress((void**)&pPh, g_Ph);
        cudaFuncSetAttribute(gemm_mma_k, cudaFuncAttributeMaxDynamicSharedMemorySize,
                             GEMM_SMEM_BYTES);
        cudaFuncSetAttribute(gemm_qkv_k, cudaFuncAttributeMaxDynamicSharedMemorySize,
                             GEMM_SMEM_BYTES);
        cudaFuncSetAttribute(scores_h_k, cudaFuncAttributeMaxDynamicSharedMemorySize,
                             SCORES_SMEM_BYTES);
        cudaFuncSetAttribute(pv_h_k, cudaFuncAttributeMaxDynamicSharedMemorySize,
                             PV_SMEM_BYTES);
        cudaFuncSetAttribute(amem_mma_k, cudaFuncAttributeMaxDynamicSharedMemorySize,
                             AMEM_SMEM_BYTES);
    }

    const size_t WSZ_U = (size_t)EMBD * EMBD_U;
    dim3 tgrid(EMBD / 32, EMBD / 32);
    dim3 tblk(32, 8);
    transpose_fp16_k<<<tgrid, tblk>>>(Wq, pWth + 0 * WSZ_U);
    transpose_fp16_k<<<tgrid, tblk>>>(Wk, pWth + 1 * WSZ_U);
    transpose_fp16_k<<<tgrid, tblk>>>(Wv, pWth + 2 * WSZ_U);
    transpose_fp16_k<<<tgrid, tblk>>>(Wo, pWth + 3 * WSZ_U);

    perm_cvt_fp16_k<<<(int)(TOTAL / 16 / 256), 256>>>(x, pxh);

    dim3 qkvgrid(EMBD / BN, MTOK / BM, 3);
    gemm_qkv_k<<<qkvgrid, 256, GEMM_SMEM_BYTES>>>(pxh, pWth, bq, bk, bv, pq, pk, pv);

    rope_k<<<(MTOK * (EMBD / 2)) / 256, 256>>>(pq, pk, pqh, pkh);
    vt_k<<<dim3(DHEAD / 32, SEGL / 32, NBH * NSEG), tblk>>>(pv, pvth);

    // parallel linear-memory path
    outer_k<<<NBH * NSEG, 256>>>(pk, pv, pmemseg, pZseg);
    prefix_mem_k<<<(NBH * 16384) / 256, 256>>>(pmemseg);
    prefix_Z_k<<<(NBH * DHEAD) / 256, 256>>>(pZseg);

    // batched attention: fp16 scores -> softmax(fp16 out) -> fp16 PV
    scores_h_k<<<dim3(SEGL / 128, SEGL / 128, NBH * NSEG), 256, SCORES_SMEM_BYTES>>>(
        pqh, pkh, pscores);
    softmax_h_k<<<dim3(SEGL / 8, NBH * NSEG), 256>>>(pscores, pPh);
    pv_h_k<<<dim3(SEGL / 128, NBH * NSEG), 256, PV_SMEM_BYTES>>>(
        pPh, pvth, beta, pattn);

    // tensorized A_mem + combine + fp16 perm-cvt fused
    amem_mma_k<<<dim3(SEGL / 128, NBH * NSEG), 256, AMEM_SMEM_BYTES>>>(
        pq, pmemseg, pZseg, beta, pattn, pattnh);

    gemm_mma_k<<<dim3(EMBD / BN, MTOK / BM), 256, GEMM_SMEM_BYTES>>>(
        pattnh, pWth + 3 * WSZ_U, bo, out);
}

// round 11
// speedup vs baseline: 5.1945x; 1.0408x over previous
#include <cuda_runtime.h>
#include <cuda_fp16.h>
#include <math.h>
#include <stdint.h>

// Problem constants
#define SEQ   4096
#define EMBD  2048
#define NB    4
#define NHEAD 16
#define DHEAD 128
#define NSEG  8
#define SEGL  512
#define NBH   (NB * NHEAD)          // 64
#define MTOK  (NB * SEQ)            // 16384
#define TOTAL ((size_t)MTOK * EMBD) // 33554432
#define EMBD_U (EMBD / 2)           // 1024 u32 per row
#define SEGL_U (SEGL / 2)           // 256

// -------- device scratch ----------------------------------------------------
__device__ float g_q[TOTAL];
__device__ float g_k[TOTAL];
__device__ float g_v[TOTAL];
__device__ float g_attn[TOTAL];
__device__ float g_memseg[(size_t)NBH * NSEG * DHEAD * DHEAD];
__device__ float g_Zseg[NBH * NSEG * DHEAD];
__device__ uint32_t g_Wth[(size_t)4 * EMBD * EMBD_U]; // transposed+permuted fp16
__device__ uint32_t g_xh[TOTAL / 2];                  // permuted fp16 x
__device__ uint32_t g_attnh[TOTAL / 2];               // permuted fp16 attn
__device__ uint32_t g_qh[TOTAL / 2];                  // fp16 q (pairs along d)
__device__ uint32_t g_kh[TOTAL / 2];                  // fp16 k (pairs along d)
__device__ uint32_t g_vth[(size_t)NBH * NSEG * DHEAD * SEGL_U]; // fp16 v^T

__device__ __forceinline__ float elu1(float x) {
    return (x > 0.f) ? (x + 1.f) : expf(x);
}

__device__ __forceinline__ uint32_t smem_u32(const void* p) {
    uint32_t a;
    asm("{ .reg .u64 t; cvta.to.shared.u64 t, %1; cvt.u32.u64 %0, t; }"
        : "=r"(a) : "l"(p));
    return a;
}

__device__ __forceinline__ void cp16(uint32_t saddr, const void* g) {
    asm volatile("cp.async.cg.shared.global [%0], [%1], 16;" :: "r"(saddr), "l"(g));
}

__device__ __forceinline__ uint32_t f2tf32(float x) {
    uint32_t u;
    asm("cvt.rna.tf32.f32 %0, %1;" : "=r"(u) : "f"(x));
    return u;
}

__device__ __forceinline__ uint32_t packh2(float lo, float hi) {
    __half2 h = __floats2half2_rn(lo, hi);
    return *(uint32_t*)&h;
}

__device__ __forceinline__ void mma_tf32(float* d, const uint32_t* a, const uint32_t* b) {
    asm volatile(
        "mma.sync.aligned.m16n8k8.row.col.f32.tf32.tf32.f32 "
        "{%0,%1,%2,%3}, {%4,%5,%6,%7}, {%8,%9}, {%0,%1,%2,%3};"
        : "+f"(d[0]), "+f"(d[1]), "+f"(d[2]), "+f"(d[3])
        : "r"(a[0]), "r"(a[1]), "r"(a[2]), "r"(a[3]), "r"(b[0]), "r"(b[1]));
}

__device__ __forceinline__ void mma_f16(float* d, const uint32_t* a, const uint32_t* b) {
    asm volatile(
        "mma.sync.aligned.m16n8k16.row.col.f32.f16.f16.f32 "
        "{%0,%1,%2,%3}, {%4,%5,%6,%7}, {%8,%9}, {%0,%1,%2,%3};"
        : "+f"(d[0]), "+f"(d[1]), "+f"(d[2]), "+f"(d[3])
        : "r"(a[0]), "r"(a[1]), "r"(a[2]), "r"(a[3]), "r"(b[0]), "r"(b[1]));
}

__device__ __forceinline__ int pposu(int j) { return (j < 4) ? 2 * j : 2 * (j - 4) + 1; }

// ============================================================================
// K0a: transpose + u32-permute + fp16 convert of weights
// ============================================================================
__global__ __launch_bounds__(256) void transpose_fp16_k(const float* __restrict__ W,
                                                        uint32_t* __restrict__ Wth)
{
    __shared__ float t[32][33];
    int bx = blockIdx.x * 32, by = blockIdx.y * 32;
    int txx = threadIdx.x;
    for (int i = threadIdx.y; i < 32; i += 8)
        t[i][txx] = W[(size_t)(by + i) * EMBD + bx + txx];
    __syncthreads();
    if (txx < 16) {
        int j = txx & 7;
        int pos = (by >> 1) + (txx >> 3) * 8 + pposu(j);
        for (int i = threadIdx.y; i < 32; i += 8) {
            uint32_t u = packh2(t[2 * txx][i], t[2 * txx + 1][i]);
            Wth[(size_t)(bx + i) * EMBD_U + pos] = u;
        }
    }
}

// ============================================================================
// K0b: u32-permute + fp16 convert of x
// ============================================================================
__global__ __launch_bounds__(256) void perm_cvt_fp16_k(const float* __restrict__ src,
                                                       uint32_t* __restrict__ dst)
{
    size_t g16 = (size_t)blockIdx.x * 256 + threadIdx.x;
    size_t base = g16 * 16;
    float4 f0 = *(const float4*)&src[base];
    float4 f1 = *(const float4*)&src[base + 4];
    float4 f2 = *(const float4*)&src[base + 8];
    float4 f3 = *(const float4*)&src[base + 12];
    uint4 o0, o1;
    o0.x = packh2(f0.x, f0.y);
    o0.y = packh2(f2.x, f2.y);
    o0.z = packh2(f0.z, f0.w);
    o0.w = packh2(f2.z, f2.w);
    o1.x = packh2(f1.x, f1.y);
    o1.y = packh2(f3.x, f3.y);
    o1.z = packh2(f1.z, f1.w);
    o1.w = packh2(f3.z, f3.w);
    *(uint4*)&dst[g16 * 8] = o0;
    *(uint4*)&dst[g16 * 8 + 4] = o1;
}

// ============================================================================
// K1: fp16 mma.sync GEMM, CTA 128x256x32, 3-stage pipeline, warp tile 64x64
// ============================================================================
#define BM 128
#define BN 256
#define BK 32
#define BKU 16
#define BKP_U 24
#define NSTG 3
#define STG_U ((BM + BN) * BKP_U)
#define GEMM_SMEM_BYTES (NSTG * STG_U * 4)

__device__ __forceinline__ void load_stage_h(const uint32_t* __restrict__ A,
                                             const uint32_t* __restrict__ Bt,
                                             int brow, int bcol, int k0u,
                                             uint32_t sA, uint32_t sB, int tid)
{
#pragma unroll
    for (int it = 0; it < 2; it++) {
        int idx = tid + it * 256;
        int row = idx >> 2, c4 = idx & 3;
        cp16(sA + (row * BKP_U + c4 * 4) * 4,
             A + (size_t)(brow + row) * EMBD_U + k0u + c4 * 4);
    }
#pragma unroll
    for (int it = 0; it < 4; it++) {
        int idx = tid + it * 256;
        int row = idx >> 2, c4 = idx & 3;
        cp16(sB + (row * BKP_U + c4 * 4) * 4,
             Bt + (size_t)(bcol + row) * EMBD_U + k0u + c4 * 4);
    }
    asm volatile("cp.async.commit_group;" ::: "memory");
}

__device__ __forceinline__ void gemm_body(
    const uint32_t* __restrict__ A, const uint32_t* __restrict__ Bt,
    const float* __restrict__ bias, float* __restrict__ C,
    uint32_t* dsm_u)
{
    uint32_t sbase = smem_u32(dsm_u);
    const int tid = threadIdx.x;
    const int wid = tid >> 5;
    const int lane = tid & 31;
    const int lr = lane >> 2;
    const int lc = lane & 3;
    const int wm = (wid >> 2) * 64;
    const int wn = (wid & 3) * 64;

    int brow = blockIdx.y * BM;
    int bcol = blockIdx.x * BN;

    float acc[4][8][4];
#pragma unroll
    for (int mt = 0; mt < 4; mt++)
#pragma unroll
        for (int nt = 0; nt < 8; nt++)
#pragma unroll
            for (int r = 0; r < 4; r++) acc[mt][nt][r] = 0.f;

    uint32_t sA[NSTG], sB[NSTG];
#pragma unroll
    for (int s = 0; s < NSTG; s++) {
        sA[s] = sbase + s * STG_U * 4;
        sB[s] = sA[s] + BM * BKP_U * 4;
    }

    load_stage_h(A, Bt, brow, bcol, 0 * BKU, sA[0], sB[0], tid);
    load_stage_h(A, Bt, brow, bcol, 1 * BKU, sA[1], sB[1], tid);
    load_stage_h(A, Bt, brow, bcol, 2 * BKU, sA[2], sB[2], tid);

    const int NIT = EMBD / BK;
    for (int it = 0; it < NIT; it++) {
        if (it < NIT - 2)       asm volatile("cp.async.wait_group 2;" ::: "memory");
        else if (it == NIT - 2) asm volatile("cp.async.wait_group 1;" ::: "memory");
        else                    asm volatile("cp.async.wait_group 0;" ::: "memory");
        __syncthreads();

        int s = it % NSTG;
        const uint32_t* As = dsm_u + (size_t)s * STG_U;
        const uint32_t* Bs = As + BM * BKP_U;

#pragma unroll
        for (int kc = 0; kc < 2; kc++) {
            int off = kc * 8 + 2 * lc;
            uint32_t af[4][4], bf[8][2];
#pragma unroll
            for (int mt = 0; mt < 4; mt++) {
                int r = wm + mt * 16 + lr;
                uint2 a0 = *(const uint2*)&As[r * BKP_U + off];
                uint2 a1 = *(const uint2*)&As[(r + 8) * BKP_U + off];
                af[mt][0] = a0.x; af[mt][2] = a0.y;
                af[mt][1] = a1.x; af[mt][3] = a1.y;
            }
#pragma unroll
            for (int nt = 0; nt < 8; nt++) {
                int cN = wn + nt * 8 + lr;
                uint2 b = *(const uint2*)&Bs[cN * BKP_U + off];
                bf[nt][0] = b.x; bf[nt][1] = b.y;
            }
#pragma unroll
            for (int mt = 0; mt < 4; mt++)
#pragma unroll
                for (int nt = 0; nt < 8; nt++)
                    mma_f16(acc[mt][nt], af[mt], bf[nt]);
        }
        __syncthreads();

        if (it + NSTG < NIT)
            load_stage_h(A, Bt, brow, bcol, (it + NSTG) * BKU, sA[s], sB[s], tid);
    }

#pragma unroll
    for (int nt = 0; nt < 8; nt++) {
        int col = bcol + wn + nt * 8 + 2 * lc;
        float b0 = bias[col], b1 = bias[col + 1];
#pragma unroll
        for (int mt = 0; mt < 4; mt++) {
            int row = brow + wm + mt * 16 + lr;
            float2 v0 = make_float2(acc[mt][nt][0] + b0, acc[mt][nt][1] + b1);
            float2 v1 = make_float2(acc[mt][nt][2] + b0, acc[mt][nt][3] + b1);
            *(float2*)&C[(size_t)row * EMBD + col] = v0;
            *(float2*)&C[(size_t)(row + 8) * EMBD + col] = v1;
        }
    }
}

__global__ __launch_bounds__(256) void gemm_mma_k(
    const uint32_t* __restrict__ A, const uint32_t* __restrict__ Bt,
    const float* __restrict__ bias, float* __restrict__ C)
{
    extern __shared__ uint32_t dsm_u[];
    gemm_body(A, Bt, bias, C, dsm_u);
}

__global__ __launch_bounds__(256) void gemm_qkv_k(
    const uint32_t* __restrict__ A, const uint32_t* __restrict__ WtBase,
    const float* __restrict__ bq, const float* __restrict__ bk,
    const float* __restrict__ bv,
    float* __restrict__ q, float* __restrict__ k, float* __restrict__ v)
{
    extern __shared__ uint32_t dsm_u[];
    int z = blockIdx.z;
    const uint32_t* Bt = WtBase + (size_t)z * EMBD * EMBD_U;
    const float* bias = (z == 0) ? bq : (z == 1) ? bk : bv;
    float* C = (z == 0) ? q : (z == 1) ? k : v;
    gemm_body(A, Bt, bias, C, dsm_u);
}

// ============================================================================
// K2: RoPE (fp32 in place) + fp16 packed copies of q,k
// ============================================================================
__global__ __launch_bounds__(256) void rope_k(float* __restrict__ q, float* __restrict__ k,
                                              uint32_t* __restrict__ qh,
                                              uint32_t* __restrict__ kh)
{
    size_t idx = (size_t)blockIdx.x * 256 + threadIdx.x;
    int rr = (int)(idx >> 10);
    int i = (int)(idx & 1023);
    int t = rr & (SEQ - 1);
    float inv = powf(10000.0f, -(float)(2 * i) * (1.0f / 2048.0f));
    float ang = (float)t * inv;
    float c = cosf(ang), s = sinf(ang);
    size_t base = (size_t)rr * EMBD + 2 * i;
    size_t ubase = (size_t)rr * EMBD_U + i;
    float a = q[base], b = q[base + 1];
    float qa = a * c - b * s, qb = a * s + b * c;
    q[base] = qa; q[base + 1] = qb;
    qh[ubase] = packh2(qa, qb);
    a = k[base]; b = k[base + 1];
    float ka = a * c - b * s, kb = a * s + b * c;
    k[base] = ka; k[base + 1] = kb;
    kh[ubase] = packh2(ka, kb);
}

// ============================================================================
// K2b: v -> fp16 transposed per segment
// ============================================================================
__global__ __launch_bounds__(256) void vt_k(const float* __restrict__ vb,
                                            uint32_t* __restrict__ vth)
{
    __shared__ float t[32][33];
    int bhs = blockIdx.z;
    int d0 = blockIdx.x * 32;
    int l0 = blockIdx.y * 32;
    size_t segbase = ((size_t)bhs) << 16;
    const float* vseg = vb + segbase;
    uint32_t* vtseg = vth + (size_t)bhs * DHEAD * SEGL_U;
    int txx = threadIdx.x;
    for (int i = threadIdx.y; i < 32; i += 8)
        t[i][txx] = vseg[(size_t)(l0 + i) * DHEAD + d0 + txx];
    __syncthreads();
    int c = txx & 15, rh = txx >> 4;
    for (int i = threadIdx.y; i < 16; i += 8) {
        int r = 2 * i + rh;
        vtseg[(size_t)(d0 + r) * SEGL_U + (l0 >> 1) + c] =
            packh2(t[2 * c][r], t[2 * c + 1][r]);
    }
}

// ============================================================================
// K3: FUSED flash attention: attn = (1-g) * softmax(scale * q k^T) v
//     CTA = 128 q-rows x one bhs; online softmax over 4 k-tiles of 128.
// ============================================================================
#define SCP 68
#define FA_SMEM_U (4 * 128 * SCP + 4 * 128 + 4 * 128 + 3 * 128)
#define FA_SMEM_BYTES (FA_SMEM_U * 4)  // 144896

__global__ __launch_bounds__(256, 1) void fattn_k(
    const uint32_t* __restrict__ qh, const uint32_t* __restrict__ kh,
    const uint32_t* __restrict__ vth, const float* __restrict__ beta,
    float* __restrict__ attnb)
{
    extern __shared__ uint32_t smu[];
    uint32_t* qs = smu;                       // [128][SCP]
    uint32_t* ks = smu + 128 * SCP;           // [128][SCP]
    uint32_t* Ps = smu + 2 * 128 * SCP;       // [128][SCP] (64 u32 used)
    uint32_t* vs = smu + 3 * 128 * SCP;       // [128][SCP] (64 u32 used)
    float* pmax = (float*)(smu + 4 * 128 * SCP); // [4][128]
    float* psum = pmax + 4 * 128;                // [4][128]
    float* m_s = psum + 4 * 128;                 // [128]
    float* f_s = m_s + 128;                      // [128]
    float* ssum_s = f_s + 128;                   // [128]

    uint32_t sq = smem_u32(qs);
    uint32_t sk = smem_u32(ks);
    uint32_t sv = smem_u32(vs);

    const float scale = 0.08838834764831845f;
    const int tid = threadIdx.x;
    const int wid = tid >> 5;
    const int lane = tid & 31;
    const int lr = lane >> 2;
    const int lc = lane & 3;
    const int wm = (wid >> 2) * 64;
    const int wn = (wid & 3) * 32;
    const int wci = wid & 3;

    int bhs = blockIdx.y;
    int l0 = blockIdx.x * 128;
    size_t segbase = ((size_t)bhs) << 16;
    size_t segbase_u = ((size_t)bhs) << 15;
    const uint32_t* qseg = qh + segbase_u;
    const uint32_t* kseg = kh + segbase_u;
    const uint32_t* vtseg = vth + (size_t)bhs * DHEAD * SEGL_U;
    float gm1 = 1.0f - 1.0f / (1.0f + expf(-beta[0]));

    // load q tile once
#pragma unroll
    for (int it = 0; it < 8; it++) {
        int idx = tid + it * 256;
        int row = idx >> 4, c4 = idx & 15;
        cp16(sq + (row * SCP + c4 * 4) * 4,
             qseg + (size_t)(l0 + row) * 64 + c4 * 4);
    }
    asm volatile("cp.async.commit_group;" ::: "memory");

    if (tid < 128) { m_s[tid] = -1e30f; ssum_s[tid] = 0.f; }

    float Oacc[4][4][4];
#pragma unroll
    for (int mt = 0; mt < 4; mt++)
#pragma unroll
        for (int nt = 0; nt < 4; nt++)
#pragma unroll
            for (int r = 0; r < 4; r++) Oacc[mt][nt][r] = 0.f;

    for (int kt = 0; kt < 4; kt++) {
        // load k tile and v^T tile for this k-block
#pragma unroll
        for (int it = 0; it < 8; it++) {
            int idx = tid + it * 256;
            int row = idx >> 4, c4 = idx & 15;
            cp16(sk + (row * SCP + c4 * 4) * 4,
                 kseg + (size_t)(kt * 128 + row) * 64 + c4 * 4);
        }
#pragma unroll
        for (int it = 0; it < 8; it++) {
            int idx = tid + it * 256;
            int row = idx >> 4, c4 = idx & 15;
            cp16(sv + (row * SCP + c4 * 4) * 4,
                 vtseg + (size_t)row * SEGL_U + kt * 64 + c4 * 4);
        }
        asm volatile("cp.async.commit_group;" ::: "memory");
        asm volatile("cp.async.wait_group 0;" ::: "memory");
        __syncthreads();

        // S = scale * q k^T  (this warp: rows wm..wm+63, cols wn..wn+31)
        float Sacc[4][4][4];
#pragma unroll
        for (int mt = 0; mt < 4; mt++)
#pragma unroll
            for (int nt = 0; nt < 4; nt++)
#pragma unroll
                for (int r = 0; r < 4; r++) Sacc[mt][nt][r] = 0.f;

#pragma unroll
        for (int kb = 0; kb < 64; kb += 8) {
            uint32_t af[4][4], bf[4][2];
#pragma unroll
            for (int mt = 0; mt < 4; mt++) {
                int r = wm + mt * 16 + lr;
                af[mt][0] = qs[r * SCP + kb + lc];
                af[mt][1] = qs[(r + 8) * SCP + kb + lc];
                af[mt][2] = qs[r * SCP + kb + lc + 4];
                af[mt][3] = qs[(r + 8) * SCP + kb + lc + 4];
            }
#pragma unroll
            for (int nt = 0; nt < 4; nt++) {
                int cN = wn + nt * 8 + lr;
                bf[nt][0] = ks[cN * SCP + kb + lc];
                bf[nt][1] = ks[cN * SCP + kb + lc + 4];
            }
#pragma unroll
            for (int mt = 0; mt < 4; mt++)
#pragma unroll
                for (int nt = 0; nt < 4; nt++)
                    mma_f16(Sacc[mt][nt], af[mt], bf[nt]);
        }
#pragma unroll
        for (int mt = 0; mt < 4; mt++)
#pragma unroll
            for (int nt = 0; nt < 4; nt++)
#pragma unroll
                for (int r = 0; r < 4; r++) Sacc[mt][nt][r] *= scale;

        // per-row partial max over this warp's 32 cols
#pragma unroll
        for (int mt = 0; mt < 4; mt++) {
#pragma unroll
            for (int h = 0; h < 2; h++) {
                float mv = -1e30f;
#pragma unroll
                for (int nt = 0; nt < 4; nt++) {
                    mv = fmaxf(mv, Sacc[mt][nt][2 * h]);
                    mv = fmaxf(mv, Sacc[mt][nt][2 * h + 1]);
                }
                mv = fmaxf(mv, __shfl_xor_sync(0xffffffffu, mv, 1));
                mv = fmaxf(mv, __shfl_xor_sync(0xffffffffu, mv, 2));
                if (lc == 0) pmax[wci * 128 + wm + mt * 16 + lr + h * 8] = mv;
            }
        }
        __syncthreads();

        // combine: new running max, rescale factor, rescale running sum
        if (tid < 128) {
            float mo = m_s[tid];
            float nm = fmaxf(fmaxf(pmax[tid], pmax[128 + tid]),
                             fmaxf(pmax[256 + tid], pmax[384 + tid]));
            float mn = fmaxf(mo, nm);
            float f = expf(mo - mn);
            m_s[tid] = mn;
            f_s[tid] = f;
            ssum_s[tid] *= f;
        }
        __syncthreads();

        // P = exp(S - m), pack to smem; row-sum partials; rescale O
#pragma unroll
        for (int mt = 0; mt < 4; mt++) {
#pragma unroll
            for (int h = 0; h < 2; h++) {
                int row = wm + mt * 16 + lr + h * 8;
                float m = m_s[row];
                float f = f_s[row];
                float rsum = 0.f;
#pragma unroll
                for (int nt = 0; nt < 4; nt++) {
                    float p0 = expf(Sacc[mt][nt][2 * h] - m);
                    float p1 = expf(Sacc[mt][nt][2 * h + 1] - m);
                    rsum += p0 + p1;
                    Ps[row * SCP + (wn >> 1) + nt * 4 + lc] = packh2(p0, p1);
                    Oacc[mt][nt][2 * h] *= f;
                    Oacc[mt][nt][2 * h + 1] *= f;
                }
                rsum += __shfl_xor_sync(0xffffffffu, rsum, 1);
                rsum += __shfl_xor_sync(0xffffffffu, rsum, 2);
                if (lc == 0) psum[wci * 128 + row] = rsum;
            }
        }
        __syncthreads();

        if (tid < 128)
            ssum_s[tid] += psum[tid] + psum[128 + tid] + psum[256 + tid] + psum[384 + tid];

        // O += P @ V  (K = 128 = this k-tile)
#pragma unroll
        for (int kb = 0; kb < 64; kb += 8) {
            uint32_t af[4][4], bf[4][2];
#pragma unroll
            for (int mt = 0; mt < 4; mt++) {
                int r = wm + mt * 16 + lr;
                af[mt][0] = Ps[r * SCP + kb + lc];
                af[mt][1] = Ps[(r + 8) * SCP + kb + lc];
                af[mt][2] = Ps[r * SCP + kb + lc + 4];
                af[mt][3] = Ps[(r + 8) * SCP + kb + lc + 4];
            }
#pragma unroll
            for (int nt = 0; nt < 4; nt++) {
                int cN = wn + nt * 8 + lr;
                bf[nt][0] = vs[cN * SCP + kb + lc];
                bf[nt][1] = vs[cN * SCP + kb + lc + 4];
            }
#pragma unroll
            for (int mt = 0; mt < 4; mt++)
#pragma unroll
                for (int nt = 0; nt < 4; nt++)
                    mma_f16(Oacc[mt][nt], af[mt], bf[nt]);
        }
        __syncthreads();
    }

    // epilogue: O / ssum * (1-g)
#pragma unroll
    for (int nt = 0; nt < 4; nt++) {
        int col = wn + nt * 8 + 2 * lc;
#pragma unroll
        for (int mt = 0; mt < 4; mt++) {
#pragma unroll
            for (int h = 0; h < 2; h++) {
                int row = wm + mt * 16 + lr + h * 8;
                float sc = gm1 / ssum_s[row];
                float2 v = make_float2(Oacc[mt][nt][2 * h] * sc,
                                       Oacc[mt][nt][2 * h + 1] * sc);
                *(float2*)&attnb[segbase + (size_t)(l0 + row) * DHEAD + col] = v;
            }
        }
    }
}

// ============================================================================
// K6: per-segment outer products (fp32 SIMT)
// ============================================================================
__global__ __launch_bounds__(256) void outer_k(
    const float* __restrict__ kb, const float* __restrict__ vb,
    float* __restrict__ memseg, float* __restrict__ Zseg)
{
    int bhs = blockIdx.x;
    size_t segbase = ((size_t)bhs) << 16;
    const float* kseg = kb + segbase;
    const float* vseg = vb + segbase;

    __shared__ float As[16][128];
    __shared__ float Bs[16][128];
    int tid = threadIdx.x;
    int tx = tid & 15, ty = tid >> 4;
    int br = tid >> 5, bc4 = tid & 31;

    float acc[8][8];
    float zacc[8];
#pragma unroll
    for (int i = 0; i < 8; i++) {
        zacc[i] = 0.f;
#pragma unroll
        for (int j = 0; j < 8; j++) acc[i][j] = 0.f;
    }

    for (int l0 = 0; l0 < SEGL; l0 += 16) {
#pragma unroll
        for (int i = 0; i < 2; i++) {
            int r = br + i * 8;
            float4 kv = *(const float4*)&kseg[(size_t)(l0 + r) * DHEAD + bc4 * 4];
            As[r][bc4 * 4 + 0] = elu1(kv.x); As[r][bc4 * 4 + 1] = elu1(kv.y);
            As[r][bc4 * 4 + 2] = elu1(kv.z); As[r][bc4 * 4 + 3] = elu1(kv.w);
            float4 vv = *(const float4*)&vseg[(size_t)(l0 + r) * DHEAD + bc4 * 4];
            *(float4*)&Bs[r][bc4 * 4] = vv;
        }
        __syncthreads();
#pragma unroll
        for (int kk = 0; kk < 16; kk++) {
            float ra[8], rb[8];
#pragma unroll
            for (int i = 0; i < 8; i++) ra[i] = As[kk][ty * 8 + i];
#pragma unroll
            for (int j = 0; j < 8; j++) rb[j] = Bs[kk][tx * 8 + j];
#pragma unroll
            for (int i = 0; i < 8; i++)
#pragma unroll
                for (int j = 0; j < 8; j++) acc[i][j] += ra[i] * rb[j];
            if (tx == 0) {
#pragma unroll
                for (int i = 0; i < 8; i++) zacc[i] += ra[i];
            }
        }
        __syncthreads();
    }
    float* memb = memseg + (size_t)bhs * DHEAD * DHEAD;
#pragma unroll
    for (int i = 0; i < 8; i++)
#pragma unroll
        for (int j = 0; j < 8; j++)
            memb[(size_t)(ty * 8 + i) * DHEAD + tx * 8 + j] = acc[i][j];
    if (tx == 0) {
#pragma unroll
        for (int i = 0; i < 8; i++) Zseg[bhs * DHEAD + ty * 8 + i] = zacc[i];
    }
}

// ============================================================================
// K7: in-place exclusive prefix over the 8 segments
// ============================================================================
__global__ __launch_bounds__(256) void prefix_mem_k(float* __restrict__ memseg)
{
    size_t idx = (size_t)blockIdx.x * 256 + threadIdx.x;
    int bh = (int)(idx >> 14);
    int off = (int)(idx & 16383);
    size_t base = ((size_t)bh * NSEG) * 16384 + off;
    float run = 0.f;
#pragma unroll
    for (int s = 0; s < NSEG; s++) {
        float t = memseg[base + (size_t)s * 16384];
        memseg[base + (size_t)s * 16384] = run;
        run += t;
    }
}

__global__ __launch_bounds__(256) void prefix_Z_k(float* __restrict__ Zseg)
{
    int idx = blockIdx.x * 256 + threadIdx.x;
    int bh = idx >> 7;
    int d = idx & 127;
    int base = bh * NSEG * DHEAD + d;
    float run = 0.f;
#pragma unroll
    for (int s = 0; s < NSEG; s++) {
        float t = Zseg[base + s * DHEAD];
        Zseg[base + s * DHEAD] = run;
        run += t;
    }
}

// ============================================================================
// K8: tensorized A_mem (tf32) + fused combine + fp16-permuted output
// ============================================================================
#define AMP 136
#define AMEM_SMEM_BYTES ((2 * 128 * AMP + 256) * 4)

__global__ __launch_bounds__(256) void amem_mma_k(
    const float* __restrict__ qb, const float* __restrict__ memseg,
    const float* __restrict__ Zseg, const float* __restrict__ beta,
    const float* __restrict__ attnb, uint32_t* __restrict__ attnh)
{
    extern __shared__ uint32_t smu[];
    uint32_t* qs = smu;
    uint32_t* ms = smu + 128 * AMP;
    float* rowsumS = (float*)(smu + 2 * 128 * AMP);
    float* Zs = rowsumS + 128;
    uint32_t sqb = smem_u32(qs);
    uint32_t smb = smem_u32(ms);

    const int tid = threadIdx.x;
    const int wid = tid >> 5;
    const int lane = tid & 31;
    const int lr = lane >> 2;
    const int lc = lane & 3;
    const int wm = (wid >> 2) * 64;
    const int wn = (wid & 3) * 32;

    int bhs = blockIdx.y;
    int l0 = blockIdx.x * 128;
    size_t segbase = ((size_t)bhs) << 16;
    size_t segbase_u = ((size_t)bhs) << 15;
    const float* qseg = qb + segbase;
    const float* memb = memseg + (size_t)bhs * DHEAD * DHEAD;
    float g = 1.0f / (1.0f + expf(-beta[0]));

#pragma unroll
    for (int it = 0; it < 16; it++) {
        int idx = tid + it * 256;
        int row = idx >> 5, c4 = idx & 31;
        cp16(sqb + (row * AMP + c4 * 4) * 4,
             qseg + (size_t)(l0 + row) * DHEAD + c4 * 4);
    }
#pragma unroll
    for (int it = 0; it < 16; it++) {
        int idx = tid + it * 256;
        int row = idx >> 5, c4 = idx & 31;
        cp16(smb + (row * AMP + c4 * 4) * 4,
             memb + (size_t)row * DHEAD + c4 * 4);
    }
    asm volatile("cp.async.commit_group;" ::: "memory");
    asm volatile("cp.async.wait_group 0;" ::: "memory");
    __syncthreads();

    {
        int r = tid >> 1;
        int half = (tid & 1) * 64;
        float partial = 0.f;
#pragma unroll 16
        for (int j = 0; j < 64; j++) {
            uint32_t* p = &qs[r * AMP + half + j];
            float e = elu1(__uint_as_float(*p));
            partial += e;
            *p = f2tf32(e);
        }
        partial += __shfl_xor_sync(0xffffffffu, partial, 1);
        if ((tid & 1) == 0) rowsumS[r] = partial;
#pragma unroll 16
        for (int j = 0; j < 64; j++) {
            uint32_t* p = &ms[r * AMP + half + j];
            *p = f2tf32(__uint_as_float(*p));
        }
    }
    if (tid < 128) Zs[tid] = Zseg[bhs * DHEAD + tid];
    __syncthreads();

    float acc[4][4][4];
#pragma unroll
    for (int mt = 0; mt < 4; mt++)
#pragma unroll
        for (int nt = 0; nt < 4; nt++)
#pragma unroll
            for (int r = 0; r < 4; r++) acc[mt][nt][r] = 0.f;

#pragma unroll
    for (int kb = 0; kb < 128; kb += 8) {
        uint32_t af[4][4], bf[4][2];
#pragma unroll
        for (int mt = 0; mt < 4; mt++) {
            int r = wm + mt * 16 + lr;
            af[mt][0] = qs[r * AMP + kb + lc];
            af[mt][1] = qs[(r + 8) * AMP + kb + lc];
            af[mt][2] = qs[r * AMP + kb + lc + 4];
            af[mt][3] = qs[(r + 8) * AMP + kb + lc + 4];
        }
#pragma unroll
        for (int nt = 0; nt < 4; nt++) {
            int cN = wn + nt * 8 + lr;
            bf[nt][0] = ms[(kb + lc) * AMP + cN];
            bf[nt][1] = ms[(kb + lc + 4) * AMP + cN];
        }
#pragma unroll
        for (int mt = 0; mt < 4; mt++)
#pragma unroll
            for (int nt = 0; nt < 4; nt++)
                mma_tf32(acc[mt][nt], af[mt], bf[nt]);
    }

#pragma unroll
    for (int nt = 0; nt < 4; nt++) {
        int col = wn + nt * 8 + 2 * lc;
        int j = (col & 15) >> 1;
        int pos = (col >> 4) * 8 + pposu(j);
        float Z0 = Zs[col], Z1 = Zs[col + 1];
#pragma unroll
        for (int mt = 0; mt < 4; mt++) {
#pragma unroll
            for (int h = 0; h < 2; h++) {
                int rloc = wm + mt * 16 + lr + h * 8;
                int row = l0 + rloc;
                float rs = rowsumS[rloc];
                float2 at = *(const float2*)&attnb[segbase + (size_t)row * DHEAD + col];
                float a0 = g * acc[mt][nt][2 * h + 0] / (rs * Z0 + 1e-6f) + at.x;
                float a1 = g * acc[mt][nt][2 * h + 1] / (rs * Z1 + 1e-6f) + at.y;
                attnh[segbase_u + (size_t)row * (DHEAD / 2) + pos] = packh2(a0, a1);
            }
        }
    }
}

// ============================================================================
// Host launch
// ============================================================================
extern "C" void kernel_launch(void* const* d_in, const int* in_sizes, int n_in,
                              void* d_out, int out_size)
{
    (void)in_sizes; (void)n_in; (void)out_size;
    const float* x    = (const float*)d_in[0];
    const float* Wq   = (const float*)d_in[1];
    const float* bq   = (const float*)d_in[2];
    const float* Wk   = (const float*)d_in[3];
    const float* bk   = (const float*)d_in[4];
    const float* Wv   = (const float*)d_in[5];
    const float* bv   = (const float*)d_in[6];
    const float* Wo   = (const float*)d_in[7];
    const float* bo   = (const float*)d_in[8];
    const float* beta = (const float*)d_in[9];
    float* out = (float*)d_out;

    static float *pq = nullptr, *pk = nullptr, *pv = nullptr, *pattn = nullptr,
                 *pmemseg = nullptr, *pZseg = nullptr;
    static uint32_t *pWth = nullptr, *pxh = nullptr, *pattnh = nullptr,
                    *pqh = nullptr, *pkh = nullptr, *pvth = nullptr;
    if (!pq) {
        cudaGetSymbolAddress((void**)&pq, g_q);
        cudaGetSymbolAddress((void**)&pk, g_k);
        cudaGetSymbolAddress((void**)&pv, g_v);
        cudaGetSymbolAddress((void**)&pattn, g_attn);
        cudaGetSymbolAddress((void**)&pmemseg, g_memseg);
        cudaGetSymbolAddress((void**)&pZseg, g_Zseg);
        cudaGetSymbolAddress((void**)&pWth, g_Wth);
        cudaGetSymbolAddress((void**)&pxh, g_xh);
        cudaGetSymbolAddress((void**)&pattnh, g_attnh);
        cudaGetSymbolAddress((void**)&pqh, g_qh);
        cudaGetSymbolAddress((void**)&pkh, g_kh);
        cudaGetSymbolAddress((void**)&pvth, g_vth);
        cudaFuncSetAttribute(gemm_mma_k, cudaFuncAttributeMaxDynamicSharedMemorySize,
                             GEMM_SMEM_BYTES);
        cudaFuncSetAttribute(gemm_qkv_k, cudaFuncAttributeMaxDynamicSharedMemorySize,
                             GEMM_SMEM_BYTES);
        cudaFuncSetAttribute(fattn_k, cudaFuncAttributeMaxDynamicSharedMemorySize,
                             FA_SMEM_BYTES);
        cudaFuncSetAttribute(amem_mma_k, cudaFuncAttributeMaxDynamicSharedMemorySize,
                             AMEM_SMEM_BYTES);
    }

    const size_t WSZ_U = (size_t)EMBD * EMBD_U;
    dim3 tgrid(EMBD / 32, EMBD / 32);
    dim3 tblk(32, 8);
    transpose_fp16_k<<<tgrid, tblk>>>(Wq, pWth + 0 * WSZ_U);
    transpose_fp16_k<<<tgrid, tblk>>>(Wk, pWth + 1 * WSZ_U);
    transpose_fp16_k<<<tgrid, tblk>>>(Wv, pWth + 2 * WSZ_U);
    transpose_fp16_k<<<tgrid, tblk>>>(Wo, pWth + 3 * WSZ_U);

    perm_cvt_fp16_k<<<(int)(TOTAL / 16 / 256), 256>>>(x, pxh);

    dim3 qkvgrid(EMBD / BN, MTOK / BM, 3);
    gemm_qkv_k<<<qkvgrid, 256, GEMM_SMEM_BYTES>>>(pxh, pWth, bq, bk, bv, pq, pk, pv);

    rope_k<<<(MTOK * (EMBD / 2)) / 256, 256>>>(pq, pk, pqh, pkh);
    vt_k<<<dim3(DHEAD / 32, SEGL / 32, NBH * NSEG), tblk>>>(pv, pvth);

    // parallel linear-memory path
    outer_k<<<NBH * NSEG, 256>>>(pk, pv, pmemseg, pZseg);
    prefix_mem_k<<<(NBH * 16384) / 256, 256>>>(pmemseg);
    prefix_Z_k<<<(NBH * DHEAD) / 256, 256>>>(pZseg);

    // fused flash attention: scores+softmax+PV in one pass
    fattn_k<<<dim3(SEGL / 128, NBH * NSEG), 256, FA_SMEM_BYTES>>>(
        pqh, pkh, pvth, beta, pattn);

    // tensorized A_mem + combine + fp16 perm-cvt fused
    amem_mma_k<<<dim3(SEGL / 128, NBH * NSEG), 256, AMEM_SMEM_BYTES>>>(
        pq, pmemseg, pZseg, beta, pattn, pattnh);

    gemm_mma_k<<<dim3(EMBD / BN, MTOK / BM), 256, GEMM_SMEM_BYTES>>>(
        pattnh, pWth + 3 * WSZ_U, bo, out);
}

// round 12
// speedup vs baseline: 5.4284x; 1.0450x over previous
#include <cuda_runtime.h>
#include <cuda_fp16.h>
#include <math.h>
#include <stdint.h>

// Problem constants
#define SEQ   4096
#define EMBD  2048
#define NB    4
#define NHEAD 16
#define DHEAD 128
#define NSEG  8
#define SEGL  512
#define NBH   (NB * NHEAD)          // 64
#define MTOK  (NB * SEQ)            // 16384
#define TOTAL ((size_t)MTOK * EMBD) // 33554432
#define EMBD_U (EMBD / 2)           // 1024 u32 per row
#define SEGL_U (SEGL / 2)           // 256

// -------- device scratch ----------------------------------------------------
__device__ float g_q[TOTAL];
__device__ float g_k[TOTAL];
__device__ float g_v[TOTAL];
__device__ uint32_t g_attnd[TOTAL / 2];               // fp16 (1-g)*A_dot
__device__ float g_memsegT[(size_t)NBH * NSEG * DHEAD * DHEAD]; // mem^T [e][d]
__device__ float g_Zseg[NBH * NSEG * DHEAD];
__device__ uint32_t g_Wth[(size_t)4 * EMBD * EMBD_U]; // transposed+permuted fp16
__device__ uint32_t g_xh[TOTAL / 2];                  // permuted fp16 x
__device__ uint32_t g_attnh[TOTAL / 2];               // permuted fp16 attn
__device__ uint32_t g_qh[TOTAL / 2];                  // fp16 q (pairs along d)
__device__ uint32_t g_kh[TOTAL / 2];                  // fp16 k (pairs along d)
__device__ uint32_t g_vth[(size_t)NBH * NSEG * DHEAD * SEGL_U]; // fp16 v^T
__device__ uint32_t g_skth[(size_t)NBH * NSEG * DHEAD * SEGL_U]; // fp16 sk^T

__device__ __forceinline__ float elu1(float x) {
    return (x > 0.f) ? (x + 1.f) : expf(x);
}

__device__ __forceinline__ uint32_t smem_u32(const void* p) {
    uint32_t a;
    asm("{ .reg .u64 t; cvta.to.shared.u64 t, %1; cvt.u32.u64 %0, t; }"
        : "=r"(a) : "l"(p));
    return a;
}

__device__ __forceinline__ void cp16(uint32_t saddr, const void* g) {
    asm volatile("cp.async.cg.shared.global [%0], [%1], 16;" :: "r"(saddr), "l"(g));
}

__device__ __forceinline__ uint32_t f2tf32(float x) {
    uint32_t u;
    asm("cvt.rna.tf32.f32 %0, %1;" : "=r"(u) : "f"(x));
    return u;
}

__device__ __forceinline__ uint32_t packh2(float lo, float hi) {
    __half2 h = __floats2half2_rn(lo, hi);
    return *(uint32_t*)&h;
}

__device__ __forceinline__ void mma_tf32(float* d, const uint32_t* a, const uint32_t* b) {
    asm volatile(
        "mma.sync.aligned.m16n8k8.row.col.f32.tf32.tf32.f32 "
        "{%0,%1,%2,%3}, {%4,%5,%6,%7}, {%8,%9}, {%0,%1,%2,%3};"
        : "+f"(d[0]), "+f"(d[1]), "+f"(d[2]), "+f"(d[3])
        : "r"(a[0]), "r"(a[1]), "r"(a[2]), "r"(a[3]), "r"(b[0]), "r"(b[1]));
}

__device__ __forceinline__ void mma_f16(float* d, const uint32_t* a, const uint32_t* b) {
    asm volatile(
        "mma.sync.aligned.m16n8k16.row.col.f32.f16.f16.f32 "
        "{%0,%1,%2,%3}, {%4,%5,%6,%7}, {%8,%9}, {%0,%1,%2,%3};"
        : "+f"(d[0]), "+f"(d[1]), "+f"(d[2]), "+f"(d[3])
        : "r"(a[0]), "r"(a[1]), "r"(a[2]), "r"(a[3]), "r"(b[0]), "r"(b[1]));
}

__device__ __forceinline__ int pposu(int j) { return (j < 4) ? 2 * j : 2 * (j - 4) + 1; }

// ============================================================================
// K0a: transpose + u32-permute + fp16 convert of weights
// ============================================================================
__global__ __launch_bounds__(256) void transpose_fp16_k(const float* __restrict__ W,
                                                        uint32_t* __restrict__ Wth)
{
    __shared__ float t[32][33];
    int bx = blockIdx.x * 32, by = blockIdx.y * 32;
    int txx = threadIdx.x;
    for (int i = threadIdx.y; i < 32; i += 8)
        t[i][txx] = W[(size_t)(by + i) * EMBD + bx + txx];
    __syncthreads();
    if (txx < 16) {
        int j = txx & 7;
        int pos = (by >> 1) + (txx >> 3) * 8 + pposu(j);
        for (int i = threadIdx.y; i < 32; i += 8) {
            uint32_t u = packh2(t[2 * txx][i], t[2 * txx + 1][i]);
            Wth[(size_t)(bx + i) * EMBD_U + pos] = u;
        }
    }
}

// ============================================================================
// K0b: u32-permute + fp16 convert of x
// ============================================================================
__global__ __launch_bounds__(256) void perm_cvt_fp16_k(const float* __restrict__ src,
                                                       uint32_t* __restrict__ dst)
{
    size_t g16 = (size_t)blockIdx.x * 256 + threadIdx.x;
    size_t base = g16 * 16;
    float4 f0 = *(const float4*)&src[base];
    float4 f1 = *(const float4*)&src[base + 4];
    float4 f2 = *(const float4*)&src[base + 8];
    float4 f3 = *(const float4*)&src[base + 12];
    uint4 o0, o1;
    o0.x = packh2(f0.x, f0.y);
    o0.y = packh2(f2.x, f2.y);
    o0.z = packh2(f0.z, f0.w);
    o0.w = packh2(f2.z, f2.w);
    o1.x = packh2(f1.x, f1.y);
    o1.y = packh2(f3.x, f3.y);
    o1.z = packh2(f1.z, f1.w);
    o1.w = packh2(f3.z, f3.w);
    *(uint4*)&dst[g16 * 8] = o0;
    *(uint4*)&dst[g16 * 8 + 4] = o1;
}

// ============================================================================
// K1: fp16 mma.sync GEMM, CTA 128x256x32, 3-stage pipeline, warp tile 64x64
// ============================================================================
#define BM 128
#define BN 256
#define BK 32
#define BKU 16
#define BKP_U 24
#define NSTG 3
#define STG_U ((BM + BN) * BKP_U)
#define GEMM_SMEM_BYTES (NSTG * STG_U * 4)

__device__ __forceinline__ void load_stage_h(const uint32_t* __restrict__ A,
                                             const uint32_t* __restrict__ Bt,
                                             int brow, int bcol, int k0u,
                                             uint32_t sA, uint32_t sB, int tid)
{
#pragma unroll
    for (int it = 0; it < 2; it++) {
        int idx = tid + it * 256;
        int row = idx >> 2, c4 = idx & 3;
        cp16(sA + (row * BKP_U + c4 * 4) * 4,
             A + (size_t)(brow + row) * EMBD_U + k0u + c4 * 4);
    }
#pragma unroll
    for (int it = 0; it < 4; it++) {
        int idx = tid + it * 256;
        int row = idx >> 2, c4 = idx & 3;
        cp16(sB + (row * BKP_U + c4 * 4) * 4,
             Bt + (size_t)(bcol + row) * EMBD_U + k0u + c4 * 4);
    }
    asm volatile("cp.async.commit_group;" ::: "memory");
}

__device__ __forceinline__ void gemm_body(
    const uint32_t* __restrict__ A, const uint32_t* __restrict__ Bt,
    const float* __restrict__ bias, float* __restrict__ C,
    uint32_t* dsm_u)
{
    uint32_t sbase = smem_u32(dsm_u);
    const int tid = threadIdx.x;
    const int wid = tid >> 5;
    const int lane = tid & 31;
    const int lr = lane >> 2;
    const int lc = lane & 3;
    const int wm = (wid >> 2) * 64;
    const int wn = (wid & 3) * 64;

    int brow = blockIdx.y * BM;
    int bcol = blockIdx.x * BN;

    float acc[4][8][4];
#pragma unroll
    for (int mt = 0; mt < 4; mt++)
#pragma unroll
        for (int nt = 0; nt < 8; nt++)
#pragma unroll
            for (int r = 0; r < 4; r++) acc[mt][nt][r] = 0.f;

    uint32_t sA[NSTG], sB[NSTG];
#pragma unroll
    for (int s = 0; s < NSTG; s++) {
        sA[s] = sbase + s * STG_U * 4;
        sB[s] = sA[s] + BM * BKP_U * 4;
    }

    load_stage_h(A, Bt, brow, bcol, 0 * BKU, sA[0], sB[0], tid);
    load_stage_h(A, Bt, brow, bcol, 1 * BKU, sA[1], sB[1], tid);
    load_stage_h(A, Bt, brow, bcol, 2 * BKU, sA[2], sB[2], tid);

    const int NIT = EMBD / BK;
    for (int it = 0; it < NIT; it++) {
        if (it < NIT - 2)       asm volatile("cp.async.wait_group 2;" ::: "memory");
        else if (it == NIT - 2) asm volatile("cp.async.wait_group 1;" ::: "memory");
        else                    asm volatile("cp.async.wait_group 0;" ::: "memory");
        __syncthreads();

        int s = it % NSTG;
        const uint32_t* As = dsm_u + (size_t)s * STG_U;
        const uint32_t* Bs = As + BM * BKP_U;

#pragma unroll
        for (int kc = 0; kc < 2; kc++) {
            int off = kc * 8 + 2 * lc;
            uint32_t af[4][4], bf[8][2];
#pragma unroll
            for (int mt = 0; mt < 4; mt++) {
                int r = wm + mt * 16 + lr;
                uint2 a0 = *(const uint2*)&As[r * BKP_U + off];
                uint2 a1 = *(const uint2*)&As[(r + 8) * BKP_U + off];
                af[mt][0] = a0.x; af[mt][2] = a0.y;
                af[mt][1] = a1.x; af[mt][3] = a1.y;
            }
#pragma unroll
            for (int nt = 0; nt < 8; nt++) {
                int cN = wn + nt * 8 + lr;
                uint2 b = *(const uint2*)&Bs[cN * BKP_U + off];
                bf[nt][0] = b.x; bf[nt][1] = b.y;
            }
#pragma unroll
            for (int mt = 0; mt < 4; mt++)
#pragma unroll
                for (int nt = 0; nt < 8; nt++)
                    mma_f16(acc[mt][nt], af[mt], bf[nt]);
        }
        __syncthreads();

        if (it + NSTG < NIT)
            load_stage_h(A, Bt, brow, bcol, (it + NSTG) * BKU, sA[s], sB[s], tid);
    }

#pragma unroll
    for (int nt = 0; nt < 8; nt++) {
        int col = bcol + wn + nt * 8 + 2 * lc;
        float b0 = bias[col], b1 = bias[col + 1];
#pragma unroll
        for (int mt = 0; mt < 4; mt++) {
            int row = brow + wm + mt * 16 + lr;
            float2 v0 = make_float2(acc[mt][nt][0] + b0, acc[mt][nt][1] + b1);
            float2 v1 = make_float2(acc[mt][nt][2] + b0, acc[mt][nt][3] + b1);
            *(float2*)&C[(size_t)row * EMBD + col] = v0;
            *(float2*)&C[(size_t)(row + 8) * EMBD + col] = v1;
        }
    }
}

__global__ __launch_bounds__(256) void gemm_mma_k(
    const uint32_t* __restrict__ A, const uint32_t* __restrict__ Bt,
    const float* __restrict__ bias, float* __restrict__ C)
{
    extern __shared__ uint32_t dsm_u[];
    gemm_body(A, Bt, bias, C, dsm_u);
}

__global__ __launch_bounds__(256) void gemm_qkv_k(
    const uint32_t* __restrict__ A, const uint32_t* __restrict__ WtBase,
    const float* __restrict__ bq, const float* __restrict__ bk,
    const float* __restrict__ bv,
    float* __restrict__ q, float* __restrict__ k, float* __restrict__ v)
{
    extern __shared__ uint32_t dsm_u[];
    int z = blockIdx.z;
    const uint32_t* Bt = WtBase + (size_t)z * EMBD * EMBD_U;
    const float* bias = (z == 0) ? bq : (z == 1) ? bk : bv;
    float* C = (z == 0) ? q : (z == 1) ? k : v;
    gemm_body(A, Bt, bias, C, dsm_u);
}

// ============================================================================
// K2: RoPE (fp32 in place) + fp16 packed copies of q,k
// ============================================================================
__global__ __launch_bounds__(256) void rope_k(float* __restrict__ q, float* __restrict__ k,
                                              uint32_t* __restrict__ qh,
                                              uint32_t* __restrict__ kh)
{
    size_t idx = (size_t)blockIdx.x * 256 + threadIdx.x;
    int rr = (int)(idx >> 10);
    int i = (int)(idx & 1023);
    int t = rr & (SEQ - 1);
    float inv = powf(10000.0f, -(float)(2 * i) * (1.0f / 2048.0f));
    float ang = (float)t * inv;
    float c = cosf(ang), s = sinf(ang);
    size_t base = (size_t)rr * EMBD + 2 * i;
    size_t ubase = (size_t)rr * EMBD_U + i;
    float a = q[base], b = q[base + 1];
    float qa = a * c - b * s, qb = a * s + b * c;
    q[base] = qa; q[base + 1] = qb;
    qh[ubase] = packh2(qa, qb);
    a = k[base]; b = k[base + 1];
    float ka = a * c - b * s, kb = a * s + b * c;
    k[base] = ka; k[base + 1] = kb;
    kh[ubase] = packh2(ka, kb);
}

// ============================================================================
// K2b: v -> fp16 transposed per segment (pairs along l)
// ============================================================================
__global__ __launch_bounds__(256) void vt_k(const float* __restrict__ vb,
                                            uint32_t* __restrict__ vth)
{
    __shared__ float t[32][33];
    int bhs = blockIdx.z;
    int d0 = blockIdx.x * 32;
    int l0 = blockIdx.y * 32;
    size_t segbase = ((size_t)bhs) << 16;
    const float* vseg = vb + segbase;
    uint32_t* vtseg = vth + (size_t)bhs * DHEAD * SEGL_U;
    int txx = threadIdx.x;
    for (int i = threadIdx.y; i < 32; i += 8)
        t[i][txx] = vseg[(size_t)(l0 + i) * DHEAD + d0 + txx];
    __syncthreads();
    int c = txx & 15, rh = txx >> 4;
    for (int i = threadIdx.y; i < 16; i += 8) {
        int r = 2 * i + rh;
        vtseg[(size_t)(d0 + r) * SEGL_U + (l0 >> 1) + c] =
            packh2(t[2 * c][r], t[2 * c + 1][r]);
    }
}

// ============================================================================
// K2c: sk^T = elu1(k)^T fp16 per segment (pairs along l)
// ============================================================================
__global__ __launch_bounds__(256) void skt_k(const float* __restrict__ kb,
                                             uint32_t* __restrict__ skth)
{
    __shared__ float t[32][33];
    int bhs = blockIdx.z;
    int d0 = blockIdx.x * 32;
    int l0 = blockIdx.y * 32;
    size_t segbase = ((size_t)bhs) << 16;
    const float* kseg = kb + segbase;
    uint32_t* sktseg = skth + (size_t)bhs * DHEAD * SEGL_U;
    int txx = threadIdx.x;
    for (int i = threadIdx.y; i < 32; i += 8)
        t[i][txx] = kseg[(size_t)(l0 + i) * DHEAD + d0 + txx];
    __syncthreads();
    int c = txx & 15, rh = txx >> 4;
    for (int i = threadIdx.y; i < 16; i += 8) {
        int r = 2 * i + rh;
        sktseg[(size_t)(d0 + r) * SEGL_U + (l0 >> 1) + c] =
            packh2(elu1(t[2 * c][r]), elu1(t[2 * c + 1][r]));
    }
}

// ============================================================================
// K2d: Zseg[bhs][d] = row-sum of skth (512 fp16 values)
// ============================================================================
__global__ __launch_bounds__(256) void zsum_k(const uint32_t* __restrict__ skth,
                                              float* __restrict__ Zseg)
{
    int bhs = blockIdx.x;
    int tid = threadIdx.x;
    int d = tid >> 1;
    int half = tid & 1;
    const uint32_t* row = skth + (size_t)bhs * DHEAD * SEGL_U
                        + (size_t)d * SEGL_U + half * 128;
    float s = 0.f;
#pragma unroll 16
    for (int j = 0; j < 128; j++) {
        __half2 h = *(const __half2*)&row[j];
        s += __low2float(h) + __high2float(h);
    }
    s += __shfl_xor_sync(0xffffffffu, s, 1);
    if (half == 0) Zseg[bhs * DHEAD + d] = s;
}

// ============================================================================
// K3: FUSED flash attention: attnd = (1-g) * softmax(scale q k^T) v  (fp16 out)
// ============================================================================
#define SCP 68
#define FA_SMEM_U (4 * 128 * SCP + 4 * 128 + 4 * 128 + 3 * 128)
#define FA_SMEM_BYTES (FA_SMEM_U * 4)  // 144896

__global__ __launch_bounds__(256, 1) void fattn_k(
    const uint32_t* __restrict__ qh, const uint32_t* __restrict__ kh,
    const uint32_t* __restrict__ vth, const float* __restrict__ beta,
    uint32_t* __restrict__ attnd)
{
    extern __shared__ uint32_t smu[];
    uint32_t* qs = smu;
    uint32_t* ks = smu + 128 * SCP;
    uint32_t* Ps = smu + 2 * 128 * SCP;
    uint32_t* vs = smu + 3 * 128 * SCP;
    float* pmax = (float*)(smu + 4 * 128 * SCP);
    float* psum = pmax + 4 * 128;
    float* m_s = psum + 4 * 128;
    float* f_s = m_s + 128;
    float* ssum_s = f_s + 128;

    uint32_t sq = smem_u32(qs);
    uint32_t sk = smem_u32(ks);
    uint32_t sv = smem_u32(vs);

    const float scale = 0.08838834764831845f;
    const int tid = threadIdx.x;
    const int wid = tid >> 5;
    const int lane = tid & 31;
    const int lr = lane >> 2;
    const int lc = lane & 3;
    const int wm = (wid >> 2) * 64;
    const int wn = (wid & 3) * 32;
    const int wci = wid & 3;

    int bhs = blockIdx.y;
    int l0 = blockIdx.x * 128;
    size_t segbase_u = ((size_t)bhs) << 15;
    const uint32_t* qseg = qh + segbase_u;
    const uint32_t* kseg = kh + segbase_u;
    const uint32_t* vtseg = vth + (size_t)bhs * DHEAD * SEGL_U;
    float gm1 = 1.0f - 1.0f / (1.0f + expf(-beta[0]));

#pragma unroll
    for (int it = 0; it < 8; it++) {
        int idx = tid + it * 256;
        int row = idx >> 4, c4 = idx & 15;
        cp16(sq + (row * SCP + c4 * 4) * 4,
             qseg + (size_t)(l0 + row) * 64 + c4 * 4);
    }
    asm volatile("cp.async.commit_group;" ::: "memory");

    if (tid < 128) { m_s[tid] = -1e30f; ssum_s[tid] = 0.f; }

    float Oacc[4][4][4];
#pragma unroll
    for (int mt = 0; mt < 4; mt++)
#pragma unroll
        for (int nt = 0; nt < 4; nt++)
#pragma unroll
            for (int r = 0; r < 4; r++) Oacc[mt][nt][r] = 0.f;

    for (int kt = 0; kt < 4; kt++) {
#pragma unroll
        for (int it = 0; it < 8; it++) {
            int idx = tid + it * 256;
            int row = idx >> 4, c4 = idx & 15;
            cp16(sk + (row * SCP + c4 * 4) * 4,
                 kseg + (size_t)(kt * 128 + row) * 64 + c4 * 4);
        }
#pragma unroll
        for (int it = 0; it < 8; it++) {
            int idx = tid + it * 256;
            int row = idx >> 4, c4 = idx & 15;
            cp16(sv + (row * SCP + c4 * 4) * 4,
                 vtseg + (size_t)row * SEGL_U + kt * 64 + c4 * 4);
        }
        asm volatile("cp.async.commit_group;" ::: "memory");
        asm volatile("cp.async.wait_group 0;" ::: "memory");
        __syncthreads();

        float Sacc[4][4][4];
#pragma unroll
        for (int mt = 0; mt < 4; mt++)
#pragma unroll
            for (int nt = 0; nt < 4; nt++)
#pragma unroll
                for (int r = 0; r < 4; r++) Sacc[mt][nt][r] = 0.f;

#pragma unroll
        for (int kb = 0; kb < 64; kb += 8) {
            uint32_t af[4][4], bf[4][2];
#pragma unroll
            for (int mt = 0; mt < 4; mt++) {
                int r = wm + mt * 16 + lr;
                af[mt][0] = qs[r * SCP + kb + lc];
                af[mt][1] = qs[(r + 8) * SCP + kb + lc];
                af[mt][2] = qs[r * SCP + kb + lc + 4];
                af[mt][3] = qs[(r + 8) * SCP + kb + lc + 4];
            }
#pragma unroll
            for (int nt = 0; nt < 4; nt++) {
                int cN = wn + nt * 8 + lr;
                bf[nt][0] = ks[cN * SCP + kb + lc];
                bf[nt][1] = ks[cN * SCP + kb + lc + 4];
            }
#pragma unroll
            for (int mt = 0; mt < 4; mt++)
#pragma unroll
                for (int nt = 0; nt < 4; nt++)
                    mma_f16(Sacc[mt][nt], af[mt], bf[nt]);
        }
#pragma unroll
        for (int mt = 0; mt < 4; mt++)
#pragma unroll
            for (int nt = 0; nt < 4; nt++)
#pragma unroll
                for (int r = 0; r < 4; r++) Sacc[mt][nt][r] *= scale;

#pragma unroll
        for (int mt = 0; mt < 4; mt++) {
#pragma unroll
            for (int h = 0; h < 2; h++) {
                float mv = -1e30f;
#pragma unroll
                for (int nt = 0; nt < 4; nt++) {
                    mv = fmaxf(mv, Sacc[mt][nt][2 * h]);
                    mv = fmaxf(mv, Sacc[mt][nt][2 * h + 1]);
                }
                mv = fmaxf(mv, __shfl_xor_sync(0xffffffffu, mv, 1));
                mv = fmaxf(mv, __shfl_xor_sync(0xffffffffu, mv, 2));
                if (lc == 0) pmax[wci * 128 + wm + mt * 16 + lr + h * 8] = mv;
            }
        }
        __syncthreads();

        if (tid < 128) {
            float mo = m_s[tid];
            float nm = fmaxf(fmaxf(pmax[tid], pmax[128 + tid]),
                             fmaxf(pmax[256 + tid], pmax[384 + tid]));
            float mn = fmaxf(mo, nm);
            float f = expf(mo - mn);
            m_s[tid] = mn;
            f_s[tid] = f;
            ssum_s[tid] *= f;
        }
        __syncthreads();

#pragma unroll
        for (int mt = 0; mt < 4; mt++) {
#pragma unroll
            for (int h = 0; h < 2; h++) {
                int row = wm + mt * 16 + lr + h * 8;
                float m = m_s[row];
                float f = f_s[row];
                float rsum = 0.f;
#pragma unroll
                for (int nt = 0; nt < 4; nt++) {
                    float p0 = expf(Sacc[mt][nt][2 * h] - m);
                    float p1 = expf(Sacc[mt][nt][2 * h + 1] - m);
                    rsum += p0 + p1;
                    Ps[row * SCP + (wn >> 1) + nt * 4 + lc] = packh2(p0, p1);
                    Oacc[mt][nt][2 * h] *= f;
                    Oacc[mt][nt][2 * h + 1] *= f;
                }
                rsum += __shfl_xor_sync(0xffffffffu, rsum, 1);
                rsum += __shfl_xor_sync(0xffffffffu, rsum, 2);
                if (lc == 0) psum[wci * 128 + row] = rsum;
            }
        }
        __syncthreads();

        if (tid < 128)
            ssum_s[tid] += psum[tid] + psum[128 + tid] + psum[256 + tid] + psum[384 + tid];

#pragma unroll
        for (int kb = 0; kb < 64; kb += 8) {
            uint32_t af[4][4], bf[4][2];
#pragma unroll
            for (int mt = 0; mt < 4; mt++) {
                int r = wm + mt * 16 + lr;
                af[mt][0] = Ps[r * SCP + kb + lc];
                af[mt][1] = Ps[(r + 8) * SCP + kb + lc];
                af[mt][2] = Ps[r * SCP + kb + lc + 4];
                af[mt][3] = Ps[(r + 8) * SCP + kb + lc + 4];
            }
#pragma unroll
            for (int nt = 0; nt < 4; nt++) {
                int cN = wn + nt * 8 + lr;
                bf[nt][0] = vs[cN * SCP + kb + lc];
                bf[nt][1] = vs[cN * SCP + kb + lc + 4];
            }
#pragma unroll
            for (int mt = 0; mt < 4; mt++)
#pragma unroll
                for (int nt = 0; nt < 4; nt++)
                    mma_f16(Oacc[mt][nt], af[mt], bf[nt]);
        }
        __syncthreads();
    }

    // epilogue: fp16-packed (1-g)*O/ssum
#pragma unroll
    for (int nt = 0; nt < 4; nt++) {
        int col = wn + nt * 8 + 2 * lc;
#pragma unroll
        for (int mt = 0; mt < 4; mt++) {
#pragma unroll
            for (int h = 0; h < 2; h++) {
                int row = wm + mt * 16 + lr + h * 8;
                float sc = gm1 / ssum_s[row];
                attnd[segbase_u + (size_t)(l0 + row) * 64 + (col >> 1)] =
                    packh2(Oacc[mt][nt][2 * h] * sc, Oacc[mt][nt][2 * h + 1] * sc);
            }
        }
    }
}

// ============================================================================
// K6: tensorized outer products: memT[e][d] = sum_l v[l][e] * sk[l][d]
//     per bhs: 128x128x512 fp16 mma; A = vth, B = skth
// ============================================================================
#define PVP 36
#define OUTER_SMEM_BYTES (2 * 2 * 128 * PVP * 4)  // 73728

__global__ __launch_bounds__(256) void outer_mma_k(
    const uint32_t* __restrict__ vth, const uint32_t* __restrict__ skth,
    float* __restrict__ memsegT)
{
    extern __shared__ uint32_t smu[];
    uint32_t* Ash = smu;                    // [2][128][PVP]  (v^T rows e)
    uint32_t* Bsh = smu + 2 * 128 * PVP;    // [2][128][PVP]  (sk^T rows d)
    uint32_t sAu = smem_u32(Ash);
    uint32_t sBu = smem_u32(Bsh);

    const int tid = threadIdx.x;
    const int wid = tid >> 5;
    const int lane = tid & 31;
    const int lr = lane >> 2;
    const int lc = lane & 3;
    const int wm = (wid >> 2) * 64;
    const int wn = (wid & 3) * 32;

    int bhs = blockIdx.x;
    const uint32_t* vtseg = vth + (size_t)bhs * DHEAD * SEGL_U;
    const uint32_t* sktseg = skth + (size_t)bhs * DHEAD * SEGL_U;

    float acc[4][4][4];
#pragma unroll
    for (int mt = 0; mt < 4; mt++)
#pragma unroll
        for (int nt = 0; nt < 4; nt++)
#pragma unroll
            for (int r = 0; r < 4; r++) acc[mt][nt][r] = 0.f;

    auto load_st = [&](int k0u, uint32_t sA, uint32_t sB) {
#pragma unroll
        for (int it = 0; it < 4; it++) {
            int idx = tid + it * 256;
            int row = idx >> 3, c4 = idx & 7;
            cp16(sA + (row * PVP + c4 * 4) * 4,
                 vtseg + (size_t)row * SEGL_U + k0u + c4 * 4);
        }
#pragma unroll
        for (int it = 0; it < 4; it++) {
            int idx = tid + it * 256;
            int row = idx >> 3, c4 = idx & 7;
            cp16(sB + (row * PVP + c4 * 4) * 4,
                 sktseg + (size_t)row * SEGL_U + k0u + c4 * 4);
        }
        asm volatile("cp.async.commit_group;" ::: "memory");
    };

    load_st(0, sAu, sBu);
    load_st(32, sAu + 128 * PVP * 4, sBu + 128 * PVP * 4);

    const int NIT = SEGL_U / 32; // 8
    for (int it = 0; it < NIT; it++) {
        int s = it & 1;
        if (it == NIT - 1) asm volatile("cp.async.wait_group 0;" ::: "memory");
        else               asm volatile("cp.async.wait_group 1;" ::: "memory");
        __syncthreads();

        const uint32_t* As = Ash + s * 128 * PVP;
        const uint32_t* Bs = Bsh + s * 128 * PVP;
#pragma unroll
        for (int kb = 0; kb < 32; kb += 8) {
            uint32_t af[4][4], bf[4][2];
#pragma unroll
            for (int mt = 0; mt < 4; mt++) {
                int r = wm + mt * 16 + lr;
                af[mt][0] = As[r * PVP + kb + lc];
                af[mt][1] = As[(r + 8) * PVP + kb + lc];
                af[mt][2] = As[r * PVP + kb + lc + 4];
                af[mt][3] = As[(r + 8) * PVP + kb + lc + 4];
            }
#pragma unroll
            for (int nt = 0; nt < 4; nt++) {
                int cN = wn + nt * 8 + lr;
                bf[nt][0] = Bs[cN * PVP + kb + lc];
                bf[nt][1] = Bs[cN * PVP + kb + lc + 4];
            }
#pragma unroll
            for (int mt = 0; mt < 4; mt++)
#pragma unroll
                for (int nt = 0; nt < 4; nt++)
                    mma_f16(acc[mt][nt], af[mt], bf[nt]);
        }
        __syncthreads();
        if (it + 2 < NIT)
            load_st((it + 2) * 32, sAu + s * 128 * PVP * 4, sBu + s * 128 * PVP * 4);
    }

    float* memb = memsegT + (size_t)bhs * DHEAD * DHEAD;
#pragma unroll
    for (int nt = 0; nt < 4; nt++) {
        int col = wn + nt * 8 + 2 * lc;
#pragma unroll
        for (int mt = 0; mt < 4; mt++) {
            int row = wm + mt * 16 + lr;
            *(float2*)&memb[(size_t)row * DHEAD + col] =
                make_float2(acc[mt][nt][0], acc[mt][nt][1]);
            *(float2*)&memb[(size_t)(row + 8) * DHEAD + col] =
                make_float2(acc[mt][nt][2], acc[mt][nt][3]);
        }
    }
}

// ============================================================================
// K7: in-place exclusive prefix over the 8 segments (layout-agnostic)
// ============================================================================
__global__ __launch_bounds__(256) void prefix_mem_k(float* __restrict__ memseg)
{
    size_t idx = (size_t)blockIdx.x * 256 + threadIdx.x;
    int bh = (int)(idx >> 14);
    int off = (int)(idx & 16383);
    size_t base = ((size_t)bh * NSEG) * 16384 + off;
    float run = 0.f;
#pragma unroll
    for (int s = 0; s < NSEG; s++) {
        float t = memseg[base + (size_t)s * 16384];
        memseg[base + (size_t)s * 16384] = run;
        run += t;
    }
}

__global__ __launch_bounds__(256) void prefix_Z_k(float* __restrict__ Zseg)
{
    int idx = blockIdx.x * 256 + threadIdx.x;
    int bh = idx >> 7;
    int d = idx & 127;
    int base = bh * NSEG * DHEAD + d;
    float run = 0.f;
#pragma unroll
    for (int s = 0; s < NSEG; s++) {
        float t = Zseg[base + s * DHEAD];
        Zseg[base + s * DHEAD] = run;
        run += t;
    }
}

// ============================================================================
// K8: tensorized A_mem (tf32, memT operand) + fused combine + fp16-perm output
// ============================================================================
#define AMP 136
#define AMEM_SMEM_BYTES ((2 * 128 * AMP + 256) * 4)

__global__ __launch_bounds__(256) void amem_mma_k(
    const float* __restrict__ qb, const float* __restrict__ memsegT,
    const float* __restrict__ Zseg, const float* __restrict__ beta,
    const uint32_t* __restrict__ attnd, uint32_t* __restrict__ attnh)
{
    extern __shared__ uint32_t smu[];
    uint32_t* qs = smu;                  // [128][AMP] tf32(elu1(q)) rows l
    uint32_t* ms = smu + 128 * AMP;      // [128][AMP] tf32(memT) rows e
    float* rowsumS = (float*)(smu + 2 * 128 * AMP);
    float* Zs = rowsumS + 128;
    uint32_t sqb = smem_u32(qs);
    uint32_t smb = smem_u32(ms);

    const int tid = threadIdx.x;
    const int wid = tid >> 5;
    const int lane = tid & 31;
    const int lr = lane >> 2;
    const int lc = lane & 3;
    const int wm = (wid >> 2) * 64;
    const int wn = (wid & 3) * 32;

    int bhs = blockIdx.y;
    int l0 = blockIdx.x * 128;
    size_t segbase = ((size_t)bhs) << 16;
    size_t segbase_u = ((size_t)bhs) << 15;
    const float* qseg = qb + segbase;
    const float* memb = memsegT + (size_t)bhs * DHEAD * DHEAD;
    float g = 1.0f / (1.0f + expf(-beta[0]));

#pragma unroll
    for (int it = 0; it < 16; it++) {
        int idx = tid + it * 256;
        int row = idx >> 5, c4 = idx & 31;
        cp16(sqb + (row * AMP + c4 * 4) * 4,
             qseg + (size_t)(l0 + row) * DHEAD + c4 * 4);
    }
#pragma unroll
    for (int it = 0; it < 16; it++) {
        int idx = tid + it * 256;
        int row = idx >> 5, c4 = idx & 31;
        cp16(smb + (row * AMP + c4 * 4) * 4,
             memb + (size_t)row * DHEAD + c4 * 4);
    }
    asm volatile("cp.async.commit_group;" ::: "memory");
    asm volatile("cp.async.wait_group 0;" ::: "memory");
    __syncthreads();

    {
        int r = tid >> 1;
        int half = (tid & 1) * 64;
        float partial = 0.f;
#pragma unroll 16
        for (int j = 0; j < 64; j++) {
            uint32_t* p = &qs[r * AMP + half + j];
            float e = elu1(__uint_as_float(*p));
            partial += e;
            *p = f2tf32(e);
        }
        partial += __shfl_xor_sync(0xffffffffu, partial, 1);
        if ((tid & 1) == 0) rowsumS[r] = partial;
#pragma unroll 16
        for (int j = 0; j < 64; j++) {
            uint32_t* p = &ms[r * AMP + half + j];
            *p = f2tf32(__uint_as_float(*p));
        }
    }
    if (tid < 128) Zs[tid] = Zseg[bhs * DHEAD + tid];
    __syncthreads();

    float acc[4][4][4];
#pragma unroll
    for (int mt = 0; mt < 4; mt++)
#pragma unroll
        for (int nt = 0; nt < 4; nt++)
#pragma unroll
            for (int r = 0; r < 4; r++) acc[mt][nt][r] = 0.f;

#pragma unroll
    for (int kb = 0; kb < 128; kb += 8) {
        uint32_t af[4][4], bf[4][2];
#pragma unroll
        for (int mt = 0; mt < 4; mt++) {
            int r = wm + mt * 16 + lr;
            af[mt][0] = qs[r * AMP + kb + lc];
            af[mt][1] = qs[(r + 8) * AMP + kb + lc];
            af[mt][2] = qs[r * AMP + kb + lc + 4];
            af[mt][3] = qs[(r + 8) * AMP + kb + lc + 4];
        }
#pragma unroll
        for (int nt = 0; nt < 4; nt++) {
            int cN = wn + nt * 8 + lr;
            bf[nt][0] = ms[cN * AMP + kb + lc];       // memT row-major
            bf[nt][1] = ms[cN * AMP + kb + lc + 4];
        }
#pragma unroll
        for (int mt = 0; mt < 4; mt++)
#pragma unroll
            for (int nt = 0; nt < 4; nt++)
                mma_tf32(acc[mt][nt], af[mt], bf[nt]);
    }

#pragma unroll
    for (int nt = 0; nt < 4; nt++) {
        int col = wn + nt * 8 + 2 * lc;
        int j = (col & 15) >> 1;
        int pos = (col >> 4) * 8 + pposu(j);
        float Z0 = Zs[col], Z1 = Zs[col + 1];
#pragma unroll
        for (int mt = 0; mt < 4; mt++) {
#pragma unroll
            for (int h = 0; h < 2; h++) {
                int rloc = wm + mt * 16 + lr + h * 8;
                int row = l0 + rloc;
                float rs = rowsumS[rloc];
                __half2 ath = *(const __half2*)&attnd[segbase_u + (size_t)row * 64 + (col >> 1)];
                float a0 = g * acc[mt][nt][2 * h + 0] / (rs * Z0 + 1e-6f) + __low2float(ath);
                float a1 = g * acc[mt][nt][2 * h + 1] / (rs * Z1 + 1e-6f) + __high2float(ath);
                attnh[segbase_u + (size_t)row * (DHEAD / 2) + pos] = packh2(a0, a1);
            }
        }
    }
}

// ============================================================================
// Host launch
// ============================================================================
extern "C" void kernel_launch(void* const* d_in, const int* in_sizes, int n_in,
                              void* d_out, int out_size)
{
    (void)in_sizes; (void)n_in; (void)out_size;
    const float* x    = (const float*)d_in[0];
    const float* Wq   = (const float*)d_in[1];
    const float* bq   = (const float*)d_in[2];
    const float* Wk   = (const float*)d_in[3];
    const float* bk   = (const float*)d_in[4];
    const float* Wv   = (const float*)d_in[5];
    const float* bv   = (const float*)d_in[6];
    const float* Wo   = (const float*)d_in[7];
    const float* bo   = (const float*)d_in[8];
    const float* beta = (const float*)d_in[9];
    float* out = (float*)d_out;

    static float *pq = nullptr, *pk = nullptr, *pv = nullptr,
                 *pmemsegT = nullptr, *pZseg = nullptr;
    static uint32_t *pWth = nullptr, *pxh = nullptr, *pattnh = nullptr,
                    *pqh = nullptr, *pkh = nullptr, *pvth = nullptr,
                    *pskth = nullptr, *pattnd = nullptr;
    if (!pq) {
        cudaGetSymbolAddress((void**)&pq, g_q);
        cudaGetSymbolAddress((void**)&pk, g_k);
        cudaGetSymbolAddress((void**)&pv, g_v);
        cudaGetSymbolAddress((void**)&pattnd, g_attnd);
        cudaGetSymbolAddress((void**)&pmemsegT, g_memsegT);
        cudaGetSymbolAddress((void**)&pZseg, g_Zseg);
        cudaGetSymbolAddress((void**)&pWth, g_Wth);
        cudaGetSymbolAddress((void**)&pxh, g_xh);
        cudaGetSymbolAddress((void**)&pattnh, g_attnh);
        cudaGetSymbolAddress((void**)&pqh, g_qh);
        cudaGetSymbolAddress((void**)&pkh, g_kh);
        cudaGetSymbolAddress((void**)&pvth, g_vth);
        cudaGetSymbolAddress((void**)&pskth, g_skth);
        cudaFuncSetAttribute(gemm_mma_k, cudaFuncAttributeMaxDynamicSharedMemorySize,
                             GEMM_SMEM_BYTES);
        cudaFuncSetAttribute(gemm_qkv_k, cudaFuncAttributeMaxDynamicSharedMemorySize,
                             GEMM_SMEM_BYTES);
        cudaFuncSetAttribute(fattn_k, cudaFuncAttributeMaxDynamicSharedMemorySize,
                             FA_SMEM_BYTES);
        cudaFuncSetAttribute(outer_mma_k, cudaFuncAttributeMaxDynamicSharedMemorySize,
                             OUTER_SMEM_BYTES);
        cudaFuncSetAttribute(amem_mma_k, cudaFuncAttributeMaxDynamicSharedMemorySize,
                             AMEM_SMEM_BYTES);
    }

    const size_t WSZ_U = (size_t)EMBD * EMBD_U;
    dim3 tgrid(EMBD / 32, EMBD / 32);
    dim3 tblk(32, 8);
    transpose_fp16_k<<<tgrid, tblk>>>(Wq, pWth + 0 * WSZ_U);
    transpose_fp16_k<<<tgrid, tblk>>>(Wk, pWth + 1 * WSZ_U);
    transpose_fp16_k<<<tgrid, tblk>>>(Wv, pWth + 2 * WSZ_U);
    transpose_fp16_k<<<tgrid, tblk>>>(Wo, pWth + 3 * WSZ_U);

    perm_cvt_fp16_k<<<(int)(TOTAL / 16 / 256), 256>>>(x, pxh);

    dim3 qkvgrid(EMBD / BN, MTOK / BM, 3);
    gemm_qkv_k<<<qkvgrid, 256, GEMM_SMEM_BYTES>>>(pxh, pWth, bq, bk, bv, pq, pk, pv);

    rope_k<<<(MTOK * (EMBD / 2)) / 256, 256>>>(pq, pk, pqh, pkh);
    vt_k<<<dim3(DHEAD / 32, SEGL / 32, NBH * NSEG), tblk>>>(pv, pvth);
    skt_k<<<dim3(DHEAD / 32, SEGL / 32, NBH * NSEG), tblk>>>(pk, pskth);

    // parallel linear-memory path (tensorized)
    outer_mma_k<<<NBH * NSEG, 256, OUTER_SMEM_BYTES>>>(pvth, pskth, pmemsegT);
    zsum_k<<<NBH * NSEG, 256>>>(pskth, pZseg);
    prefix_mem_k<<<(NBH * 16384) / 256, 256>>>(pmemsegT);
    prefix_Z_k<<<(NBH * DHEAD) / 256, 256>>>(pZseg);

    // fused flash attention (fp16 output)
    fattn_k<<<dim3(SEGL / 128, NBH * NSEG), 256, FA_SMEM_BYTES>>>(
        pqh, pkh, pvth, beta, pattnd);

    // tensorized A_mem + combine + fp16 perm-cvt fused
    amem_mma_k<<<dim3(SEGL / 128, NBH * NSEG), 256, AMEM_SMEM_BYTES>>>(
        pq, pmemsegT, pZseg, beta, pattnd, pattnh);

    gemm_mma_k<<<dim3(EMBD / BN, MTOK / BM), 256, GEMM_SMEM_BYTES>>>(
        pattnh, pWth + 3 * WSZ_U, bo, out);
}

// round 13
// speedup vs baseline: 5.5666x; 1.0255x over previous
#include <cuda_runtime.h>
#include <cuda_fp16.h>
#include <math.h>
#include <stdint.h>

// Problem constants
#define SEQ   4096
#define EMBD  2048
#define NB    4
#define NHEAD 16
#define DHEAD 128
#define NSEG  8
#define SEGL  512
#define NBH   (NB * NHEAD)          // 64
#define MTOK  (NB * SEQ)            // 16384
#define TOTAL ((size_t)MTOK * EMBD) // 33554432
#define EMBD_U (EMBD / 2)           // 1024 u32 per row
#define SEGL_U (SEGL / 2)           // 256

// -------- device scratch ----------------------------------------------------
__device__ uint32_t g_attnd[TOTAL / 2];               // fp16 (1-g)*A_dot
__device__ float g_memsegT[(size_t)NBH * NSEG * DHEAD * DHEAD]; // mem^T [e][d]
__device__ float g_Zseg[NBH * NSEG * DHEAD];
__device__ uint32_t g_Wth[(size_t)4 * EMBD * EMBD_U]; // transposed+permuted fp16
__device__ uint32_t g_xh[TOTAL / 2];                  // permuted fp16 x
__device__ uint32_t g_attnh[TOTAL / 2];               // permuted fp16 attn
__device__ uint32_t g_qh[TOTAL / 2];                  // fp16 q (pairs along d, roped)
__device__ uint32_t g_kh[TOTAL / 2];                  // fp16 k (pairs along d, roped)
__device__ uint32_t g_vh[TOTAL / 2];                  // fp16 v (pairs along d)
__device__ uint32_t g_vth[(size_t)NBH * NSEG * DHEAD * SEGL_U]; // fp16 v^T
__device__ uint32_t g_skth[(size_t)NBH * NSEG * DHEAD * SEGL_U]; // fp16 sk^T
__device__ float g_cost[(size_t)SEQ * 1024];          // rope cos table
__device__ float g_sint[(size_t)SEQ * 1024];          // rope sin table

__device__ __forceinline__ float elu1(float x) {
    return (x > 0.f) ? (x + 1.f) : expf(x);
}

__device__ __forceinline__ uint32_t smem_u32(const void* p) {
    uint32_t a;
    asm("{ .reg .u64 t; cvta.to.shared.u64 t, %1; cvt.u32.u64 %0, t; }"
        : "=r"(a) : "l"(p));
    return a;
}

__device__ __forceinline__ void cp16(uint32_t saddr, const void* g) {
    asm volatile("cp.async.cg.shared.global [%0], [%1], 16;" :: "r"(saddr), "l"(g));
}

__device__ __forceinline__ uint32_t f2tf32(float x) {
    uint32_t u;
    asm("cvt.rna.tf32.f32 %0, %1;" : "=r"(u) : "f"(x));
    return u;
}

__device__ __forceinline__ uint32_t packh2(float lo, float hi) {
    __half2 h = __floats2half2_rn(lo, hi);
    return *(uint32_t*)&h;
}

__device__ __forceinline__ void mma_tf32(float* d, const uint32_t* a, const uint32_t* b) {
    asm volatile(
        "mma.sync.aligned.m16n8k8.row.col.f32.tf32.tf32.f32 "
        "{%0,%1,%2,%3}, {%4,%5,%6,%7}, {%8,%9}, {%0,%1,%2,%3};"
        : "+f"(d[0]), "+f"(d[1]), "+f"(d[2]), "+f"(d[3])
        : "r"(a[0]), "r"(a[1]), "r"(a[2]), "r"(a[3]), "r"(b[0]), "r"(b[1]));
}

__device__ __forceinline__ void mma_f16(float* d, const uint32_t* a, const uint32_t* b) {
    asm volatile(
        "mma.sync.aligned.m16n8k16.row.col.f32.f16.f16.f32 "
        "{%0,%1,%2,%3}, {%4,%5,%6,%7}, {%8,%9}, {%0,%1,%2,%3};"
        : "+f"(d[0]), "+f"(d[1]), "+f"(d[2]), "+f"(d[3])
        : "r"(a[0]), "r"(a[1]), "r"(a[2]), "r"(a[3]), "r"(b[0]), "r"(b[1]));
}

__device__ __forceinline__ int pposu(int j) { return (j < 4) ? 2 * j : 2 * (j - 4) + 1; }

// ============================================================================
// K0a: transpose + u32-permute + fp16 convert of weights
// ============================================================================
__global__ __launch_bounds__(256) void transpose_fp16_k(const float* __restrict__ W,
                                                        uint32_t* __restrict__ Wth)
{
    __shared__ float t[32][33];
    int bx = blockIdx.x * 32, by = blockIdx.y * 32;
    int txx = threadIdx.x;
    for (int i = threadIdx.y; i < 32; i += 8)
        t[i][txx] = W[(size_t)(by + i) * EMBD + bx + txx];
    __syncthreads();
    if (txx < 16) {
        int j = txx & 7;
        int pos = (by >> 1) + (txx >> 3) * 8 + pposu(j);
        for (int i = threadIdx.y; i < 32; i += 8) {
            uint32_t u = packh2(t[2 * txx][i], t[2 * txx + 1][i]);
            Wth[(size_t)(bx + i) * EMBD_U + pos] = u;
        }
    }
}

// ============================================================================
// K0b: u32-permute + fp16 convert of x
// ============================================================================
__global__ __launch_bounds__(256) void perm_cvt_fp16_k(const float* __restrict__ src,
                                                       uint32_t* __restrict__ dst)
{
    size_t g16 = (size_t)blockIdx.x * 256 + threadIdx.x;
    size_t base = g16 * 16;
    float4 f0 = *(const float4*)&src[base];
    float4 f1 = *(const float4*)&src[base + 4];
    float4 f2 = *(const float4*)&src[base + 8];
    float4 f3 = *(const float4*)&src[base + 12];
    uint4 o0, o1;
    o0.x = packh2(f0.x, f0.y);
    o0.y = packh2(f2.x, f2.y);
    o0.z = packh2(f0.z, f0.w);
    o0.w = packh2(f2.z, f2.w);
    o1.x = packh2(f1.x, f1.y);
    o1.y = packh2(f3.x, f3.y);
    o1.z = packh2(f1.z, f1.w);
    o1.w = packh2(f3.z, f3.w);
    *(uint4*)&dst[g16 * 8] = o0;
    *(uint4*)&dst[g16 * 8 + 4] = o1;
}

// ============================================================================
// K0c: rope cos/sin tables: [t][i] for t in [0,4096), i in [0,1024)
// ============================================================================
__global__ __launch_bounds__(256) void rope_tab_k(float* __restrict__ cost,
                                                  float* __restrict__ sint)
{
    size_t idx = (size_t)blockIdx.x * 256 + threadIdx.x;
    int t = (int)(idx >> 10);
    int i = (int)(idx & 1023);
    float inv = powf(10000.0f, -(float)(2 * i) * (1.0f / 2048.0f));
    float ang = (float)t * inv;
    cost[idx] = cosf(ang);
    sint[idx] = sinf(ang);
}

// ============================================================================
// K1: fp16 mma.sync GEMM mainloop (shared), CTA 128x256x32, 3-stage pipeline
// ============================================================================
#define BM 128
#define BN 256
#define BK 32
#define BKU 16
#define BKP_U 24
#define NSTG 3
#define STG_U ((BM + BN) * BKP_U)
#define GEMM_SMEM_BYTES (NSTG * STG_U * 4)

__device__ __forceinline__ void load_stage_h(const uint32_t* __restrict__ A,
                                             const uint32_t* __restrict__ Bt,
                                             int brow, int bcol, int k0u,
                                             uint32_t sA, uint32_t sB, int tid)
{
#pragma unroll
    for (int it = 0; it < 2; it++) {
        int idx = tid + it * 256;
        int row = idx >> 2, c4 = idx & 3;
        cp16(sA + (row * BKP_U + c4 * 4) * 4,
             A + (size_t)(brow + row) * EMBD_U + k0u + c4 * 4);
    }
#pragma unroll
    for (int it = 0; it < 4; it++) {
        int idx = tid + it * 256;
        int row = idx >> 2, c4 = idx & 3;
        cp16(sB + (row * BKP_U + c4 * 4) * 4,
             Bt + (size_t)(bcol + row) * EMBD_U + k0u + c4 * 4);
    }
    asm volatile("cp.async.commit_group;" ::: "memory");
}

__device__ __forceinline__ void gemm_mainloop(
    const uint32_t* __restrict__ A, const uint32_t* __restrict__ Bt,
    uint32_t* dsm_u, float acc[4][8][4], int brow, int bcol,
    int tid, int wm, int wn, int lr, int lc)
{
    uint32_t sbase = smem_u32(dsm_u);
    uint32_t sA[NSTG], sB[NSTG];
#pragma unroll
    for (int s = 0; s < NSTG; s++) {
        sA[s] = sbase + s * STG_U * 4;
        sB[s] = sA[s] + BM * BKP_U * 4;
    }

    load_stage_h(A, Bt, brow, bcol, 0 * BKU, sA[0], sB[0], tid);
    load_stage_h(A, Bt, brow, bcol, 1 * BKU, sA[1], sB[1], tid);
    load_stage_h(A, Bt, brow, bcol, 2 * BKU, sA[2], sB[2], tid);

    const int NIT = EMBD / BK;
    for (int it = 0; it < NIT; it++) {
        if (it < NIT - 2)       asm volatile("cp.async.wait_group 2;" ::: "memory");
        else if (it == NIT - 2) asm volatile("cp.async.wait_group 1;" ::: "memory");
        else                    asm volatile("cp.async.wait_group 0;" ::: "memory");
        __syncthreads();

        int s = it % NSTG;
        const uint32_t* As = dsm_u + (size_t)s * STG_U;
        const uint32_t* Bs = As + BM * BKP_U;

#pragma unroll
        for (int kc = 0; kc < 2; kc++) {
            int off = kc * 8 + 2 * lc;
            uint32_t af[4][4], bf[8][2];
#pragma unroll
            for (int mt = 0; mt < 4; mt++) {
                int r = wm + mt * 16 + lr;
                uint2 a0 = *(const uint2*)&As[r * BKP_U + off];
                uint2 a1 = *(const uint2*)&As[(r + 8) * BKP_U + off];
                af[mt][0] = a0.x; af[mt][2] = a0.y;
                af[mt][1] = a1.x; af[mt][3] = a1.y;
            }
#pragma unroll
            for (int nt = 0; nt < 8; nt++) {
                int cN = wn + nt * 8 + lr;
                uint2 b = *(const uint2*)&Bs[cN * BKP_U + off];
                bf[nt][0] = b.x; bf[nt][1] = b.y;
            }
#pragma unroll
            for (int mt = 0; mt < 4; mt++)
#pragma unroll
                for (int nt = 0; nt < 8; nt++)
                    mma_f16(acc[mt][nt], af[mt], bf[nt]);
        }
        __syncthreads();

        if (it + NSTG < NIT)
            load_stage_h(A, Bt, brow, bcol, (it + NSTG) * BKU, sA[s], sB[s], tid);
    }
}

// final GEMM: fp32 output + bias
__global__ __launch_bounds__(256) void gemm_mma_k(
    const uint32_t* __restrict__ A, const uint32_t* __restrict__ Bt,
    const float* __restrict__ bias, float* __restrict__ C)
{
    extern __shared__ uint32_t dsm_u[];
    const int tid = threadIdx.x;
    const int wid = tid >> 5;
    const int lane = tid & 31;
    const int lr = lane >> 2, lc = lane & 3;
    const int wm = (wid >> 2) * 64, wn = (wid & 3) * 64;
    int brow = blockIdx.y * BM, bcol = blockIdx.x * BN;

    float acc[4][8][4];
#pragma unroll
    for (int mt = 0; mt < 4; mt++)
#pragma unroll
        for (int nt = 0; nt < 8; nt++)
#pragma unroll
            for (int r = 0; r < 4; r++) acc[mt][nt][r] = 0.f;

    gemm_mainloop(A, Bt, dsm_u, acc, brow, bcol, tid, wm, wn, lr, lc);

#pragma unroll
    for (int nt = 0; nt < 8; nt++) {
        int col = bcol + wn + nt * 8 + 2 * lc;
        float b0 = bias[col], b1 = bias[col + 1];
#pragma unroll
        for (int mt = 0; mt < 4; mt++) {
            int row = brow + wm + mt * 16 + lr;
            float2 v0 = make_float2(acc[mt][nt][0] + b0, acc[mt][nt][1] + b1);
            float2 v1 = make_float2(acc[mt][nt][2] + b0, acc[mt][nt][3] + b1);
            *(float2*)&C[(size_t)row * EMBD + col] = v0;
            *(float2*)&C[(size_t)(row + 8) * EMBD + col] = v1;
        }
    }
}

// QKV GEMM: fused bias + rope (z<2) + fp16 pack, writes qh/kh/vh
__global__ __launch_bounds__(256) void gemm_qkv_k(
    const uint32_t* __restrict__ A, const uint32_t* __restrict__ WtBase,
    const float* __restrict__ bq, const float* __restrict__ bk,
    const float* __restrict__ bv,
    uint32_t* __restrict__ qh, uint32_t* __restrict__ kh, uint32_t* __restrict__ vh,
    const float* __restrict__ cost, const float* __restrict__ sint)
{
    extern __shared__ uint32_t dsm_u[];
    const int tid = threadIdx.x;
    const int wid = tid >> 5;
    const int lane = tid & 31;
    const int lr = lane >> 2, lc = lane & 3;
    const int wm = (wid >> 2) * 64, wn = (wid & 3) * 64;
    int brow = blockIdx.y * BM, bcol = blockIdx.x * BN;

    int z = blockIdx.z;
    const uint32_t* Bt = WtBase + (size_t)z * EMBD * EMBD_U;
    const float* bias = (z == 0) ? bq : (z == 1) ? bk : bv;
    uint32_t* Ch = (z == 0) ? qh : (z == 1) ? kh : vh;
    bool dorope = (z < 2);

    float acc[4][8][4];
#pragma unroll
    for (int mt = 0; mt < 4; mt++)
#pragma unroll
        for (int nt = 0; nt < 8; nt++)
#pragma unroll
            for (int r = 0; r < 4; r++) acc[mt][nt][r] = 0.f;

    gemm_mainloop(A, Bt, dsm_u, acc, brow, bcol, tid, wm, wn, lr, lc);

#pragma unroll
    for (int nt = 0; nt < 8; nt++) {
        int col = bcol + wn + nt * 8 + 2 * lc;
        int pi = col >> 1;
        float b0 = bias[col], b1 = bias[col + 1];
#pragma unroll
        for (int mt = 0; mt < 4; mt++) {
#pragma unroll
            for (int h = 0; h < 2; h++) {
                int row = brow + wm + mt * 16 + lr + h * 8;
                float a0 = acc[mt][nt][2 * h + 0] + b0;
                float a1 = acc[mt][nt][2 * h + 1] + b1;
                if (dorope) {
                    int t = row & (SEQ - 1);
                    float c = cost[(size_t)t * 1024 + pi];
                    float s = sint[(size_t)t * 1024 + pi];
                    float r0 = a0 * c - a1 * s;
                    float r1 = a0 * s + a1 * c;
                    a0 = r0; a1 = r1;
                }
                Ch[(size_t)row * EMBD_U + pi] = packh2(a0, a1);
            }
        }
    }
}

// ============================================================================
// K2b: fp16 v -> fp16 transposed per segment (pairs along l)
// ============================================================================
__global__ __launch_bounds__(256) void vt_h_k(const uint32_t* __restrict__ vh,
                                              uint32_t* __restrict__ vth)
{
    __shared__ float t[32][68];
    int bhs = blockIdx.z;
    int p0 = blockIdx.x * 32;   // d-pair base (0 or 32)
    int l0 = blockIdx.y * 32;
    const uint32_t* seg = vh + ((size_t)bhs << 15);
    uint32_t* vtseg = vth + (size_t)bhs * DHEAD * SEGL_U;
    int txx = threadIdx.x, ty = threadIdx.y;
    for (int i = ty; i < 32; i += 8) {
        __half2 h = *(const __half2*)&seg[(size_t)(l0 + i) * 64 + p0 + txx];
        t[i][2 * txx] = __low2float(h);
        t[i][2 * txx + 1] = __high2float(h);
    }
    __syncthreads();
    int tid = ty * 32 + txx;
#pragma unroll
    for (int j = 0; j < 4; j++) {
        int flat = tid + j * 256;
        int d = flat >> 4, c = flat & 15;
        vtseg[(size_t)(2 * p0 + d) * SEGL_U + (l0 >> 1) + c] =
            packh2(t[2 * c][d], t[2 * c + 1][d]);
    }
}

// ============================================================================
// K2c: sk^T = elu1(fp16 k)^T fp16 per segment (pairs along l)
// ============================================================================
__global__ __launch_bounds__(256) void skt_h_k(const uint32_t* __restrict__ kh,
                                               uint32_t* __restrict__ skth)
{
    __shared__ float t[32][68];
    int bhs = blockIdx.z;
    int p0 = blockIdx.x * 32;
    int l0 = blockIdx.y * 32;
    const uint32_t* seg = kh + ((size_t)bhs << 15);
    uint32_t* sktseg = skth + (size_t)bhs * DHEAD * SEGL_U;
    int txx = threadIdx.x, ty = threadIdx.y;
    for (int i = ty; i < 32; i += 8) {
        __half2 h = *(const __half2*)&seg[(size_t)(l0 + i) * 64 + p0 + txx];
        t[i][2 * txx] = __low2float(h);
        t[i][2 * txx + 1] = __high2float(h);
    }
    __syncthreads();
    int tid = ty * 32 + txx;
#pragma unroll
    for (int j = 0; j < 4; j++) {
        int flat = tid + j * 256;
        int d = flat >> 4, c = flat & 15;
        sktseg[(size_t)(2 * p0 + d) * SEGL_U + (l0 >> 1) + c] =
            packh2(elu1(t[2 * c][d]), elu1(t[2 * c + 1][d]));
    }
}

// ============================================================================
// K2d: Zseg[bhs][d] = row-sum of skth
// ============================================================================
__global__ __launch_bounds__(256) void zsum_k(const uint32_t* __restrict__ skth,
                                              float* __restrict__ Zseg)
{
    int bhs = blockIdx.x;
    int tid = threadIdx.x;
    int d = tid >> 1;
    int half = tid & 1;
    const uint32_t* row = skth + (size_t)bhs * DHEAD * SEGL_U
                        + (size_t)d * SEGL_U + half * 128;
    float s = 0.f;
#pragma unroll 16
    for (int j = 0; j < 128; j++) {
        __half2 h = *(const __half2*)&row[j];
        s += __low2float(h) + __high2float(h);
    }
    s += __shfl_xor_sync(0xffffffffu, s, 1);
    if (half == 0) Zseg[bhs * DHEAD + d] = s;
}

// ============================================================================
// K3: FUSED flash attention: attnd = (1-g) * softmax(scale q k^T) v  (fp16 out)
// ============================================================================
#define SCP 68
#define FA_SMEM_U (4 * 128 * SCP + 4 * 128 + 4 * 128 + 3 * 128)
#define FA_SMEM_BYTES (FA_SMEM_U * 4)  // 144896

__global__ __launch_bounds__(256, 1) void fattn_k(
    const uint32_t* __restrict__ qh, const uint32_t* __restrict__ kh,
    const uint32_t* __restrict__ vth, const float* __restrict__ beta,
    uint32_t* __restrict__ attnd)
{
    extern __shared__ uint32_t smu[];
    uint32_t* qs = smu;
    uint32_t* ks = smu + 128 * SCP;
    uint32_t* Ps = smu + 2 * 128 * SCP;
    uint32_t* vs = smu + 3 * 128 * SCP;
    float* pmax = (float*)(smu + 4 * 128 * SCP);
    float* psum = pmax + 4 * 128;
    float* m_s = psum + 4 * 128;
    float* f_s = m_s + 128;
    float* ssum_s = f_s + 128;

    uint32_t sq = smem_u32(qs);
    uint32_t sk = smem_u32(ks);
    uint32_t sv = smem_u32(vs);

    const float scale = 0.08838834764831845f;
    const int tid = threadIdx.x;
    const int wid = tid >> 5;
    const int lane = tid & 31;
    const int lr = lane >> 2;
    const int lc = lane & 3;
    const int wm = (wid >> 2) * 64;
    const int wn = (wid & 3) * 32;
    const int wci = wid & 3;

    int bhs = blockIdx.y;
    int l0 = blockIdx.x * 128;
    size_t segbase_u = ((size_t)bhs) << 15;
    const uint32_t* qseg = qh + segbase_u;
    const uint32_t* kseg = kh + segbase_u;
    const uint32_t* vtseg = vth + (size_t)bhs * DHEAD * SEGL_U;
    float gm1 = 1.0f - 1.0f / (1.0f + expf(-beta[0]));

#pragma unroll
    for (int it = 0; it < 8; it++) {
        int idx = tid + it * 256;
        int row = idx >> 4, c4 = idx & 15;
        cp16(sq + (row * SCP + c4 * 4) * 4,
             qseg + (size_t)(l0 + row) * 64 + c4 * 4);
    }
    asm volatile("cp.async.commit_group;" ::: "memory");

    if (tid < 128) { m_s[tid] = -1e30f; ssum_s[tid] = 0.f; }

    float Oacc[4][4][4];
#pragma unroll
    for (int mt = 0; mt < 4; mt++)
#pragma unroll
        for (int nt = 0; nt < 4; nt++)
#pragma unroll
            for (int r = 0; r < 4; r++) Oacc[mt][nt][r] = 0.f;

    for (int kt = 0; kt < 4; kt++) {
#pragma unroll
        for (int it = 0; it < 8; it++) {
            int idx = tid + it * 256;
            int row = idx >> 4, c4 = idx & 15;
            cp16(sk + (row * SCP + c4 * 4) * 4,
                 kseg + (size_t)(kt * 128 + row) * 64 + c4 * 4);
        }
#pragma unroll
        for (int it = 0; it < 8; it++) {
            int idx = tid + it * 256;
            int row = idx >> 4, c4 = idx & 15;
            cp16(sv + (row * SCP + c4 * 4) * 4,
                 vtseg + (size_t)row * SEGL_U + kt * 64 + c4 * 4);
        }
        asm volatile("cp.async.commit_group;" ::: "memory");
        asm volatile("cp.async.wait_group 0;" ::: "memory");
        __syncthreads();

        float Sacc[4][4][4];
#pragma unroll
        for (int mt = 0; mt < 4; mt++)
#pragma unroll
            for (int nt = 0; nt < 4; nt++)
#pragma unroll
                for (int r = 0; r < 4; r++) Sacc[mt][nt][r] = 0.f;

#pragma unroll
        for (int kb = 0; kb < 64; kb += 8) {
            uint32_t af[4][4], bf[4][2];
#pragma unroll
            for (int mt = 0; mt < 4; mt++) {
                int r = wm + mt * 16 + lr;
                af[mt][0] = qs[r * SCP + kb + lc];
                af[mt][1] = qs[(r + 8) * SCP + kb + lc];
                af[mt][2] = qs[r * SCP + kb + lc + 4];
                af[mt][3] = qs[(r + 8) * SCP + kb + lc + 4];
            }
#pragma unroll
            for (int nt = 0; nt < 4; nt++) {
                int cN = wn + nt * 8 + lr;
                bf[nt][0] = ks[cN * SCP + kb + lc];
                bf[nt][1] = ks[cN * SCP + kb + lc + 4];
            }
#pragma unroll
            for (int mt = 0; mt < 4; mt++)
#pragma unroll
                for (int nt = 0; nt < 4; nt++)
                    mma_f16(Sacc[mt][nt], af[mt], bf[nt]);
        }
#pragma unroll
        for (int mt = 0; mt < 4; mt++)
#pragma unroll
            for (int nt = 0; nt < 4; nt++)
#pragma unroll
                for (int r = 0; r < 4; r++) Sacc[mt][nt][r] *= scale;

#pragma unroll
        for (int mt = 0; mt < 4; mt++) {
#pragma unroll
            for (int h = 0; h < 2; h++) {
                float mv = -1e30f;
#pragma unroll
                for (int nt = 0; nt < 4; nt++) {
                    mv = fmaxf(mv, Sacc[mt][nt][2 * h]);
                    mv = fmaxf(mv, Sacc[mt][nt][2 * h + 1]);
                }
                mv = fmaxf(mv, __shfl_xor_sync(0xffffffffu, mv, 1));
                mv = fmaxf(mv, __shfl_xor_sync(0xffffffffu, mv, 2));
                if (lc == 0) pmax[wci * 128 + wm + mt * 16 + lr + h * 8] = mv;
            }
        }
        __syncthreads();

        if (tid < 128) {
            float mo = m_s[tid];
            float nm = fmaxf(fmaxf(pmax[tid], pmax[128 + tid]),
                             fmaxf(pmax[256 + tid], pmax[384 + tid]));
            float mn = fmaxf(mo, nm);
            float f = expf(mo - mn);
            m_s[tid] = mn;
            f_s[tid] = f;
            ssum_s[tid] *= f;
        }
        __syncthreads();

#pragma unroll
        for (int mt = 0; mt < 4; mt++) {
#pragma unroll
            for (int h = 0; h < 2; h++) {
                int row = wm + mt * 16 + lr + h * 8;
                float m = m_s[row];
                float f = f_s[row];
                float rsum = 0.f;
#pragma unroll
                for (int nt = 0; nt < 4; nt++) {
                    float p0 = expf(Sacc[mt][nt][2 * h] - m);
                    float p1 = expf(Sacc[mt][nt][2 * h + 1] - m);
                    rsum += p0 + p1;
                    Ps[row * SCP + (wn >> 1) + nt * 4 + lc] = packh2(p0, p1);
                    Oacc[mt][nt][2 * h] *= f;
                    Oacc[mt][nt][2 * h + 1] *= f;
                }
                rsum += __shfl_xor_sync(0xffffffffu, rsum, 1);
                rsum += __shfl_xor_sync(0xffffffffu, rsum, 2);
                if (lc == 0) psum[wci * 128 + row] = rsum;
            }
        }
        __syncthreads();

        if (tid < 128)
            ssum_s[tid] += psum[tid] + psum[128 + tid] + psum[256 + tid] + psum[384 + tid];

#pragma unroll
        for (int kb = 0; kb < 64; kb += 8) {
            uint32_t af[4][4], bf[4][2];
#pragma unroll
            for (int mt = 0; mt < 4; mt++) {
                int r = wm + mt * 16 + lr;
                af[mt][0] = Ps[r * SCP + kb + lc];
                af[mt][1] = Ps[(r + 8) * SCP + kb + lc];
                af[mt][2] = Ps[r * SCP + kb + lc + 4];
                af[mt][3] = Ps[(r + 8) * SCP + kb + lc + 4];
            }
#pragma unroll
            for (int nt = 0; nt < 4; nt++) {
                int cN = wn + nt * 8 + lr;
                bf[nt][0] = vs[cN * SCP + kb + lc];
                bf[nt][1] = vs[cN * SCP + kb + lc + 4];
            }
#pragma unroll
            for (int mt = 0; mt < 4; mt++)
#pragma unroll
                for (int nt = 0; nt < 4; nt++)
                    mma_f16(Oacc[mt][nt], af[mt], bf[nt]);
        }
        __syncthreads();
    }

#pragma unroll
    for (int nt = 0; nt < 4; nt++) {
        int col = wn + nt * 8 + 2 * lc;
#pragma unroll
        for (int mt = 0; mt < 4; mt++) {
#pragma unroll
            for (int h = 0; h < 2; h++) {
                int row = wm + mt * 16 + lr + h * 8;
                float sc = gm1 / ssum_s[row];
                attnd[segbase_u + (size_t)(l0 + row) * 64 + (col >> 1)] =
                    packh2(Oacc[mt][nt][2 * h] * sc, Oacc[mt][nt][2 * h + 1] * sc);
            }
        }
    }
}

// ============================================================================
// K6: tensorized outer products: memT[e][d] = sum_l v[l][e] * sk[l][d]
// ============================================================================
#define PVP 36
#define OUTER_SMEM_BYTES (2 * 2 * 128 * PVP * 4)

__global__ __launch_bounds__(256) void outer_mma_k(
    const uint32_t* __restrict__ vth, const uint32_t* __restrict__ skth,
    float* __restrict__ memsegT)
{
    extern __shared__ uint32_t smu[];
    uint32_t* Ash = smu;
    uint32_t* Bsh = smu + 2 * 128 * PVP;
    uint32_t sAu = smem_u32(Ash);
    uint32_t sBu = smem_u32(Bsh);

    const int tid = threadIdx.x;
    const int wid = tid >> 5;
    const int lane = tid & 31;
    const int lr = lane >> 2;
    const int lc = lane & 3;
    const int wm = (wid >> 2) * 64;
    const int wn = (wid & 3) * 32;

    int bhs = blockIdx.x;
    const uint32_t* vtseg = vth + (size_t)bhs * DHEAD * SEGL_U;
    const uint32_t* sktseg = skth + (size_t)bhs * DHEAD * SEGL_U;

    float acc[4][4][4];
#pragma unroll
    for (int mt = 0; mt < 4; mt++)
#pragma unroll
        for (int nt = 0; nt < 4; nt++)
#pragma unroll
            for (int r = 0; r < 4; r++) acc[mt][nt][r] = 0.f;

    auto load_st = [&](int k0u, uint32_t sA, uint32_t sB) {
#pragma unroll
        for (int it = 0; it < 4; it++) {
            int idx = tid + it * 256;
            int row = idx >> 3, c4 = idx & 7;
            cp16(sA + (row * PVP + c4 * 4) * 4,
                 vtseg + (size_t)row * SEGL_U + k0u + c4 * 4);
        }
#pragma unroll
        for (int it = 0; it < 4; it++) {
            int idx = tid + it * 256;
            int row = idx >> 3, c4 = idx & 7;
            cp16(sB + (row * PVP + c4 * 4) * 4,
                 sktseg + (size_t)row * SEGL_U + k0u + c4 * 4);
        }
        asm volatile("cp.async.commit_group;" ::: "memory");
    };

    load_st(0, sAu, sBu);
    load_st(32, sAu + 128 * PVP * 4, sBu + 128 * PVP * 4);

    const int NIT = SEGL_U / 32;
    for (int it = 0; it < NIT; it++) {
        int s = it & 1;
        if (it == NIT - 1) asm volatile("cp.async.wait_group 0;" ::: "memory");
        else               asm volatile("cp.async.wait_group 1;" ::: "memory");
        __syncthreads();

        const uint32_t* As = Ash + s * 128 * PVP;
        const uint32_t* Bs = Bsh + s * 128 * PVP;
#pragma unroll
        for (int kb = 0; kb < 32; kb += 8) {
            uint32_t af[4][4], bf[4][2];
#pragma unroll
            for (int mt = 0; mt < 4; mt++) {
                int r = wm + mt * 16 + lr;
                af[mt][0] = As[r * PVP + kb + lc];
                af[mt][1] = As[(r + 8) * PVP + kb + lc];
                af[mt][2] = As[r * PVP + kb + lc + 4];
                af[mt][3] = As[(r + 8) * PVP + kb + lc + 4];
            }
#pragma unroll
            for (int nt = 0; nt < 4; nt++) {
                int cN = wn + nt * 8 + lr;
                bf[nt][0] = Bs[cN * PVP + kb + lc];
                bf[nt][1] = Bs[cN * PVP + kb + lc + 4];
            }
#pragma unroll
            for (int mt = 0; mt < 4; mt++)
#pragma unroll
                for (int nt = 0; nt < 4; nt++)
                    mma_f16(acc[mt][nt], af[mt], bf[nt]);
        }
        __syncthreads();
        if (it + 2 < NIT)
            load_st((it + 2) * 32, sAu + s * 128 * PVP * 4, sBu + s * 128 * PVP * 4);
    }

    float* memb = memsegT + (size_t)bhs * DHEAD * DHEAD;
#pragma unroll
    for (int nt = 0; nt < 4; nt++) {
        int col = wn + nt * 8 + 2 * lc;
#pragma unroll
        for (int mt = 0; mt < 4; mt++) {
            int row = wm + mt * 16 + lr;
            *(float2*)&memb[(size_t)row * DHEAD + col] =
                make_float2(acc[mt][nt][0], acc[mt][nt][1]);
            *(float2*)&memb[(size_t)(row + 8) * DHEAD + col] =
                make_float2(acc[mt][nt][2], acc[mt][nt][3]);
        }
    }
}

// ============================================================================
// K7: in-place exclusive prefix over the 8 segments
// ============================================================================
__global__ __launch_bounds__(256) void prefix_mem_k(float* __restrict__ memseg)
{
    size_t idx = (size_t)blockIdx.x * 256 + threadIdx.x;
    int bh = (int)(idx >> 14);
    int off = (int)(idx & 16383);
    size_t base = ((size_t)bh * NSEG) * 16384 + off;
    float run = 0.f;
#pragma unroll
    for (int s = 0; s < NSEG; s++) {
        float t = memseg[base + (size_t)s * 16384];
        memseg[base + (size_t)s * 16384] = run;
        run += t;
    }
}

__global__ __launch_bounds__(256) void prefix_Z_k(float* __restrict__ Zseg)
{
    int idx = blockIdx.x * 256 + threadIdx.x;
    int bh = idx >> 7;
    int d = idx & 127;
    int base = bh * NSEG * DHEAD + d;
    float run = 0.f;
#pragma unroll
    for (int s = 0; s < NSEG; s++) {
        float t = Zseg[base + s * DHEAD];
        Zseg[base + s * DHEAD] = run;
        run += t;
    }
}

// ============================================================================
// K8: tensorized A_mem (tf32, memT + fp16 q) + fused combine + fp16-perm out
// ============================================================================
#define AMP 136
#define AMEM_SMEM_BYTES ((2 * 128 * AMP + 256) * 4)

__global__ __launch_bounds__(256) void amem_mma_k(
    const uint32_t* __restrict__ qh, const float* __restrict__ memsegT,
    const float* __restrict__ Zseg, const float* __restrict__ beta,
    const uint32_t* __restrict__ attnd, uint32_t* __restrict__ attnh)
{
    extern __shared__ uint32_t smu[];
    uint32_t* qs = smu;                  // [128][AMP] tf32(elu1(q)) rows l
    uint32_t* ms = smu + 128 * AMP;      // [128][AMP] tf32(memT) rows e
    float* rowsumS = (float*)(smu + 2 * 128 * AMP);
    float* Zs = rowsumS + 128;
    uint32_t smb = smem_u32(ms);

    const int tid = threadIdx.x;
    const int wid = tid >> 5;
    const int lane = tid & 31;
    const int lr = lane >> 2;
    const int lc = lane & 3;
    const int wm = (wid >> 2) * 64;
    const int wn = (wid & 3) * 32;

    int bhs = blockIdx.y;
    int l0 = blockIdx.x * 128;
    size_t segbase_u = ((size_t)bhs) << 15;
    const uint32_t* qhseg = qh + segbase_u;
    const float* memb = memsegT + (size_t)bhs * DHEAD * DHEAD;
    float g = 1.0f / (1.0f + expf(-beta[0]));

    // stage mem via cp.async
#pragma unroll
    for (int it = 0; it < 16; it++) {
        int idx = tid + it * 256;
        int row = idx >> 5, c4 = idx & 31;
        cp16(smb + (row * AMP + c4 * 4) * 4,
             memb + (size_t)row * DHEAD + c4 * 4);
    }
    asm volatile("cp.async.commit_group;" ::: "memory");

    // direct-convert q: fp16 -> elu1 -> tf32 into qs
#pragma unroll
    for (int it = 0; it < 32; it++) {
        int flat = it * 256 + tid;
        int row = flat >> 6, col = flat & 63;
        __half2 h = *(const __half2*)&qhseg[(size_t)(l0 + row) * 64 + col];
        qs[row * AMP + 2 * col]     = f2tf32(elu1(__low2float(h)));
        qs[row * AMP + 2 * col + 1] = f2tf32(elu1(__high2float(h)));
    }
    asm volatile("cp.async.wait_group 0;" ::: "memory");
    __syncthreads();

    // rowsum (reads back tf32-rounded values) + mem tf32 convert
    {
        int r = tid >> 1;
        int half = (tid & 1) * 64;
        float partial = 0.f;
#pragma unroll 16
        for (int j = 0; j < 64; j++)
            partial += __uint_as_float(qs[r * AMP + half + j]);
        partial += __shfl_xor_sync(0xffffffffu, partial, 1);
        if ((tid & 1) == 0) rowsumS[r] = partial;
#pragma unroll 16
        for (int j = 0; j < 64; j++) {
            uint32_t* p = &ms[r * AMP + half + j];
            *p = f2tf32(__uint_as_float(*p));
        }
    }
    if (tid < 128) Zs[tid] = Zseg[bhs * DHEAD + tid];
    __syncthreads();

    float acc[4][4][4];
#pragma unroll
    for (int mt = 0; mt < 4; mt++)
#pragma unroll
        for (int nt = 0; nt < 4; nt++)
#pragma unroll
            for (int r = 0; r < 4; r++) acc[mt][nt][r] = 0.f;

#pragma unroll
    for (int kb = 0; kb < 128; kb += 8) {
        uint32_t af[4][4], bf[4][2];
#pragma unroll
        for (int mt = 0; mt < 4; mt++) {
            int r = wm + mt * 16 + lr;
            af[mt][0] = qs[r * AMP + kb + lc];
            af[mt][1] = qs[(r + 8) * AMP + kb + lc];
            af[mt][2] = qs[r * AMP + kb + lc + 4];
            af[mt][3] = qs[(r + 8) * AMP + kb + lc + 4];
        }
#pragma unroll
        for (int nt = 0; nt < 4; nt++) {
            int cN = wn + nt * 8 + lr;
            bf[nt][0] = ms[cN * AMP + kb + lc];
            bf[nt][1] = ms[cN * AMP + kb + lc + 4];
        }
#pragma unroll
        for (int mt = 0; mt < 4; mt++)
#pragma unroll
            for (int nt = 0; nt < 4; nt++)
                mma_tf32(acc[mt][nt], af[mt], bf[nt]);
    }

#pragma unroll
    for (int nt = 0; nt < 4; nt++) {
        int col = wn + nt * 8 + 2 * lc;
        int j = (col & 15) >> 1;
        int pos = (col >> 4) * 8 + pposu(j);
        float Z0 = Zs[col], Z1 = Zs[col + 1];
#pragma unroll
        for (int mt = 0; mt < 4; mt++) {
#pragma unroll
            for (int h = 0; h < 2; h++) {
                int rloc = wm + mt * 16 + lr + h * 8;
                int row = l0 + rloc;
                float rs = rowsumS[rloc];
                __half2 ath = *(const __half2*)&attnd[segbase_u + (size_t)row * 64 + (col >> 1)];
                float a0 = g * acc[mt][nt][2 * h + 0] / (rs * Z0 + 1e-6f) + __low2float(ath);
                float a1 = g * acc[mt][nt][2 * h + 1] / (rs * Z1 + 1e-6f) + __high2float(ath);
                attnh[segbase_u + (size_t)row * (DHEAD / 2) + pos] = packh2(a0, a1);
            }
        }
    }
}

// ============================================================================
// Host launch
// ============================================================================
extern "C" void kernel_launch(void* const* d_in, const int* in_sizes, int n_in,
                              void* d_out, int out_size)
{
    (void)in_sizes; (void)n_in; (void)out_size;
    const float* x    = (const float*)d_in[0];
    const float* Wq   = (const float*)d_in[1];
    const float* bq   = (const float*)d_in[2];
    const float* Wk   = (const float*)d_in[3];
    const float* bk   = (const float*)d_in[4];
    const float* Wv   = (const float*)d_in[5];
    const float* bv   = (const float*)d_in[6];
    const float* Wo   = (const float*)d_in[7];
    const float* bo   = (const float*)d_in[8];
    const float* beta = (const float*)d_in[9];
    float* out = (float*)d_out;

    static float *pmemsegT = nullptr, *pZseg = nullptr, *pcost = nullptr, *psint = nullptr;
    static uint32_t *pWth = nullptr, *pxh = nullptr, *pattnh = nullptr,
                    *pqh = nullptr, *pkh = nullptr, *pvh = nullptr,
                    *pvth = nullptr, *pskth = nullptr, *pattnd = nullptr;
    if (!pWth) {
        cudaGetSymbolAddress((void**)&pattnd, g_attnd);
        cudaGetSymbolAddress((void**)&pmemsegT, g_memsegT);
        cudaGetSymbolAddress((void**)&pZseg, g_Zseg);
        cudaGetSymbolAddress((void**)&pWth, g_Wth);
        cudaGetSymbolAddress((void**)&pxh, g_xh);
        cudaGetSymbolAddress((void**)&pattnh, g_attnh);
        cudaGetSymbolAddress((void**)&pqh, g_qh);
        cudaGetSymbolAddress((void**)&pkh, g_kh);
        cudaGetSymbolAddress((void**)&pvh, g_vh);
        cudaGetSymbolAddress((void**)&pvth, g_vth);
        cudaGetSymbolAddress((void**)&pskth, g_skth);
        cudaGetSymbolAddress((void**)&pcost, g_cost);
        cudaGetSymbolAddress((void**)&psint, g_sint);
        cudaFuncSetAttribute(gemm_mma_k, cudaFuncAttributeMaxDynamicSharedMemorySize,
                             GEMM_SMEM_BYTES);
        cudaFuncSetAttribute(gemm_qkv_k, cudaFuncAttributeMaxDynamicSharedMemorySize,
                             GEMM_SMEM_BYTES);
        cudaFuncSetAttribute(fattn_k, cudaFuncAttributeMaxDynamicSharedMemorySize,
                             FA_SMEM_BYTES);
        cudaFuncSetAttribute(outer_mma_k, cudaFuncAttributeMaxDynamicSharedMemorySize,
                             OUTER_SMEM_BYTES);
        cudaFuncSetAttribute(amem_mma_k, cudaFuncAttributeMaxDynamicSharedMemorySize,
                             AMEM_SMEM_BYTES);
    }

    const size_t WSZ_U = (size_t)EMBD * EMBD_U;
    dim3 tgrid(EMBD / 32, EMBD / 32);
    dim3 tblk(32, 8);
    transpose_fp16_k<<<tgrid, tblk>>>(Wq, pWth + 0 * WSZ_U);
    transpose_fp16_k<<<tgrid, tblk>>>(Wk, pWth + 1 * WSZ_U);
    transpose_fp16_k<<<tgrid, tblk>>>(Wv, pWth + 2 * WSZ_U);
    transpose_fp16_k<<<tgrid, tblk>>>(Wo, pWth + 3 * WSZ_U);

    perm_cvt_fp16_k<<<(int)(TOTAL / 16 / 256), 256>>>(x, pxh);
    rope_tab_k<<<(SEQ * 1024) / 256, 256>>>(pcost, psint);

    // QKV GEMM with fused rope + fp16 pack
    dim3 qkvgrid(EMBD / BN, MTOK / BM, 3);
    gemm_qkv_k<<<qkvgrid, 256, GEMM_SMEM_BYTES>>>(pxh, pWth, bq, bk, bv,
                                                  pqh, pkh, pvh, pcost, psint);

    vt_h_k<<<dim3(2, SEGL / 32, NBH * NSEG), tblk>>>(pvh, pvth);
    skt_h_k<<<dim3(2, SEGL / 32, NBH * NSEG), tblk>>>(pkh, pskth);

    // parallel linear-memory path (tensorized)
    outer_mma_k<<<NBH * NSEG, 256, OUTER_SMEM_BYTES>>>(pvth, pskth, pmemsegT);
    zsum_k<<<NBH * NSEG, 256>>>(pskth, pZseg);
    prefix_mem_k<<<(NBH * 16384) / 256, 256>>>(pmemsegT);
    prefix_Z_k<<<(NBH * DHEAD) / 256, 256>>>(pZseg);

    // fused flash attention (fp16 output)
    fattn_k<<<dim3(SEGL / 128, NBH * NSEG), 256, FA_SMEM_BYTES>>>(
        pqh, pkh, pvth, beta, pattnd);

    // tensorized A_mem + combine + fp16 perm-cvt fused
    amem_mma_k<<<dim3(SEGL / 128, NBH * NSEG), 256, AMEM_SMEM_BYTES>>>(
        pqh, pmemsegT, pZseg, beta, pattnd, pattnh);

    gemm_mma_k<<<dim3(EMBD / BN, MTOK / BM), 256, GEMM_SMEM_BYTES>>>(
        pattnh, pWth + 3 * WSZ_U, bo, out);
}

// round 14
// speedup vs baseline: 5.6782x; 1.0200x over previous
#include <cuda_runtime.h>
#include <cuda_fp16.h>
#include <math.h>
#include <stdint.h>

// Problem constants
#define SEQ   4096
#define EMBD  2048
#define NB    4
#define NHEAD 16
#define DHEAD 128
#define NSEG  8
#define SEGL  512
#define NBH   (NB * NHEAD)          // 64
#define MTOK  (NB * SEQ)            // 16384
#define TOTAL ((size_t)MTOK * EMBD) // 33554432
#define EMBD_U (EMBD / 2)           // 1024 u32 per row
#define SEGL_U (SEGL / 2)           // 256

// -------- device scratch ----------------------------------------------------
__device__ float g_memsegT[(size_t)NBH * NSEG * DHEAD * DHEAD]; // mem^T [e][d]
__device__ float g_Zseg[NBH * NSEG * DHEAD];
__device__ uint32_t g_Wth[(size_t)4 * EMBD * EMBD_U]; // transposed+permuted fp16
__device__ uint32_t g_xh[TOTAL / 2];                  // permuted fp16 x
__device__ uint32_t g_attnh[TOTAL / 2];               // permuted fp16 attn
__device__ uint32_t g_qh[TOTAL / 2];                  // fp16 q (pairs along d, roped)
__device__ uint32_t g_kh[TOTAL / 2];                  // fp16 k (pairs along d, roped)
__device__ uint32_t g_vh[TOTAL / 2];                  // fp16 v (pairs along d)
__device__ uint32_t g_vth[(size_t)NBH * NSEG * DHEAD * SEGL_U]; // fp16 v^T
__device__ uint32_t g_skth[(size_t)NBH * NSEG * DHEAD * SEGL_U]; // fp16 sk^T
__device__ float g_cost[(size_t)SEQ * 1024];          // rope cos table
__device__ float g_sint[(size_t)SEQ * 1024];          // rope sin table

__device__ __forceinline__ float elu1(float x) {
    return (x > 0.f) ? (x + 1.f) : expf(x);
}

__device__ __forceinline__ uint32_t smem_u32(const void* p) {
    uint32_t a;
    asm("{ .reg .u64 t; cvta.to.shared.u64 t, %1; cvt.u32.u64 %0, t; }"
        : "=r"(a) : "l"(p));
    return a;
}

__device__ __forceinline__ void cp16(uint32_t saddr, const void* g) {
    asm volatile("cp.async.cg.shared.global [%0], [%1], 16;" :: "r"(saddr), "l"(g));
}

__device__ __forceinline__ uint32_t f2tf32(float x) {
    uint32_t u;
    asm("cvt.rna.tf32.f32 %0, %1;" : "=r"(u) : "f"(x));
    return u;
}

__device__ __forceinline__ uint32_t packh2(float lo, float hi) {
    __half2 h = __floats2half2_rn(lo, hi);
    return *(uint32_t*)&h;
}

__device__ __forceinline__ void mma_tf32(float* d, const uint32_t* a, const uint32_t* b) {
    asm volatile(
        "mma.sync.aligned.m16n8k8.row.col.f32.tf32.tf32.f32 "
        "{%0,%1,%2,%3}, {%4,%5,%6,%7}, {%8,%9}, {%0,%1,%2,%3};"
        : "+f"(d[0]), "+f"(d[1]), "+f"(d[2]), "+f"(d[3])
        : "r"(a[0]), "r"(a[1]), "r"(a[2]), "r"(a[3]), "r"(b[0]), "r"(b[1]));
}

__device__ __forceinline__ void mma_f16(float* d, const uint32_t* a, const uint32_t* b) {
    asm volatile(
        "mma.sync.aligned.m16n8k16.row.col.f32.f16.f16.f32 "
        "{%0,%1,%2,%3}, {%4,%5,%6,%7}, {%8,%9}, {%0,%1,%2,%3};"
        : "+f"(d[0]), "+f"(d[1]), "+f"(d[2]), "+f"(d[3])
        : "r"(a[0]), "r"(a[1]), "r"(a[2]), "r"(a[3]), "r"(b[0]), "r"(b[1]));
}

__device__ __forceinline__ int pposu(int j) { return (j < 4) ? 2 * j : 2 * (j - 4) + 1; }

// ============================================================================
// K0a: transpose + u32-permute + fp16 convert of weights
// ============================================================================
__global__ __launch_bounds__(256) void transpose_fp16_k(const float* __restrict__ W,
                                                        uint32_t* __restrict__ Wth)
{
    __shared__ float t[32][33];
    int bx = blockIdx.x * 32, by = blockIdx.y * 32;
    int txx = threadIdx.x;
    for (int i = threadIdx.y; i < 32; i += 8)
        t[i][txx] = W[(size_t)(by + i) * EMBD + bx + txx];
    __syncthreads();
    if (txx < 16) {
        int j = txx & 7;
        int pos = (by >> 1) + (txx >> 3) * 8 + pposu(j);
        for (int i = threadIdx.y; i < 32; i += 8) {
            uint32_t u = packh2(t[2 * txx][i], t[2 * txx + 1][i]);
            Wth[(size_t)(bx + i) * EMBD_U + pos] = u;
        }
    }
}

// ============================================================================
// K0b: u32-permute + fp16 convert of x
// ============================================================================
__global__ __launch_bounds__(256) void perm_cvt_fp16_k(const float* __restrict__ src,
                                                       uint32_t* __restrict__ dst)
{
    size_t g16 = (size_t)blockIdx.x * 256 + threadIdx.x;
    size_t base = g16 * 16;
    float4 f0 = *(const float4*)&src[base];
    float4 f1 = *(const float4*)&src[base + 4];
    float4 f2 = *(const float4*)&src[base + 8];
    float4 f3 = *(const float4*)&src[base + 12];
    uint4 o0, o1;
    o0.x = packh2(f0.x, f0.y);
    o0.y = packh2(f2.x, f2.y);
    o0.z = packh2(f0.z, f0.w);
    o0.w = packh2(f2.z, f2.w);
    o1.x = packh2(f1.x, f1.y);
    o1.y = packh2(f3.x, f3.y);
    o1.z = packh2(f1.z, f1.w);
    o1.w = packh2(f3.z, f3.w);
    *(uint4*)&dst[g16 * 8] = o0;
    *(uint4*)&dst[g16 * 8 + 4] = o1;
}

// ============================================================================
// K0c: rope cos/sin tables
// ============================================================================
__global__ __launch_bounds__(256) void rope_tab_k(float* __restrict__ cost,
                                                  float* __restrict__ sint)
{
    size_t idx = (size_t)blockIdx.x * 256 + threadIdx.x;
    int t = (int)(idx >> 10);
    int i = (int)(idx & 1023);
    float inv = powf(10000.0f, -(float)(2 * i) * (1.0f / 2048.0f));
    float ang = (float)t * inv;
    cost[idx] = cosf(ang);
    sint[idx] = sinf(ang);
}

// ============================================================================
// K1: fp16 mma.sync GEMM mainloop (shared), CTA 128x256x32, 3-stage pipeline
// ============================================================================
#define BM 128
#define BN 256
#define BK 32
#define BKU 16
#define BKP_U 24
#define NSTG 3
#define STG_U ((BM + BN) * BKP_U)
#define GEMM_SMEM_BYTES (NSTG * STG_U * 4)

__device__ __forceinline__ void load_stage_h(const uint32_t* __restrict__ A,
                                             const uint32_t* __restrict__ Bt,
                                             int brow, int bcol, int k0u,
                                             uint32_t sA, uint32_t sB, int tid)
{
#pragma unroll
    for (int it = 0; it < 2; it++) {
        int idx = tid + it * 256;
        int row = idx >> 2, c4 = idx & 3;
        cp16(sA + (row * BKP_U + c4 * 4) * 4,
             A + (size_t)(brow + row) * EMBD_U + k0u + c4 * 4);
    }
#pragma unroll
    for (int it = 0; it < 4; it++) {
        int idx = tid + it * 256;
        int row = idx >> 2, c4 = idx & 3;
        cp16(sB + (row * BKP_U + c4 * 4) * 4,
             Bt + (size_t)(bcol + row) * EMBD_U + k0u + c4 * 4);
    }
    asm volatile("cp.async.commit_group;" ::: "memory");
}

__device__ __forceinline__ void gemm_mainloop(
    const uint32_t* __restrict__ A, const uint32_t* __restrict__ Bt,
    uint32_t* dsm_u, float acc[4][8][4], int brow, int bcol,
    int tid, int wm, int wn, int lr, int lc)
{
    uint32_t sbase = smem_u32(dsm_u);
    uint32_t sA[NSTG], sB[NSTG];
#pragma unroll
    for (int s = 0; s < NSTG; s++) {
        sA[s] = sbase + s * STG_U * 4;
        sB[s] = sA[s] + BM * BKP_U * 4;
    }

    load_stage_h(A, Bt, brow, bcol, 0 * BKU, sA[0], sB[0], tid);
    load_stage_h(A, Bt, brow, bcol, 1 * BKU, sA[1], sB[1], tid);
    load_stage_h(A, Bt, brow, bcol, 2 * BKU, sA[2], sB[2], tid);

    const int NIT = EMBD / BK;
    for (int it = 0; it < NIT; it++) {
        if (it < NIT - 2)       asm volatile("cp.async.wait_group 2;" ::: "memory");
        else if (it == NIT - 2) asm volatile("cp.async.wait_group 1;" ::: "memory");
        else                    asm volatile("cp.async.wait_group 0;" ::: "memory");
        __syncthreads();

        int s = it % NSTG;
        const uint32_t* As = dsm_u + (size_t)s * STG_U;
        const uint32_t* Bs = As + BM * BKP_U;

#pragma unroll
        for (int kc = 0; kc < 2; kc++) {
            int off = kc * 8 + 2 * lc;
            uint32_t af[4][4], bf[8][2];
#pragma unroll
            for (int mt = 0; mt < 4; mt++) {
                int r = wm + mt * 16 + lr;
                uint2 a0 = *(const uint2*)&As[r * BKP_U + off];
                uint2 a1 = *(const uint2*)&As[(r + 8) * BKP_U + off];
                af[mt][0] = a0.x; af[mt][2] = a0.y;
                af[mt][1] = a1.x; af[mt][3] = a1.y;
            }
#pragma unroll
            for (int nt = 0; nt < 8; nt++) {
                int cN = wn + nt * 8 + lr;
                uint2 b = *(const uint2*)&Bs[cN * BKP_U + off];
                bf[nt][0] = b.x; bf[nt][1] = b.y;
            }
#pragma unroll
            for (int mt = 0; mt < 4; mt++)
#pragma unroll
                for (int nt = 0; nt < 8; nt++)
                    mma_f16(acc[mt][nt], af[mt], bf[nt]);
        }
        __syncthreads();

        if (it + NSTG < NIT)
            load_stage_h(A, Bt, brow, bcol, (it + NSTG) * BKU, sA[s], sB[s], tid);
    }
}

// final GEMM: fp32 output + bias
__global__ __launch_bounds__(256) void gemm_mma_k(
    const uint32_t* __restrict__ A, const uint32_t* __restrict__ Bt,
    const float* __restrict__ bias, float* __restrict__ C)
{
    extern __shared__ uint32_t dsm_u[];
    const int tid = threadIdx.x;
    const int wid = tid >> 5;
    const int lane = tid & 31;
    const int lr = lane >> 2, lc = lane & 3;
    const int wm = (wid >> 2) * 64, wn = (wid & 3) * 64;
    int brow = blockIdx.y * BM, bcol = blockIdx.x * BN;

    float acc[4][8][4];
#pragma unroll
    for (int mt = 0; mt < 4; mt++)
#pragma unroll
        for (int nt = 0; nt < 8; nt++)
#pragma unroll
            for (int r = 0; r < 4; r++) acc[mt][nt][r] = 0.f;

    gemm_mainloop(A, Bt, dsm_u, acc, brow, bcol, tid, wm, wn, lr, lc);

#pragma unroll
    for (int nt = 0; nt < 8; nt++) {
        int col = bcol + wn + nt * 8 + 2 * lc;
        float b0 = bias[col], b1 = bias[col + 1];
#pragma unroll
        for (int mt = 0; mt < 4; mt++) {
            int row = brow + wm + mt * 16 + lr;
            float2 v0 = make_float2(acc[mt][nt][0] + b0, acc[mt][nt][1] + b1);
            float2 v1 = make_float2(acc[mt][nt][2] + b0, acc[mt][nt][3] + b1);
            *(float2*)&C[(size_t)row * EMBD + col] = v0;
            *(float2*)&C[(size_t)(row + 8) * EMBD + col] = v1;
        }
    }
}

// QKV GEMM: fused bias + rope (z<2) + fp16 pack
__global__ __launch_bounds__(256) void gemm_qkv_k(
    const uint32_t* __restrict__ A, const uint32_t* __restrict__ WtBase,
    const float* __restrict__ bq, const float* __restrict__ bk,
    const float* __restrict__ bv,
    uint32_t* __restrict__ qh, uint32_t* __restrict__ kh, uint32_t* __restrict__ vh,
    const float* __restrict__ cost, const float* __restrict__ sint)
{
    extern __shared__ uint32_t dsm_u[];
    const int tid = threadIdx.x;
    const int wid = tid >> 5;
    const int lane = tid & 31;
    const int lr = lane >> 2, lc = lane & 3;
    const int wm = (wid >> 2) * 64, wn = (wid & 3) * 64;
    int brow = blockIdx.y * BM, bcol = blockIdx.x * BN;

    int z = blockIdx.z;
    const uint32_t* Bt = WtBase + (size_t)z * EMBD * EMBD_U;
    const float* bias = (z == 0) ? bq : (z == 1) ? bk : bv;
    uint32_t* Ch = (z == 0) ? qh : (z == 1) ? kh : vh;
    bool dorope = (z < 2);

    float acc[4][8][4];
#pragma unroll
    for (int mt = 0; mt < 4; mt++)
#pragma unroll
        for (int nt = 0; nt < 8; nt++)
#pragma unroll
            for (int r = 0; r < 4; r++) acc[mt][nt][r] = 0.f;

    gemm_mainloop(A, Bt, dsm_u, acc, brow, bcol, tid, wm, wn, lr, lc);

#pragma unroll
    for (int nt = 0; nt < 8; nt++) {
        int col = bcol + wn + nt * 8 + 2 * lc;
        int pi = col >> 1;
        float b0 = bias[col], b1 = bias[col + 1];
#pragma unroll
        for (int mt = 0; mt < 4; mt++) {
#pragma unroll
            for (int h = 0; h < 2; h++) {
                int row = brow + wm + mt * 16 + lr + h * 8;
                float a0 = acc[mt][nt][2 * h + 0] + b0;
                float a1 = acc[mt][nt][2 * h + 1] + b1;
                if (dorope) {
                    int t = row & (SEQ - 1);
                    float c = cost[(size_t)t * 1024 + pi];
                    float s = sint[(size_t)t * 1024 + pi];
                    float r0 = a0 * c - a1 * s;
                    float r1 = a0 * s + a1 * c;
                    a0 = r0; a1 = r1;
                }
                Ch[(size_t)row * EMBD_U + pi] = packh2(a0, a1);
            }
        }
    }
}

// ============================================================================
// K2b: fp16 v -> fp16 transposed per segment (pairs along l)
// ============================================================================
__global__ __launch_bounds__(256) void vt_h_k(const uint32_t* __restrict__ vh,
                                              uint32_t* __restrict__ vth)
{
    __shared__ float t[32][68];
    int bhs = blockIdx.z;
    int p0 = blockIdx.x * 32;
    int l0 = blockIdx.y * 32;
    const uint32_t* seg = vh + ((size_t)bhs << 15);
    uint32_t* vtseg = vth + (size_t)bhs * DHEAD * SEGL_U;
    int txx = threadIdx.x, ty = threadIdx.y;
    for (int i = ty; i < 32; i += 8) {
        __half2 h = *(const __half2*)&seg[(size_t)(l0 + i) * 64 + p0 + txx];
        t[i][2 * txx] = __low2float(h);
        t[i][2 * txx + 1] = __high2float(h);
    }
    __syncthreads();
    int tid = ty * 32 + txx;
#pragma unroll
    for (int j = 0; j < 4; j++) {
        int flat = tid + j * 256;
        int d = flat >> 4, c = flat & 15;
        vtseg[(size_t)(2 * p0 + d) * SEGL_U + (l0 >> 1) + c] =
            packh2(t[2 * c][d], t[2 * c + 1][d]);
    }
}

// ============================================================================
// K2c: sk^T = elu1(fp16 k)^T fp16 per segment (pairs along l)
// ============================================================================
__global__ __launch_bounds__(256) void skt_h_k(const uint32_t* __restrict__ kh,
                                               uint32_t* __restrict__ skth)
{
    __shared__ float t[32][68];
    int bhs = blockIdx.z;
    int p0 = blockIdx.x * 32;
    int l0 = blockIdx.y * 32;
    const uint32_t* seg = kh + ((size_t)bhs << 15);
    uint32_t* sktseg = skth + (size_t)bhs * DHEAD * SEGL_U;
    int txx = threadIdx.x, ty = threadIdx.y;
    for (int i = ty; i < 32; i += 8) {
        __half2 h = *(const __half2*)&seg[(size_t)(l0 + i) * 64 + p0 + txx];
        t[i][2 * txx] = __low2float(h);
        t[i][2 * txx + 1] = __high2float(h);
    }
    __syncthreads();
    int tid = ty * 32 + txx;
#pragma unroll
    for (int j = 0; j < 4; j++) {
        int flat = tid + j * 256;
        int d = flat >> 4, c = flat & 15;
        sktseg[(size_t)(2 * p0 + d) * SEGL_U + (l0 >> 1) + c] =
            packh2(elu1(t[2 * c][d]), elu1(t[2 * c + 1][d]));
    }
}

// ============================================================================
// K2d: Zseg[bhs][d] = row-sum of skth
// ============================================================================
__global__ __launch_bounds__(256) void zsum_k(const uint32_t* __restrict__ skth,
                                              float* __restrict__ Zseg)
{
    int bhs = blockIdx.x;
    int tid = threadIdx.x;
    int d = tid >> 1;
    int half = tid & 1;
    const uint32_t* row = skth + (size_t)bhs * DHEAD * SEGL_U
                        + (size_t)d * SEGL_U + half * 128;
    float s = 0.f;
#pragma unroll 16
    for (int j = 0; j < 128; j++) {
        __half2 h = *(const __half2*)&row[j];
        s += __low2float(h) + __high2float(h);
    }
    s += __shfl_xor_sync(0xffffffffu, s, 1);
    if (half == 0) Zseg[bhs * DHEAD + d] = s;
}

// ============================================================================
// K3: FUSED flash attention + A_mem + combine:  (fattn + amem in one kernel)
//     attnh = permcvt( g*(sq@memT^T)/(rs*Z+eps) + (1-g)*softmax(qk^T)v )
// ============================================================================
#define SCP 68
#define AMP 136
// u32 layout: qs[0,8704) | ks/aq[8704,17408)/aq..26112 | Ps[17408,26112) | vs/ms[26112,43520)
#define FAM_U32 (43520 + 1536)
#define FAM_SMEM_BYTES (FAM_U32 * 4)   // 180224

__global__ __launch_bounds__(256, 1) void fam_k(
    const uint32_t* __restrict__ qh, const uint32_t* __restrict__ kh,
    const uint32_t* __restrict__ vth, const float* __restrict__ memsegT,
    const float* __restrict__ Zseg, const float* __restrict__ beta,
    uint32_t* __restrict__ attnh)
{
    extern __shared__ uint32_t smu[];
    uint32_t* qs = smu;                       // [128][SCP] fp16 q
    uint32_t* ks = smu + 128 * SCP;           // flash k tile
    uint32_t* Ps = smu + 2 * 128 * SCP;       // flash P tile
    uint32_t* vs = smu + 3 * 128 * SCP;       // flash v tile
    uint32_t* aq = smu + 128 * SCP;           // amem: tf32 elu1(q) [128][AMP] (overlays ks+Ps)
    uint32_t* ms = smu + 3 * 128 * SCP;       // amem: tf32 memT [128][AMP] (overlays vs + ext)
    float* pmax = (float*)(smu + 43520);      // [4][128]
    float* psum = pmax + 4 * 128;             // [4][128]
    float* m_s = psum + 4 * 128;              // [128]
    float* f_s = m_s + 128;                   // [128]
    float* ssum_s = f_s + 128;                // [128]
    float* Zs = ssum_s + 128;                 // [128]

    uint32_t sq = smem_u32(qs);
    uint32_t sk = smem_u32(ks);
    uint32_t sv = smem_u32(vs);
    uint32_t smb = smem_u32(ms);

    const float scale = 0.08838834764831845f;
    const int tid = threadIdx.x;
    const int wid = tid >> 5;
    const int lane = tid & 31;
    const int lr = lane >> 2;
    const int lc = lane & 3;
    const int wm = (wid >> 2) * 64;
    const int wn = (wid & 3) * 32;
    const int wci = wid & 3;

    int bhs = blockIdx.y;
    int l0 = blockIdx.x * 128;
    size_t segbase_u = ((size_t)bhs) << 15;
    const uint32_t* qseg = qh + segbase_u;
    const uint32_t* kseg = kh + segbase_u;
    const uint32_t* vtseg = vth + (size_t)bhs * DHEAD * SEGL_U;
    const float* memb = memsegT + (size_t)bhs * DHEAD * DHEAD;
    float g = 1.0f / (1.0f + expf(-beta[0]));
    float gm1 = 1.0f - g;

    // load q tile once
#pragma unroll
    for (int it = 0; it < 8; it++) {
        int idx = tid + it * 256;
        int row = idx >> 4, c4 = idx & 15;
        cp16(sq + (row * SCP + c4 * 4) * 4,
             qseg + (size_t)(l0 + row) * 64 + c4 * 4);
    }
    asm volatile("cp.async.commit_group;" ::: "memory");

    if (tid < 128) { m_s[tid] = -1e30f; ssum_s[tid] = 0.f; }

    float Oacc[4][4][4];
#pragma unroll
    for (int mt = 0; mt < 4; mt++)
#pragma unroll
        for (int nt = 0; nt < 4; nt++)
#pragma unroll
            for (int r = 0; r < 4; r++) Oacc[mt][nt][r] = 0.f;

    // ---------------- flash phase (4 k-tiles, online softmax) ----------------
    for (int kt = 0; kt < 4; kt++) {
#pragma unroll
        for (int it = 0; it < 8; it++) {
            int idx = tid + it * 256;
            int row = idx >> 4, c4 = idx & 15;
            cp16(sk + (row * SCP + c4 * 4) * 4,
                 kseg + (size_t)(kt * 128 + row) * 64 + c4 * 4);
        }
#pragma unroll
        for (int it = 0; it < 8; it++) {
            int idx = tid + it * 256;
            int row = idx >> 4, c4 = idx & 15;
            cp16(sv + (row * SCP + c4 * 4) * 4,
                 vtseg + (size_t)row * SEGL_U + kt * 64 + c4 * 4);
        }
        asm volatile("cp.async.commit_group;" ::: "memory");
        asm volatile("cp.async.wait_group 0;" ::: "memory");
        __syncthreads();

        float Sacc[4][4][4];
#pragma unroll
        for (int mt = 0; mt < 4; mt++)
#pragma unroll
            for (int nt = 0; nt < 4; nt++)
#pragma unroll
                for (int r = 0; r < 4; r++) Sacc[mt][nt][r] = 0.f;

#pragma unroll
        for (int kb = 0; kb < 64; kb += 8) {
            uint32_t af[4][4], bf[4][2];
#pragma unroll
            for (int mt = 0; mt < 4; mt++) {
                int r = wm + mt * 16 + lr;
                af[mt][0] = qs[r * SCP + kb + lc];
                af[mt][1] = qs[(r + 8) * SCP + kb + lc];
                af[mt][2] = qs[r * SCP + kb + lc + 4];
                af[mt][3] = qs[(r + 8) * SCP + kb + lc + 4];
            }
#pragma unroll
            for (int nt = 0; nt < 4; nt++) {
                int cN = wn + nt * 8 + lr;
                bf[nt][0] = ks[cN * SCP + kb + lc];
                bf[nt][1] = ks[cN * SCP + kb + lc + 4];
            }
#pragma unroll
            for (int mt = 0; mt < 4; mt++)
#pragma unroll
                for (int nt = 0; nt < 4; nt++)
                    mma_f16(Sacc[mt][nt], af[mt], bf[nt]);
        }
#pragma unroll
        for (int mt = 0; mt < 4; mt++)
#pragma unroll
            for (int nt = 0; nt < 4; nt++)
#pragma unroll
                for (int r = 0; r < 4; r++) Sacc[mt][nt][r] *= scale;

#pragma unroll
        for (int mt = 0; mt < 4; mt++) {
#pragma unroll
            for (int h = 0; h < 2; h++) {
                float mv = -1e30f;
#pragma unroll
                for (int nt = 0; nt < 4; nt++) {
                    mv = fmaxf(mv, Sacc[mt][nt][2 * h]);
                    mv = fmaxf(mv, Sacc[mt][nt][2 * h + 1]);
                }
                mv = fmaxf(mv, __shfl_xor_sync(0xffffffffu, mv, 1));
                mv = fmaxf(mv, __shfl_xor_sync(0xffffffffu, mv, 2));
                if (lc == 0) pmax[wci * 128 + wm + mt * 16 + lr + h * 8] = mv;
            }
        }
        __syncthreads();

        if (tid < 128) {
            float mo = m_s[tid];
            float nm = fmaxf(fmaxf(pmax[tid], pmax[128 + tid]),
                             fmaxf(pmax[256 + tid], pmax[384 + tid]));
            float mn = fmaxf(mo, nm);
            float f = expf(mo - mn);
            m_s[tid] = mn;
            f_s[tid] = f;
            ssum_s[tid] *= f;
        }
        __syncthreads();

#pragma unroll
        for (int mt = 0; mt < 4; mt++) {
#pragma unroll
            for (int h = 0; h < 2; h++) {
                int row = wm + mt * 16 + lr + h * 8;
                float m = m_s[row];
                float f = f_s[row];
                float rsum = 0.f;
#pragma unroll
                for (int nt = 0; nt < 4; nt++) {
                    float p0 = expf(Sacc[mt][nt][2 * h] - m);
                    float p1 = expf(Sacc[mt][nt][2 * h + 1] - m);
                    rsum += p0 + p1;
                    Ps[row * SCP + (wn >> 1) + nt * 4 + lc] = packh2(p0, p1);
                    Oacc[mt][nt][2 * h] *= f;
                    Oacc[mt][nt][2 * h + 1] *= f;
                }
                rsum += __shfl_xor_sync(0xffffffffu, rsum, 1);
                rsum += __shfl_xor_sync(0xffffffffu, rsum, 2);
                if (lc == 0) psum[wci * 128 + row] = rsum;
            }
        }
        __syncthreads();

        if (tid < 128)
            ssum_s[tid] += psum[tid] + psum[128 + tid] + psum[256 + tid] + psum[384 + tid];

#pragma unroll
        for (int kb = 0; kb < 64; kb += 8) {
            uint32_t af[4][4], bf[4][2];
#pragma unroll
            for (int mt = 0; mt < 4; mt++) {
                int r = wm + mt * 16 + lr;
                af[mt][0] = Ps[r * SCP + kb + lc];
                af[mt][1] = Ps[(r + 8) * SCP + kb + lc];
                af[mt][2] = Ps[r * SCP + kb + lc + 4];
                af[mt][3] = Ps[(r + 8) * SCP + kb + lc + 4];
            }
#pragma unroll
            for (int nt = 0; nt < 4; nt++) {
                int cN = wn + nt * 8 + lr;
                bf[nt][0] = vs[cN * SCP + kb + lc];
                bf[nt][1] = vs[cN * SCP + kb + lc + 4];
            }
#pragma unroll
            for (int mt = 0; mt < 4; mt++)
#pragma unroll
                for (int nt = 0; nt < 4; nt++)
                    mma_f16(Oacc[mt][nt], af[mt], bf[nt]);
        }
        __syncthreads();
    }

    // ---------------- amem phase (reuses smem: aq over ks/Ps, ms over vs) ----
    // stage memT tile via cp.async (fp32 128x128)
#pragma unroll
    for (int it = 0; it < 16; it++) {
        int idx = tid + it * 256;
        int row = idx >> 5, c4 = idx & 31;
        cp16(smb + (row * AMP + c4 * 4) * 4,
             memb + (size_t)row * DHEAD + c4 * 4);
    }
    asm volatile("cp.async.commit_group;" ::: "memory");

    // build aq: tf32(elu1(q)) from resident fp16 qs
#pragma unroll
    for (int it = 0; it < 32; it++) {
        int flat = it * 256 + tid;
        int row = flat >> 6, col = flat & 63;
        __half2 h = *(const __half2*)&qs[row * SCP + col];
        aq[row * AMP + 2 * col]     = f2tf32(elu1(__low2float(h)));
        aq[row * AMP + 2 * col + 1] = f2tf32(elu1(__high2float(h)));
    }
    asm volatile("cp.async.wait_group 0;" ::: "memory");
    __syncthreads();

    // rowsum of aq + convert ms fp32 -> tf32
    {
        int r = tid >> 1;
        int half = (tid & 1) * 64;
        float partial = 0.f;
#pragma unroll 16
        for (int j = 0; j < 64; j++)
            partial += __uint_as_float(aq[r * AMP + half + j]);
        partial += __shfl_xor_sync(0xffffffffu, partial, 1);
        if ((tid & 1) == 0) pmax[r] = partial;   // reuse pmax as rowsum
#pragma unroll 16
        for (int j = 0; j < 64; j++) {
            uint32_t* p = &ms[r * AMP + half + j];
            *p = f2tf32(__uint_as_float(*p));
        }
    }
    if (tid < 128) Zs[tid] = Zseg[bhs * DHEAD + tid];
    __syncthreads();

    float acc[4][4][4];
#pragma unroll
    for (int mt = 0; mt < 4; mt++)
#pragma unroll
        for (int nt = 0; nt < 4; nt++)
#pragma unroll
            for (int r = 0; r < 4; r++) acc[mt][nt][r] = 0.f;

#pragma unroll
    for (int kb = 0; kb < 128; kb += 8) {
        uint32_t af[4][4], bf[4][2];
#pragma unroll
        for (int mt = 0; mt < 4; mt++) {
            int r = wm + mt * 16 + lr;
            af[mt][0] = aq[r * AMP + kb + lc];
            af[mt][1] = aq[(r + 8) * AMP + kb + lc];
            af[mt][2] = aq[r * AMP + kb + lc + 4];
            af[mt][3] = aq[(r + 8) * AMP + kb + lc + 4];
        }
#pragma unroll
        for (int nt = 0; nt < 4; nt++) {
            int cN = wn + nt * 8 + lr;
            bf[nt][0] = ms[cN * AMP + kb + lc];
            bf[nt][1] = ms[cN * AMP + kb + lc + 4];
        }
#pragma unroll
        for (int mt = 0; mt < 4; mt++)
#pragma unroll
            for (int nt = 0; nt < 4; nt++)
                mma_tf32(acc[mt][nt], af[mt], bf[nt]);
    }

    // fused epilogue: combine both terms, pack permuted fp16
#pragma unroll
    for (int nt = 0; nt < 4; nt++) {
        int col = wn + nt * 8 + 2 * lc;
        int j = (col & 15) >> 1;
        int pos = (col >> 4) * 8 + pposu(j);
        float Z0 = Zs[col], Z1 = Zs[col + 1];
#pragma unroll
        for (int mt = 0; mt < 4; mt++) {
#pragma unroll
            for (int h = 0; h < 2; h++) {
                int rloc = wm + mt * 16 + lr + h * 8;
                int row = l0 + rloc;
                float rs = pmax[rloc];             // rowsum
                float sc = gm1 / ssum_s[rloc];
                float a0 = g * acc[mt][nt][2 * h + 0] / (rs * Z0 + 1e-6f)
                         + Oacc[mt][nt][2 * h + 0] * sc;
                float a1 = g * acc[mt][nt][2 * h + 1] / (rs * Z1 + 1e-6f)
                         + Oacc[mt][nt][2 * h + 1] * sc;
                attnh[segbase_u + (size_t)row * (DHEAD / 2) + pos] = packh2(a0, a1);
            }
        }
    }
}

// ============================================================================
// K6: tensorized outer products: memT[e][d] = sum_l v[l][e] * sk[l][d]
// ============================================================================
#define PVP 36
#define OUTER_SMEM_BYTES (2 * 2 * 128 * PVP * 4)

__global__ __launch_bounds__(256) void outer_mma_k(
    const uint32_t* __restrict__ vth, const uint32_t* __restrict__ skth,
    float* __restrict__ memsegT)
{
    extern __shared__ uint32_t smu[];
    uint32_t* Ash = smu;
    uint32_t* Bsh = smu + 2 * 128 * PVP;
    uint32_t sAu = smem_u32(Ash);
    uint32_t sBu = smem_u32(Bsh);

    const int tid = threadIdx.x;
    const int wid = tid >> 5;
    const int lane = tid & 31;
    const int lr = lane >> 2;
    const int lc = lane & 3;
    const int wm = (wid >> 2) * 64;
    const int wn = (wid & 3) * 32;

    int bhs = blockIdx.x;
    const uint32_t* vtseg = vth + (size_t)bhs * DHEAD * SEGL_U;
    const uint32_t* sktseg = skth + (size_t)bhs * DHEAD * SEGL_U;

    float acc[4][4][4];
#pragma unroll
    for (int mt = 0; mt < 4; mt++)
#pragma unroll
        for (int nt = 0; nt < 4; nt++)
#pragma unroll
            for (int r = 0; r < 4; r++) acc[mt][nt][r] = 0.f;

    auto load_st = [&](int k0u, uint32_t sA, uint32_t sB) {
#pragma unroll
        for (int it = 0; it < 4; it++) {
            int idx = tid + it * 256;
            int row = idx >> 3, c4 = idx & 7;
            cp16(sA + (row * PVP + c4 * 4) * 4,
                 vtseg + (size_t)row * SEGL_U + k0u + c4 * 4);
        }
#pragma unroll
        for (int it = 0; it < 4; it++) {
            int idx = tid + it * 256;
            int row = idx >> 3, c4 = idx & 7;
            cp16(sB + (row * PVP + c4 * 4) * 4,
                 sktseg + (size_t)row * SEGL_U + k0u + c4 * 4);
        }
        asm volatile("cp.async.commit_group;" ::: "memory");
    };

    load_st(0, sAu, sBu);
    load_st(32, sAu + 128 * PVP * 4, sBu + 128 * PVP * 4);

    const int NIT = SEGL_U / 32;
    for (int it = 0; it < NIT; it++) {
        int s = it & 1;
        if (it == NIT - 1) asm volatile("cp.async.wait_group 0;" ::: "memory");
        else               asm volatile("cp.async.wait_group 1;" ::: "memory");
        __syncthreads();

        const uint32_t* As = Ash + s * 128 * PVP;
        const uint32_t* Bs = Bsh + s * 128 * PVP;
#pragma unroll
        for (int kb = 0; kb < 32; kb += 8) {
            uint32_t af[4][4], bf[4][2];
#pragma unroll
            for (int mt = 0; mt < 4; mt++) {
                int r = wm + mt * 16 + lr;
                af[mt][0] = As[r * PVP + kb + lc];
                af[mt][1] = As[(r + 8) * PVP + kb + lc];
                af[mt][2] = As[r * PVP + kb + lc + 4];
                af[mt][3] = As[(r + 8) * PVP + kb + lc + 4];
            }
#pragma unroll
            for (int nt = 0; nt < 4; nt++) {
                int cN = wn + nt * 8 + lr;
                bf[nt][0] = Bs[cN * PVP + kb + lc];
                bf[nt][1] = Bs[cN * PVP + kb + lc + 4];
            }
#pragma unroll
            for (int mt = 0; mt < 4; mt++)
#pragma unroll
                for (int nt = 0; nt < 4; nt++)
                    mma_f16(acc[mt][nt], af[mt], bf[nt]);
        }
        __syncthreads();
        if (it + 2 < NIT)
            load_st((it + 2) * 32, sAu + s * 128 * PVP * 4, sBu + s * 128 * PVP * 4);
    }

    float* memb = memsegT + (size_t)bhs * DHEAD * DHEAD;
#pragma unroll
    for (int nt = 0; nt < 4; nt++) {
        int col = wn + nt * 8 + 2 * lc;
#pragma unroll
        for (int mt = 0; mt < 4; mt++) {
            int row = wm + mt * 16 + lr;
            *(float2*)&memb[(size_t)row * DHEAD + col] =
                make_float2(acc[mt][nt][0], acc[mt][nt][1]);
            *(float2*)&memb[(size_t)(row + 8) * DHEAD + col] =
                make_float2(acc[mt][nt][2], acc[mt][nt][3]);
        }
    }
}

// ============================================================================
// K7: in-place exclusive prefix over the 8 segments
// ============================================================================
__global__ __launch_bounds__(256) void prefix_mem_k(float* __restrict__ memseg)
{
    size_t idx = (size_t)blockIdx.x * 256 + threadIdx.x;
    int bh = (int)(idx >> 14);
    int off = (int)(idx & 16383);
    size_t base = ((size_t)bh * NSEG) * 16384 + off;
    float run = 0.f;
#pragma unroll
    for (int s = 0; s < NSEG; s++) {
        float t = memseg[base + (size_t)s * 16384];
        memseg[base + (size_t)s * 16384] = run;
        run += t;
    }
}

__global__ __launch_bounds__(256) void prefix_Z_k(float* __restrict__ Zseg)
{
    int idx = blockIdx.x * 256 + threadIdx.x;
    int bh = idx >> 7;
    int d = idx & 127;
    int base = bh * NSEG * DHEAD + d;
    float run = 0.f;
#pragma unroll
    for (int s = 0; s < NSEG; s++) {
        float t = Zseg[base + s * DHEAD];
        Zseg[base + s * DHEAD] = run;
        run += t;
    }
}

// ============================================================================
// Host launch
// ============================================================================
extern "C" void kernel_launch(void* const* d_in, const int* in_sizes, int n_in,
                              void* d_out, int out_size)
{
    (void)in_sizes; (void)n_in; (void)out_size;
    const float* x    = (const float*)d_in[0];
    const float* Wq   = (const float*)d_in[1];
    const float* bq   = (const float*)d_in[2];
    const float* Wk   = (const float*)d_in[3];
    const float* bk   = (const float*)d_in[4];
    const float* Wv   = (const float*)d_in[5];
    const float* bv   = (const float*)d_in[6];
    const float* Wo   = (const float*)d_in[7];
    const float* bo   = (const float*)d_in[8];
    const float* beta = (const float*)d_in[9];
    float* out = (float*)d_out;

    static float *pmemsegT = nullptr, *pZseg = nullptr, *pcost = nullptr, *psint = nullptr;
    static uint32_t *pWth = nullptr, *pxh = nullptr, *pattnh = nullptr,
                    *pqh = nullptr, *pkh = nullptr, *pvh = nullptr,
                    *pvth = nullptr, *pskth = nullptr;
    if (!pWth) {
        cudaGetSymbolAddress((void**)&pmemsegT, g_memsegT);
        cudaGetSymbolAddress((void**)&pZseg, g_Zseg);
        cudaGetSymbolAddress((void**)&pWth, g_Wth);
        cudaGetSymbolAddress((void**)&pxh, g_xh);
        cudaGetSymbolAddress((void**)&pattnh, g_attnh);
        cudaGetSymbolAddress((void**)&pqh, g_qh);
        cudaGetSymbolAddress((void**)&pkh, g_kh);
        cudaGetSymbolAddress((void**)&pvh, g_vh);
        cudaGetSymbolAddress((void**)&pvth, g_vth);
        cudaGetSymbolAddress((void**)&pskth, g_skth);
        cudaGetSymbolAddress((void**)&pcost, g_cost);
        cudaGetSymbolAddress((void**)&psint, g_sint);
        cudaFuncSetAttribute(gemm_mma_k, cudaFuncAttributeMaxDynamicSharedMemorySize,
                             GEMM_SMEM_BYTES);
        cudaFuncSetAttribute(gemm_qkv_k, cudaFuncAttributeMaxDynamicSharedMemorySize,
                             GEMM_SMEM_BYTES);
        cudaFuncSetAttribute(fam_k, cudaFuncAttributeMaxDynamicSharedMemorySize,
                             FAM_SMEM_BYTES);
        cudaFuncSetAttribute(outer_mma_k, cudaFuncAttributeMaxDynamicSharedMemorySize,
                             OUTER_SMEM_BYTES);
    }

    const size_t WSZ_U = (size_t)EMBD * EMBD_U;
    dim3 tgrid(EMBD / 32, EMBD / 32);
    dim3 tblk(32, 8);
    transpose_fp16_k<<<tgrid, tblk>>>(Wq, pWth + 0 * WSZ_U);
    transpose_fp16_k<<<tgrid, tblk>>>(Wk, pWth + 1 * WSZ_U);
    transpose_fp16_k<<<tgrid, tblk>>>(Wv, pWth + 2 * WSZ_U);
    transpose_fp16_k<<<tgrid, tblk>>>(Wo, pWth + 3 * WSZ_U);

    perm_cvt_fp16_k<<<(int)(TOTAL / 16 / 256), 256>>>(x, pxh);
    rope_tab_k<<<(SEQ * 1024) / 256, 256>>>(pcost, psint);

    // QKV GEMM with fused rope + fp16 pack
    dim3 qkvgrid(EMBD / BN, MTOK / BM, 3);
    gemm_qkv_k<<<qkvgrid, 256, GEMM_SMEM_BYTES>>>(pxh, pWth, bq, bk, bv,
                                                  pqh, pkh, pvh, pcost, psint);

    vt_h_k<<<dim3(2, SEGL / 32, NBH * NSEG), tblk>>>(pvh, pvth);
    skt_h_k<<<dim3(2, SEGL / 32, NBH * NSEG), tblk>>>(pkh, pskth);

    // parallel linear-memory path (tensorized)
    outer_mma_k<<<NBH * NSEG, 256, OUTER_SMEM_BYTES>>>(pvth, pskth, pmemsegT);
    zsum_k<<<NBH * NSEG, 256>>>(pskth, pZseg);
    prefix_mem_k<<<(NBH * 16384) / 256, 256>>>(pmemsegT);
    prefix_Z_k<<<(NBH * DHEAD) / 256, 256>>>(pZseg);

    // fused flash attention + A_mem + combine, fp16-permuted output
    fam_k<<<dim3(SEGL / 128, NBH * NSEG), 256, FAM_SMEM_BYTES>>>(
        pqh, pkh, pvth, pmemsegT, pZseg, beta, pattnh);

    gemm_mma_k<<<dim3(EMBD / BN, MTOK / BM), 256, GEMM_SMEM_BYTES>>>(
        pattnh, pWth + 3 * WSZ_U, bo, out);
}